// round 9
// baseline (speedup 1.0000x reference)
#include <cuda_runtime.h>
#include <cuda_bf16.h>
#include <math.h>
#include <stdint.h>

// ---------------- problem constants ----------------
#define D_MODEL 1024
#define NHEAD   16
#define DHEAD   64
#define FF_DIM  4096
#define NSEQ    256
#define NB      4
#define NTOK    50257
#define NEXP    2000
#define NKTOP   20
#define NROWS   (NB*NSEQ)      // 1024
#define QKV_LD  3072
#define NBLK_V  393            // ceil(50257/128)

#define RW 20                  // smem row width in words (bank-conflict pad)
#define BF_DSM_WORDS (3*128*RW)            // per matrix
#define BF_DSM_BYTES (2*BF_DSM_WORDS*4)    // 61440

// ---------------- scratch (static device memory; no allocation) ----------------
__device__ float g_x    [NROWS*D_MODEL];
__device__ float g_qkv  [NROWS*QKV_LD];
__device__ float g_tmp  [NROWS*D_MODEL];
__device__ float g_sm_attn[NB*D_MODEL];
__device__ float g_sm_x   [NB*D_MODEL];
__device__ float g_sm_tmp [NB*D_MODEL];
__device__ float g_sm_ctx [NB*D_MODEL];
__device__ float g_sm_ffh [NB*FF_DIM];
__device__ float g_pmax[NROWS*NBLK_V];
__device__ float g_psum[NROWS*NBLK_V];
__device__ float g_lse [NROWS];
__device__ float g_lab [NB*(NSEQ-1)];
__device__ float g_stats[32];   // [0..19] jw, [20] imp

// bf16 weight/activation mirrors
__device__ __align__(256) __nv_bfloat16 h_dec [NTOK*D_MODEL];
__device__ __align__(256) __nv_bfloat16 h_Wqkv[2*QKV_LD*D_MODEL];
__device__ __align__(256) __nv_bfloat16 h_Wo  [2*D_MODEL*D_MODEL];
__device__ __align__(256) __nv_bfloat16 h_W1  [2*FF_DIM*D_MODEL];
__device__ __align__(256) __nv_bfloat16 h_W2  [2*D_MODEL*FF_DIM];
__device__ __align__(256) __nv_bfloat16 h_x   [NROWS*D_MODEL];
__device__ __align__(256) __nv_bfloat16 h_attn[NROWS*D_MODEL];
__device__ __align__(256) __nv_bfloat16 h_ffh [NROWS*FF_DIM];

// ---------------- fp32 -> bf16 conversion (2x float4 per thread) ----------------
__global__ void f2h_kernel(const float* __restrict__ src, __nv_bfloat16* __restrict__ dst, int n4)
{
    int i = (blockIdx.x*blockDim.x + threadIdx.x) * 2;
    #pragma unroll
    for (int t = 0; t < 2; t++) {
        int j = i + t;
        if (j < n4) {
            float4 v = ((const float4*)src)[j];
            ((__nv_bfloat162*)dst)[2*j+0] = __floats2bfloat162_rn(v.x, v.y);
            ((__nv_bfloat162*)dst)[2*j+1] = __floats2bfloat162_rn(v.z, v.w);
        }
    }
}

// ---------------- embedding gather ----------------
__global__ void embed_kernel(const int* __restrict__ inputs, const float* __restrict__ emb)
{
    int r = blockIdx.x;
    int tok = inputs[r];
    const float4* src = (const float4*)(emb + (size_t)tok * D_MODEL);
    float4* dst = (float4*)(g_x + (size_t)r * D_MODEL);
    dst[threadIdx.x] = src[threadIdx.x];
}

// ================= cp.async / ldmatrix helpers =================
__device__ __forceinline__ void cp_async16(void* smem, const void* gmem)
{
    uint32_t s = (uint32_t)__cvta_generic_to_shared(smem);
    asm volatile("cp.async.ca.shared.global [%0], [%1], 16;\n" :: "r"(s), "l"(gmem));
}
__device__ __forceinline__ void cp_commit()
{
    asm volatile("cp.async.commit_group;\n" ::: "memory");
}
template<int N> __device__ __forceinline__ void cp_wait()
{
    asm volatile("cp.async.wait_group %0;\n" :: "n"(N) : "memory");
}
__device__ __forceinline__ void ldsm_x4(uint32_t& r0, uint32_t& r1, uint32_t& r2, uint32_t& r3,
                                        const void* smem)
{
    uint32_t a = (uint32_t)__cvta_generic_to_shared(smem);
    asm volatile("ldmatrix.sync.aligned.m8n8.x4.shared.b16 {%0,%1,%2,%3}, [%4];\n"
                 : "=r"(r0), "=r"(r1), "=r"(r2), "=r"(r3) : "r"(a));
}
__device__ __forceinline__ void ldsm_x2(uint32_t& r0, uint32_t& r1, const void* smem)
{
    uint32_t a = (uint32_t)__cvta_generic_to_shared(smem);
    asm volatile("ldmatrix.sync.aligned.m8n8.x2.shared.b16 {%0,%1}, [%2];\n"
                 : "=r"(r0), "=r"(r1) : "r"(a));
}

// ================= tf32 GEMM (loc KV path only) =================
__device__ __forceinline__ void mma_mainloop(
    float acc[4][4][4],
    const float* __restrict__ A, const float* __restrict__ W,
    int K, int m0, int n0)
{
    __shared__ uint32_t As[2][128][20];
    __shared__ uint32_t Bs[2][128][20];
    int tid  = threadIdx.x;
    int lane = tid & 31, wid = tid >> 5;
    int wm = wid >> 2, wn = wid & 3;
    int g = lane >> 2, tig = lane & 3;

    int r0c = tid >> 2,         c0c = (tid & 3) << 2;
    int r1c = (tid + 256) >> 2, c1c = (tid & 3) << 2;
    const float* pa0 = A + (size_t)(m0 + r0c)*K + c0c;
    const float* pa1 = A + (size_t)(m0 + r1c)*K + c1c;
    const float* pb0 = W + (size_t)(n0 + r0c)*K + c0c;
    const float* pb1 = W + (size_t)(n0 + r1c)*K + c1c;

    int niter = K >> 4;
    cp_async16(&As[0][r0c][c0c], pa0);
    cp_async16(&As[0][r1c][c1c], pa1);
    cp_async16(&Bs[0][r0c][c0c], pb0);
    cp_async16(&Bs[0][r1c][c1c], pb1);
    cp_commit();

    for (int it = 0; it < niter; it++) {
        int st = it & 1;
        if (it + 1 < niter) {
            int off = (it + 1) << 4;
            int sn = st ^ 1;
            cp_async16(&As[sn][r0c][c0c], pa0 + off);
            cp_async16(&As[sn][r1c][c1c], pa1 + off);
            cp_async16(&Bs[sn][r0c][c0c], pb0 + off);
            cp_async16(&Bs[sn][r1c][c1c], pb1 + off);
            cp_commit();
            cp_wait<1>();
        } else {
            cp_wait<0>();
        }
        __syncthreads();
        #pragma unroll
        for (int ks = 0; ks < 16; ks += 8) {
            uint32_t af[4][4], bf[4][2];
            #pragma unroll
            for (int mt = 0; mt < 4; mt++) {
                int r0 = wm*64 + mt*16;
                af[mt][0] = As[st][r0+g  ][ks+tig  ];
                af[mt][1] = As[st][r0+g+8][ks+tig  ];
                af[mt][2] = As[st][r0+g  ][ks+tig+4];
                af[mt][3] = As[st][r0+g+8][ks+tig+4];
            }
            #pragma unroll
            for (int nt = 0; nt < 4; nt++) {
                int c0 = wn*32 + nt*8;
                bf[nt][0] = Bs[st][c0+g][ks+tig  ];
                bf[nt][1] = Bs[st][c0+g][ks+tig+4];
            }
            #pragma unroll
            for (int mt = 0; mt < 4; mt++)
                #pragma unroll
                for (int nt = 0; nt < 4; nt++) {
                    asm volatile(
                        "mma.sync.aligned.m16n8k8.row.col.f32.tf32.tf32.f32 "
                        "{%0,%1,%2,%3}, {%4,%5,%6,%7}, {%8,%9}, {%0,%1,%2,%3};\n"
                        : "+f"(acc[mt][nt][0]), "+f"(acc[mt][nt][1]),
                          "+f"(acc[mt][nt][2]), "+f"(acc[mt][nt][3])
                        : "r"(af[mt][0]), "r"(af[mt][1]),
                          "r"(af[mt][2]), "r"(af[mt][3]),
                          "r"(bf[nt][0]), "r"(bf[nt][1]));
                }
        }
        __syncthreads();
    }
}

__global__ __launch_bounds__(256, 2) void gemm_tc_kernel(
    const float* __restrict__ A, const float* __restrict__ W,
    const float* __restrict__ bias, float* __restrict__ C,
    int K, int ldC)
{
    float acc[4][4][4];
    #pragma unroll
    for (int a = 0; a < 4; a++)
        #pragma unroll
        for (int b = 0; b < 4; b++)
            #pragma unroll
            for (int c = 0; c < 4; c++) acc[a][b][c] = 0.f;

    int m0 = blockIdx.y * 128, n0 = blockIdx.x * 128;
    mma_mainloop(acc, A, W, K, m0, n0);

    int tid = threadIdx.x;
    int lane = tid & 31, wid = tid >> 5;
    int wm = wid >> 2, wn = wid & 3;
    int g = lane >> 2, tig = lane & 3;
    int rowb = m0 + wm*64;
    int colb = n0 + wn*32;
    #pragma unroll
    for (int nt = 0; nt < 4; nt++) {
        int c = colb + nt*8 + 2*tig;
        float b0 = bias[c], b1 = bias[c+1];
        #pragma unroll
        for (int mt = 0; mt < 4; mt++) {
            int r = rowb + mt*16 + g;
            *(float2*)(C + (size_t)r*ldC + c)     = make_float2(acc[mt][nt][0]+b0, acc[mt][nt][1]+b1);
            *(float2*)(C + (size_t)(r+8)*ldC + c) = make_float2(acc[mt][nt][2]+b0, acc[mt][nt][3]+b1);
        }
    }
}

// ================= bf16 GEMM core: 3-stage cp.async, ONE sync per iter ==========
__device__ __forceinline__ void mma_bf16_mainloop(
    float acc[4][4][4], uint32_t* __restrict__ As, uint32_t* __restrict__ Bs,
    const __nv_bfloat16* __restrict__ A, const __nv_bfloat16* __restrict__ W,
    int K, int m0, int n0, int nmax)
{
    int tid  = threadIdx.x;
    int lane = tid & 31, wid = tid >> 5;
    int wm = wid >> 2, wn = wid & 3;

    int a_row = (lane & 7) + ((lane >> 3) & 1) * 8;
    int a_wrd = (lane >> 4) * 4;
    int b_row = lane & 7;
    int b_wrd = ((lane >> 3) & 1) * 4;

    int r0c = tid >> 2, r1c = r0c + 64;
    int cw = (tid & 3) * 4;   // word col
    int ce = (tid & 3) * 8;   // element col
    int nr0 = n0 + r0c; nr0 = (nr0 < nmax) ? nr0 : (nmax - 1);
    int nr1 = n0 + r1c; nr1 = (nr1 < nmax) ? nr1 : (nmax - 1);
    const __nv_bfloat16* pa0 = A + (size_t)(m0 + r0c)*K + ce;
    const __nv_bfloat16* pa1 = A + (size_t)(m0 + r1c)*K + ce;
    const __nv_bfloat16* pb0 = W + (size_t)nr0*K + ce;
    const __nv_bfloat16* pb1 = W + (size_t)nr1*K + ce;

    int niter = K >> 5;
    // prime chunks 0,1 into stages 0,1 (one commit group per chunk)
    #pragma unroll
    for (int c = 0; c < 2; c++) {
        int base = (c*128)*RW;
        cp_async16(&As[base + r0c*RW + cw], pa0 + c*32);
        cp_async16(&As[base + r1c*RW + cw], pa1 + c*32);
        cp_async16(&Bs[base + r0c*RW + cw], pb0 + c*32);
        cp_async16(&Bs[base + r1c*RW + cw], pb1 + c*32);
        cp_commit();
    }

    for (int it = 0; it < niter; it++) {
        int st = it % 3;
        // chunk `it` must be resident: allow 1 outstanding group (chunk it+1)
        if (it + 1 < niter) cp_wait<1>(); else cp_wait<0>();
        __syncthreads();   // joins: prev-iter reads done + chunk `it` visible to all
        // prefetch chunk it+2 into buffer (it+2)%3 (read finished in iter it-1)
        if (it + 2 < niter) {
            int c = it + 2, s2 = c % 3;
            int base = (s2*128)*RW;
            cp_async16(&As[base + r0c*RW + cw], pa0 + c*32);
            cp_async16(&As[base + r1c*RW + cw], pa1 + c*32);
            cp_async16(&Bs[base + r0c*RW + cw], pb0 + c*32);
            cp_async16(&Bs[base + r1c*RW + cw], pb1 + c*32);
            cp_commit();
        }
        int sbase = (st*128)*RW;
        #pragma unroll
        for (int ks = 0; ks < 2; ks++) {
            int kb = ks*8;
            uint32_t af[4][4], bf[4][2];
            #pragma unroll
            for (int mt = 0; mt < 4; mt++) {
                int r0 = wm*64 + mt*16;
                ldsm_x4(af[mt][0], af[mt][1], af[mt][2], af[mt][3],
                        &As[sbase + (r0 + a_row)*RW + kb + a_wrd]);
            }
            #pragma unroll
            for (int nt = 0; nt < 4; nt++) {
                int c0 = wn*32 + nt*8;
                ldsm_x2(bf[nt][0], bf[nt][1],
                        &Bs[sbase + (c0 + b_row)*RW + kb + b_wrd]);
            }
            #pragma unroll
            for (int mt = 0; mt < 4; mt++)
                #pragma unroll
                for (int nt = 0; nt < 4; nt++) {
                    asm volatile(
                        "mma.sync.aligned.m16n8k16.row.col.f32.bf16.bf16.f32 "
                        "{%0,%1,%2,%3}, {%4,%5,%6,%7}, {%8,%9}, {%0,%1,%2,%3};\n"
                        : "+f"(acc[mt][nt][0]), "+f"(acc[mt][nt][1]),
                          "+f"(acc[mt][nt][2]), "+f"(acc[mt][nt][3])
                        : "r"(af[mt][0]), "r"(af[mt][1]),
                          "r"(af[mt][2]), "r"(af[mt][3]),
                          "r"(bf[nt][0]), "r"(bf[nt][1]));
                }
        }
    }
    __syncthreads();
}

// bf16 GEMM -> fp32 out (+bias)
__global__ __launch_bounds__(256, 2) void gemm_bf_f32_kernel(
    const __nv_bfloat16* __restrict__ A, const __nv_bfloat16* __restrict__ W,
    const float* __restrict__ bias, float* __restrict__ C, int K, int ldC)
{
    extern __shared__ uint32_t dsm[];
    uint32_t* As = dsm;
    uint32_t* Bs = dsm + BF_DSM_WORDS;
    float acc[4][4][4];
    #pragma unroll
    for (int a = 0; a < 4; a++)
        #pragma unroll
        for (int b = 0; b < 4; b++)
            #pragma unroll
            for (int c = 0; c < 4; c++) acc[a][b][c] = 0.f;
    int m0 = blockIdx.y * 128, n0 = blockIdx.x * 128;
    mma_bf16_mainloop(acc, As, Bs, A, W, K, m0, n0, 0x40000000);

    int tid = threadIdx.x;
    int lane = tid & 31, wid = tid >> 5;
    int wm = wid >> 2, wn = wid & 3;
    int g = lane >> 2, tig = lane & 3;
    int rowb = m0 + wm*64, colb = n0 + wn*32;
    #pragma unroll
    for (int nt = 0; nt < 4; nt++) {
        int c = colb + nt*8 + 2*tig;
        float b0 = bias[c], b1 = bias[c+1];
        #pragma unroll
        for (int mt = 0; mt < 4; mt++) {
            int r = rowb + mt*16 + g;
            *(float2*)(C + (size_t)r*ldC + c)     = make_float2(acc[mt][nt][0]+b0, acc[mt][nt][1]+b1);
            *(float2*)(C + (size_t)(r+8)*ldC + c) = make_float2(acc[mt][nt][2]+b0, acc[mt][nt][3]+b1);
        }
    }
}

// bf16 GEMM -> bf16 out (+bias, +relu)  (FF1 path)
__global__ __launch_bounds__(256, 2) void gemm_bf_bf_relu_kernel(
    const __nv_bfloat16* __restrict__ A, const __nv_bfloat16* __restrict__ W,
    const float* __restrict__ bias, __nv_bfloat16* __restrict__ C, int K, int ldC)
{
    extern __shared__ uint32_t dsm[];
    uint32_t* As = dsm;
    uint32_t* Bs = dsm + BF_DSM_WORDS;
    float acc[4][4][4];
    #pragma unroll
    for (int a = 0; a < 4; a++)
        #pragma unroll
        for (int b = 0; b < 4; b++)
            #pragma unroll
            for (int c = 0; c < 4; c++) acc[a][b][c] = 0.f;
    int m0 = blockIdx.y * 128, n0 = blockIdx.x * 128;
    mma_bf16_mainloop(acc, As, Bs, A, W, K, m0, n0, 0x40000000);

    int tid = threadIdx.x;
    int lane = tid & 31, wid = tid >> 5;
    int wm = wid >> 2, wn = wid & 3;
    int g = lane >> 2, tig = lane & 3;
    int rowb = m0 + wm*64, colb = n0 + wn*32;
    #pragma unroll
    for (int nt = 0; nt < 4; nt++) {
        int c = colb + nt*8 + 2*tig;
        float b0 = bias[c], b1 = bias[c+1];
        #pragma unroll
        for (int mt = 0; mt < 4; mt++) {
            int r = rowb + mt*16 + g;
            float v0 = fmaxf(acc[mt][nt][0]+b0, 0.f);
            float v1 = fmaxf(acc[mt][nt][1]+b1, 0.f);
            float v2 = fmaxf(acc[mt][nt][2]+b0, 0.f);
            float v3 = fmaxf(acc[mt][nt][3]+b1, 0.f);
            *(__nv_bfloat162*)(C + (size_t)r*ldC + c)     = __floats2bfloat162_rn(v0, v1);
            *(__nv_bfloat162*)(C + (size_t)(r+8)*ldC + c) = __floats2bfloat162_rn(v2, v3);
        }
    }
}

// decoder bf16 GEMM + fused online-lse partials (m-tiles adjacent for L2 reuse)
__global__ __launch_bounds__(256, 2) void gemm_lse_bf_kernel(
    const __nv_bfloat16* __restrict__ A, const __nv_bfloat16* __restrict__ W, int K)
{
    extern __shared__ uint32_t dsm[];
    uint32_t* As = dsm;
    uint32_t* Bs = dsm + BF_DSM_WORDS;
    float acc[4][4][4];
    #pragma unroll
    for (int a = 0; a < 4; a++)
        #pragma unroll
        for (int b = 0; b < 4; b++)
            #pragma unroll
            for (int c = 0; c < 4; c++) acc[a][b][c] = 0.f;
    int m0 = blockIdx.x * 128, n0 = blockIdx.y * 128;
    int nblk = blockIdx.y;
    mma_bf16_mainloop(acc, As, Bs, A, W, K, m0, n0, NTOK);

    __shared__ float red_m[4][128];
    __shared__ float red_s[4][128];
    int tid = threadIdx.x;
    int lane = tid & 31, wid = tid >> 5;
    int wm = wid >> 2, wn = wid & 3;
    int g = lane >> 2, tig = lane & 3;
    int colb = n0 + wn*32;

    #pragma unroll
    for (int mt = 0; mt < 4; mt++) {
        #pragma unroll
        for (int h = 0; h < 2; h++) {
            float m = -INFINITY;
            #pragma unroll
            for (int nt = 0; nt < 4; nt++) {
                int c = colb + nt*8 + 2*tig;
                if (c     < NTOK) m = fmaxf(m, acc[mt][nt][h*2+0]);
                if (c + 1 < NTOK) m = fmaxf(m, acc[mt][nt][h*2+1]);
            }
            m = fmaxf(m, __shfl_xor_sync(0xffffffffu, m, 1));
            m = fmaxf(m, __shfl_xor_sync(0xffffffffu, m, 2));
            float s = 0.f;
            #pragma unroll
            for (int nt = 0; nt < 4; nt++) {
                int c = colb + nt*8 + 2*tig;
                if (c     < NTOK) s += __expf(acc[mt][nt][h*2+0] - m);
                if (c + 1 < NTOK) s += __expf(acc[mt][nt][h*2+1] - m);
            }
            s += __shfl_xor_sync(0xffffffffu, s, 1);
            s += __shfl_xor_sync(0xffffffffu, s, 2);
            if (tig == 0) {
                int lr = wm*64 + mt*16 + h*8 + g;
                red_m[wn][lr] = m;
                red_s[wn][lr] = s;
            }
        }
    }
    __syncthreads();
    if (tid < 128) {
        float m0v = red_m[0][tid], m1v = red_m[1][tid];
        float m2v = red_m[2][tid], m3v = red_m[3][tid];
        float mx = fmaxf(fmaxf(m0v, m1v), fmaxf(m2v, m3v));
        float s = red_s[0][tid]*__expf(m0v-mx) + red_s[1][tid]*__expf(m1v-mx)
                + red_s[2][tid]*__expf(m2v-mx) + red_s[3][tid]*__expf(m3v-mx);
        int row = m0 + tid;
        g_pmax[(size_t)row*NBLK_V + nblk] = mx;
        g_psum[(size_t)row*NBLK_V + nblk] = s;
    }
}

__global__ void lse_reduce_kernel()
{
    int r = blockIdx.x, tid = threadIdx.x;
    __shared__ float red[128];
    float m = -INFINITY;
    for (int i = tid; i < NBLK_V; i += 128) m = fmaxf(m, g_pmax[(size_t)r*NBLK_V + i]);
    red[tid] = m; __syncthreads();
    for (int s = 64; s > 0; s >>= 1) { if (tid < s) red[tid] = fmaxf(red[tid], red[tid+s]); __syncthreads(); }
    float gm = red[0]; __syncthreads();
    double sum = 0.0;
    for (int i = tid; i < NBLK_V; i += 128)
        sum += (double)g_psum[(size_t)r*NBLK_V + i] * exp((double)g_pmax[(size_t)r*NBLK_V + i] - (double)gm);
    __shared__ double redd[128];
    redd[tid] = sum; __syncthreads();
    for (int s = 64; s > 0; s >>= 1) { if (tid < s) redd[tid] += redd[tid+s]; __syncthreads(); }
    if (tid == 0) g_lse[r] = gm + (float)log(redd[0]);
}

// ---------------- small-M GEMM ----------------
__global__ void rowdot_kernel(
    const float* __restrict__ A, long strideA,
    const float* __restrict__ W, const float* __restrict__ bias,
    float* __restrict__ C, long strideC,
    int M, int K, float alpha, int relu)
{
    int n = blockIdx.x;
    int tid = threadIdx.x;   // 128
    const float* w = W + (size_t)n * K;
    __shared__ float red[128];
    for (int m = 0; m < M; m++) {
        const float* a = A + (size_t)m * strideA;
        float s = 0.f;
        for (int k = tid; k < K; k += 128) s += a[k]*w[k];
        red[tid] = s; __syncthreads();
        for (int st = 64; st > 0; st >>= 1) { if (tid < st) red[tid] += red[tid+st]; __syncthreads(); }
        if (tid == 0) {
            float v = alpha*red[0] + (bias ? bias[n] : 0.f);
            if (relu) v = fmaxf(v, 0.f);
            C[(size_t)m*strideC + n] = v;
        }
        __syncthreads();
    }
}

// ---------------- attention, 8 queries per block, bf16 out ----------------
#define QT 8
__global__ __launch_bounds__(256) void attn8_kernel(
    const float* __restrict__ qkv, __nv_bfloat16* __restrict__ out)
{
    int qt = blockIdx.x, h = blockIdx.y, b = blockIdx.z;
    int tid = threadIdx.x;
    __shared__ float qs[QT][DHEAD];
    __shared__ float sc[QT][NSEQ];
    __shared__ float den[QT];
    const float* base = qkv + (size_t)b*NSEQ*QKV_LD;
    if (tid < 128) {
        int q = tid >> 4;
        int c = (tid & 15) * 4;
        *(float4*)&qs[q][c] =
            *(const float4*)(base + (size_t)(qt*QT+q)*QKV_LD + h*DHEAD + c);
    }
    __syncthreads();
    {
        int j = tid;
        float4 kreg[16];
        const float4* kr = (const float4*)(base + (size_t)j*QKV_LD + D_MODEL + h*DHEAD);
        #pragma unroll
        for (int t = 0; t < 16; t++) kreg[t] = kr[t];
        #pragma unroll
        for (int q = 0; q < QT; q++) {
            float d = 0.f;
            #pragma unroll
            for (int t = 0; t < 16; t++) {
                float4 q4 = *(float4*)&qs[q][t*4];
                d += q4.x*kreg[t].x + q4.y*kreg[t].y + q4.z*kreg[t].z + q4.w*kreg[t].w;
            }
            sc[q][j] = d * 0.125f;
        }
    }
    __syncthreads();
    {
        int w = tid >> 5, lane = tid & 31;
        float v[8];
        float m = -INFINITY;
        #pragma unroll
        for (int t = 0; t < 8; t++) { v[t] = sc[w][lane + 32*t]; m = fmaxf(m, v[t]); }
        #pragma unroll
        for (int o = 16; o; o >>= 1) m = fmaxf(m, __shfl_xor_sync(0xffffffffu, m, o));
        float s = 0.f;
        #pragma unroll
        for (int t = 0; t < 8; t++) { v[t] = expf(v[t]-m); s += v[t]; }
        #pragma unroll
        for (int o = 16; o; o >>= 1) s += __shfl_xor_sync(0xffffffffu, s, o);
        #pragma unroll
        for (int t = 0; t < 8; t++) sc[w][lane + 32*t] = v[t];
        if (lane == 0) den[w] = s;
    }
    __syncthreads();
    {
        int d = tid & 63, qp = tid >> 6;
        int q0 = qp*2, q1 = qp*2+1;
        const float* vb = base + 2*D_MODEL + h*DHEAD + d;
        float a0 = 0.f, a1 = 0.f;
        #pragma unroll 8
        for (int j = 0; j < NSEQ; j++) {
            float v = vb[(size_t)j*QKV_LD];
            a0 += sc[q0][j]*v;
            a1 += sc[q1][j]*v;
        }
        out[((size_t)(b*NSEQ + qt*QT + q0))*D_MODEL + h*DHEAD + d] = __float2bfloat16(a0/den[q0]);
        out[((size_t)(b*NSEQ + qt*QT + q1))*D_MODEL + h*DHEAD + d] = __float2bfloat16(a1/den[q1]);
    }
}

// ---------------- loc attention (single query per (h,b)), fp32 out ----------------
__global__ __launch_bounds__(256) void attn_kernel(
    const float* __restrict__ qkv, float* __restrict__ out, int nq, int sq_base)
{
    int qi = blockIdx.x, h = blockIdx.y, b = blockIdx.z;
    int sq = sq_base + qi;
    int tid = threadIdx.x;
    __shared__ float4 qrow[DHEAD/4];
    __shared__ float sc[NSEQ];
    __shared__ float red[256];
    __shared__ float sden;
    __shared__ float osum[4][DHEAD];
    const float* base = qkv + (size_t)b * NSEQ * QKV_LD;
    if (tid < DHEAD/4)
        qrow[tid] = ((const float4*)(base + (size_t)sq*QKV_LD + h*DHEAD))[tid];
    __syncthreads();
    {
        const float4* krow = (const float4*)(base + (size_t)tid*QKV_LD + D_MODEL + h*DHEAD);
        float d = 0.f;
        #pragma unroll
        for (int t = 0; t < DHEAD/4; t++) {
            float4 k4 = krow[t];
            float4 q4 = qrow[t];
            d += q4.x*k4.x + q4.y*k4.y + q4.z*k4.z + q4.w*k4.w;
        }
        sc[tid] = d * 0.125f;
    }
    __syncthreads();
    red[tid] = sc[tid]; __syncthreads();
    for (int s = 128; s > 0; s >>= 1) { if (tid < s) red[tid] = fmaxf(red[tid], red[tid+s]); __syncthreads(); }
    float mx = red[0]; __syncthreads();
    float e = expf(sc[tid] - mx);
    red[tid] = e; __syncthreads();
    for (int s = 128; s > 0; s >>= 1) { if (tid < s) red[tid] += red[tid+s]; __syncthreads(); }
    if (tid == 0) sden = red[0];
    __syncthreads();
    sc[tid] = e;
    __syncthreads();
    int d = tid & 63, g = tid >> 6;
    const float* vb = base + 2*D_MODEL + h*DHEAD + d;
    float o = 0.f;
    for (int j = g*64; j < (g+1)*64; j++) o += sc[j] * vb[(size_t)j*QKV_LD];
    osum[g][d] = o; __syncthreads();
    if (tid < DHEAD) {
        float r = (osum[0][tid]+osum[1][tid]+osum[2][tid]+osum[3][tid]) / sden;
        out[((size_t)(b*nq + qi))*D_MODEL + h*DHEAD + tid] = r;
    }
}

// ---------------- residual + layernorm (fp32 out + optional bf16 mirror) ----------
__global__ void ln_kernel(
    const float* __restrict__ in1, long s1,
    const float* __restrict__ in2, long s2,
    float* __restrict__ out, long so,
    __nv_bfloat16* __restrict__ outh,
    const float* __restrict__ gam, const float* __restrict__ bet)
{
    int r = blockIdx.x, tid = threadIdx.x;
    __shared__ float xr[D_MODEL];
    __shared__ float red[256];
    const float* p1 = in1 + (size_t)r*s1;
    const float* p2 = in2 + (size_t)r*s2;
    float ls = 0.f;
    for (int d = tid; d < D_MODEL; d += 256) { float v = p1[d]+p2[d]; xr[d] = v; ls += v; }
    red[tid] = ls; __syncthreads();
    for (int s = 128; s > 0; s >>= 1) { if (tid < s) red[tid] += red[tid+s]; __syncthreads(); }
    float mean = red[0] * (1.f/D_MODEL); __syncthreads();
    float lv = 0.f;
    for (int d = tid; d < D_MODEL; d += 256) { float t = xr[d]-mean; lv += t*t; }
    red[tid] = lv; __syncthreads();
    for (int s = 128; s > 0; s >>= 1) { if (tid < s) red[tid] += red[tid+s]; __syncthreads(); }
    float rstd = 1.f / sqrtf(red[0]*(1.f/D_MODEL) + 1e-5f);
    for (int d = tid; d < D_MODEL; d += 256) {
        float v = (xr[d]-mean)*rstd*gam[d] + bet[d];
        out[(size_t)r*so + d] = v;
        if (outh) outh[(size_t)r*D_MODEL + d] = __float2bfloat16(v);
    }
}

// ---------------- gating statistics + top-k + softmax + importance ----------------
__global__ void stats_kernel(const float* __restrict__ w, const float* __restrict__ noise)
{
    __shared__ float tot[NEXP];
    __shared__ double redd[256];
    __shared__ float fv[256];
    __shared__ int   fi[256];
    __shared__ float topv[NKTOP];
    __shared__ double smean, sstd;
    int tid = threadIdx.x;
    double ls = 0.0;
    for (int n = tid; n < NEXP; n += 256) {
        float f = 0.25f*(w[n] + w[NEXP+n] + w[2*NEXP+n] + w[3*NEXP+n]);
        tot[n] = f; ls += (double)f;
    }
    redd[tid] = ls; __syncthreads();
    for (int s = 128; s > 0; s >>= 1) { if (tid < s) redd[tid] += redd[tid+s]; __syncthreads(); }
    if (tid == 0) smean = redd[0] / NEXP;
    __syncthreads();
    double mfm = smean;
    ls = 0.0;
    for (int n = tid; n < NEXP; n += 256) { double t = (double)tot[n]-mfm; ls += t*t; }
    redd[tid] = ls; __syncthreads();
    for (int s = 128; s > 0; s >>= 1) { if (tid < s) redd[tid] += redd[tid+s]; __syncthreads(); }
    if (tid == 0) sstd = sqrt(redd[0] / (NEXP-1));
    __syncthreads();
    float stdfm = (float)sstd;
    for (int n = tid; n < NEXP; n += 256) tot[n] = tot[n] + noise[n]*stdfm;
    __syncthreads();
    ls = 0.0;
    for (int n = tid; n < NEXP; n += 256) ls += (double)tot[n];
    redd[tid] = ls; __syncthreads();
    for (int s = 128; s > 0; s >>= 1) { if (tid < s) redd[tid] += redd[tid+s]; __syncthreads(); }
    if (tid == 0) smean = redd[0] / NEXP;
    __syncthreads();
    double mt = smean;
    ls = 0.0;
    for (int n = tid; n < NEXP; n += 256) { double t = (double)tot[n]-mt; ls += t*t; }
    redd[tid] = ls; __syncthreads();
    for (int s = 128; s > 0; s >>= 1) { if (tid < s) redd[tid] += redd[tid+s]; __syncthreads(); }
    if (tid == 0) {
        double st = sqrt(redd[0] / (NEXP-1));
        double ratio = st / mt;
        g_stats[20] = (float)(0.1 * ratio * ratio);
    }
    __syncthreads();
    for (int it = 0; it < NKTOP; it++) {
        float bv = -INFINITY; int bi = 0x7fffffff;
        for (int n = tid; n < NEXP; n += 256) {
            float v = tot[n];
            if (v > bv || (v == bv && n < bi)) { bv = v; bi = n; }
        }
        fv[tid] = bv; fi[tid] = bi; __syncthreads();
        for (int s = 128; s > 0; s >>= 1) {
            if (tid < s) {
                float v2 = fv[tid+s]; int i2 = fi[tid+s];
                if (v2 > fv[tid] || (v2 == fv[tid] && i2 < fi[tid])) { fv[tid] = v2; fi[tid] = i2; }
            }
            __syncthreads();
        }
        if (tid == 0) { topv[it] = fv[0]; tot[fi[0]] = -INFINITY; }
        __syncthreads();
    }
    if (tid == 0) {
        float m = topv[0];
        float s = 0.f;
        float e[NKTOP];
        for (int k = 0; k < NKTOP; k++) { e[k] = expf(topv[k]-m); s += e[k]; }
        for (int k = 0; k < NKTOP; k++) g_stats[k] = e[k]/s;
    }
}

// ---------------- response mixture (fp32 + bf16 mirror) ----------------
__global__ void mix_kernel(const float* __restrict__ responses)
{
    __shared__ float w[NKTOP];
    if (threadIdx.x < NKTOP) w[threadIdx.x] = g_stats[threadIdx.x];
    __syncthreads();
    int i = blockIdx.x*blockDim.x + threadIdx.x;
    if (i < (NROWS*D_MODEL)/4) {
        float4 s = make_float4(0.f, 0.f, 0.f, 0.f);
        #pragma unroll
        for (int k = 0; k < NKTOP; k++) {
            float4 v = ((const float4*)responses)[(size_t)k*((NROWS*D_MODEL)/4) + i];
            float wk = w[k];
            s.x += wk*v.x; s.y += wk*v.y; s.z += wk*v.z; s.w += wk*v.w;
        }
        ((float4*)g_x)[i] = s;
        ((__nv_bfloat162*)h_x)[2*i+0] = __floats2bfloat162_rn(s.x, s.y);
        ((__nv_bfloat162*)h_x)[2*i+1] = __floats2bfloat162_rn(s.z, s.w);
    }
}

// ---------------- label logit + final loss ----------------
__global__ void lablogit_kernel(const int* __restrict__ inputs, const float* __restrict__ dec_w)
{
    int s = blockIdx.x, b = blockIdx.y, tid = threadIdx.x;
    int lbl = inputs[b*NSEQ + s + 1];
    const float* a = g_x + ((size_t)(b*NSEQ + s))*D_MODEL;
    const float* wp = dec_w + (size_t)lbl*D_MODEL;
    __shared__ float red[128];
    float acc = 0.f;
    for (int k = tid; k < D_MODEL; k += 128) acc += a[k]*wp[k];
    red[tid] = acc; __syncthreads();
    for (int st = 64; st > 0; st >>= 1) { if (tid < st) red[tid] += red[tid+st]; __syncthreads(); }
    if (tid == 0) g_lab[b*(NSEQ-1)+s] = red[0];
}

__global__ void final_kernel(float* __restrict__ out)
{
    __shared__ double red[256];
    int tid = threadIdx.x;
    double s = 0.0;
    for (int i = tid; i < NB*(NSEQ-1); i += 256) {
        int b = i/(NSEQ-1), sp = i%(NSEQ-1);
        s += (double)g_lab[i] - (double)g_lse[b*NSEQ+sp];
    }
    red[tid] = s; __syncthreads();
    for (int st = 128; st > 0; st >>= 1) { if (tid < st) red[tid] += red[tid+st]; __syncthreads(); }
    if (tid == 0) {
        double ce = -red[0] / (double)(NB*(NSEQ-1));
        out[0] = (float)(ce + (double)g_stats[20]);
    }
}

// ---------------- host driver ----------------
extern "C" void kernel_launch(void* const* d_in, const int* in_sizes, int n_in,
                              void* d_out, int out_size)
{
    (void)in_sizes; (void)n_in; (void)out_size;
    const int*   inputs    = (const int*)  d_in[0];
    const float* responses = (const float*)d_in[1];
    const float* noise     = (const float*)d_in[2];
    const float* emb       = (const float*)d_in[3];
    const float* loc_Wqkv  = (const float*)d_in[4];
    const float* loc_bqkv  = (const float*)d_in[5];
    const float* loc_Wo    = (const float*)d_in[6];
    const float* loc_bo    = (const float*)d_in[7];
    const float* loc_ln1g  = (const float*)d_in[8];
    const float* loc_ln1b  = (const float*)d_in[9];
    const float* loc_W1    = (const float*)d_in[10];
    const float* loc_b1    = (const float*)d_in[11];
    const float* loc_W2    = (const float*)d_in[12];
    const float* loc_b2    = (const float*)d_in[13];
    const float* loc_ln2g  = (const float*)d_in[14];
    const float* loc_ln2b  = (const float*)d_in[15];
    const float* enc_Wqkv  = (const float*)d_in[16];
    const float* enc_bqkv  = (const float*)d_in[17];
    const float* enc_Wo    = (const float*)d_in[18];
    const float* enc_bo    = (const float*)d_in[19];
    const float* enc_ln1g  = (const float*)d_in[20];
    const float* enc_ln1b  = (const float*)d_in[21];
    const float* enc_W1    = (const float*)d_in[22];
    const float* enc_b1    = (const float*)d_in[23];
    const float* enc_W2    = (const float*)d_in[24];
    const float* enc_b2    = (const float*)d_in[25];
    const float* enc_ln2g  = (const float*)d_in[26];
    const float* enc_ln2b  = (const float*)d_in[27];
    const float* gate_w    = (const float*)d_in[28];
    const float* gate_b    = (const float*)d_in[29];
    const float* dec_w     = (const float*)d_in[30];
    float* out = (float*)d_out;

    float *p_x, *p_qkv, *p_tmp;
    float *p_sm_attn, *p_sm_x, *p_sm_tmp, *p_sm_ctx, *p_sm_ffh;
    __nv_bfloat16 *p_hdec, *p_hWqkv, *p_hWo, *p_hW1, *p_hW2, *p_hx, *p_hattn, *p_hffh;
    cudaGetSymbolAddress((void**)&p_x, g_x);
    cudaGetSymbolAddress((void**)&p_qkv, g_qkv);
    cudaGetSymbolAddress((void**)&p_tmp, g_tmp);
    cudaGetSymbolAddress((void**)&p_sm_attn, g_sm_attn);
    cudaGetSymbolAddress((void**)&p_sm_x, g_sm_x);
    cudaGetSymbolAddress((void**)&p_sm_tmp, g_sm_tmp);
    cudaGetSymbolAddress((void**)&p_sm_ctx, g_sm_ctx);
    cudaGetSymbolAddress((void**)&p_sm_ffh, g_sm_ffh);
    cudaGetSymbolAddress((void**)&p_hdec, h_dec);
    cudaGetSymbolAddress((void**)&p_hWqkv, h_Wqkv);
    cudaGetSymbolAddress((void**)&p_hWo, h_Wo);
    cudaGetSymbolAddress((void**)&p_hW1, h_W1);
    cudaGetSymbolAddress((void**)&p_hW2, h_W2);
    cudaGetSymbolAddress((void**)&p_hx, h_x);
    cudaGetSymbolAddress((void**)&p_hattn, h_attn);
    cudaGetSymbolAddress((void**)&p_hffh, h_ffh);

    // dynamic smem opt-in for the 3-stage bf16 GEMMs
    cudaFuncSetAttribute(gemm_bf_f32_kernel,     cudaFuncAttributeMaxDynamicSharedMemorySize, BF_DSM_BYTES);
    cudaFuncSetAttribute(gemm_bf_bf_relu_kernel, cudaFuncAttributeMaxDynamicSharedMemorySize, BF_DSM_BYTES);
    cudaFuncSetAttribute(gemm_lse_bf_kernel,     cudaFuncAttributeMaxDynamicSharedMemorySize, BF_DSM_BYTES);

    // ---- capture-forked side stream for weight conversions ----
    cudaStream_t s2;
    cudaStreamCreateWithFlags(&s2, cudaStreamNonBlocking);
    cudaEvent_t evFork, evEnc, evDec;
    cudaEventCreateWithFlags(&evFork, cudaEventDisableTiming);
    cudaEventCreateWithFlags(&evEnc,  cudaEventDisableTiming);
    cudaEventCreateWithFlags(&evDec,  cudaEventDisableTiming);

    cudaEventRecord(evFork, 0);
    cudaStreamWaitEvent(s2, evFork, 0);

    f2h_kernel<<<(2*QKV_LD*D_MODEL/8 + 255)/256, 256, 0, s2>>>(enc_Wqkv, p_hWqkv, 2*QKV_LD*D_MODEL/4);
    f2h_kernel<<<(2*D_MODEL*D_MODEL/8 + 255)/256, 256, 0, s2>>>(enc_Wo, p_hWo, 2*D_MODEL*D_MODEL/4);
    f2h_kernel<<<(2*FF_DIM*D_MODEL/8 + 255)/256, 256, 0, s2>>>(enc_W1, p_hW1, 2*FF_DIM*D_MODEL/4);
    f2h_kernel<<<(2*D_MODEL*FF_DIM/8 + 255)/256, 256, 0, s2>>>(enc_W2, p_hW2, 2*D_MODEL*FF_DIM/4);
    cudaEventRecord(evEnc, s2);
    f2h_kernel<<<(NTOK*D_MODEL/8 + 255)/256, 256, 0, s2>>>(dec_w, p_hdec, NTOK*D_MODEL/4);
    cudaEventRecord(evDec, s2);

    // default stream: embed + loc layer + gating (overlapped with f2h)
    embed_kernel<<<NROWS, 256>>>(inputs, emb);
    gemm_tc_kernel<<<dim3(2048/128, NROWS/128), 256>>>(
        p_x, loc_Wqkv + (size_t)D_MODEL*D_MODEL, loc_bqkv + D_MODEL,
        p_qkv + D_MODEL, D_MODEL, QKV_LD);
    rowdot_kernel<<<D_MODEL, 128>>>(
        p_x + (size_t)(NSEQ-1)*D_MODEL, (long)NSEQ*D_MODEL,
        loc_Wqkv, loc_bqkv,
        p_qkv + (size_t)(NSEQ-1)*QKV_LD, (long)NSEQ*QKV_LD,
        NB, D_MODEL, 1.f, 0);
    attn_kernel<<<dim3(1, NHEAD, NB), 256>>>(p_qkv, p_sm_attn, 1, NSEQ-1);
    rowdot_kernel<<<D_MODEL, 128>>>(p_sm_attn, D_MODEL, loc_Wo, loc_bo,
                                    p_sm_tmp, D_MODEL, NB, D_MODEL, 1.f, 0);
    ln_kernel<<<NB, 256>>>(p_x + (size_t)(NSEQ-1)*D_MODEL, (long)NSEQ*D_MODEL,
                           p_sm_tmp, D_MODEL, p_sm_x, D_MODEL, (__nv_bfloat16*)0,
                           loc_ln1g, loc_ln1b);
    rowdot_kernel<<<FF_DIM, 128>>>(p_sm_x, D_MODEL, loc_W1, loc_b1,
                                   p_sm_ffh, FF_DIM, NB, D_MODEL, 1.f, 1);
    rowdot_kernel<<<D_MODEL, 128>>>(p_sm_ffh, FF_DIM, loc_W2, loc_b2,
                                    p_sm_tmp, D_MODEL, NB, FF_DIM, 1.f, 0);
    ln_kernel<<<NB, 256>>>(p_sm_x, D_MODEL, p_sm_tmp, D_MODEL,
                           p_sm_ctx, D_MODEL, (__nv_bfloat16*)0,
                           loc_ln2g, loc_ln2b);

    rowdot_kernel<<<NEXP, 128>>>(p_sm_ctx, D_MODEL, gate_w, gate_b,
                                 out + 1, NEXP, NB, D_MODEL, 32.f, 0);
    stats_kernel<<<1, 256>>>(out + 1, noise);
    mix_kernel<<<(NROWS*D_MODEL/4 + 255)/256, 256>>>(responses);

    // join: encoder weights must be converted before the encoder loop
    cudaStreamWaitEvent(0, evEnc, 0);

    // two encoder layers (bf16 tensor cores, 3-stage pipeline)
    for (int l = 0; l < 2; l++) {
        const __nv_bfloat16* Wqkv = p_hWqkv + (size_t)l*QKV_LD*D_MODEL;
        const float*         bqkv = enc_bqkv + (size_t)l*QKV_LD;
        const __nv_bfloat16* Wo   = p_hWo   + (size_t)l*D_MODEL*D_MODEL;
        const float*         bo   = enc_bo  + (size_t)l*D_MODEL;
        const float* g1   = enc_ln1g + (size_t)l*D_MODEL;
        const float* b1l  = enc_ln1b + (size_t)l*D_MODEL;
        const __nv_bfloat16* W1   = p_hW1   + (size_t)l*FF_DIM*D_MODEL;
        const float*         bb1  = enc_b1  + (size_t)l*FF_DIM;
        const __nv_bfloat16* W2   = p_hW2   + (size_t)l*D_MODEL*FF_DIM;
        const float*         bb2  = enc_b2  + (size_t)l*D_MODEL;
        const float* g2   = enc_ln2g + (size_t)l*D_MODEL;
        const float* b2l  = enc_ln2b + (size_t)l*D_MODEL;

        gemm_bf_f32_kernel<<<dim3(QKV_LD/128, NROWS/128), 256, BF_DSM_BYTES>>>(
            p_hx, Wqkv, bqkv, p_qkv, D_MODEL, QKV_LD);
        attn8_kernel<<<dim3(NSEQ/QT, NHEAD, NB), 256>>>(p_qkv, p_hattn);
        gemm_bf_f32_kernel<<<dim3(D_MODEL/128, NROWS/128), 256, BF_DSM_BYTES>>>(
            p_hattn, Wo, bo, p_tmp, D_MODEL, D_MODEL);
        ln_kernel<<<NROWS, 256>>>(p_x, D_MODEL, p_tmp, D_MODEL, p_x, D_MODEL, p_hx, g1, b1l);
        gemm_bf_bf_relu_kernel<<<dim3(FF_DIM/128, NROWS/128), 256, BF_DSM_BYTES>>>(
            p_hx, W1, bb1, p_hffh, D_MODEL, FF_DIM);
        gemm_bf_f32_kernel<<<dim3(D_MODEL/128, NROWS/128), 256, BF_DSM_BYTES>>>(
            p_hffh, W2, bb2, p_tmp, FF_DIM, D_MODEL);
        ln_kernel<<<NROWS, 256>>>(p_x, D_MODEL, p_tmp, D_MODEL, p_x, D_MODEL, p_hx, g2, b2l);
    }

    // join: decoder bf16 weights ready
    cudaStreamWaitEvent(0, evDec, 0);

    // fused decoder GEMM + logsumexp (m-tiles adjacent for L2 reuse of dec_w)
    gemm_lse_bf_kernel<<<dim3(NROWS/128, NBLK_V), 256, BF_DSM_BYTES>>>(p_hx, p_hdec, D_MODEL);
    lse_reduce_kernel<<<NROWS, 128>>>();
    lablogit_kernel<<<dim3(NSEQ-1, NB), 128>>>(inputs, dec_w);
    final_kernel<<<1, 256>>>(out);

    cudaEventDestroy(evFork);
    cudaEventDestroy(evEnc);
    cudaEventDestroy(evDec);
    cudaStreamDestroy(s2);
}

// round 10
// speedup vs baseline: 1.0698x; 1.0698x over previous
#include <cuda_runtime.h>
#include <cuda_bf16.h>
#include <math.h>
#include <stdint.h>

// ---------------- problem constants ----------------
#define D_MODEL 1024
#define NHEAD   16
#define DHEAD   64
#define FF_DIM  4096
#define NSEQ    256
#define NB      4
#define NTOK    50257
#define NEXP    2000
#define NKTOP   20
#define NROWS   (NB*NSEQ)      // 1024
#define QKV_LD  3072
#define NBLK_V  393            // ceil(50257/128)

#define SX      16.0f          // fp8 scale for activations
#define SW      512.0f         // fp8 scale for dec_w
#define INV_SXW (1.0f/(SX*SW))

// ---------------- scratch (static device memory; no allocation) ----------------
__device__ float g_x    [NROWS*D_MODEL];
__device__ float g_qkv  [NROWS*QKV_LD];
__device__ float g_tmp  [NROWS*D_MODEL];
__device__ float g_sm_attn[NB*D_MODEL];
__device__ float g_sm_x   [NB*D_MODEL];
__device__ float g_sm_tmp [NB*D_MODEL];
__device__ float g_sm_ctx [NB*D_MODEL];
__device__ float g_sm_ffh [NB*FF_DIM];
__device__ float g_pmax[NROWS*NBLK_V];
__device__ float g_psum[NROWS*NBLK_V];
__device__ float g_lse [NROWS];
__device__ float g_lab [NB*(NSEQ-1)];
__device__ float g_stats[32];   // [0..19] jw, [20] imp

// bf16 weight/activation mirrors (encoders)
__device__ __align__(256) __nv_bfloat16 h_Wqkv[2*QKV_LD*D_MODEL];
__device__ __align__(256) __nv_bfloat16 h_Wo  [2*D_MODEL*D_MODEL];
__device__ __align__(256) __nv_bfloat16 h_W1  [2*FF_DIM*D_MODEL];
__device__ __align__(256) __nv_bfloat16 h_W2  [2*D_MODEL*FF_DIM];
__device__ __align__(256) __nv_bfloat16 h_x   [NROWS*D_MODEL];
__device__ __align__(256) __nv_bfloat16 h_attn[NROWS*D_MODEL];
__device__ __align__(256) __nv_bfloat16 h_ffh [NROWS*FF_DIM];

// fp8 mirrors (decoder)
__device__ __align__(256) uint8_t q_x  [NROWS*D_MODEL];
__device__ __align__(256) uint8_t q_dec[NTOK*D_MODEL];

// ---------------- conversions ----------------
__global__ void f2h_kernel(const float* __restrict__ src, __nv_bfloat16* __restrict__ dst, int n4)
{
    int i = (blockIdx.x*blockDim.x + threadIdx.x) * 2;
    #pragma unroll
    for (int t = 0; t < 2; t++) {
        int j = i + t;
        if (j < n4) {
            float4 v = ((const float4*)src)[j];
            ((__nv_bfloat162*)dst)[2*j+0] = __floats2bfloat162_rn(v.x, v.y);
            ((__nv_bfloat162*)dst)[2*j+1] = __floats2bfloat162_rn(v.z, v.w);
        }
    }
}

__device__ __forceinline__ uint16_t pack_e4m3(float lo, float hi)
{
    uint16_t r;
    asm("cvt.rn.satfinite.e4m3x2.f32 %0, %1, %2;" : "=h"(r) : "f"(hi), "f"(lo));
    return r;
}

__global__ void q8_kernel(const float* __restrict__ src, uint8_t* __restrict__ dst,
                          int n4, float scale)
{
    int i = (blockIdx.x*blockDim.x + threadIdx.x) * 2;
    #pragma unroll
    for (int t = 0; t < 2; t++) {
        int j = i + t;
        if (j < n4) {
            float4 v = ((const float4*)src)[j];
            uint32_t lo = pack_e4m3(v.x*scale, v.y*scale);
            uint32_t hi = pack_e4m3(v.z*scale, v.w*scale);
            ((uint32_t*)dst)[j] = lo | (hi << 16);
        }
    }
}

// ---------------- embedding gather ----------------
__global__ void embed_kernel(const int* __restrict__ inputs, const float* __restrict__ emb)
{
    int r = blockIdx.x;
    int tok = inputs[r];
    const float4* src = (const float4*)(emb + (size_t)tok * D_MODEL);
    float4* dst = (float4*)(g_x + (size_t)r * D_MODEL);
    dst[threadIdx.x] = src[threadIdx.x];
}

// ================= cp.async / ldmatrix helpers =================
__device__ __forceinline__ void cp_async16(void* smem, const void* gmem)
{
    uint32_t s = (uint32_t)__cvta_generic_to_shared(smem);
    asm volatile("cp.async.ca.shared.global [%0], [%1], 16;\n" :: "r"(s), "l"(gmem));
}
__device__ __forceinline__ void cp_commit()
{
    asm volatile("cp.async.commit_group;\n" ::: "memory");
}
template<int N> __device__ __forceinline__ void cp_wait()
{
    asm volatile("cp.async.wait_group %0;\n" :: "n"(N) : "memory");
}
__device__ __forceinline__ void ldsm_x4(uint32_t& r0, uint32_t& r1, uint32_t& r2, uint32_t& r3,
                                        const void* smem)
{
    uint32_t a = (uint32_t)__cvta_generic_to_shared(smem);
    asm volatile("ldmatrix.sync.aligned.m8n8.x4.shared.b16 {%0,%1,%2,%3}, [%4];\n"
                 : "=r"(r0), "=r"(r1), "=r"(r2), "=r"(r3) : "r"(a));
}
__device__ __forceinline__ void ldsm_x2(uint32_t& r0, uint32_t& r1, const void* smem)
{
    uint32_t a = (uint32_t)__cvta_generic_to_shared(smem);
    asm volatile("ldmatrix.sync.aligned.m8n8.x2.shared.b16 {%0,%1}, [%2];\n"
                 : "=r"(r0), "=r"(r1) : "r"(a));
}

// ================= tf32 GEMM (loc KV path only) =================
__device__ __forceinline__ void mma_mainloop(
    float acc[4][4][4],
    const float* __restrict__ A, const float* __restrict__ W,
    int K, int m0, int n0)
{
    __shared__ uint32_t As[2][128][20];
    __shared__ uint32_t Bs[2][128][20];
    int tid  = threadIdx.x;
    int lane = tid & 31, wid = tid >> 5;
    int wm = wid >> 2, wn = wid & 3;
    int g = lane >> 2, tig = lane & 3;

    int r0c = tid >> 2,         c0c = (tid & 3) << 2;
    int r1c = (tid + 256) >> 2, c1c = (tid & 3) << 2;
    const float* pa0 = A + (size_t)(m0 + r0c)*K + c0c;
    const float* pa1 = A + (size_t)(m0 + r1c)*K + c1c;
    const float* pb0 = W + (size_t)(n0 + r0c)*K + c0c;
    const float* pb1 = W + (size_t)(n0 + r1c)*K + c1c;

    int niter = K >> 4;
    cp_async16(&As[0][r0c][c0c], pa0);
    cp_async16(&As[0][r1c][c1c], pa1);
    cp_async16(&Bs[0][r0c][c0c], pb0);
    cp_async16(&Bs[0][r1c][c1c], pb1);
    cp_commit();

    for (int it = 0; it < niter; it++) {
        int st = it & 1;
        if (it + 1 < niter) {
            int off = (it + 1) << 4;
            int sn = st ^ 1;
            cp_async16(&As[sn][r0c][c0c], pa0 + off);
            cp_async16(&As[sn][r1c][c1c], pa1 + off);
            cp_async16(&Bs[sn][r0c][c0c], pb0 + off);
            cp_async16(&Bs[sn][r1c][c1c], pb1 + off);
            cp_commit();
            cp_wait<1>();
        } else {
            cp_wait<0>();
        }
        __syncthreads();
        #pragma unroll
        for (int ks = 0; ks < 16; ks += 8) {
            uint32_t af[4][4], bf[4][2];
            #pragma unroll
            for (int mt = 0; mt < 4; mt++) {
                int r0 = wm*64 + mt*16;
                af[mt][0] = As[st][r0+g  ][ks+tig  ];
                af[mt][1] = As[st][r0+g+8][ks+tig  ];
                af[mt][2] = As[st][r0+g  ][ks+tig+4];
                af[mt][3] = As[st][r0+g+8][ks+tig+4];
            }
            #pragma unroll
            for (int nt = 0; nt < 4; nt++) {
                int c0 = wn*32 + nt*8;
                bf[nt][0] = Bs[st][c0+g][ks+tig  ];
                bf[nt][1] = Bs[st][c0+g][ks+tig+4];
            }
            #pragma unroll
            for (int mt = 0; mt < 4; mt++)
                #pragma unroll
                for (int nt = 0; nt < 4; nt++) {
                    asm volatile(
                        "mma.sync.aligned.m16n8k8.row.col.f32.tf32.tf32.f32 "
                        "{%0,%1,%2,%3}, {%4,%5,%6,%7}, {%8,%9}, {%0,%1,%2,%3};\n"
                        : "+f"(acc[mt][nt][0]), "+f"(acc[mt][nt][1]),
                          "+f"(acc[mt][nt][2]), "+f"(acc[mt][nt][3])
                        : "r"(af[mt][0]), "r"(af[mt][1]),
                          "r"(af[mt][2]), "r"(af[mt][3]),
                          "r"(bf[nt][0]), "r"(bf[nt][1]));
                }
        }
        __syncthreads();
    }
}

__global__ __launch_bounds__(256, 2) void gemm_tc_kernel(
    const float* __restrict__ A, const float* __restrict__ W,
    const float* __restrict__ bias, float* __restrict__ C,
    int K, int ldC)
{
    float acc[4][4][4];
    #pragma unroll
    for (int a = 0; a < 4; a++)
        #pragma unroll
        for (int b = 0; b < 4; b++)
            #pragma unroll
            for (int c = 0; c < 4; c++) acc[a][b][c] = 0.f;

    int m0 = blockIdx.y * 128, n0 = blockIdx.x * 128;
    mma_mainloop(acc, A, W, K, m0, n0);

    int tid = threadIdx.x;
    int lane = tid & 31, wid = tid >> 5;
    int wm = wid >> 2, wn = wid & 3;
    int g = lane >> 2, tig = lane & 3;
    int rowb = m0 + wm*64;
    int colb = n0 + wn*32;
    #pragma unroll
    for (int nt = 0; nt < 4; nt++) {
        int c = colb + nt*8 + 2*tig;
        float b0 = bias[c], b1 = bias[c+1];
        #pragma unroll
        for (int mt = 0; mt < 4; mt++) {
            int r = rowb + mt*16 + g;
            *(float2*)(C + (size_t)r*ldC + c)     = make_float2(acc[mt][nt][0]+b0, acc[mt][nt][1]+b1);
            *(float2*)(C + (size_t)(r+8)*ldC + c) = make_float2(acc[mt][nt][2]+b0, acc[mt][nt][3]+b1);
        }
    }
}

// ================= bf16 GEMM core (m16n8k16, ldmatrix), 2-stage =================
__device__ __forceinline__ void mma_bf16_mainloop(
    float acc[4][4][4],
    const __nv_bfloat16* __restrict__ A, const __nv_bfloat16* __restrict__ W,
    int K, int m0, int n0)
{
    __shared__ uint32_t As[2][128][20];
    __shared__ uint32_t Bs[2][128][20];
    int tid  = threadIdx.x;
    int lane = tid & 31, wid = tid >> 5;
    int wm = wid >> 2, wn = wid & 3;

    int a_row = (lane & 7) + ((lane >> 3) & 1) * 8;
    int a_wrd = (lane >> 4) * 4;
    int b_row = lane & 7;
    int b_wrd = ((lane >> 3) & 1) * 4;

    int r0c = tid >> 2, r1c = r0c + 64;
    int cw = (tid & 3) * 4;   // word col
    int ce = (tid & 3) * 8;   // element col
    const __nv_bfloat16* pa0 = A + (size_t)(m0 + r0c)*K + ce;
    const __nv_bfloat16* pa1 = A + (size_t)(m0 + r1c)*K + ce;
    const __nv_bfloat16* pb0 = W + (size_t)(n0 + r0c)*K + ce;
    const __nv_bfloat16* pb1 = W + (size_t)(n0 + r1c)*K + ce;

    int niter = K >> 5;
    cp_async16(&As[0][r0c][cw], pa0);
    cp_async16(&As[0][r1c][cw], pa1);
    cp_async16(&Bs[0][r0c][cw], pb0);
    cp_async16(&Bs[0][r1c][cw], pb1);
    cp_commit();

    for (int it = 0; it < niter; it++) {
        int st = it & 1;
        if (it + 1 < niter) {
            int off = (it + 1) << 5;
            int sn = st ^ 1;
            cp_async16(&As[sn][r0c][cw], pa0 + off);
            cp_async16(&As[sn][r1c][cw], pa1 + off);
            cp_async16(&Bs[sn][r0c][cw], pb0 + off);
            cp_async16(&Bs[sn][r1c][cw], pb1 + off);
            cp_commit();
            cp_wait<1>();
        } else {
            cp_wait<0>();
        }
        __syncthreads();
        #pragma unroll
        for (int ks = 0; ks < 2; ks++) {
            int kb = ks*8;
            uint32_t af[4][4], bf[4][2];
            #pragma unroll
            for (int mt = 0; mt < 4; mt++) {
                int r0 = wm*64 + mt*16;
                ldsm_x4(af[mt][0], af[mt][1], af[mt][2], af[mt][3],
                        &As[st][r0 + a_row][kb + a_wrd]);
            }
            #pragma unroll
            for (int nt = 0; nt < 4; nt++) {
                int c0 = wn*32 + nt*8;
                ldsm_x2(bf[nt][0], bf[nt][1],
                        &Bs[st][c0 + b_row][kb + b_wrd]);
            }
            #pragma unroll
            for (int mt = 0; mt < 4; mt++)
                #pragma unroll
                for (int nt = 0; nt < 4; nt++) {
                    asm volatile(
                        "mma.sync.aligned.m16n8k16.row.col.f32.bf16.bf16.f32 "
                        "{%0,%1,%2,%3}, {%4,%5,%6,%7}, {%8,%9}, {%0,%1,%2,%3};\n"
                        : "+f"(acc[mt][nt][0]), "+f"(acc[mt][nt][1]),
                          "+f"(acc[mt][nt][2]), "+f"(acc[mt][nt][3])
                        : "r"(af[mt][0]), "r"(af[mt][1]),
                          "r"(af[mt][2]), "r"(af[mt][3]),
                          "r"(bf[nt][0]), "r"(bf[nt][1]));
                }
        }
        __syncthreads();
    }
}

// bf16 GEMM -> fp32 out (+bias)
__global__ __launch_bounds__(256, 2) void gemm_bf_f32_kernel(
    const __nv_bfloat16* __restrict__ A, const __nv_bfloat16* __restrict__ W,
    const float* __restrict__ bias, float* __restrict__ C, int K, int ldC)
{
    float acc[4][4][4];
    #pragma unroll
    for (int a = 0; a < 4; a++)
        #pragma unroll
        for (int b = 0; b < 4; b++)
            #pragma unroll
            for (int c = 0; c < 4; c++) acc[a][b][c] = 0.f;
    int m0 = blockIdx.y * 128, n0 = blockIdx.x * 128;
    mma_bf16_mainloop(acc, A, W, K, m0, n0);

    int tid = threadIdx.x;
    int lane = tid & 31, wid = tid >> 5;
    int wm = wid >> 2, wn = wid & 3;
    int g = lane >> 2, tig = lane & 3;
    int rowb = m0 + wm*64, colb = n0 + wn*32;
    #pragma unroll
    for (int nt = 0; nt < 4; nt++) {
        int c = colb + nt*8 + 2*tig;
        float b0 = bias[c], b1 = bias[c+1];
        #pragma unroll
        for (int mt = 0; mt < 4; mt++) {
            int r = rowb + mt*16 + g;
            *(float2*)(C + (size_t)r*ldC + c)     = make_float2(acc[mt][nt][0]+b0, acc[mt][nt][1]+b1);
            *(float2*)(C + (size_t)(r+8)*ldC + c) = make_float2(acc[mt][nt][2]+b0, acc[mt][nt][3]+b1);
        }
    }
}

// bf16 GEMM -> bf16 out (+bias, +relu)  (FF1 path)
__global__ __launch_bounds__(256, 2) void gemm_bf_bf_relu_kernel(
    const __nv_bfloat16* __restrict__ A, const __nv_bfloat16* __restrict__ W,
    const float* __restrict__ bias, __nv_bfloat16* __restrict__ C, int K, int ldC)
{
    float acc[4][4][4];
    #pragma unroll
    for (int a = 0; a < 4; a++)
        #pragma unroll
        for (int b = 0; b < 4; b++)
            #pragma unroll
            for (int c = 0; c < 4; c++) acc[a][b][c] = 0.f;
    int m0 = blockIdx.y * 128, n0 = blockIdx.x * 128;
    mma_bf16_mainloop(acc, A, W, K, m0, n0);

    int tid = threadIdx.x;
    int lane = tid & 31, wid = tid >> 5;
    int wm = wid >> 2, wn = wid & 3;
    int g = lane >> 2, tig = lane & 3;
    int rowb = m0 + wm*64, colb = n0 + wn*32;
    #pragma unroll
    for (int nt = 0; nt < 4; nt++) {
        int c = colb + nt*8 + 2*tig;
        float b0 = bias[c], b1 = bias[c+1];
        #pragma unroll
        for (int mt = 0; mt < 4; mt++) {
            int r = rowb + mt*16 + g;
            float v0 = fmaxf(acc[mt][nt][0]+b0, 0.f);
            float v1 = fmaxf(acc[mt][nt][1]+b1, 0.f);
            float v2 = fmaxf(acc[mt][nt][2]+b0, 0.f);
            float v3 = fmaxf(acc[mt][nt][3]+b1, 0.f);
            *(__nv_bfloat162*)(C + (size_t)r*ldC + c)     = __floats2bfloat162_rn(v0, v1);
            *(__nv_bfloat162*)(C + (size_t)(r+8)*ldC + c) = __floats2bfloat162_rn(v2, v3);
        }
    }
}

// ================= fp8 decoder GEMM + fused online-lse partials =================
// A: q_x [NROWS,1024] e4m3 (x*SX), W: q_dec [NTOK,1024] e4m3 (w*SW).
// m16n8k32 fp8 mma; BK=64 fp8 per chunk (64B rows), 2-stage; m-tiles adjacent.
__global__ __launch_bounds__(256, 2) void gemm_lse_fp8_kernel(
    const uint8_t* __restrict__ A, const uint8_t* __restrict__ W, int K)
{
    __shared__ uint32_t As[2][128][20];   // 16 words used = 64 fp8
    __shared__ uint32_t Bs[2][128][20];
    __shared__ float red_m[4][128];
    __shared__ float red_s[4][128];

    float acc[4][4][4];
    #pragma unroll
    for (int a = 0; a < 4; a++)
        #pragma unroll
        for (int b = 0; b < 4; b++)
            #pragma unroll
            for (int c = 0; c < 4; c++) acc[a][b][c] = 0.f;

    int m0 = blockIdx.x * 128, n0 = blockIdx.y * 128;
    int nblk = blockIdx.y;

    int tid  = threadIdx.x;
    int lane = tid & 31, wid = tid >> 5;
    int wm = wid >> 2, wn = wid & 3;
    int g = lane >> 2, tig = lane & 3;

    int a_row = (lane & 7) + ((lane >> 3) & 1) * 8;
    int a_wrd = (lane >> 4) * 4;           // 0 or 4 words (16B halves of k32)
    int b_row = lane & 7;
    int b_wrd = ((lane >> 3) & 1) * 4;

    int r0c = tid >> 2, r1c = r0c + 64;
    int cw = (tid & 3) * 4;   // word col
    int ce = (tid & 3) * 16;  // fp8 element col (= bytes)
    int nr0 = n0 + r0c; nr0 = (nr0 < NTOK) ? nr0 : (NTOK - 1);
    int nr1 = n0 + r1c; nr1 = (nr1 < NTOK) ? nr1 : (NTOK - 1);
    const uint8_t* pa0 = A + (size_t)(m0 + r0c)*K + ce;
    const uint8_t* pa1 = A + (size_t)(m0 + r1c)*K + ce;
    const uint8_t* pb0 = W + (size_t)nr0*K + ce;
    const uint8_t* pb1 = W + (size_t)nr1*K + ce;

    int niter = K >> 6;   // 16 chunks of 64 fp8
    cp_async16(&As[0][r0c][cw], pa0);
    cp_async16(&As[0][r1c][cw], pa1);
    cp_async16(&Bs[0][r0c][cw], pb0);
    cp_async16(&Bs[0][r1c][cw], pb1);
    cp_commit();

    for (int it = 0; it < niter; it++) {
        int st = it & 1;
        if (it + 1 < niter) {
            int off = (it + 1) << 6;   // bytes
            int sn = st ^ 1;
            cp_async16(&As[sn][r0c][cw], pa0 + off);
            cp_async16(&As[sn][r1c][cw], pa1 + off);
            cp_async16(&Bs[sn][r0c][cw], pb0 + off);
            cp_async16(&Bs[sn][r1c][cw], pb1 + off);
            cp_commit();
            cp_wait<1>();
        } else {
            cp_wait<0>();
        }
        __syncthreads();
        #pragma unroll
        for (int ks = 0; ks < 2; ks++) {
            int kb = ks*8;   // 8 words = 32 fp8 per mma k-step
            uint32_t af[4][4], bf[4][2];
            #pragma unroll
            for (int mt = 0; mt < 4; mt++) {
                int r0 = wm*64 + mt*16;
                ldsm_x4(af[mt][0], af[mt][1], af[mt][2], af[mt][3],
                        &As[st][r0 + a_row][kb + a_wrd]);
            }
            #pragma unroll
            for (int nt = 0; nt < 4; nt++) {
                int c0 = wn*32 + nt*8;
                ldsm_x2(bf[nt][0], bf[nt][1],
                        &Bs[st][c0 + b_row][kb + b_wrd]);
            }
            #pragma unroll
            for (int mt = 0; mt < 4; mt++)
                #pragma unroll
                for (int nt = 0; nt < 4; nt++) {
                    asm volatile(
                        "mma.sync.aligned.m16n8k32.row.col.f32.e4m3.e4m3.f32 "
                        "{%0,%1,%2,%3}, {%4,%5,%6,%7}, {%8,%9}, {%0,%1,%2,%3};\n"
                        : "+f"(acc[mt][nt][0]), "+f"(acc[mt][nt][1]),
                          "+f"(acc[mt][nt][2]), "+f"(acc[mt][nt][3])
                        : "r"(af[mt][0]), "r"(af[mt][1]),
                          "r"(af[mt][2]), "r"(af[mt][3]),
                          "r"(bf[nt][0]), "r"(bf[nt][1]));
                }
        }
        __syncthreads();
    }

    // unscale
    #pragma unroll
    for (int a = 0; a < 4; a++)
        #pragma unroll
        for (int b = 0; b < 4; b++)
            #pragma unroll
            for (int c = 0; c < 4; c++) acc[a][b][c] *= INV_SXW;

    // fused lse partials
    int colb = n0 + wn*32;
    #pragma unroll
    for (int mt = 0; mt < 4; mt++) {
        #pragma unroll
        for (int h = 0; h < 2; h++) {
            float m = -INFINITY;
            #pragma unroll
            for (int nt = 0; nt < 4; nt++) {
                int c = colb + nt*8 + 2*tig;
                if (c     < NTOK) m = fmaxf(m, acc[mt][nt][h*2+0]);
                if (c + 1 < NTOK) m = fmaxf(m, acc[mt][nt][h*2+1]);
            }
            m = fmaxf(m, __shfl_xor_sync(0xffffffffu, m, 1));
            m = fmaxf(m, __shfl_xor_sync(0xffffffffu, m, 2));
            float s = 0.f;
            #pragma unroll
            for (int nt = 0; nt < 4; nt++) {
                int c = colb + nt*8 + 2*tig;
                if (c     < NTOK) s += __expf(acc[mt][nt][h*2+0] - m);
                if (c + 1 < NTOK) s += __expf(acc[mt][nt][h*2+1] - m);
            }
            s += __shfl_xor_sync(0xffffffffu, s, 1);
            s += __shfl_xor_sync(0xffffffffu, s, 2);
            if (tig == 0) {
                int lr = wm*64 + mt*16 + h*8 + g;
                red_m[wn][lr] = m;
                red_s[wn][lr] = s;
            }
        }
    }
    __syncthreads();
    if (tid < 128) {
        float m0v = red_m[0][tid], m1v = red_m[1][tid];
        float m2v = red_m[2][tid], m3v = red_m[3][tid];
        float mx = fmaxf(fmaxf(m0v, m1v), fmaxf(m2v, m3v));
        float s = red_s[0][tid]*__expf(m0v-mx) + red_s[1][tid]*__expf(m1v-mx)
                + red_s[2][tid]*__expf(m2v-mx) + red_s[3][tid]*__expf(m3v-mx);
        int row = m0 + tid;
        g_pmax[(size_t)row*NBLK_V + nblk] = mx;
        g_psum[(size_t)row*NBLK_V + nblk] = s;
    }
}

__global__ void lse_reduce_kernel()
{
    int r = blockIdx.x, tid = threadIdx.x;
    __shared__ float red[128];
    float m = -INFINITY;
    for (int i = tid; i < NBLK_V; i += 128) m = fmaxf(m, g_pmax[(size_t)r*NBLK_V + i]);
    red[tid] = m; __syncthreads();
    for (int s = 64; s > 0; s >>= 1) { if (tid < s) red[tid] = fmaxf(red[tid], red[tid+s]); __syncthreads(); }
    float gm = red[0]; __syncthreads();
    double sum = 0.0;
    for (int i = tid; i < NBLK_V; i += 128)
        sum += (double)g_psum[(size_t)r*NBLK_V + i] * exp((double)g_pmax[(size_t)r*NBLK_V + i] - (double)gm);
    __shared__ double redd[128];
    redd[tid] = sum; __syncthreads();
    for (int s = 64; s > 0; s >>= 1) { if (tid < s) redd[tid] += redd[tid+s]; __syncthreads(); }
    if (tid == 0) g_lse[r] = gm + (float)log(redd[0]);
}

// ---------------- small-M GEMM ----------------
__global__ void rowdot_kernel(
    const float* __restrict__ A, long strideA,
    const float* __restrict__ W, const float* __restrict__ bias,
    float* __restrict__ C, long strideC,
    int M, int K, float alpha, int relu)
{
    int n = blockIdx.x;
    int tid = threadIdx.x;   // 128
    const float* w = W + (size_t)n * K;
    __shared__ float red[128];
    for (int m = 0; m < M; m++) {
        const float* a = A + (size_t)m * strideA;
        float s = 0.f;
        for (int k = tid; k < K; k += 128) s += a[k]*w[k];
        red[tid] = s; __syncthreads();
        for (int st = 64; st > 0; st >>= 1) { if (tid < st) red[tid] += red[tid+st]; __syncthreads(); }
        if (tid == 0) {
            float v = alpha*red[0] + (bias ? bias[n] : 0.f);
            if (relu) v = fmaxf(v, 0.f);
            C[(size_t)m*strideC + n] = v;
        }
        __syncthreads();
    }
}

// ---------------- attention, 8 queries per block, bf16 out ----------------
#define QT 8
__global__ __launch_bounds__(256) void attn8_kernel(
    const float* __restrict__ qkv, __nv_bfloat16* __restrict__ out)
{
    int qt = blockIdx.x, h = blockIdx.y, b = blockIdx.z;
    int tid = threadIdx.x;
    __shared__ float qs[QT][DHEAD];
    __shared__ float sc[QT][NSEQ];
    __shared__ float den[QT];
    const float* base = qkv + (size_t)b*NSEQ*QKV_LD;
    if (tid < 128) {
        int q = tid >> 4;
        int c = (tid & 15) * 4;
        *(float4*)&qs[q][c] =
            *(const float4*)(base + (size_t)(qt*QT+q)*QKV_LD + h*DHEAD + c);
    }
    __syncthreads();
    {
        int j = tid;
        float4 kreg[16];
        const float4* kr = (const float4*)(base + (size_t)j*QKV_LD + D_MODEL + h*DHEAD);
        #pragma unroll
        for (int t = 0; t < 16; t++) kreg[t] = kr[t];
        #pragma unroll
        for (int q = 0; q < QT; q++) {
            float d = 0.f;
            #pragma unroll
            for (int t = 0; t < 16; t++) {
                float4 q4 = *(float4*)&qs[q][t*4];
                d += q4.x*kreg[t].x + q4.y*kreg[t].y + q4.z*kreg[t].z + q4.w*kreg[t].w;
            }
            sc[q][j] = d * 0.125f;
        }
    }
    __syncthreads();
    {
        int w = tid >> 5, lane = tid & 31;
        float v[8];
        float m = -INFINITY;
        #pragma unroll
        for (int t = 0; t < 8; t++) { v[t] = sc[w][lane + 32*t]; m = fmaxf(m, v[t]); }
        #pragma unroll
        for (int o = 16; o; o >>= 1) m = fmaxf(m, __shfl_xor_sync(0xffffffffu, m, o));
        float s = 0.f;
        #pragma unroll
        for (int t = 0; t < 8; t++) { v[t] = expf(v[t]-m); s += v[t]; }
        #pragma unroll
        for (int o = 16; o; o >>= 1) s += __shfl_xor_sync(0xffffffffu, s, o);
        #pragma unroll
        for (int t = 0; t < 8; t++) sc[w][lane + 32*t] = v[t];
        if (lane == 0) den[w] = s;
    }
    __syncthreads();
    {
        int d = tid & 63, qp = tid >> 6;
        int q0 = qp*2, q1 = qp*2+1;
        const float* vb = base + 2*D_MODEL + h*DHEAD + d;
        float a0 = 0.f, a1 = 0.f;
        #pragma unroll 8
        for (int j = 0; j < NSEQ; j++) {
            float v = vb[(size_t)j*QKV_LD];
            a0 += sc[q0][j]*v;
            a1 += sc[q1][j]*v;
        }
        out[((size_t)(b*NSEQ + qt*QT + q0))*D_MODEL + h*DHEAD + d] = __float2bfloat16(a0/den[q0]);
        out[((size_t)(b*NSEQ + qt*QT + q1))*D_MODEL + h*DHEAD + d] = __float2bfloat16(a1/den[q1]);
    }
}

// ---------------- loc attention (single query per (h,b)), fp32 out ----------------
__global__ __launch_bounds__(256) void attn_kernel(
    const float* __restrict__ qkv, float* __restrict__ out, int nq, int sq_base)
{
    int qi = blockIdx.x, h = blockIdx.y, b = blockIdx.z;
    int sq = sq_base + qi;
    int tid = threadIdx.x;
    __shared__ float4 qrow[DHEAD/4];
    __shared__ float sc[NSEQ];
    __shared__ float red[256];
    __shared__ float sden;
    __shared__ float osum[4][DHEAD];
    const float* base = qkv + (size_t)b * NSEQ * QKV_LD;
    if (tid < DHEAD/4)
        qrow[tid] = ((const float4*)(base + (size_t)sq*QKV_LD + h*DHEAD))[tid];
    __syncthreads();
    {
        const float4* krow = (const float4*)(base + (size_t)tid*QKV_LD + D_MODEL + h*DHEAD);
        float d = 0.f;
        #pragma unroll
        for (int t = 0; t < DHEAD/4; t++) {
            float4 k4 = krow[t];
            float4 q4 = qrow[t];
            d += q4.x*k4.x + q4.y*k4.y + q4.z*k4.z + q4.w*k4.w;
        }
        sc[tid] = d * 0.125f;
    }
    __syncthreads();
    red[tid] = sc[tid]; __syncthreads();
    for (int s = 128; s > 0; s >>= 1) { if (tid < s) red[tid] = fmaxf(red[tid], red[tid+s]); __syncthreads(); }
    float mx = red[0]; __syncthreads();
    float e = expf(sc[tid] - mx);
    red[tid] = e; __syncthreads();
    for (int s = 128; s > 0; s >>= 1) { if (tid < s) red[tid] += red[tid+s]; __syncthreads(); }
    if (tid == 0) sden = red[0];
    __syncthreads();
    sc[tid] = e;
    __syncthreads();
    int d = tid & 63, g = tid >> 6;
    const float* vb = base + 2*D_MODEL + h*DHEAD + d;
    float o = 0.f;
    for (int j = g*64; j < (g+1)*64; j++) o += sc[j] * vb[(size_t)j*QKV_LD];
    osum[g][d] = o; __syncthreads();
    if (tid < DHEAD) {
        float r = (osum[0][tid]+osum[1][tid]+osum[2][tid]+osum[3][tid]) / sden;
        out[((size_t)(b*nq + qi))*D_MODEL + h*DHEAD + tid] = r;
    }
}

// ---------------- residual + layernorm (fp32 out + optional bf16 mirror) ----------
__global__ void ln_kernel(
    const float* __restrict__ in1, long s1,
    const float* __restrict__ in2, long s2,
    float* __restrict__ out, long so,
    __nv_bfloat16* __restrict__ outh,
    const float* __restrict__ gam, const float* __restrict__ bet)
{
    int r = blockIdx.x, tid = threadIdx.x;
    __shared__ float xr[D_MODEL];
    __shared__ float red[256];
    const float* p1 = in1 + (size_t)r*s1;
    const float* p2 = in2 + (size_t)r*s2;
    float ls = 0.f;
    for (int d = tid; d < D_MODEL; d += 256) { float v = p1[d]+p2[d]; xr[d] = v; ls += v; }
    red[tid] = ls; __syncthreads();
    for (int s = 128; s > 0; s >>= 1) { if (tid < s) red[tid] += red[tid+s]; __syncthreads(); }
    float mean = red[0] * (1.f/D_MODEL); __syncthreads();
    float lv = 0.f;
    for (int d = tid; d < D_MODEL; d += 256) { float t = xr[d]-mean; lv += t*t; }
    red[tid] = lv; __syncthreads();
    for (int s = 128; s > 0; s >>= 1) { if (tid < s) red[tid] += red[tid+s]; __syncthreads(); }
    float rstd = 1.f / sqrtf(red[0]*(1.f/D_MODEL) + 1e-5f);
    for (int d = tid; d < D_MODEL; d += 256) {
        float v = (xr[d]-mean)*rstd*gam[d] + bet[d];
        out[(size_t)r*so + d] = v;
        if (outh) outh[(size_t)r*D_MODEL + d] = __float2bfloat16(v);
    }
}

// ---------------- gating statistics + top-k + softmax + importance ----------------
__global__ void stats_kernel(const float* __restrict__ w, const float* __restrict__ noise)
{
    __shared__ float tot[NEXP];
    __shared__ double redd[256];
    __shared__ float fv[256];
    __shared__ int   fi[256];
    __shared__ float topv[NKTOP];
    __shared__ double smean, sstd;
    int tid = threadIdx.x;
    double ls = 0.0;
    for (int n = tid; n < NEXP; n += 256) {
        float f = 0.25f*(w[n] + w[NEXP+n] + w[2*NEXP+n] + w[3*NEXP+n]);
        tot[n] = f; ls += (double)f;
    }
    redd[tid] = ls; __syncthreads();
    for (int s = 128; s > 0; s >>= 1) { if (tid < s) redd[tid] += redd[tid+s]; __syncthreads(); }
    if (tid == 0) smean = redd[0] / NEXP;
    __syncthreads();
    double mfm = smean;
    ls = 0.0;
    for (int n = tid; n < NEXP; n += 256) { double t = (double)tot[n]-mfm; ls += t*t; }
    redd[tid] = ls; __syncthreads();
    for (int s = 128; s > 0; s >>= 1) { if (tid < s) redd[tid] += redd[tid+s]; __syncthreads(); }
    if (tid == 0) sstd = sqrt(redd[0] / (NEXP-1));
    __syncthreads();
    float stdfm = (float)sstd;
    for (int n = tid; n < NEXP; n += 256) tot[n] = tot[n] + noise[n]*stdfm;
    __syncthreads();
    ls = 0.0;
    for (int n = tid; n < NEXP; n += 256) ls += (double)tot[n];
    redd[tid] = ls; __syncthreads();
    for (int s = 128; s > 0; s >>= 1) { if (tid < s) redd[tid] += redd[tid+s]; __syncthreads(); }
    if (tid == 0) smean = redd[0] / NEXP;
    __syncthreads();
    double mt = smean;
    ls = 0.0;
    for (int n = tid; n < NEXP; n += 256) { double t = (double)tot[n]-mt; ls += t*t; }
    redd[tid] = ls; __syncthreads();
    for (int s = 128; s > 0; s >>= 1) { if (tid < s) redd[tid] += redd[tid+s]; __syncthreads(); }
    if (tid == 0) {
        double st = sqrt(redd[0] / (NEXP-1));
        double ratio = st / mt;
        g_stats[20] = (float)(0.1 * ratio * ratio);
    }
    __syncthreads();
    for (int it = 0; it < NKTOP; it++) {
        float bv = -INFINITY; int bi = 0x7fffffff;
        for (int n = tid; n < NEXP; n += 256) {
            float v = tot[n];
            if (v > bv || (v == bv && n < bi)) { bv = v; bi = n; }
        }
        fv[tid] = bv; fi[tid] = bi; __syncthreads();
        for (int s = 128; s > 0; s >>= 1) {
            if (tid < s) {
                float v2 = fv[tid+s]; int i2 = fi[tid+s];
                if (v2 > fv[tid] || (v2 == fv[tid] && i2 < fi[tid])) { fv[tid] = v2; fi[tid] = i2; }
            }
            __syncthreads();
        }
        if (tid == 0) { topv[it] = fv[0]; tot[fi[0]] = -INFINITY; }
        __syncthreads();
    }
    if (tid == 0) {
        float m = topv[0];
        float s = 0.f;
        float e[NKTOP];
        for (int k = 0; k < NKTOP; k++) { e[k] = expf(topv[k]-m); s += e[k]; }
        for (int k = 0; k < NKTOP; k++) g_stats[k] = e[k]/s;
    }
}

// ---------------- response mixture (fp32 + bf16 mirror) ----------------
__global__ void mix_kernel(const float* __restrict__ responses)
{
    __shared__ float w[NKTOP];
    if (threadIdx.x < NKTOP) w[threadIdx.x] = g_stats[threadIdx.x];
    __syncthreads();
    int i = blockIdx.x*blockDim.x + threadIdx.x;
    if (i < (NROWS*D_MODEL)/4) {
        float4 s = make_float4(0.f, 0.f, 0.f, 0.f);
        #pragma unroll
        for (int k = 0; k < NKTOP; k++) {
            float4 v = ((const float4*)responses)[(size_t)k*((NROWS*D_MODEL)/4) + i];
            float wk = w[k];
            s.x += wk*v.x; s.y += wk*v.y; s.z += wk*v.z; s.w += wk*v.w;
        }
        ((float4*)g_x)[i] = s;
        ((__nv_bfloat162*)h_x)[2*i+0] = __floats2bfloat162_rn(s.x, s.y);
        ((__nv_bfloat162*)h_x)[2*i+1] = __floats2bfloat162_rn(s.z, s.w);
    }
}

// ---------------- label logit + final loss ----------------
__global__ void lablogit_kernel(const int* __restrict__ inputs, const float* __restrict__ dec_w)
{
    int s = blockIdx.x, b = blockIdx.y, tid = threadIdx.x;
    int lbl = inputs[b*NSEQ + s + 1];
    const float* a = g_x + ((size_t)(b*NSEQ + s))*D_MODEL;
    const float* wp = dec_w + (size_t)lbl*D_MODEL;
    __shared__ float red[128];
    float acc = 0.f;
    for (int k = tid; k < D_MODEL; k += 128) acc += a[k]*wp[k];
    red[tid] = acc; __syncthreads();
    for (int st = 64; st > 0; st >>= 1) { if (tid < st) red[tid] += red[tid+st]; __syncthreads(); }
    if (tid == 0) g_lab[b*(NSEQ-1)+s] = red[0];
}

__global__ void final_kernel(float* __restrict__ out)
{
    __shared__ double red[256];
    int tid = threadIdx.x;
    double s = 0.0;
    for (int i = tid; i < NB*(NSEQ-1); i += 256) {
        int b = i/(NSEQ-1), sp = i%(NSEQ-1);
        s += (double)g_lab[i] - (double)g_lse[b*NSEQ+sp];
    }
    red[tid] = s; __syncthreads();
    for (int st = 128; st > 0; st >>= 1) { if (tid < st) red[tid] += red[tid+st]; __syncthreads(); }
    if (tid == 0) {
        double ce = -red[0] / (double)(NB*(NSEQ-1));
        out[0] = (float)(ce + (double)g_stats[20]);
    }
}

// ---------------- host driver ----------------
extern "C" void kernel_launch(void* const* d_in, const int* in_sizes, int n_in,
                              void* d_out, int out_size)
{
    (void)in_sizes; (void)n_in; (void)out_size;
    const int*   inputs    = (const int*)  d_in[0];
    const float* responses = (const float*)d_in[1];
    const float* noise     = (const float*)d_in[2];
    const float* emb       = (const float*)d_in[3];
    const float* loc_Wqkv  = (const float*)d_in[4];
    const float* loc_bqkv  = (const float*)d_in[5];
    const float* loc_Wo    = (const float*)d_in[6];
    const float* loc_bo    = (const float*)d_in[7];
    const float* loc_ln1g  = (const float*)d_in[8];
    const float* loc_ln1b  = (const float*)d_in[9];
    const float* loc_W1    = (const float*)d_in[10];
    const float* loc_b1    = (const float*)d_in[11];
    const float* loc_W2    = (const float*)d_in[12];
    const float* loc_b2    = (const float*)d_in[13];
    const float* loc_ln2g  = (const float*)d_in[14];
    const float* loc_ln2b  = (const float*)d_in[15];
    const float* enc_Wqkv  = (const float*)d_in[16];
    const float* enc_bqkv  = (const float*)d_in[17];
    const float* enc_Wo    = (const float*)d_in[18];
    const float* enc_bo    = (const float*)d_in[19];
    const float* enc_ln1g  = (const float*)d_in[20];
    const float* enc_ln1b  = (const float*)d_in[21];
    const float* enc_W1    = (const float*)d_in[22];
    const float* enc_b1    = (const float*)d_in[23];
    const float* enc_W2    = (const float*)d_in[24];
    const float* enc_b2    = (const float*)d_in[25];
    const float* enc_ln2g  = (const float*)d_in[26];
    const float* enc_ln2b  = (const float*)d_in[27];
    const float* gate_w    = (const float*)d_in[28];
    const float* gate_b    = (const float*)d_in[29];
    const float* dec_w     = (const float*)d_in[30];
    float* out = (float*)d_out;

    float *p_x, *p_qkv, *p_tmp;
    float *p_sm_attn, *p_sm_x, *p_sm_tmp, *p_sm_ctx, *p_sm_ffh;
    __nv_bfloat16 *p_hWqkv, *p_hWo, *p_hW1, *p_hW2, *p_hx, *p_hattn, *p_hffh;
    uint8_t *p_qx, *p_qdec;
    cudaGetSymbolAddress((void**)&p_x, g_x);
    cudaGetSymbolAddress((void**)&p_qkv, g_qkv);
    cudaGetSymbolAddress((void**)&p_tmp, g_tmp);
    cudaGetSymbolAddress((void**)&p_sm_attn, g_sm_attn);
    cudaGetSymbolAddress((void**)&p_sm_x, g_sm_x);
    cudaGetSymbolAddress((void**)&p_sm_tmp, g_sm_tmp);
    cudaGetSymbolAddress((void**)&p_sm_ctx, g_sm_ctx);
    cudaGetSymbolAddress((void**)&p_sm_ffh, g_sm_ffh);
    cudaGetSymbolAddress((void**)&p_hWqkv, h_Wqkv);
    cudaGetSymbolAddress((void**)&p_hWo, h_Wo);
    cudaGetSymbolAddress((void**)&p_hW1, h_W1);
    cudaGetSymbolAddress((void**)&p_hW2, h_W2);
    cudaGetSymbolAddress((void**)&p_hx, h_x);
    cudaGetSymbolAddress((void**)&p_hattn, h_attn);
    cudaGetSymbolAddress((void**)&p_hffh, h_ffh);
    cudaGetSymbolAddress((void**)&p_qx, q_x);
    cudaGetSymbolAddress((void**)&p_qdec, q_dec);

    // ---- capture-forked side stream for weight conversions ----
    cudaStream_t s2;
    cudaStreamCreateWithFlags(&s2, cudaStreamNonBlocking);
    cudaEvent_t evFork, evEnc, evDec;
    cudaEventCreateWithFlags(&evFork, cudaEventDisableTiming);
    cudaEventCreateWithFlags(&evEnc,  cudaEventDisableTiming);
    cudaEventCreateWithFlags(&evDec,  cudaEventDisableTiming);

    cudaEventRecord(evFork, 0);
    cudaStreamWaitEvent(s2, evFork, 0);

    f2h_kernel<<<(2*QKV_LD*D_MODEL/8 + 255)/256, 256, 0, s2>>>(enc_Wqkv, p_hWqkv, 2*QKV_LD*D_MODEL/4);
    f2h_kernel<<<(2*D_MODEL*D_MODEL/8 + 255)/256, 256, 0, s2>>>(enc_Wo, p_hWo, 2*D_MODEL*D_MODEL/4);
    f2h_kernel<<<(2*FF_DIM*D_MODEL/8 + 255)/256, 256, 0, s2>>>(enc_W1, p_hW1, 2*FF_DIM*D_MODEL/4);
    f2h_kernel<<<(2*D_MODEL*FF_DIM/8 + 255)/256, 256, 0, s2>>>(enc_W2, p_hW2, 2*D_MODEL*FF_DIM/4);
    cudaEventRecord(evEnc, s2);
    q8_kernel<<<(NTOK*D_MODEL/8 + 255)/256, 256, 0, s2>>>(dec_w, p_qdec, NTOK*D_MODEL/4, SW);
    cudaEventRecord(evDec, s2);

    // default stream: embed + loc layer + gating (overlapped with conversions)
    embed_kernel<<<NROWS, 256>>>(inputs, emb);
    gemm_tc_kernel<<<dim3(2048/128, NROWS/128), 256>>>(
        p_x, loc_Wqkv + (size_t)D_MODEL*D_MODEL, loc_bqkv + D_MODEL,
        p_qkv + D_MODEL, D_MODEL, QKV_LD);
    rowdot_kernel<<<D_MODEL, 128>>>(
        p_x + (size_t)(NSEQ-1)*D_MODEL, (long)NSEQ*D_MODEL,
        loc_Wqkv, loc_bqkv,
        p_qkv + (size_t)(NSEQ-1)*QKV_LD, (long)NSEQ*QKV_LD,
        NB, D_MODEL, 1.f, 0);
    attn_kernel<<<dim3(1, NHEAD, NB), 256>>>(p_qkv, p_sm_attn, 1, NSEQ-1);
    rowdot_kernel<<<D_MODEL, 128>>>(p_sm_attn, D_MODEL, loc_Wo, loc_bo,
                                    p_sm_tmp, D_MODEL, NB, D_MODEL, 1.f, 0);
    ln_kernel<<<NB, 256>>>(p_x + (size_t)(NSEQ-1)*D_MODEL, (long)NSEQ*D_MODEL,
                           p_sm_tmp, D_MODEL, p_sm_x, D_MODEL, (__nv_bfloat16*)0,
                           loc_ln1g, loc_ln1b);
    rowdot_kernel<<<FF_DIM, 128>>>(p_sm_x, D_MODEL, loc_W1, loc_b1,
                                   p_sm_ffh, FF_DIM, NB, D_MODEL, 1.f, 1);
    rowdot_kernel<<<D_MODEL, 128>>>(p_sm_ffh, FF_DIM, loc_W2, loc_b2,
                                    p_sm_tmp, D_MODEL, NB, FF_DIM, 1.f, 0);
    ln_kernel<<<NB, 256>>>(p_sm_x, D_MODEL, p_sm_tmp, D_MODEL,
                           p_sm_ctx, D_MODEL, (__nv_bfloat16*)0,
                           loc_ln2g, loc_ln2b);

    rowdot_kernel<<<NEXP, 128>>>(p_sm_ctx, D_MODEL, gate_w, gate_b,
                                 out + 1, NEXP, NB, D_MODEL, 32.f, 0);
    stats_kernel<<<1, 256>>>(out + 1, noise);
    mix_kernel<<<(NROWS*D_MODEL/4 + 255)/256, 256>>>(responses);

    // join: encoder weights must be converted before the encoder loop
    cudaStreamWaitEvent(0, evEnc, 0);

    // two encoder layers (bf16 tensor cores)
    for (int l = 0; l < 2; l++) {
        const __nv_bfloat16* Wqkv = p_hWqkv + (size_t)l*QKV_LD*D_MODEL;
        const float*         bqkv = enc_bqkv + (size_t)l*QKV_LD;
        const __nv_bfloat16* Wo   = p_hWo   + (size_t)l*D_MODEL*D_MODEL;
        const float*         bo   = enc_bo  + (size_t)l*D_MODEL;
        const float* g1   = enc_ln1g + (size_t)l*D_MODEL;
        const float* b1l  = enc_ln1b + (size_t)l*D_MODEL;
        const __nv_bfloat16* W1   = p_hW1   + (size_t)l*FF_DIM*D_MODEL;
        const float*         bb1  = enc_b1  + (size_t)l*FF_DIM;
        const __nv_bfloat16* W2   = p_hW2   + (size_t)l*D_MODEL*FF_DIM;
        const float*         bb2  = enc_b2  + (size_t)l*D_MODEL;
        const float* g2   = enc_ln2g + (size_t)l*D_MODEL;
        const float* b2l  = enc_ln2b + (size_t)l*D_MODEL;

        gemm_bf_f32_kernel<<<dim3(QKV_LD/128, NROWS/128), 256>>>(
            p_hx, Wqkv, bqkv, p_qkv, D_MODEL, QKV_LD);
        attn8_kernel<<<dim3(NSEQ/QT, NHEAD, NB), 256>>>(p_qkv, p_hattn);
        gemm_bf_f32_kernel<<<dim3(D_MODEL/128, NROWS/128), 256>>>(
            p_hattn, Wo, bo, p_tmp, D_MODEL, D_MODEL);
        ln_kernel<<<NROWS, 256>>>(p_x, D_MODEL, p_tmp, D_MODEL, p_x, D_MODEL, p_hx, g1, b1l);
        gemm_bf_bf_relu_kernel<<<dim3(FF_DIM/128, NROWS/128), 256>>>(
            p_hx, W1, bb1, p_hffh, D_MODEL, FF_DIM);
        gemm_bf_f32_kernel<<<dim3(D_MODEL/128, NROWS/128), 256>>>(
            p_hffh, W2, bb2, p_tmp, FF_DIM, D_MODEL);
        ln_kernel<<<NROWS, 256>>>(p_x, D_MODEL, p_tmp, D_MODEL, p_x, D_MODEL, p_hx, g2, b2l);
    }

    // quantize final activations to fp8
    q8_kernel<<<(NROWS*D_MODEL/8 + 255)/256, 256>>>(p_x, p_qx, NROWS*D_MODEL/4, SX);

    // join: decoder fp8 weights ready
    cudaStreamWaitEvent(0, evDec, 0);

    // fused fp8 decoder GEMM + logsumexp (m-tiles adjacent; fp8 dec_w is L2-resident)
    gemm_lse_fp8_kernel<<<dim3(NROWS/128, NBLK_V), 256>>>(p_qx, p_qdec, D_MODEL);
    lse_reduce_kernel<<<NROWS, 128>>>();
    lablogit_kernel<<<dim3(NSEQ-1, NB), 128>>>(inputs, dec_w);
    final_kernel<<<1, 256>>>(out);

    cudaEventDestroy(evFork);
    cudaEventDestroy(evEnc);
    cudaEventDestroy(evDec);
    cudaStreamDestroy(s2);
}

// round 11
// speedup vs baseline: 1.1298x; 1.0561x over previous
#include <cuda_runtime.h>
#include <cuda_bf16.h>
#include <math.h>
#include <stdint.h>

// ---------------- problem constants ----------------
#define D_MODEL 1024
#define NHEAD   16
#define DHEAD   64
#define FF_DIM  4096
#define NSEQ    256
#define NB      4
#define NTOK    50257
#define NEXP    2000
#define NKTOP   20
#define NROWS   (NB*NSEQ)      // 1024
#define QKV_LD  3072
#define NBLK_V  393            // ceil(50257/128)

// fp8 per-tensor scales
#define SX  16.0f     // activations (post-LN / mix)
#define SW  512.0f    // weights (~0.02)
#define SA  64.0f     // attention outputs (~0.1)
#define SF  32.0f     // FF hidden (post-relu, ~0.3)

// ---------------- scratch (static device memory; no allocation) ----------------
__device__ float g_x    [NROWS*D_MODEL];
__device__ float g_qkv  [NROWS*QKV_LD];
__device__ float g_tmp  [NROWS*D_MODEL];
__device__ float g_sm_attn[NB*D_MODEL];
__device__ float g_sm_x   [NB*D_MODEL];
__device__ float g_sm_tmp [NB*D_MODEL];
__device__ float g_sm_ctx [NB*D_MODEL];
__device__ float g_sm_ffh [NB*FF_DIM];
__device__ float g_pmax[NROWS*NBLK_V];
__device__ float g_psum[NROWS*NBLK_V];
__device__ float g_lse [NROWS];
__device__ float g_lab [NB*(NSEQ-1)];
__device__ float g_stats[32];   // [0..19] jw, [20] imp

// fp8 mirrors
__device__ __align__(256) uint8_t q_Wqkv[2*QKV_LD*D_MODEL];
__device__ __align__(256) uint8_t q_Wo  [2*D_MODEL*D_MODEL];
__device__ __align__(256) uint8_t q_W1  [2*FF_DIM*D_MODEL];
__device__ __align__(256) uint8_t q_W2  [2*D_MODEL*FF_DIM];
__device__ __align__(256) uint8_t q_dec [NTOK*D_MODEL];
__device__ __align__(256) uint8_t q_x   [NROWS*D_MODEL];
__device__ __align__(256) uint8_t q_attn[NROWS*D_MODEL];
__device__ __align__(256) uint8_t q_ffh [NROWS*FF_DIM];

// ---------------- fp8 pack helper + conversion kernel ----------------
__device__ __forceinline__ uint16_t pack_e4m3(float lo, float hi)
{
    uint16_t r;
    asm("cvt.rn.satfinite.e4m3x2.f32 %0, %1, %2;" : "=h"(r) : "f"(hi), "f"(lo));
    return r;
}

__global__ void q8_kernel(const float* __restrict__ src, uint8_t* __restrict__ dst,
                          int n4, float scale)
{
    int i = (blockIdx.x*blockDim.x + threadIdx.x) * 2;
    #pragma unroll
    for (int t = 0; t < 2; t++) {
        int j = i + t;
        if (j < n4) {
            float4 v = ((const float4*)src)[j];
            uint32_t lo = pack_e4m3(v.x*scale, v.y*scale);
            uint32_t hi = pack_e4m3(v.z*scale, v.w*scale);
            ((uint32_t*)dst)[j] = lo | (hi << 16);
        }
    }
}

// ---------------- embedding gather ----------------
__global__ void embed_kernel(const int* __restrict__ inputs, const float* __restrict__ emb)
{
    int r = blockIdx.x;
    int tok = inputs[r];
    const float4* src = (const float4*)(emb + (size_t)tok * D_MODEL);
    float4* dst = (float4*)(g_x + (size_t)r * D_MODEL);
    dst[threadIdx.x] = src[threadIdx.x];
}

// ================= cp.async / ldmatrix helpers =================
__device__ __forceinline__ void cp_async16(void* smem, const void* gmem)
{
    uint32_t s = (uint32_t)__cvta_generic_to_shared(smem);
    asm volatile("cp.async.ca.shared.global [%0], [%1], 16;\n" :: "r"(s), "l"(gmem));
}
__device__ __forceinline__ void cp_commit()
{
    asm volatile("cp.async.commit_group;\n" ::: "memory");
}
template<int N> __device__ __forceinline__ void cp_wait()
{
    asm volatile("cp.async.wait_group %0;\n" :: "n"(N) : "memory");
}
__device__ __forceinline__ void ldsm_x4(uint32_t& r0, uint32_t& r1, uint32_t& r2, uint32_t& r3,
                                        const void* smem)
{
    uint32_t a = (uint32_t)__cvta_generic_to_shared(smem);
    asm volatile("ldmatrix.sync.aligned.m8n8.x4.shared.b16 {%0,%1,%2,%3}, [%4];\n"
                 : "=r"(r0), "=r"(r1), "=r"(r2), "=r"(r3) : "r"(a));
}
__device__ __forceinline__ void ldsm_x2(uint32_t& r0, uint32_t& r1, const void* smem)
{
    uint32_t a = (uint32_t)__cvta_generic_to_shared(smem);
    asm volatile("ldmatrix.sync.aligned.m8n8.x2.shared.b16 {%0,%1}, [%2];\n"
                 : "=r"(r0), "=r"(r1) : "r"(a));
}

// ================= tf32 GEMM (loc KV path only; weights-output precision) =========
__device__ __forceinline__ void mma_mainloop(
    float acc[4][4][4],
    const float* __restrict__ A, const float* __restrict__ W,
    int K, int m0, int n0)
{
    __shared__ uint32_t As[2][128][20];
    __shared__ uint32_t Bs[2][128][20];
    int tid  = threadIdx.x;
    int lane = tid & 31, wid = tid >> 5;
    int wm = wid >> 2, wn = wid & 3;
    int g = lane >> 2, tig = lane & 3;

    int r0c = tid >> 2,         c0c = (tid & 3) << 2;
    int r1c = (tid + 256) >> 2, c1c = (tid & 3) << 2;
    const float* pa0 = A + (size_t)(m0 + r0c)*K + c0c;
    const float* pa1 = A + (size_t)(m0 + r1c)*K + c1c;
    const float* pb0 = W + (size_t)(n0 + r0c)*K + c0c;
    const float* pb1 = W + (size_t)(n0 + r1c)*K + c1c;

    int niter = K >> 4;
    cp_async16(&As[0][r0c][c0c], pa0);
    cp_async16(&As[0][r1c][c1c], pa1);
    cp_async16(&Bs[0][r0c][c0c], pb0);
    cp_async16(&Bs[0][r1c][c1c], pb1);
    cp_commit();

    for (int it = 0; it < niter; it++) {
        int st = it & 1;
        if (it + 1 < niter) {
            int off = (it + 1) << 4;
            int sn = st ^ 1;
            cp_async16(&As[sn][r0c][c0c], pa0 + off);
            cp_async16(&As[sn][r1c][c1c], pa1 + off);
            cp_async16(&Bs[sn][r0c][c0c], pb0 + off);
            cp_async16(&Bs[sn][r1c][c1c], pb1 + off);
            cp_commit();
            cp_wait<1>();
        } else {
            cp_wait<0>();
        }
        __syncthreads();
        #pragma unroll
        for (int ks = 0; ks < 16; ks += 8) {
            uint32_t af[4][4], bf[4][2];
            #pragma unroll
            for (int mt = 0; mt < 4; mt++) {
                int r0 = wm*64 + mt*16;
                af[mt][0] = As[st][r0+g  ][ks+tig  ];
                af[mt][1] = As[st][r0+g+8][ks+tig  ];
                af[mt][2] = As[st][r0+g  ][ks+tig+4];
                af[mt][3] = As[st][r0+g+8][ks+tig+4];
            }
            #pragma unroll
            for (int nt = 0; nt < 4; nt++) {
                int c0 = wn*32 + nt*8;
                bf[nt][0] = Bs[st][c0+g][ks+tig  ];
                bf[nt][1] = Bs[st][c0+g][ks+tig+4];
            }
            #pragma unroll
            for (int mt = 0; mt < 4; mt++)
                #pragma unroll
                for (int nt = 0; nt < 4; nt++) {
                    asm volatile(
                        "mma.sync.aligned.m16n8k8.row.col.f32.tf32.tf32.f32 "
                        "{%0,%1,%2,%3}, {%4,%5,%6,%7}, {%8,%9}, {%0,%1,%2,%3};\n"
                        : "+f"(acc[mt][nt][0]), "+f"(acc[mt][nt][1]),
                          "+f"(acc[mt][nt][2]), "+f"(acc[mt][nt][3])
                        : "r"(af[mt][0]), "r"(af[mt][1]),
                          "r"(af[mt][2]), "r"(af[mt][3]),
                          "r"(bf[nt][0]), "r"(bf[nt][1]));
                }
        }
        __syncthreads();
    }
}

__global__ __launch_bounds__(256, 2) void gemm_tc_kernel(
    const float* __restrict__ A, const float* __restrict__ W,
    const float* __restrict__ bias, float* __restrict__ C,
    int K, int ldC)
{
    float acc[4][4][4];
    #pragma unroll
    for (int a = 0; a < 4; a++)
        #pragma unroll
        for (int b = 0; b < 4; b++)
            #pragma unroll
            for (int c = 0; c < 4; c++) acc[a][b][c] = 0.f;

    int m0 = blockIdx.y * 128, n0 = blockIdx.x * 128;
    mma_mainloop(acc, A, W, K, m0, n0);

    int tid = threadIdx.x;
    int lane = tid & 31, wid = tid >> 5;
    int wm = wid >> 2, wn = wid & 3;
    int g = lane >> 2, tig = lane & 3;
    int rowb = m0 + wm*64;
    int colb = n0 + wn*32;
    #pragma unroll
    for (int nt = 0; nt < 4; nt++) {
        int c = colb + nt*8 + 2*tig;
        float b0 = bias[c], b1 = bias[c+1];
        #pragma unroll
        for (int mt = 0; mt < 4; mt++) {
            int r = rowb + mt*16 + g;
            *(float2*)(C + (size_t)r*ldC + c)     = make_float2(acc[mt][nt][0]+b0, acc[mt][nt][1]+b1);
            *(float2*)(C + (size_t)(r+8)*ldC + c) = make_float2(acc[mt][nt][2]+b0, acc[mt][nt][3]+b1);
        }
    }
}

// ================= fp8 GEMM core (m16n8k32 e4m3), BK=64, 2-stage =================
// MODE 0: fp32 out = acc*inv + bias.
// MODE 1: fp8  out = e4m3(relu(acc*inv + bias) * outscale).
// MODE 2: fused decoder lse partials (n-clamped to NTOK, m-tiles adjacent grid).
template<int MODE>
__global__ __launch_bounds__(256, 2) void gemm_fp8_kernel(
    const uint8_t* __restrict__ A, const uint8_t* __restrict__ W,
    const float* __restrict__ bias, void* __restrict__ Cout,
    int K, int ldC, float inv, float outscale)
{
    __shared__ uint32_t As[2][128][20];   // 16 words used = 64 fp8
    __shared__ uint32_t Bs[2][128][20];

    float acc[4][4][4];
    #pragma unroll
    for (int a = 0; a < 4; a++)
        #pragma unroll
        for (int b = 0; b < 4; b++)
            #pragma unroll
            for (int c = 0; c < 4; c++) acc[a][b][c] = 0.f;

    int m0, n0, nblk = 0;
    if (MODE == 2) { m0 = blockIdx.x * 128; n0 = blockIdx.y * 128; nblk = blockIdx.y; }
    else           { m0 = blockIdx.y * 128; n0 = blockIdx.x * 128; }

    int tid  = threadIdx.x;
    int lane = tid & 31, wid = tid >> 5;
    int wm = wid >> 2, wn = wid & 3;
    int g = lane >> 2, tig = lane & 3;

    int a_row = (lane & 7) + ((lane >> 3) & 1) * 8;
    int a_wrd = (lane >> 4) * 4;
    int b_row = lane & 7;
    int b_wrd = ((lane >> 3) & 1) * 4;

    int r0c = tid >> 2, r1c = r0c + 64;
    int cw = (tid & 3) * 4;   // word col
    int ce = (tid & 3) * 16;  // byte col
    int nr0 = n0 + r0c, nr1 = n0 + r1c;
    if (MODE == 2) { nr0 = (nr0 < NTOK) ? nr0 : (NTOK - 1); nr1 = (nr1 < NTOK) ? nr1 : (NTOK - 1); }
    const uint8_t* pa0 = A + (size_t)(m0 + r0c)*K + ce;
    const uint8_t* pa1 = A + (size_t)(m0 + r1c)*K + ce;
    const uint8_t* pb0 = W + (size_t)nr0*K + ce;
    const uint8_t* pb1 = W + (size_t)nr1*K + ce;

    int niter = K >> 6;
    cp_async16(&As[0][r0c][cw], pa0);
    cp_async16(&As[0][r1c][cw], pa1);
    cp_async16(&Bs[0][r0c][cw], pb0);
    cp_async16(&Bs[0][r1c][cw], pb1);
    cp_commit();

    for (int it = 0; it < niter; it++) {
        int st = it & 1;
        if (it + 1 < niter) {
            int off = (it + 1) << 6;
            int sn = st ^ 1;
            cp_async16(&As[sn][r0c][cw], pa0 + off);
            cp_async16(&As[sn][r1c][cw], pa1 + off);
            cp_async16(&Bs[sn][r0c][cw], pb0 + off);
            cp_async16(&Bs[sn][r1c][cw], pb1 + off);
            cp_commit();
            cp_wait<1>();
        } else {
            cp_wait<0>();
        }
        __syncthreads();
        #pragma unroll
        for (int ks = 0; ks < 2; ks++) {
            int kb = ks*8;
            uint32_t af[4][4], bf[4][2];
            #pragma unroll
            for (int mt = 0; mt < 4; mt++) {
                int r0 = wm*64 + mt*16;
                ldsm_x4(af[mt][0], af[mt][1], af[mt][2], af[mt][3],
                        &As[st][r0 + a_row][kb + a_wrd]);
            }
            #pragma unroll
            for (int nt = 0; nt < 4; nt++) {
                int c0 = wn*32 + nt*8;
                ldsm_x2(bf[nt][0], bf[nt][1],
                        &Bs[st][c0 + b_row][kb + b_wrd]);
            }
            #pragma unroll
            for (int mt = 0; mt < 4; mt++)
                #pragma unroll
                for (int nt = 0; nt < 4; nt++) {
                    asm volatile(
                        "mma.sync.aligned.m16n8k32.row.col.f32.e4m3.e4m3.f32 "
                        "{%0,%1,%2,%3}, {%4,%5,%6,%7}, {%8,%9}, {%0,%1,%2,%3};\n"
                        : "+f"(acc[mt][nt][0]), "+f"(acc[mt][nt][1]),
                          "+f"(acc[mt][nt][2]), "+f"(acc[mt][nt][3])
                        : "r"(af[mt][0]), "r"(af[mt][1]),
                          "r"(af[mt][2]), "r"(af[mt][3]),
                          "r"(bf[nt][0]), "r"(bf[nt][1]));
                }
        }
        __syncthreads();
    }

    // unscale
    #pragma unroll
    for (int a = 0; a < 4; a++)
        #pragma unroll
        for (int b = 0; b < 4; b++)
            #pragma unroll
            for (int c = 0; c < 4; c++) acc[a][b][c] *= inv;

    int rowb = m0 + wm*64, colb = n0 + wn*32;

    if (MODE == 0) {
        float* C = (float*)Cout;
        #pragma unroll
        for (int nt = 0; nt < 4; nt++) {
            int c = colb + nt*8 + 2*tig;
            float b0 = bias[c], b1 = bias[c+1];
            #pragma unroll
            for (int mt = 0; mt < 4; mt++) {
                int r = rowb + mt*16 + g;
                *(float2*)(C + (size_t)r*ldC + c)     = make_float2(acc[mt][nt][0]+b0, acc[mt][nt][1]+b1);
                *(float2*)(C + (size_t)(r+8)*ldC + c) = make_float2(acc[mt][nt][2]+b0, acc[mt][nt][3]+b1);
            }
        }
    } else if (MODE == 1) {
        uint8_t* C = (uint8_t*)Cout;
        #pragma unroll
        for (int nt = 0; nt < 4; nt++) {
            int c = colb + nt*8 + 2*tig;
            float b0 = bias[c], b1 = bias[c+1];
            #pragma unroll
            for (int mt = 0; mt < 4; mt++) {
                int r = rowb + mt*16 + g;
                float v0 = fmaxf(acc[mt][nt][0]+b0, 0.f)*outscale;
                float v1 = fmaxf(acc[mt][nt][1]+b1, 0.f)*outscale;
                float v2 = fmaxf(acc[mt][nt][2]+b0, 0.f)*outscale;
                float v3 = fmaxf(acc[mt][nt][3]+b1, 0.f)*outscale;
                *(uint16_t*)(C + (size_t)r*ldC + c)     = pack_e4m3(v0, v1);
                *(uint16_t*)(C + (size_t)(r+8)*ldC + c) = pack_e4m3(v2, v3);
            }
        }
    } else {
        __shared__ float red_m[4][128];
        __shared__ float red_s[4][128];
        #pragma unroll
        for (int mt = 0; mt < 4; mt++) {
            #pragma unroll
            for (int h = 0; h < 2; h++) {
                float m = -INFINITY;
                #pragma unroll
                for (int nt = 0; nt < 4; nt++) {
                    int c = colb + nt*8 + 2*tig;
                    if (c     < NTOK) m = fmaxf(m, acc[mt][nt][h*2+0]);
                    if (c + 1 < NTOK) m = fmaxf(m, acc[mt][nt][h*2+1]);
                }
                m = fmaxf(m, __shfl_xor_sync(0xffffffffu, m, 1));
                m = fmaxf(m, __shfl_xor_sync(0xffffffffu, m, 2));
                float s = 0.f;
                #pragma unroll
                for (int nt = 0; nt < 4; nt++) {
                    int c = colb + nt*8 + 2*tig;
                    if (c     < NTOK) s += __expf(acc[mt][nt][h*2+0] - m);
                    if (c + 1 < NTOK) s += __expf(acc[mt][nt][h*2+1] - m);
                }
                s += __shfl_xor_sync(0xffffffffu, s, 1);
                s += __shfl_xor_sync(0xffffffffu, s, 2);
                if (tig == 0) {
                    int lr = wm*64 + mt*16 + h*8 + g;
                    red_m[wn][lr] = m;
                    red_s[wn][lr] = s;
                }
            }
        }
        __syncthreads();
        if (tid < 128) {
            float m0v = red_m[0][tid], m1v = red_m[1][tid];
            float m2v = red_m[2][tid], m3v = red_m[3][tid];
            float mx = fmaxf(fmaxf(m0v, m1v), fmaxf(m2v, m3v));
            float s = red_s[0][tid]*__expf(m0v-mx) + red_s[1][tid]*__expf(m1v-mx)
                    + red_s[2][tid]*__expf(m2v-mx) + red_s[3][tid]*__expf(m3v-mx);
            int row = m0 + tid;
            g_pmax[(size_t)row*NBLK_V + nblk] = mx;
            g_psum[(size_t)row*NBLK_V + nblk] = s;
        }
    }
}

__global__ void lse_reduce_kernel()
{
    int r = blockIdx.x, tid = threadIdx.x;
    __shared__ float red[128];
    float m = -INFINITY;
    for (int i = tid; i < NBLK_V; i += 128) m = fmaxf(m, g_pmax[(size_t)r*NBLK_V + i]);
    red[tid] = m; __syncthreads();
    for (int s = 64; s > 0; s >>= 1) { if (tid < s) red[tid] = fmaxf(red[tid], red[tid+s]); __syncthreads(); }
    float gm = red[0]; __syncthreads();
    double sum = 0.0;
    for (int i = tid; i < NBLK_V; i += 128)
        sum += (double)g_psum[(size_t)r*NBLK_V + i] * exp((double)g_pmax[(size_t)r*NBLK_V + i] - (double)gm);
    __shared__ double redd[128];
    redd[tid] = sum; __syncthreads();
    for (int s = 64; s > 0; s >>= 1) { if (tid < s) redd[tid] += redd[tid+s]; __syncthreads(); }
    if (tid == 0) g_lse[r] = gm + (float)log(redd[0]);
}

// ---------------- small-M GEMM ----------------
__global__ void rowdot_kernel(
    const float* __restrict__ A, long strideA,
    const float* __restrict__ W, const float* __restrict__ bias,
    float* __restrict__ C, long strideC,
    int M, int K, float alpha, int relu)
{
    int n = blockIdx.x;
    int tid = threadIdx.x;   // 128
    const float* w = W + (size_t)n * K;
    __shared__ float red[128];
    for (int m = 0; m < M; m++) {
        const float* a = A + (size_t)m * strideA;
        float s = 0.f;
        for (int k = tid; k < K; k += 128) s += a[k]*w[k];
        red[tid] = s; __syncthreads();
        for (int st = 64; st > 0; st >>= 1) { if (tid < st) red[tid] += red[tid+st]; __syncthreads(); }
        if (tid == 0) {
            float v = alpha*red[0] + (bias ? bias[n] : 0.f);
            if (relu) v = fmaxf(v, 0.f);
            C[(size_t)m*strideC + n] = v;
        }
        __syncthreads();
    }
}

// ---------------- attention, 8 queries per block, fp8 out ----------------
#define QT 8
__global__ __launch_bounds__(256) void attn8_kernel(
    const float* __restrict__ qkv, uint8_t* __restrict__ out)
{
    int qt = blockIdx.x, h = blockIdx.y, b = blockIdx.z;
    int tid = threadIdx.x;
    __shared__ float qs[QT][DHEAD];
    __shared__ float sc[QT][NSEQ];
    __shared__ float den[QT];
    const float* base = qkv + (size_t)b*NSEQ*QKV_LD;
    if (tid < 128) {
        int q = tid >> 4;
        int c = (tid & 15) * 4;
        *(float4*)&qs[q][c] =
            *(const float4*)(base + (size_t)(qt*QT+q)*QKV_LD + h*DHEAD + c);
    }
    __syncthreads();
    {
        int j = tid;
        float4 kreg[16];
        const float4* kr = (const float4*)(base + (size_t)j*QKV_LD + D_MODEL + h*DHEAD);
        #pragma unroll
        for (int t = 0; t < 16; t++) kreg[t] = kr[t];
        #pragma unroll
        for (int q = 0; q < QT; q++) {
            float d = 0.f;
            #pragma unroll
            for (int t = 0; t < 16; t++) {
                float4 q4 = *(float4*)&qs[q][t*4];
                d += q4.x*kreg[t].x + q4.y*kreg[t].y + q4.z*kreg[t].z + q4.w*kreg[t].w;
            }
            sc[q][j] = d * 0.125f;
        }
    }
    __syncthreads();
    {
        int w = tid >> 5, lane = tid & 31;
        float v[8];
        float m = -INFINITY;
        #pragma unroll
        for (int t = 0; t < 8; t++) { v[t] = sc[w][lane + 32*t]; m = fmaxf(m, v[t]); }
        #pragma unroll
        for (int o = 16; o; o >>= 1) m = fmaxf(m, __shfl_xor_sync(0xffffffffu, m, o));
        float s = 0.f;
        #pragma unroll
        for (int t = 0; t < 8; t++) { v[t] = expf(v[t]-m); s += v[t]; }
        #pragma unroll
        for (int o = 16; o; o >>= 1) s += __shfl_xor_sync(0xffffffffu, s, o);
        #pragma unroll
        for (int t = 0; t < 8; t++) sc[w][lane + 32*t] = v[t];
        if (lane == 0) den[w] = s;
    }
    __syncthreads();
    {
        int d = tid & 63, qp = tid >> 6;
        int q0 = qp*2, q1 = qp*2+1;
        const float* vb = base + 2*D_MODEL + h*DHEAD + d;
        float a0 = 0.f, a1 = 0.f;
        #pragma unroll 8
        for (int j = 0; j < NSEQ; j++) {
            float v = vb[(size_t)j*QKV_LD];
            a0 += sc[q0][j]*v;
            a1 += sc[q1][j]*v;
        }
        uint16_t p0 = pack_e4m3(a0/den[q0]*SA, 0.f);
        uint16_t p1 = pack_e4m3(a1/den[q1]*SA, 0.f);
        out[((size_t)(b*NSEQ + qt*QT + q0))*D_MODEL + h*DHEAD + d] = (uint8_t)p0;
        out[((size_t)(b*NSEQ + qt*QT + q1))*D_MODEL + h*DHEAD + d] = (uint8_t)p1;
    }
}

// ---------------- loc attention (single query per (h,b)), fp32 out ----------------
__global__ __launch_bounds__(256) void attn_kernel(
    const float* __restrict__ qkv, float* __restrict__ out, int nq, int sq_base)
{
    int qi = blockIdx.x, h = blockIdx.y, b = blockIdx.z;
    int sq = sq_base + qi;
    int tid = threadIdx.x;
    __shared__ float4 qrow[DHEAD/4];
    __shared__ float sc[NSEQ];
    __shared__ float red[256];
    __shared__ float sden;
    __shared__ float osum[4][DHEAD];
    const float* base = qkv + (size_t)b * NSEQ * QKV_LD;
    if (tid < DHEAD/4)
        qrow[tid] = ((const float4*)(base + (size_t)sq*QKV_LD + h*DHEAD))[tid];
    __syncthreads();
    {
        const float4* krow = (const float4*)(base + (size_t)tid*QKV_LD + D_MODEL + h*DHEAD);
        float d = 0.f;
        #pragma unroll
        for (int t = 0; t < DHEAD/4; t++) {
            float4 k4 = krow[t];
            float4 q4 = qrow[t];
            d += q4.x*k4.x + q4.y*k4.y + q4.z*k4.z + q4.w*k4.w;
        }
        sc[tid] = d * 0.125f;
    }
    __syncthreads();
    red[tid] = sc[tid]; __syncthreads();
    for (int s = 128; s > 0; s >>= 1) { if (tid < s) red[tid] = fmaxf(red[tid], red[tid+s]); __syncthreads(); }
    float mx = red[0]; __syncthreads();
    float e = expf(sc[tid] - mx);
    red[tid] = e; __syncthreads();
    for (int s = 128; s > 0; s >>= 1) { if (tid < s) red[tid] += red[tid+s]; __syncthreads(); }
    if (tid == 0) sden = red[0];
    __syncthreads();
    sc[tid] = e;
    __syncthreads();
    int d = tid & 63, g = tid >> 6;
    const float* vb = base + 2*D_MODEL + h*DHEAD + d;
    float o = 0.f;
    for (int j = g*64; j < (g+1)*64; j++) o += sc[j] * vb[(size_t)j*QKV_LD];
    osum[g][d] = o; __syncthreads();
    if (tid < DHEAD) {
        float r = (osum[0][tid]+osum[1][tid]+osum[2][tid]+osum[3][tid]) / sden;
        out[((size_t)(b*nq + qi))*D_MODEL + h*DHEAD + tid] = r;
    }
}

// ---------------- residual + layernorm (fp32 out + optional fp8 mirror) ----------
__global__ void ln_kernel(
    const float* __restrict__ in1, long s1,
    const float* __restrict__ in2, long s2,
    float* __restrict__ out, long so,
    uint8_t* __restrict__ outq, float qs,
    const float* __restrict__ gam, const float* __restrict__ bet)
{
    int r = blockIdx.x, tid = threadIdx.x;
    __shared__ float xr[D_MODEL];
    __shared__ float red[256];
    const float* p1 = in1 + (size_t)r*s1;
    const float* p2 = in2 + (size_t)r*s2;
    float ls = 0.f;
    for (int d = tid; d < D_MODEL; d += 256) { float v = p1[d]+p2[d]; xr[d] = v; ls += v; }
    red[tid] = ls; __syncthreads();
    for (int s = 128; s > 0; s >>= 1) { if (tid < s) red[tid] += red[tid+s]; __syncthreads(); }
    float mean = red[0] * (1.f/D_MODEL); __syncthreads();
    float lv = 0.f;
    for (int d = tid; d < D_MODEL; d += 256) { float t = xr[d]-mean; lv += t*t; }
    red[tid] = lv; __syncthreads();
    for (int s = 128; s > 0; s >>= 1) { if (tid < s) red[tid] += red[tid+s]; __syncthreads(); }
    float rstd = 1.f / sqrtf(red[0]*(1.f/D_MODEL) + 1e-5f);
    for (int d = tid*2; d < D_MODEL; d += 512) {
        float v0 = (xr[d]  -mean)*rstd*gam[d]   + bet[d];
        float v1 = (xr[d+1]-mean)*rstd*gam[d+1] + bet[d+1];
        *(float2*)(out + (size_t)r*so + d) = make_float2(v0, v1);
        if (outq) *(uint16_t*)(outq + (size_t)r*D_MODEL + d) = pack_e4m3(v0*qs, v1*qs);
    }
}

// ---------------- gating statistics + top-k + softmax + importance ----------------
__global__ void stats_kernel(const float* __restrict__ w, const float* __restrict__ noise)
{
    __shared__ float tot[NEXP];
    __shared__ double redd[256];
    __shared__ float fv[256];
    __shared__ int   fi[256];
    __shared__ float topv[NKTOP];
    __shared__ double smean, sstd;
    int tid = threadIdx.x;
    double ls = 0.0;
    for (int n = tid; n < NEXP; n += 256) {
        float f = 0.25f*(w[n] + w[NEXP+n] + w[2*NEXP+n] + w[3*NEXP+n]);
        tot[n] = f; ls += (double)f;
    }
    redd[tid] = ls; __syncthreads();
    for (int s = 128; s > 0; s >>= 1) { if (tid < s) redd[tid] += redd[tid+s]; __syncthreads(); }
    if (tid == 0) smean = redd[0] / NEXP;
    __syncthreads();
    double mfm = smean;
    ls = 0.0;
    for (int n = tid; n < NEXP; n += 256) { double t = (double)tot[n]-mfm; ls += t*t; }
    redd[tid] = ls; __syncthreads();
    for (int s = 128; s > 0; s >>= 1) { if (tid < s) redd[tid] += redd[tid+s]; __syncthreads(); }
    if (tid == 0) sstd = sqrt(redd[0] / (NEXP-1));
    __syncthreads();
    float stdfm = (float)sstd;
    for (int n = tid; n < NEXP; n += 256) tot[n] = tot[n] + noise[n]*stdfm;
    __syncthreads();
    ls = 0.0;
    for (int n = tid; n < NEXP; n += 256) ls += (double)tot[n];
    redd[tid] = ls; __syncthreads();
    for (int s = 128; s > 0; s >>= 1) { if (tid < s) redd[tid] += redd[tid+s]; __syncthreads(); }
    if (tid == 0) smean = redd[0] / NEXP;
    __syncthreads();
    double mt = smean;
    ls = 0.0;
    for (int n = tid; n < NEXP; n += 256) { double t = (double)tot[n]-mt; ls += t*t; }
    redd[tid] = ls; __syncthreads();
    for (int s = 128; s > 0; s >>= 1) { if (tid < s) redd[tid] += redd[tid+s]; __syncthreads(); }
    if (tid == 0) {
        double st = sqrt(redd[0] / (NEXP-1));
        double ratio = st / mt;
        g_stats[20] = (float)(0.1 * ratio * ratio);
    }
    __syncthreads();
    for (int it = 0; it < NKTOP; it++) {
        float bv = -INFINITY; int bi = 0x7fffffff;
        for (int n = tid; n < NEXP; n += 256) {
            float v = tot[n];
            if (v > bv || (v == bv && n < bi)) { bv = v; bi = n; }
        }
        fv[tid] = bv; fi[tid] = bi; __syncthreads();
        for (int s = 128; s > 0; s >>= 1) {
            if (tid < s) {
                float v2 = fv[tid+s]; int i2 = fi[tid+s];
                if (v2 > fv[tid] || (v2 == fv[tid] && i2 < fi[tid])) { fv[tid] = v2; fi[tid] = i2; }
            }
            __syncthreads();
        }
        if (tid == 0) { topv[it] = fv[0]; tot[fi[0]] = -INFINITY; }
        __syncthreads();
    }
    if (tid == 0) {
        float m = topv[0];
        float s = 0.f;
        float e[NKTOP];
        for (int k = 0; k < NKTOP; k++) { e[k] = expf(topv[k]-m); s += e[k]; }
        for (int k = 0; k < NKTOP; k++) g_stats[k] = e[k]/s;
    }
}

// ---------------- response mixture (fp32 + fp8 mirror) ----------------
__global__ void mix_kernel(const float* __restrict__ responses)
{
    __shared__ float w[NKTOP];
    if (threadIdx.x < NKTOP) w[threadIdx.x] = g_stats[threadIdx.x];
    __syncthreads();
    int i = blockIdx.x*blockDim.x + threadIdx.x;
    if (i < (NROWS*D_MODEL)/4) {
        float4 s = make_float4(0.f, 0.f, 0.f, 0.f);
        #pragma unroll
        for (int k = 0; k < NKTOP; k++) {
            float4 v = ((const float4*)responses)[(size_t)k*((NROWS*D_MODEL)/4) + i];
            float wk = w[k];
            s.x += wk*v.x; s.y += wk*v.y; s.z += wk*v.z; s.w += wk*v.w;
        }
        ((float4*)g_x)[i] = s;
        uint32_t lo = pack_e4m3(s.x*SX, s.y*SX);
        uint32_t hi = pack_e4m3(s.z*SX, s.w*SX);
        ((uint32_t*)q_x)[i] = lo | (hi << 16);
    }
}

// ---------------- label logit + final loss ----------------
__global__ void lablogit_kernel(const int* __restrict__ inputs, const float* __restrict__ dec_w)
{
    int s = blockIdx.x, b = blockIdx.y, tid = threadIdx.x;
    int lbl = inputs[b*NSEQ + s + 1];
    const float* a = g_x + ((size_t)(b*NSEQ + s))*D_MODEL;
    const float* wp = dec_w + (size_t)lbl*D_MODEL;
    __shared__ float red[128];
    float acc = 0.f;
    for (int k = tid; k < D_MODEL; k += 128) acc += a[k]*wp[k];
    red[tid] = acc; __syncthreads();
    for (int st = 64; st > 0; st >>= 1) { if (tid < st) red[tid] += red[tid+st]; __syncthreads(); }
    if (tid == 0) g_lab[b*(NSEQ-1)+s] = red[0];
}

__global__ void final_kernel(float* __restrict__ out)
{
    __shared__ double red[256];
    int tid = threadIdx.x;
    double s = 0.0;
    for (int i = tid; i < NB*(NSEQ-1); i += 256) {
        int b = i/(NSEQ-1), sp = i%(NSEQ-1);
        s += (double)g_lab[i] - (double)g_lse[b*NSEQ+sp];
    }
    red[tid] = s; __syncthreads();
    for (int st = 128; st > 0; st >>= 1) { if (tid < st) red[tid] += red[tid+st]; __syncthreads(); }
    if (tid == 0) {
        double ce = -red[0] / (double)(NB*(NSEQ-1));
        out[0] = (float)(ce + (double)g_stats[20]);
    }
}

// ---------------- host driver ----------------
extern "C" void kernel_launch(void* const* d_in, const int* in_sizes, int n_in,
                              void* d_out, int out_size)
{
    (void)in_sizes; (void)n_in; (void)out_size;
    const int*   inputs    = (const int*)  d_in[0];
    const float* responses = (const float*)d_in[1];
    const float* noise     = (const float*)d_in[2];
    const float* emb       = (const float*)d_in[3];
    const float* loc_Wqkv  = (const float*)d_in[4];
    const float* loc_bqkv  = (const float*)d_in[5];
    const float* loc_Wo    = (const float*)d_in[6];
    const float* loc_bo    = (const float*)d_in[7];
    const float* loc_ln1g  = (const float*)d_in[8];
    const float* loc_ln1b  = (const float*)d_in[9];
    const float* loc_W1    = (const float*)d_in[10];
    const float* loc_b1    = (const float*)d_in[11];
    const float* loc_W2    = (const float*)d_in[12];
    const float* loc_b2    = (const float*)d_in[13];
    const float* loc_ln2g  = (const float*)d_in[14];
    const float* loc_ln2b  = (const float*)d_in[15];
    const float* enc_Wqkv  = (const float*)d_in[16];
    const float* enc_bqkv  = (const float*)d_in[17];
    const float* enc_Wo    = (const float*)d_in[18];
    const float* enc_bo    = (const float*)d_in[19];
    const float* enc_ln1g  = (const float*)d_in[20];
    const float* enc_ln1b  = (const float*)d_in[21];
    const float* enc_W1    = (const float*)d_in[22];
    const float* enc_b1    = (const float*)d_in[23];
    const float* enc_W2    = (const float*)d_in[24];
    const float* enc_b2    = (const float*)d_in[25];
    const float* enc_ln2g  = (const float*)d_in[26];
    const float* enc_ln2b  = (const float*)d_in[27];
    const float* gate_w    = (const float*)d_in[28];
    const float* gate_b    = (const float*)d_in[29];
    const float* dec_w     = (const float*)d_in[30];
    float* out = (float*)d_out;

    float *p_x, *p_qkv, *p_tmp;
    float *p_sm_attn, *p_sm_x, *p_sm_tmp, *p_sm_ctx, *p_sm_ffh;
    uint8_t *p_qWqkv, *p_qWo, *p_qW1, *p_qW2, *p_qdec, *p_qx, *p_qattn, *p_qffh;
    cudaGetSymbolAddress((void**)&p_x, g_x);
    cudaGetSymbolAddress((void**)&p_qkv, g_qkv);
    cudaGetSymbolAddress((void**)&p_tmp, g_tmp);
    cudaGetSymbolAddress((void**)&p_sm_attn, g_sm_attn);
    cudaGetSymbolAddress((void**)&p_sm_x, g_sm_x);
    cudaGetSymbolAddress((void**)&p_sm_tmp, g_sm_tmp);
    cudaGetSymbolAddress((void**)&p_sm_ctx, g_sm_ctx);
    cudaGetSymbolAddress((void**)&p_sm_ffh, g_sm_ffh);
    cudaGetSymbolAddress((void**)&p_qWqkv, q_Wqkv);
    cudaGetSymbolAddress((void**)&p_qWo, q_Wo);
    cudaGetSymbolAddress((void**)&p_qW1, q_W1);
    cudaGetSymbolAddress((void**)&p_qW2, q_W2);
    cudaGetSymbolAddress((void**)&p_qdec, q_dec);
    cudaGetSymbolAddress((void**)&p_qx, q_x);
    cudaGetSymbolAddress((void**)&p_qattn, q_attn);
    cudaGetSymbolAddress((void**)&p_qffh, q_ffh);

    // ---- capture-forked side stream for weight conversions ----
    cudaStream_t s2;
    cudaStreamCreateWithFlags(&s2, cudaStreamNonBlocking);
    cudaEvent_t evFork, evEnc, evDec;
    cudaEventCreateWithFlags(&evFork, cudaEventDisableTiming);
    cudaEventCreateWithFlags(&evEnc,  cudaEventDisableTiming);
    cudaEventCreateWithFlags(&evDec,  cudaEventDisableTiming);

    cudaEventRecord(evFork, 0);
    cudaStreamWaitEvent(s2, evFork, 0);

    q8_kernel<<<(2*QKV_LD*D_MODEL/8 + 255)/256, 256, 0, s2>>>(enc_Wqkv, p_qWqkv, 2*QKV_LD*D_MODEL/4, SW);
    q8_kernel<<<(2*D_MODEL*D_MODEL/8 + 255)/256, 256, 0, s2>>>(enc_Wo, p_qWo, 2*D_MODEL*D_MODEL/4, SW);
    q8_kernel<<<(2*FF_DIM*D_MODEL/8 + 255)/256, 256, 0, s2>>>(enc_W1, p_qW1, 2*FF_DIM*D_MODEL/4, SW);
    q8_kernel<<<(2*D_MODEL*FF_DIM/8 + 255)/256, 256, 0, s2>>>(enc_W2, p_qW2, 2*D_MODEL*FF_DIM/4, SW);
    cudaEventRecord(evEnc, s2);
    q8_kernel<<<(NTOK*D_MODEL/8 + 255)/256, 256, 0, s2>>>(dec_w, p_qdec, NTOK*D_MODEL/4, SW);
    cudaEventRecord(evDec, s2);

    // default stream: embed + loc layer + gating (overlapped with conversions)
    embed_kernel<<<NROWS, 256>>>(inputs, emb);
    gemm_tc_kernel<<<dim3(2048/128, NROWS/128), 256>>>(
        p_x, loc_Wqkv + (size_t)D_MODEL*D_MODEL, loc_bqkv + D_MODEL,
        p_qkv + D_MODEL, D_MODEL, QKV_LD);
    rowdot_kernel<<<D_MODEL, 128>>>(
        p_x + (size_t)(NSEQ-1)*D_MODEL, (long)NSEQ*D_MODEL,
        loc_Wqkv, loc_bqkv,
        p_qkv + (size_t)(NSEQ-1)*QKV_LD, (long)NSEQ*QKV_LD,
        NB, D_MODEL, 1.f, 0);
    attn_kernel<<<dim3(1, NHEAD, NB), 256>>>(p_qkv, p_sm_attn, 1, NSEQ-1);
    rowdot_kernel<<<D_MODEL, 128>>>(p_sm_attn, D_MODEL, loc_Wo, loc_bo,
                                    p_sm_tmp, D_MODEL, NB, D_MODEL, 1.f, 0);
    ln_kernel<<<NB, 256>>>(p_x + (size_t)(NSEQ-1)*D_MODEL, (long)NSEQ*D_MODEL,
                           p_sm_tmp, D_MODEL, p_sm_x, D_MODEL, (uint8_t*)0, 0.f,
                           loc_ln1g, loc_ln1b);
    rowdot_kernel<<<FF_DIM, 128>>>(p_sm_x, D_MODEL, loc_W1, loc_b1,
                                   p_sm_ffh, FF_DIM, NB, D_MODEL, 1.f, 1);
    rowdot_kernel<<<D_MODEL, 128>>>(p_sm_ffh, FF_DIM, loc_W2, loc_b2,
                                    p_sm_tmp, D_MODEL, NB, FF_DIM, 1.f, 0);
    ln_kernel<<<NB, 256>>>(p_sm_x, D_MODEL, p_sm_tmp, D_MODEL,
                           p_sm_ctx, D_MODEL, (uint8_t*)0, 0.f,
                           loc_ln2g, loc_ln2b);

    rowdot_kernel<<<NEXP, 128>>>(p_sm_ctx, D_MODEL, gate_w, gate_b,
                                 out + 1, NEXP, NB, D_MODEL, 32.f, 0);
    stats_kernel<<<1, 256>>>(out + 1, noise);
    mix_kernel<<<(NROWS*D_MODEL/4 + 255)/256, 256>>>(responses);

    // join: encoder weights must be converted before the encoder loop
    cudaStreamWaitEvent(0, evEnc, 0);

    // two encoder layers (fp8 tensor cores; residual stream fp32)
    const float invXW = 1.f/(SX*SW);
    const float invAW = 1.f/(SA*SW);
    const float invFW = 1.f/(SF*SW);
    for (int l = 0; l < 2; l++) {
        const uint8_t* Wqkv = p_qWqkv + (size_t)l*QKV_LD*D_MODEL;
        const float*   bqkv = enc_bqkv + (size_t)l*QKV_LD;
        const uint8_t* Wo   = p_qWo   + (size_t)l*D_MODEL*D_MODEL;
        const float*   bo   = enc_bo  + (size_t)l*D_MODEL;
        const float* g1   = enc_ln1g + (size_t)l*D_MODEL;
        const float* b1l  = enc_ln1b + (size_t)l*D_MODEL;
        const uint8_t* W1   = p_qW1   + (size_t)l*FF_DIM*D_MODEL;
        const float*   bb1  = enc_b1  + (size_t)l*FF_DIM;
        const uint8_t* W2   = p_qW2   + (size_t)l*D_MODEL*FF_DIM;
        const float*   bb2  = enc_b2  + (size_t)l*D_MODEL;
        const float* g2   = enc_ln2g + (size_t)l*D_MODEL;
        const float* b2l  = enc_ln2b + (size_t)l*D_MODEL;

        gemm_fp8_kernel<0><<<dim3(QKV_LD/128, NROWS/128), 256>>>(
            p_qx, Wqkv, bqkv, p_qkv, D_MODEL, QKV_LD, invXW, 0.f);
        attn8_kernel<<<dim3(NSEQ/QT, NHEAD, NB), 256>>>(p_qkv, p_qattn);
        gemm_fp8_kernel<0><<<dim3(D_MODEL/128, NROWS/128), 256>>>(
            p_qattn, Wo, bo, p_tmp, D_MODEL, D_MODEL, invAW, 0.f);
        ln_kernel<<<NROWS, 256>>>(p_x, D_MODEL, p_tmp, D_MODEL, p_x, D_MODEL,
                                  p_qx, SX, g1, b1l);
        gemm_fp8_kernel<1><<<dim3(FF_DIM/128, NROWS/128), 256>>>(
            p_qx, W1, bb1, p_qffh, D_MODEL, FF_DIM, invXW, SF);
        gemm_fp8_kernel<0><<<dim3(D_MODEL/128, NROWS/128), 256>>>(
            p_qffh, W2, bb2, p_tmp, FF_DIM, D_MODEL, invFW, 0.f);
        ln_kernel<<<NROWS, 256>>>(p_x, D_MODEL, p_tmp, D_MODEL, p_x, D_MODEL,
                                  p_qx, SX, g2, b2l);
    }

    // join: decoder fp8 weights ready (final ln already wrote q_x)
    cudaStreamWaitEvent(0, evDec, 0);

    // fused fp8 decoder GEMM + logsumexp (m-tiles adjacent; fp8 dec_w L2-resident)
    gemm_fp8_kernel<2><<<dim3(NROWS/128, NBLK_V), 256>>>(
        p_qx, p_qdec, (const float*)0, (void*)0, D_MODEL, 0, invXW, 0.f);
    lse_reduce_kernel<<<NROWS, 128>>>();
    lablogit_kernel<<<dim3(NSEQ-1, NB), 128>>>(inputs, dec_w);
    final_kernel<<<1, 256>>>(out);

    cudaEventDestroy(evFork);
    cudaEventDestroy(evEnc);
    cudaEventDestroy(evDec);
    cudaStreamDestroy(s2);
}

// round 12
// speedup vs baseline: 1.2058x; 1.0673x over previous
#include <cuda_runtime.h>
#include <cuda_bf16.h>
#include <math.h>
#include <stdint.h>

// ---------------- problem constants ----------------
#define D_MODEL 1024
#define NHEAD   16
#define DHEAD   64
#define FF_DIM  4096
#define NSEQ    256
#define NB      4
#define NTOK    50257
#define NEXP    2000
#define NKTOP   20
#define NROWS   (NB*NSEQ)      // 1024
#define QKV_LD  3072
#define NBLK_V  393            // ceil(50257/128)

// fp8 per-tensor scales
#define SX  16.0f
#define SW  512.0f
#define SA  64.0f
#define SF  32.0f

// ---------------- scratch ----------------
__device__ float g_x    [NROWS*D_MODEL];
__device__ float g_qkv  [NROWS*QKV_LD];
__device__ float g_tmp  [NROWS*D_MODEL];
__device__ float g_sm_attn[NB*D_MODEL];
__device__ float g_sm_x   [NB*D_MODEL];
__device__ float g_sm_tmp [NB*D_MODEL];
__device__ float g_sm_ctx [NB*D_MODEL];
__device__ float g_sm_ffh [NB*FF_DIM];
__device__ float g_pmax[NROWS*NBLK_V];
__device__ float g_psum[NROWS*NBLK_V];
__device__ float g_lse [NROWS];
__device__ float g_lab [NB*(NSEQ-1)];
__device__ float g_stats[32];

// fp8 mirrors
__device__ __align__(256) uint8_t q_Wqkv[2*QKV_LD*D_MODEL];
__device__ __align__(256) uint8_t q_Wo  [2*D_MODEL*D_MODEL];
__device__ __align__(256) uint8_t q_W1  [2*FF_DIM*D_MODEL];
__device__ __align__(256) uint8_t q_W2  [2*D_MODEL*FF_DIM];
__device__ __align__(256) uint8_t q_dec [NTOK*D_MODEL];
__device__ __align__(256) uint8_t q_x   [NROWS*D_MODEL];
__device__ __align__(256) uint8_t q_attn[NROWS*D_MODEL];
__device__ __align__(256) uint8_t q_ffh [NROWS*FF_DIM];

// ---------------- fp8 pack helper + conversion kernel ----------------
__device__ __forceinline__ uint16_t pack_e4m3(float lo, float hi)
{
    uint16_t r;
    asm("cvt.rn.satfinite.e4m3x2.f32 %0, %1, %2;" : "=h"(r) : "f"(hi), "f"(lo));
    return r;
}

__global__ void q8_kernel(const float* __restrict__ src, uint8_t* __restrict__ dst,
                          int n4, float scale)
{
    int i = (blockIdx.x*blockDim.x + threadIdx.x) * 2;
    #pragma unroll
    for (int t = 0; t < 2; t++) {
        int j = i + t;
        if (j < n4) {
            float4 v = ((const float4*)src)[j];
            uint32_t lo = pack_e4m3(v.x*scale, v.y*scale);
            uint32_t hi = pack_e4m3(v.z*scale, v.w*scale);
            ((uint32_t*)dst)[j] = lo | (hi << 16);
        }
    }
}

// ---------------- embedding gather ----------------
__global__ void embed_kernel(const int* __restrict__ inputs, const float* __restrict__ emb)
{
    int r = blockIdx.x;
    int tok = inputs[r];
    const float4* src = (const float4*)(emb + (size_t)tok * D_MODEL);
    float4* dst = (float4*)(g_x + (size_t)r * D_MODEL);
    dst[threadIdx.x] = src[threadIdx.x];
}

// ================= cp.async / ldmatrix helpers =================
__device__ __forceinline__ void cp_async16(void* smem, const void* gmem)
{
    uint32_t s = (uint32_t)__cvta_generic_to_shared(smem);
    asm volatile("cp.async.ca.shared.global [%0], [%1], 16;\n" :: "r"(s), "l"(gmem));
}
__device__ __forceinline__ void cp_commit()
{
    asm volatile("cp.async.commit_group;\n" ::: "memory");
}
template<int N> __device__ __forceinline__ void cp_wait()
{
    asm volatile("cp.async.wait_group %0;\n" :: "n"(N) : "memory");
}
__device__ __forceinline__ void ldsm_x4(uint32_t& r0, uint32_t& r1, uint32_t& r2, uint32_t& r3,
                                        const void* smem)
{
    uint32_t a = (uint32_t)__cvta_generic_to_shared(smem);
    asm volatile("ldmatrix.sync.aligned.m8n8.x4.shared.b16 {%0,%1,%2,%3}, [%4];\n"
                 : "=r"(r0), "=r"(r1), "=r"(r2), "=r"(r3) : "r"(a));
}
__device__ __forceinline__ void ldsm_x2(uint32_t& r0, uint32_t& r1, const void* smem)
{
    uint32_t a = (uint32_t)__cvta_generic_to_shared(smem);
    asm volatile("ldmatrix.sync.aligned.m8n8.x2.shared.b16 {%0,%1}, [%2];\n"
                 : "=r"(r0), "=r"(r1) : "r"(a));
}
__device__ __forceinline__ void mma_e4m3(float* a4, uint32_t a0, uint32_t a1, uint32_t a2, uint32_t a3,
                                         uint32_t b0, uint32_t b1)
{
    asm volatile(
        "mma.sync.aligned.m16n8k32.row.col.f32.e4m3.e4m3.f32 "
        "{%0,%1,%2,%3}, {%4,%5,%6,%7}, {%8,%9}, {%0,%1,%2,%3};\n"
        : "+f"(a4[0]), "+f"(a4[1]), "+f"(a4[2]), "+f"(a4[3])
        : "r"(a0), "r"(a1), "r"(a2), "r"(a3), "r"(b0), "r"(b1));
}

// ================= tf32 GEMM (loc KV path only) =================
__device__ __forceinline__ void mma_mainloop(
    float acc[4][4][4],
    const float* __restrict__ A, const float* __restrict__ W,
    int K, int m0, int n0)
{
    __shared__ uint32_t As[2][128][20];
    __shared__ uint32_t Bs[2][128][20];
    int tid  = threadIdx.x;
    int lane = tid & 31, wid = tid >> 5;
    int wm = wid >> 2, wn = wid & 3;
    int g = lane >> 2, tig = lane & 3;

    int r0c = tid >> 2,         c0c = (tid & 3) << 2;
    int r1c = (tid + 256) >> 2, c1c = (tid & 3) << 2;
    const float* pa0 = A + (size_t)(m0 + r0c)*K + c0c;
    const float* pa1 = A + (size_t)(m0 + r1c)*K + c1c;
    const float* pb0 = W + (size_t)(n0 + r0c)*K + c0c;
    const float* pb1 = W + (size_t)(n0 + r1c)*K + c1c;

    int niter = K >> 4;
    cp_async16(&As[0][r0c][c0c], pa0);
    cp_async16(&As[0][r1c][c1c], pa1);
    cp_async16(&Bs[0][r0c][c0c], pb0);
    cp_async16(&Bs[0][r1c][c1c], pb1);
    cp_commit();

    for (int it = 0; it < niter; it++) {
        int st = it & 1;
        if (it + 1 < niter) {
            int off = (it + 1) << 4;
            int sn = st ^ 1;
            cp_async16(&As[sn][r0c][c0c], pa0 + off);
            cp_async16(&As[sn][r1c][c1c], pa1 + off);
            cp_async16(&Bs[sn][r0c][c0c], pb0 + off);
            cp_async16(&Bs[sn][r1c][c1c], pb1 + off);
            cp_commit();
            cp_wait<1>();
        } else {
            cp_wait<0>();
        }
        __syncthreads();
        #pragma unroll
        for (int ks = 0; ks < 16; ks += 8) {
            uint32_t af[4][4], bf[4][2];
            #pragma unroll
            for (int mt = 0; mt < 4; mt++) {
                int r0 = wm*64 + mt*16;
                af[mt][0] = As[st][r0+g  ][ks+tig  ];
                af[mt][1] = As[st][r0+g+8][ks+tig  ];
                af[mt][2] = As[st][r0+g  ][ks+tig+4];
                af[mt][3] = As[st][r0+g+8][ks+tig+4];
            }
            #pragma unroll
            for (int nt = 0; nt < 4; nt++) {
                int c0 = wn*32 + nt*8;
                bf[nt][0] = Bs[st][c0+g][ks+tig  ];
                bf[nt][1] = Bs[st][c0+g][ks+tig+4];
            }
            #pragma unroll
            for (int mt = 0; mt < 4; mt++)
                #pragma unroll
                for (int nt = 0; nt < 4; nt++) {
                    asm volatile(
                        "mma.sync.aligned.m16n8k8.row.col.f32.tf32.tf32.f32 "
                        "{%0,%1,%2,%3}, {%4,%5,%6,%7}, {%8,%9}, {%0,%1,%2,%3};\n"
                        : "+f"(acc[mt][nt][0]), "+f"(acc[mt][nt][1]),
                          "+f"(acc[mt][nt][2]), "+f"(acc[mt][nt][3])
                        : "r"(af[mt][0]), "r"(af[mt][1]),
                          "r"(af[mt][2]), "r"(af[mt][3]),
                          "r"(bf[nt][0]), "r"(bf[nt][1]));
                }
        }
        __syncthreads();
    }
}

__global__ __launch_bounds__(256, 2) void gemm_tc_kernel(
    const float* __restrict__ A, const float* __restrict__ W,
    const float* __restrict__ bias, float* __restrict__ C,
    int K, int ldC)
{
    float acc[4][4][4];
    #pragma unroll
    for (int a = 0; a < 4; a++)
        #pragma unroll
        for (int b = 0; b < 4; b++)
            #pragma unroll
            for (int c = 0; c < 4; c++) acc[a][b][c] = 0.f;

    int m0 = blockIdx.y * 128, n0 = blockIdx.x * 128;
    mma_mainloop(acc, A, W, K, m0, n0);

    int tid = threadIdx.x;
    int lane = tid & 31, wid = tid >> 5;
    int wm = wid >> 2, wn = wid & 3;
    int g = lane >> 2, tig = lane & 3;
    int rowb = m0 + wm*64;
    int colb = n0 + wn*32;
    #pragma unroll
    for (int nt = 0; nt < 4; nt++) {
        int c = colb + nt*8 + 2*tig;
        float b0 = bias[c], b1 = bias[c+1];
        #pragma unroll
        for (int mt = 0; mt < 4; mt++) {
            int r = rowb + mt*16 + g;
            *(float2*)(C + (size_t)r*ldC + c)     = make_float2(acc[mt][nt][0]+b0, acc[mt][nt][1]+b1);
            *(float2*)(C + (size_t)(r+8)*ldC + c) = make_float2(acc[mt][nt][2]+b0, acc[mt][nt][3]+b1);
        }
    }
}

// ================= fp8 GEMM 128x128 (decoder + FF1) =================
// MODE 1: fp8 out (+bias+relu).  MODE 2: decoder lse partials.
template<int MODE>
__global__ __launch_bounds__(256, 2) void gemm_fp8_kernel(
    const uint8_t* __restrict__ A, const uint8_t* __restrict__ W,
    const float* __restrict__ bias, void* __restrict__ Cout,
    int K, int ldC, float inv, float outscale)
{
    __shared__ uint32_t As[2][128][20];
    __shared__ uint32_t Bs[2][128][20];

    float acc[4][4][4];
    #pragma unroll
    for (int a = 0; a < 4; a++)
        #pragma unroll
        for (int b = 0; b < 4; b++)
            #pragma unroll
            for (int c = 0; c < 4; c++) acc[a][b][c] = 0.f;

    int m0, n0, nblk = 0;
    if (MODE == 2) { m0 = blockIdx.x * 128; n0 = blockIdx.y * 128; nblk = blockIdx.y; }
    else           { m0 = blockIdx.y * 128; n0 = blockIdx.x * 128; }

    int tid  = threadIdx.x;
    int lane = tid & 31, wid = tid >> 5;
    int wm = wid >> 2, wn = wid & 3;
    int g = lane >> 2, tig = lane & 3;

    int a_row = (lane & 7) + ((lane >> 3) & 1) * 8;
    int a_wrd = (lane >> 4) * 4;
    int b_row = lane & 7;
    int b_wrd = ((lane >> 3) & 1) * 4;

    int r0c = tid >> 2, r1c = r0c + 64;
    int cw = (tid & 3) * 4;
    int ce = (tid & 3) * 16;
    int nr0 = n0 + r0c, nr1 = n0 + r1c;
    if (MODE == 2) { nr0 = (nr0 < NTOK) ? nr0 : (NTOK - 1); nr1 = (nr1 < NTOK) ? nr1 : (NTOK - 1); }
    const uint8_t* pa0 = A + (size_t)(m0 + r0c)*K + ce;
    const uint8_t* pa1 = A + (size_t)(m0 + r1c)*K + ce;
    const uint8_t* pb0 = W + (size_t)nr0*K + ce;
    const uint8_t* pb1 = W + (size_t)nr1*K + ce;

    int niter = K >> 6;
    cp_async16(&As[0][r0c][cw], pa0);
    cp_async16(&As[0][r1c][cw], pa1);
    cp_async16(&Bs[0][r0c][cw], pb0);
    cp_async16(&Bs[0][r1c][cw], pb1);
    cp_commit();

    for (int it = 0; it < niter; it++) {
        int st = it & 1;
        if (it + 1 < niter) {
            int off = (it + 1) << 6;
            int sn = st ^ 1;
            cp_async16(&As[sn][r0c][cw], pa0 + off);
            cp_async16(&As[sn][r1c][cw], pa1 + off);
            cp_async16(&Bs[sn][r0c][cw], pb0 + off);
            cp_async16(&Bs[sn][r1c][cw], pb1 + off);
            cp_commit();
            cp_wait<1>();
        } else {
            cp_wait<0>();
        }
        __syncthreads();
        #pragma unroll
        for (int ks = 0; ks < 2; ks++) {
            int kb = ks*8;
            uint32_t af[4][4], bf[4][2];
            #pragma unroll
            for (int mt = 0; mt < 4; mt++) {
                int r0 = wm*64 + mt*16;
                ldsm_x4(af[mt][0], af[mt][1], af[mt][2], af[mt][3],
                        &As[st][r0 + a_row][kb + a_wrd]);
            }
            #pragma unroll
            for (int nt = 0; nt < 4; nt++) {
                int c0 = wn*32 + nt*8;
                ldsm_x2(bf[nt][0], bf[nt][1],
                        &Bs[st][c0 + b_row][kb + b_wrd]);
            }
            #pragma unroll
            for (int mt = 0; mt < 4; mt++)
                #pragma unroll
                for (int nt = 0; nt < 4; nt++)
                    mma_e4m3(acc[mt][nt], af[mt][0], af[mt][1], af[mt][2], af[mt][3],
                             bf[nt][0], bf[nt][1]);
        }
        __syncthreads();
    }

    #pragma unroll
    for (int a = 0; a < 4; a++)
        #pragma unroll
        for (int b = 0; b < 4; b++)
            #pragma unroll
            for (int c = 0; c < 4; c++) acc[a][b][c] *= inv;

    int rowb = m0 + wm*64, colb = n0 + wn*32;

    if (MODE == 1) {
        uint8_t* C = (uint8_t*)Cout;
        #pragma unroll
        for (int nt = 0; nt < 4; nt++) {
            int c = colb + nt*8 + 2*tig;
            float b0 = bias[c], b1 = bias[c+1];
            #pragma unroll
            for (int mt = 0; mt < 4; mt++) {
                int r = rowb + mt*16 + g;
                float v0 = fmaxf(acc[mt][nt][0]+b0, 0.f)*outscale;
                float v1 = fmaxf(acc[mt][nt][1]+b1, 0.f)*outscale;
                float v2 = fmaxf(acc[mt][nt][2]+b0, 0.f)*outscale;
                float v3 = fmaxf(acc[mt][nt][3]+b1, 0.f)*outscale;
                *(uint16_t*)(C + (size_t)r*ldC + c)     = pack_e4m3(v0, v1);
                *(uint16_t*)(C + (size_t)(r+8)*ldC + c) = pack_e4m3(v2, v3);
            }
        }
    } else {
        __shared__ float red_m[4][128];
        __shared__ float red_s[4][128];
        #pragma unroll
        for (int mt = 0; mt < 4; mt++) {
            #pragma unroll
            for (int h = 0; h < 2; h++) {
                float m = -INFINITY;
                #pragma unroll
                for (int nt = 0; nt < 4; nt++) {
                    int c = colb + nt*8 + 2*tig;
                    if (c     < NTOK) m = fmaxf(m, acc[mt][nt][h*2+0]);
                    if (c + 1 < NTOK) m = fmaxf(m, acc[mt][nt][h*2+1]);
                }
                m = fmaxf(m, __shfl_xor_sync(0xffffffffu, m, 1));
                m = fmaxf(m, __shfl_xor_sync(0xffffffffu, m, 2));
                float s = 0.f;
                #pragma unroll
                for (int nt = 0; nt < 4; nt++) {
                    int c = colb + nt*8 + 2*tig;
                    if (c     < NTOK) s += __expf(acc[mt][nt][h*2+0] - m);
                    if (c + 1 < NTOK) s += __expf(acc[mt][nt][h*2+1] - m);
                }
                s += __shfl_xor_sync(0xffffffffu, s, 1);
                s += __shfl_xor_sync(0xffffffffu, s, 2);
                if (tig == 0) {
                    int lr = wm*64 + mt*16 + h*8 + g;
                    red_m[wn][lr] = m;
                    red_s[wn][lr] = s;
                }
            }
        }
        __syncthreads();
        if (tid < 128) {
            float m0v = red_m[0][tid], m1v = red_m[1][tid];
            float m2v = red_m[2][tid], m3v = red_m[3][tid];
            float mx = fmaxf(fmaxf(m0v, m1v), fmaxf(m2v, m3v));
            float s = red_s[0][tid]*__expf(m0v-mx) + red_s[1][tid]*__expf(m1v-mx)
                    + red_s[2][tid]*__expf(m2v-mx) + red_s[3][tid]*__expf(m3v-mx);
            int row = m0 + tid;
            g_pmax[(size_t)row*NBLK_V + nblk] = mx;
            g_psum[(size_t)row*NBLK_V + nblk] = s;
        }
    }
}

// ================= fp8 GEMM 64x64 (small-grid encoder GEMMs) =================
// MODE 0: fp32 out (+bias).  MODE 1: fp8 out (+bias+relu).
template<int MODE>
__global__ __launch_bounds__(256) void gemm_fp8_64_kernel(
    const uint8_t* __restrict__ A, const uint8_t* __restrict__ W,
    const float* __restrict__ bias, void* __restrict__ Cout,
    int K, int ldC, float inv, float outscale)
{
    __shared__ uint32_t As[2][64][20];
    __shared__ uint32_t Bs[2][64][20];

    float acc[2][2][4];
    #pragma unroll
    for (int a = 0; a < 2; a++)
        #pragma unroll
        for (int b = 0; b < 2; b++)
            #pragma unroll
            for (int c = 0; c < 4; c++) acc[a][b][c] = 0.f;

    int m0 = blockIdx.y * 64, n0 = blockIdx.x * 64;

    int tid  = threadIdx.x;
    int lane = tid & 31, wid = tid >> 5;
    int wm = wid >> 2, wn = wid & 3;       // 2 x 4 warps; warp tile 32x16
    int g = lane >> 2, tig = lane & 3;

    int a_row = (lane & 7) + ((lane >> 3) & 1) * 8;
    int a_wrd = (lane >> 4) * 4;
    int b_row = lane & 7;
    int b_wrd = ((lane >> 3) & 1) * 4;

    int r0c = tid >> 2;            // 0..63
    int cw = (tid & 3) * 4;
    int ce = (tid & 3) * 16;
    const uint8_t* pa0 = A + (size_t)(m0 + r0c)*K + ce;
    const uint8_t* pb0 = W + (size_t)(n0 + r0c)*K + ce;

    int niter = K >> 6;
    cp_async16(&As[0][r0c][cw], pa0);
    cp_async16(&Bs[0][r0c][cw], pb0);
    cp_commit();

    for (int it = 0; it < niter; it++) {
        int st = it & 1;
        if (it + 1 < niter) {
            int off = (it + 1) << 6;
            int sn = st ^ 1;
            cp_async16(&As[sn][r0c][cw], pa0 + off);
            cp_async16(&Bs[sn][r0c][cw], pb0 + off);
            cp_commit();
            cp_wait<1>();
        } else {
            cp_wait<0>();
        }
        __syncthreads();
        #pragma unroll
        for (int ks = 0; ks < 2; ks++) {
            int kb = ks*8;
            uint32_t af[2][4], bf[2][2];
            #pragma unroll
            for (int mt = 0; mt < 2; mt++) {
                int r0 = wm*32 + mt*16;
                ldsm_x4(af[mt][0], af[mt][1], af[mt][2], af[mt][3],
                        &As[st][r0 + a_row][kb + a_wrd]);
            }
            #pragma unroll
            for (int nt = 0; nt < 2; nt++) {
                int c0 = wn*16 + nt*8;
                ldsm_x2(bf[nt][0], bf[nt][1],
                        &Bs[st][c0 + b_row][kb + b_wrd]);
            }
            #pragma unroll
            for (int mt = 0; mt < 2; mt++)
                #pragma unroll
                for (int nt = 0; nt < 2; nt++)
                    mma_e4m3(acc[mt][nt], af[mt][0], af[mt][1], af[mt][2], af[mt][3],
                             bf[nt][0], bf[nt][1]);
        }
        __syncthreads();
    }

    #pragma unroll
    for (int a = 0; a < 2; a++)
        #pragma unroll
        for (int b = 0; b < 2; b++)
            #pragma unroll
            for (int c = 0; c < 4; c++) acc[a][b][c] *= inv;

    int rowb = m0 + wm*32, colb = n0 + wn*16;
    if (MODE == 0) {
        float* C = (float*)Cout;
        #pragma unroll
        for (int nt = 0; nt < 2; nt++) {
            int c = colb + nt*8 + 2*tig;
            float b0 = bias[c], b1 = bias[c+1];
            #pragma unroll
            for (int mt = 0; mt < 2; mt++) {
                int r = rowb + mt*16 + g;
                *(float2*)(C + (size_t)r*ldC + c)     = make_float2(acc[mt][nt][0]+b0, acc[mt][nt][1]+b1);
                *(float2*)(C + (size_t)(r+8)*ldC + c) = make_float2(acc[mt][nt][2]+b0, acc[mt][nt][3]+b1);
            }
        }
    } else {
        uint8_t* C = (uint8_t*)Cout;
        #pragma unroll
        for (int nt = 0; nt < 2; nt++) {
            int c = colb + nt*8 + 2*tig;
            float b0 = bias[c], b1 = bias[c+1];
            #pragma unroll
            for (int mt = 0; mt < 2; mt++) {
                int r = rowb + mt*16 + g;
                float v0 = fmaxf(acc[mt][nt][0]+b0, 0.f)*outscale;
                float v1 = fmaxf(acc[mt][nt][1]+b1, 0.f)*outscale;
                float v2 = fmaxf(acc[mt][nt][2]+b0, 0.f)*outscale;
                float v3 = fmaxf(acc[mt][nt][3]+b1, 0.f)*outscale;
                *(uint16_t*)(C + (size_t)r*ldC + c)     = pack_e4m3(v0, v1);
                *(uint16_t*)(C + (size_t)(r+8)*ldC + c) = pack_e4m3(v2, v3);
            }
        }
    }
}

__global__ void lse_reduce_kernel()
{
    int r = blockIdx.x, tid = threadIdx.x;
    __shared__ float red[128];
    float m = -INFINITY;
    for (int i = tid; i < NBLK_V; i += 128) m = fmaxf(m, g_pmax[(size_t)r*NBLK_V + i]);
    red[tid] = m; __syncthreads();
    for (int s = 64; s > 0; s >>= 1) { if (tid < s) red[tid] = fmaxf(red[tid], red[tid+s]); __syncthreads(); }
    float gm = red[0]; __syncthreads();
    double sum = 0.0;
    for (int i = tid; i < NBLK_V; i += 128)
        sum += (double)g_psum[(size_t)r*NBLK_V + i] * exp((double)g_pmax[(size_t)r*NBLK_V + i] - (double)gm);
    __shared__ double redd[128];
    redd[tid] = sum; __syncthreads();
    for (int s = 64; s > 0; s >>= 1) { if (tid < s) redd[tid] += redd[tid+s]; __syncthreads(); }
    if (tid == 0) g_lse[r] = gm + (float)log(redd[0]);
}

// ---------------- small-M GEMM ----------------
__global__ void rowdot_kernel(
    const float* __restrict__ A, long strideA,
    const float* __restrict__ W, const float* __restrict__ bias,
    float* __restrict__ C, long strideC,
    int M, int K, float alpha, int relu)
{
    int n = blockIdx.x;
    int tid = threadIdx.x;   // 128
    const float* w = W + (size_t)n * K;
    __shared__ float red[128];
    for (int m = 0; m < M; m++) {
        const float* a = A + (size_t)m * strideA;
        float s = 0.f;
        for (int k = tid; k < K; k += 128) s += a[k]*w[k];
        red[tid] = s; __syncthreads();
        for (int st = 64; st > 0; st >>= 1) { if (tid < st) red[tid] += red[tid+st]; __syncthreads(); }
        if (tid == 0) {
            float v = alpha*red[0] + (bias ? bias[n] : 0.f);
            if (relu) v = fmaxf(v, 0.f);
            C[(size_t)m*strideC + n] = v;
        }
        __syncthreads();
    }
}

// ---------------- attention, 8 queries per block, fp8 out ----------------
#define QT 8
__global__ __launch_bounds__(256) void attn8_kernel(
    const float* __restrict__ qkv, uint8_t* __restrict__ out)
{
    int qt = blockIdx.x, h = blockIdx.y, b = blockIdx.z;
    int tid = threadIdx.x;
    __shared__ float qs[QT][DHEAD];
    __shared__ float sc[QT][NSEQ];
    __shared__ float den[QT];
    const float* base = qkv + (size_t)b*NSEQ*QKV_LD;
    if (tid < 128) {
        int q = tid >> 4;
        int c = (tid & 15) * 4;
        *(float4*)&qs[q][c] =
            *(const float4*)(base + (size_t)(qt*QT+q)*QKV_LD + h*DHEAD + c);
    }
    __syncthreads();
    {
        int j = tid;
        float4 kreg[16];
        const float4* kr = (const float4*)(base + (size_t)j*QKV_LD + D_MODEL + h*DHEAD);
        #pragma unroll
        for (int t = 0; t < 16; t++) kreg[t] = kr[t];
        #pragma unroll
        for (int q = 0; q < QT; q++) {
            float d = 0.f;
            #pragma unroll
            for (int t = 0; t < 16; t++) {
                float4 q4 = *(float4*)&qs[q][t*4];
                d += q4.x*kreg[t].x + q4.y*kreg[t].y + q4.z*kreg[t].z + q4.w*kreg[t].w;
            }
            sc[q][j] = d * 0.125f;
        }
    }
    __syncthreads();
    {
        int w = tid >> 5, lane = tid & 31;
        float v[8];
        float m = -INFINITY;
        #pragma unroll
        for (int t = 0; t < 8; t++) { v[t] = sc[w][lane + 32*t]; m = fmaxf(m, v[t]); }
        #pragma unroll
        for (int o = 16; o; o >>= 1) m = fmaxf(m, __shfl_xor_sync(0xffffffffu, m, o));
        float s = 0.f;
        #pragma unroll
        for (int t = 0; t < 8; t++) { v[t] = expf(v[t]-m); s += v[t]; }
        #pragma unroll
        for (int o = 16; o; o >>= 1) s += __shfl_xor_sync(0xffffffffu, s, o);
        #pragma unroll
        for (int t = 0; t < 8; t++) sc[w][lane + 32*t] = v[t];
        if (lane == 0) den[w] = s;
    }
    __syncthreads();
    {
        int d = tid & 63, qp = tid >> 6;
        int q0 = qp*2, q1 = qp*2+1;
        const float* vb = base + 2*D_MODEL + h*DHEAD + d;
        float a0 = 0.f, a1 = 0.f;
        #pragma unroll 8
        for (int j = 0; j < NSEQ; j++) {
            float v = vb[(size_t)j*QKV_LD];
            a0 += sc[q0][j]*v;
            a1 += sc[q1][j]*v;
        }
        uint16_t p0 = pack_e4m3(a0/den[q0]*SA, 0.f);
        uint16_t p1 = pack_e4m3(a1/den[q1]*SA, 0.f);
        out[((size_t)(b*NSEQ + qt*QT + q0))*D_MODEL + h*DHEAD + d] = (uint8_t)p0;
        out[((size_t)(b*NSEQ + qt*QT + q1))*D_MODEL + h*DHEAD + d] = (uint8_t)p1;
    }
}

// ---------------- loc attention (single query per (h,b)), fp32 out ----------------
__global__ __launch_bounds__(256) void attn_kernel(
    const float* __restrict__ qkv, float* __restrict__ out, int nq, int sq_base)
{
    int qi = blockIdx.x, h = blockIdx.y, b = blockIdx.z;
    int sq = sq_base + qi;
    int tid = threadIdx.x;
    __shared__ float4 qrow[DHEAD/4];
    __shared__ float sc[NSEQ];
    __shared__ float red[256];
    __shared__ float sden;
    __shared__ float osum[4][DHEAD];
    const float* base = qkv + (size_t)b * NSEQ * QKV_LD;
    if (tid < DHEAD/4)
        qrow[tid] = ((const float4*)(base + (size_t)sq*QKV_LD + h*DHEAD))[tid];
    __syncthreads();
    {
        const float4* krow = (const float4*)(base + (size_t)tid*QKV_LD + D_MODEL + h*DHEAD);
        float d = 0.f;
        #pragma unroll
        for (int t = 0; t < DHEAD/4; t++) {
            float4 k4 = krow[t];
            float4 q4 = qrow[t];
            d += q4.x*k4.x + q4.y*k4.y + q4.z*k4.z + q4.w*k4.w;
        }
        sc[tid] = d * 0.125f;
    }
    __syncthreads();
    red[tid] = sc[tid]; __syncthreads();
    for (int s = 128; s > 0; s >>= 1) { if (tid < s) red[tid] = fmaxf(red[tid], red[tid+s]); __syncthreads(); }
    float mx = red[0]; __syncthreads();
    float e = expf(sc[tid] - mx);
    red[tid] = e; __syncthreads();
    for (int s = 128; s > 0; s >>= 1) { if (tid < s) red[tid] += red[tid+s]; __syncthreads(); }
    if (tid == 0) sden = red[0];
    __syncthreads();
    sc[tid] = e;
    __syncthreads();
    int d = tid & 63, g = tid >> 6;
    const float* vb = base + 2*D_MODEL + h*DHEAD + d;
    float o = 0.f;
    for (int j = g*64; j < (g+1)*64; j++) o += sc[j] * vb[(size_t)j*QKV_LD];
    osum[g][d] = o; __syncthreads();
    if (tid < DHEAD) {
        float r = (osum[0][tid]+osum[1][tid]+osum[2][tid]+osum[3][tid]) / sden;
        out[((size_t)(b*nq + qi))*D_MODEL + h*DHEAD + tid] = r;
    }
}

// ---------------- residual + layernorm (fp32 out + optional fp8 mirror) ----------
__global__ void ln_kernel(
    const float* __restrict__ in1, long s1,
    const float* __restrict__ in2, long s2,
    float* __restrict__ out, long so,
    uint8_t* __restrict__ outq, float qs,
    const float* __restrict__ gam, const float* __restrict__ bet)
{
    int r = blockIdx.x, tid = threadIdx.x;
    __shared__ float xr[D_MODEL];
    __shared__ float red[256];
    const float* p1 = in1 + (size_t)r*s1;
    const float* p2 = in2 + (size_t)r*s2;
    float ls = 0.f;
    for (int d = tid; d < D_MODEL; d += 256) { float v = p1[d]+p2[d]; xr[d] = v; ls += v; }
    red[tid] = ls; __syncthreads();
    for (int s = 128; s > 0; s >>= 1) { if (tid < s) red[tid] += red[tid+s]; __syncthreads(); }
    float mean = red[0] * (1.f/D_MODEL); __syncthreads();
    float lv = 0.f;
    for (int d = tid; d < D_MODEL; d += 256) { float t = xr[d]-mean; lv += t*t; }
    red[tid] = lv; __syncthreads();
    for (int s = 128; s > 0; s >>= 1) { if (tid < s) red[tid] += red[tid+s]; __syncthreads(); }
    float rstd = 1.f / sqrtf(red[0]*(1.f/D_MODEL) + 1e-5f);
    for (int d = tid*2; d < D_MODEL; d += 512) {
        float v0 = (xr[d]  -mean)*rstd*gam[d]   + bet[d];
        float v1 = (xr[d+1]-mean)*rstd*gam[d+1] + bet[d+1];
        *(float2*)(out + (size_t)r*so + d) = make_float2(v0, v1);
        if (outq) *(uint16_t*)(outq + (size_t)r*D_MODEL + d) = pack_e4m3(v0*qs, v1*qs);
    }
}

// ---------------- gating statistics + top-k + softmax + importance ----------------
__global__ void stats_kernel(const float* __restrict__ w, const float* __restrict__ noise)
{
    __shared__ float tot[NEXP];
    __shared__ double redd[256];
    __shared__ float fv[256];
    __shared__ int   fi[256];
    __shared__ float topv[NKTOP];
    __shared__ double smean, sstd;
    int tid = threadIdx.x;
    double ls = 0.0;
    for (int n = tid; n < NEXP; n += 256) {
        float f = 0.25f*(w[n] + w[NEXP+n] + w[2*NEXP+n] + w[3*NEXP+n]);
        tot[n] = f; ls += (double)f;
    }
    redd[tid] = ls; __syncthreads();
    for (int s = 128; s > 0; s >>= 1) { if (tid < s) redd[tid] += redd[tid+s]; __syncthreads(); }
    if (tid == 0) smean = redd[0] / NEXP;
    __syncthreads();
    double mfm = smean;
    ls = 0.0;
    for (int n = tid; n < NEXP; n += 256) { double t = (double)tot[n]-mfm; ls += t*t; }
    redd[tid] = ls; __syncthreads();
    for (int s = 128; s > 0; s >>= 1) { if (tid < s) redd[tid] += redd[tid+s]; __syncthreads(); }
    if (tid == 0) sstd = sqrt(redd[0] / (NEXP-1));
    __syncthreads();
    float stdfm = (float)sstd;
    for (int n = tid; n < NEXP; n += 256) tot[n] = tot[n] + noise[n]*stdfm;
    __syncthreads();
    ls = 0.0;
    for (int n = tid; n < NEXP; n += 256) ls += (double)tot[n];
    redd[tid] = ls; __syncthreads();
    for (int s = 128; s > 0; s >>= 1) { if (tid < s) redd[tid] += redd[tid+s]; __syncthreads(); }
    if (tid == 0) smean = redd[0] / NEXP;
    __syncthreads();
    double mt = smean;
    ls = 0.0;
    for (int n = tid; n < NEXP; n += 256) { double t = (double)tot[n]-mt; ls += t*t; }
    redd[tid] = ls; __syncthreads();
    for (int s = 128; s > 0; s >>= 1) { if (tid < s) redd[tid] += redd[tid+s]; __syncthreads(); }
    if (tid == 0) {
        double st = sqrt(redd[0] / (NEXP-1));
        double ratio = st / mt;
        g_stats[20] = (float)(0.1 * ratio * ratio);
    }
    __syncthreads();
    for (int it = 0; it < NKTOP; it++) {
        float bv = -INFINITY; int bi = 0x7fffffff;
        for (int n = tid; n < NEXP; n += 256) {
            float v = tot[n];
            if (v > bv || (v == bv && n < bi)) { bv = v; bi = n; }
        }
        fv[tid] = bv; fi[tid] = bi; __syncthreads();
        for (int s = 128; s > 0; s >>= 1) {
            if (tid < s) {
                float v2 = fv[tid+s]; int i2 = fi[tid+s];
                if (v2 > fv[tid] || (v2 == fv[tid] && i2 < fi[tid])) { fv[tid] = v2; fi[tid] = i2; }
            }
            __syncthreads();
        }
        if (tid == 0) { topv[it] = fv[0]; tot[fi[0]] = -INFINITY; }
        __syncthreads();
    }
    if (tid == 0) {
        float m = topv[0];
        float s = 0.f;
        float e[NKTOP];
        for (int k = 0; k < NKTOP; k++) { e[k] = expf(topv[k]-m); s += e[k]; }
        for (int k = 0; k < NKTOP; k++) g_stats[k] = e[k]/s;
    }
}

// ---------------- response mixture (fp32 + fp8 mirror) ----------------
__global__ void mix_kernel(const float* __restrict__ responses)
{
    __shared__ float w[NKTOP];
    if (threadIdx.x < NKTOP) w[threadIdx.x] = g_stats[threadIdx.x];
    __syncthreads();
    int i = blockIdx.x*blockDim.x + threadIdx.x;
    if (i < (NROWS*D_MODEL)/4) {
        float4 s = make_float4(0.f, 0.f, 0.f, 0.f);
        #pragma unroll
        for (int k = 0; k < NKTOP; k++) {
            float4 v = ((const float4*)responses)[(size_t)k*((NROWS*D_MODEL)/4) + i];
            float wk = w[k];
            s.x += wk*v.x; s.y += wk*v.y; s.z += wk*v.z; s.w += wk*v.w;
        }
        ((float4*)g_x)[i] = s;
        uint32_t lo = pack_e4m3(s.x*SX, s.y*SX);
        uint32_t hi = pack_e4m3(s.z*SX, s.w*SX);
        ((uint32_t*)q_x)[i] = lo | (hi << 16);
    }
}

// ---------------- label logit + final loss ----------------
__global__ void lablogit_kernel(const int* __restrict__ inputs, const float* __restrict__ dec_w)
{
    int s = blockIdx.x, b = blockIdx.y, tid = threadIdx.x;
    int lbl = inputs[b*NSEQ + s + 1];
    const float* a = g_x + ((size_t)(b*NSEQ + s))*D_MODEL;
    const float* wp = dec_w + (size_t)lbl*D_MODEL;
    __shared__ float red[128];
    float acc = 0.f;
    for (int k = tid; k < D_MODEL; k += 128) acc += a[k]*wp[k];
    red[tid] = acc; __syncthreads();
    for (int st = 64; st > 0; st >>= 1) { if (tid < st) red[tid] += red[tid+st]; __syncthreads(); }
    if (tid == 0) g_lab[b*(NSEQ-1)+s] = red[0];
}

__global__ void final_kernel(float* __restrict__ out)
{
    __shared__ double red[256];
    int tid = threadIdx.x;
    double s = 0.0;
    for (int i = tid; i < NB*(NSEQ-1); i += 256) {
        int b = i/(NSEQ-1), sp = i%(NSEQ-1);
        s += (double)g_lab[i] - (double)g_lse[b*NSEQ+sp];
    }
    red[tid] = s; __syncthreads();
    for (int st = 128; st > 0; st >>= 1) { if (tid < st) red[tid] += red[tid+st]; __syncthreads(); }
    if (tid == 0) {
        double ce = -red[0] / (double)(NB*(NSEQ-1));
        out[0] = (float)(ce + (double)g_stats[20]);
    }
}

// ---------------- host driver ----------------
extern "C" void kernel_launch(void* const* d_in, const int* in_sizes, int n_in,
                              void* d_out, int out_size)
{
    (void)in_sizes; (void)n_in; (void)out_size;
    const int*   inputs    = (const int*)  d_in[0];
    const float* responses = (const float*)d_in[1];
    const float* noise     = (const float*)d_in[2];
    const float* emb       = (const float*)d_in[3];
    const float* loc_Wqkv  = (const float*)d_in[4];
    const float* loc_bqkv  = (const float*)d_in[5];
    const float* loc_Wo    = (const float*)d_in[6];
    const float* loc_bo    = (const float*)d_in[7];
    const float* loc_ln1g  = (const float*)d_in[8];
    const float* loc_ln1b  = (const float*)d_in[9];
    const float* loc_W1    = (const float*)d_in[10];
    const float* loc_b1    = (const float*)d_in[11];
    const float* loc_W2    = (const float*)d_in[12];
    const float* loc_b2    = (const float*)d_in[13];
    const float* loc_ln2g  = (const float*)d_in[14];
    const float* loc_ln2b  = (const float*)d_in[15];
    const float* enc_Wqkv  = (const float*)d_in[16];
    const float* enc_bqkv  = (const float*)d_in[17];
    const float* enc_Wo    = (const float*)d_in[18];
    const float* enc_bo    = (const float*)d_in[19];
    const float* enc_ln1g  = (const float*)d_in[20];
    const float* enc_ln1b  = (const float*)d_in[21];
    const float* enc_W1    = (const float*)d_in[22];
    const float* enc_b1    = (const float*)d_in[23];
    const float* enc_W2    = (const float*)d_in[24];
    const float* enc_b2    = (const float*)d_in[25];
    const float* enc_ln2g  = (const float*)d_in[26];
    const float* enc_ln2b  = (const float*)d_in[27];
    const float* gate_w    = (const float*)d_in[28];
    const float* gate_b    = (const float*)d_in[29];
    const float* dec_w     = (const float*)d_in[30];
    float* out = (float*)d_out;

    float *p_x, *p_qkv, *p_tmp;
    float *p_sm_attn, *p_sm_x, *p_sm_tmp, *p_sm_ctx, *p_sm_ffh;
    uint8_t *p_qWqkv, *p_qWo, *p_qW1, *p_qW2, *p_qdec, *p_qx, *p_qattn, *p_qffh;
    cudaGetSymbolAddress((void**)&p_x, g_x);
    cudaGetSymbolAddress((void**)&p_qkv, g_qkv);
    cudaGetSymbolAddress((void**)&p_tmp, g_tmp);
    cudaGetSymbolAddress((void**)&p_sm_attn, g_sm_attn);
    cudaGetSymbolAddress((void**)&p_sm_x, g_sm_x);
    cudaGetSymbolAddress((void**)&p_sm_tmp, g_sm_tmp);
    cudaGetSymbolAddress((void**)&p_sm_ctx, g_sm_ctx);
    cudaGetSymbolAddress((void**)&p_sm_ffh, g_sm_ffh);
    cudaGetSymbolAddress((void**)&p_qWqkv, q_Wqkv);
    cudaGetSymbolAddress((void**)&p_qWo, q_Wo);
    cudaGetSymbolAddress((void**)&p_qW1, q_W1);
    cudaGetSymbolAddress((void**)&p_qW2, q_W2);
    cudaGetSymbolAddress((void**)&p_qdec, q_dec);
    cudaGetSymbolAddress((void**)&p_qx, q_x);
    cudaGetSymbolAddress((void**)&p_qattn, q_attn);
    cudaGetSymbolAddress((void**)&p_qffh, q_ffh);

    // ---- capture-forked side stream for weight conversions ----
    cudaStream_t s2;
    cudaStreamCreateWithFlags(&s2, cudaStreamNonBlocking);
    cudaEvent_t evFork, evEnc, evDec;
    cudaEventCreateWithFlags(&evFork, cudaEventDisableTiming);
    cudaEventCreateWithFlags(&evEnc,  cudaEventDisableTiming);
    cudaEventCreateWithFlags(&evDec,  cudaEventDisableTiming);

    cudaEventRecord(evFork, 0);
    cudaStreamWaitEvent(s2, evFork, 0);

    q8_kernel<<<(2*QKV_LD*D_MODEL/8 + 255)/256, 256, 0, s2>>>(enc_Wqkv, p_qWqkv, 2*QKV_LD*D_MODEL/4, SW);
    q8_kernel<<<(2*D_MODEL*D_MODEL/8 + 255)/256, 256, 0, s2>>>(enc_Wo, p_qWo, 2*D_MODEL*D_MODEL/4, SW);
    q8_kernel<<<(2*FF_DIM*D_MODEL/8 + 255)/256, 256, 0, s2>>>(enc_W1, p_qW1, 2*FF_DIM*D_MODEL/4, SW);
    q8_kernel<<<(2*D_MODEL*FF_DIM/8 + 255)/256, 256, 0, s2>>>(enc_W2, p_qW2, 2*D_MODEL*FF_DIM/4, SW);
    cudaEventRecord(evEnc, s2);
    q8_kernel<<<(NTOK*D_MODEL/8 + 255)/256, 256, 0, s2>>>(dec_w, p_qdec, NTOK*D_MODEL/4, SW);
    cudaEventRecord(evDec, s2);

    // default stream: embed + loc layer + gating
    embed_kernel<<<NROWS, 256>>>(inputs, emb);
    gemm_tc_kernel<<<dim3(2048/128, NROWS/128), 256>>>(
        p_x, loc_Wqkv + (size_t)D_MODEL*D_MODEL, loc_bqkv + D_MODEL,
        p_qkv + D_MODEL, D_MODEL, QKV_LD);
    rowdot_kernel<<<D_MODEL, 128>>>(
        p_x + (size_t)(NSEQ-1)*D_MODEL, (long)NSEQ*D_MODEL,
        loc_Wqkv, loc_bqkv,
        p_qkv + (size_t)(NSEQ-1)*QKV_LD, (long)NSEQ*QKV_LD,
        NB, D_MODEL, 1.f, 0);
    attn_kernel<<<dim3(1, NHEAD, NB), 256>>>(p_qkv, p_sm_attn, 1, NSEQ-1);
    rowdot_kernel<<<D_MODEL, 128>>>(p_sm_attn, D_MODEL, loc_Wo, loc_bo,
                                    p_sm_tmp, D_MODEL, NB, D_MODEL, 1.f, 0);
    ln_kernel<<<NB, 256>>>(p_x + (size_t)(NSEQ-1)*D_MODEL, (long)NSEQ*D_MODEL,
                           p_sm_tmp, D_MODEL, p_sm_x, D_MODEL, (uint8_t*)0, 0.f,
                           loc_ln1g, loc_ln1b);
    rowdot_kernel<<<FF_DIM, 128>>>(p_sm_x, D_MODEL, loc_W1, loc_b1,
                                   p_sm_ffh, FF_DIM, NB, D_MODEL, 1.f, 1);
    rowdot_kernel<<<D_MODEL, 128>>>(p_sm_ffh, FF_DIM, loc_W2, loc_b2,
                                    p_sm_tmp, D_MODEL, NB, FF_DIM, 1.f, 0);
    ln_kernel<<<NB, 256>>>(p_sm_x, D_MODEL, p_sm_tmp, D_MODEL,
                           p_sm_ctx, D_MODEL, (uint8_t*)0, 0.f,
                           loc_ln2g, loc_ln2b);

    rowdot_kernel<<<NEXP, 128>>>(p_sm_ctx, D_MODEL, gate_w, gate_b,
                                 out + 1, NEXP, NB, D_MODEL, 32.f, 0);
    stats_kernel<<<1, 256>>>(out + 1, noise);
    mix_kernel<<<(NROWS*D_MODEL/4 + 255)/256, 256>>>(responses);

    cudaStreamWaitEvent(0, evEnc, 0);

    // two encoder layers (fp8 tensor cores; 64x64 tiles for small GEMMs)
    const float invXW = 1.f/(SX*SW);
    const float invAW = 1.f/(SA*SW);
    const float invFW = 1.f/(SF*SW);
    for (int l = 0; l < 2; l++) {
        const uint8_t* Wqkv = p_qWqkv + (size_t)l*QKV_LD*D_MODEL;
        const float*   bqkv = enc_bqkv + (size_t)l*QKV_LD;
        const uint8_t* Wo   = p_qWo   + (size_t)l*D_MODEL*D_MODEL;
        const float*   bo   = enc_bo  + (size_t)l*D_MODEL;
        const float* g1   = enc_ln1g + (size_t)l*D_MODEL;
        const float* b1l  = enc_ln1b + (size_t)l*D_MODEL;
        const uint8_t* W1   = p_qW1   + (size_t)l*FF_DIM*D_MODEL;
        const float*   bb1  = enc_b1  + (size_t)l*FF_DIM;
        const uint8_t* W2   = p_qW2   + (size_t)l*D_MODEL*FF_DIM;
        const float*   bb2  = enc_b2  + (size_t)l*D_MODEL;
        const float* g2   = enc_ln2g + (size_t)l*D_MODEL;
        const float* b2l  = enc_ln2b + (size_t)l*D_MODEL;

        gemm_fp8_64_kernel<0><<<dim3(QKV_LD/64, NROWS/64), 256>>>(
            p_qx, Wqkv, bqkv, p_qkv, D_MODEL, QKV_LD, invXW, 0.f);
        attn8_kernel<<<dim3(NSEQ/QT, NHEAD, NB), 256>>>(p_qkv, p_qattn);
        gemm_fp8_64_kernel<0><<<dim3(D_MODEL/64, NROWS/64), 256>>>(
            p_qattn, Wo, bo, p_tmp, D_MODEL, D_MODEL, invAW, 0.f);
        ln_kernel<<<NROWS, 256>>>(p_x, D_MODEL, p_tmp, D_MODEL, p_x, D_MODEL,
                                  p_qx, SX, g1, b1l);
        gemm_fp8_kernel<1><<<dim3(FF_DIM/128, NROWS/128), 256>>>(
            p_qx, W1, bb1, p_qffh, D_MODEL, FF_DIM, invXW, SF);
        gemm_fp8_64_kernel<0><<<dim3(D_MODEL/64, NROWS/64), 256>>>(
            p_qffh, W2, bb2, p_tmp, FF_DIM, D_MODEL, invFW, 0.f);
        ln_kernel<<<NROWS, 256>>>(p_x, D_MODEL, p_tmp, D_MODEL, p_x, D_MODEL,
                                  p_qx, SX, g2, b2l);
    }

    cudaStreamWaitEvent(0, evDec, 0);

    gemm_fp8_kernel<2><<<dim3(NROWS/128, NBLK_V), 256>>>(
        p_qx, p_qdec, (const float*)0, (void*)0, D_MODEL, 0, invXW, 0.f);
    lse_reduce_kernel<<<NROWS, 128>>>();
    lablogit_kernel<<<dim3(NSEQ-1, NB), 128>>>(inputs, dec_w);
    final_kernel<<<1, 256>>>(out);

    cudaEventDestroy(evFork);
    cudaEventDestroy(evEnc);
    cudaEventDestroy(evDec);
    cudaStreamDestroy(s2);
}

// round 13
// speedup vs baseline: 1.2095x; 1.0031x over previous
#include <cuda_runtime.h>
#include <cuda_bf16.h>
#include <math.h>
#include <stdint.h>

// ---------------- problem constants ----------------
#define D_MODEL 1024
#define NHEAD   16
#define DHEAD   64
#define FF_DIM  4096
#define NSEQ    256
#define NB      4
#define NTOK    50257
#define NEXP    2000
#define NKTOP   20
#define NROWS   (NB*NSEQ)      // 1024
#define QKV_LD  3072
#define NBLK_V  393            // ceil(50257/128)

// fp8 per-tensor scales
#define SX  16.0f
#define SW  512.0f
#define SA  64.0f
#define SF  32.0f

// ---------------- scratch ----------------
__device__ float g_x    [NROWS*D_MODEL];
__device__ float g_qkv  [NROWS*QKV_LD];
__device__ float g_tmp  [NROWS*D_MODEL];
__device__ float g_sm_attn[NB*D_MODEL];
__device__ float g_sm_x   [NB*D_MODEL];
__device__ float g_sm_tmp [NB*D_MODEL];
__device__ float g_sm_ctx [NB*D_MODEL];
__device__ float g_sm_ffh [NB*FF_DIM];
__device__ float g_psum[NROWS*NBLK_V];
__device__ float g_lse [NROWS];
__device__ float g_lab [NB*(NSEQ-1)];
__device__ float g_stats[32];

// fp8 mirrors
__device__ __align__(256) uint8_t q_Wqkv[2*QKV_LD*D_MODEL];
__device__ __align__(256) uint8_t q_Wo  [2*D_MODEL*D_MODEL];
__device__ __align__(256) uint8_t q_W1  [2*FF_DIM*D_MODEL];
__device__ __align__(256) uint8_t q_W2  [2*D_MODEL*FF_DIM];
__device__ __align__(256) uint8_t q_dec [NTOK*D_MODEL];
__device__ __align__(256) uint8_t q_x   [NROWS*D_MODEL];
__device__ __align__(256) uint8_t q_attn[NROWS*D_MODEL];
__device__ __align__(256) uint8_t q_ffh [NROWS*FF_DIM];

// ---------------- fp8 pack + fast fma-pipe exp ----------------
__device__ __forceinline__ uint16_t pack_e4m3(float lo, float hi)
{
    uint16_t r;
    asm("cvt.rn.satfinite.e4m3x2.f32 %0, %1, %2;" : "=h"(r) : "f"(hi), "f"(lo));
    return r;
}

// exp(x) on the FMA pipe: 2^t, t = x*log2e; degree-6 Taylor of 2^f on [0,1)
// plus exponent-bit splice.  |rel err| < 2e-5 for |x| < 60.
__device__ __forceinline__ float fast_exp(float x)
{
    float t = x * 1.4426950408889634f;
    float fi = floorf(t);
    float f = t - fi;
    float p = 1.5403530e-4f;
    p = fmaf(p, f, 1.3333558e-3f);
    p = fmaf(p, f, 9.6180489e-3f);
    p = fmaf(p, f, 5.5504109e-2f);
    p = fmaf(p, f, 2.4022651e-1f);
    p = fmaf(p, f, 6.9314718e-1f);
    p = fmaf(p, f, 1.0f);
    return __int_as_float(__float_as_int(p) + (((int)fi) << 23));
}

__global__ void q8_kernel(const float* __restrict__ src, uint8_t* __restrict__ dst,
                          int n4, float scale)
{
    int i = (blockIdx.x*blockDim.x + threadIdx.x) * 2;
    #pragma unroll
    for (int t = 0; t < 2; t++) {
        int j = i + t;
        if (j < n4) {
            float4 v = ((const float4*)src)[j];
            uint32_t lo = pack_e4m3(v.x*scale, v.y*scale);
            uint32_t hi = pack_e4m3(v.z*scale, v.w*scale);
            ((uint32_t*)dst)[j] = lo | (hi << 16);
        }
    }
}

// ---------------- embedding gather ----------------
__global__ void embed_kernel(const int* __restrict__ inputs, const float* __restrict__ emb)
{
    int r = blockIdx.x;
    int tok = inputs[r];
    const float4* src = (const float4*)(emb + (size_t)tok * D_MODEL);
    float4* dst = (float4*)(g_x + (size_t)r * D_MODEL);
    dst[threadIdx.x] = src[threadIdx.x];
}

// ================= cp.async / ldmatrix helpers =================
__device__ __forceinline__ void cp_async16(void* smem, const void* gmem)
{
    uint32_t s = (uint32_t)__cvta_generic_to_shared(smem);
    asm volatile("cp.async.ca.shared.global [%0], [%1], 16;\n" :: "r"(s), "l"(gmem));
}
__device__ __forceinline__ void cp_commit()
{
    asm volatile("cp.async.commit_group;\n" ::: "memory");
}
template<int N> __device__ __forceinline__ void cp_wait()
{
    asm volatile("cp.async.wait_group %0;\n" :: "n"(N) : "memory");
}
__device__ __forceinline__ void ldsm_x4(uint32_t& r0, uint32_t& r1, uint32_t& r2, uint32_t& r3,
                                        const void* smem)
{
    uint32_t a = (uint32_t)__cvta_generic_to_shared(smem);
    asm volatile("ldmatrix.sync.aligned.m8n8.x4.shared.b16 {%0,%1,%2,%3}, [%4];\n"
                 : "=r"(r0), "=r"(r1), "=r"(r2), "=r"(r3) : "r"(a));
}
__device__ __forceinline__ void ldsm_x2(uint32_t& r0, uint32_t& r1, const void* smem)
{
    uint32_t a = (uint32_t)__cvta_generic_to_shared(smem);
    asm volatile("ldmatrix.sync.aligned.m8n8.x2.shared.b16 {%0,%1}, [%2];\n"
                 : "=r"(r0), "=r"(r1) : "r"(a));
}
__device__ __forceinline__ void mma_e4m3(float* a4, uint32_t a0, uint32_t a1, uint32_t a2, uint32_t a3,
                                         uint32_t b0, uint32_t b1)
{
    asm volatile(
        "mma.sync.aligned.m16n8k32.row.col.f32.e4m3.e4m3.f32 "
        "{%0,%1,%2,%3}, {%4,%5,%6,%7}, {%8,%9}, {%0,%1,%2,%3};\n"
        : "+f"(a4[0]), "+f"(a4[1]), "+f"(a4[2]), "+f"(a4[3])
        : "r"(a0), "r"(a1), "r"(a2), "r"(a3), "r"(b0), "r"(b1));
}
__device__ __forceinline__ void mma_tf32(float* a4, uint32_t a0, uint32_t a1, uint32_t a2, uint32_t a3,
                                         uint32_t b0, uint32_t b1)
{
    asm volatile(
        "mma.sync.aligned.m16n8k8.row.col.f32.tf32.tf32.f32 "
        "{%0,%1,%2,%3}, {%4,%5,%6,%7}, {%8,%9}, {%0,%1,%2,%3};\n"
        : "+f"(a4[0]), "+f"(a4[1]), "+f"(a4[2]), "+f"(a4[3])
        : "r"(a0), "r"(a1), "r"(a2), "r"(a3), "r"(b0), "r"(b1));
}

// ================= tf32 GEMM 64x64 (loc KV path) =================
__global__ __launch_bounds__(256) void gemm_tc64_kernel(
    const float* __restrict__ A, const float* __restrict__ W,
    const float* __restrict__ bias, float* __restrict__ C,
    int K, int ldC)
{
    __shared__ uint32_t As[2][64][20];
    __shared__ uint32_t Bs[2][64][20];
    float acc[2][2][4];
    #pragma unroll
    for (int a = 0; a < 2; a++)
        #pragma unroll
        for (int b = 0; b < 2; b++)
            #pragma unroll
            for (int c = 0; c < 4; c++) acc[a][b][c] = 0.f;

    int m0 = blockIdx.y * 64, n0 = blockIdx.x * 64;
    int tid  = threadIdx.x;
    int lane = tid & 31, wid = tid >> 5;
    int wm = wid >> 2, wn = wid & 3;     // warp tile 32 x 16
    int g = lane >> 2, tig = lane & 3;

    int r0c = tid >> 2, c0c = (tid & 3) << 2;
    const float* pa0 = A + (size_t)(m0 + r0c)*K + c0c;
    const float* pb0 = W + (size_t)(n0 + r0c)*K + c0c;

    int niter = K >> 4;
    cp_async16(&As[0][r0c][c0c], pa0);
    cp_async16(&Bs[0][r0c][c0c], pb0);
    cp_commit();

    for (int it = 0; it < niter; it++) {
        int st = it & 1;
        if (it + 1 < niter) {
            int off = (it + 1) << 4;
            int sn = st ^ 1;
            cp_async16(&As[sn][r0c][c0c], pa0 + off);
            cp_async16(&Bs[sn][r0c][c0c], pb0 + off);
            cp_commit();
            cp_wait<1>();
        } else {
            cp_wait<0>();
        }
        __syncthreads();
        #pragma unroll
        for (int ks = 0; ks < 16; ks += 8) {
            uint32_t af[2][4], bf[2][2];
            #pragma unroll
            for (int mt = 0; mt < 2; mt++) {
                int r0 = wm*32 + mt*16;
                af[mt][0] = As[st][r0+g  ][ks+tig  ];
                af[mt][1] = As[st][r0+g+8][ks+tig  ];
                af[mt][2] = As[st][r0+g  ][ks+tig+4];
                af[mt][3] = As[st][r0+g+8][ks+tig+4];
            }
            #pragma unroll
            for (int nt = 0; nt < 2; nt++) {
                int c0 = wn*16 + nt*8;
                bf[nt][0] = Bs[st][c0+g][ks+tig  ];
                bf[nt][1] = Bs[st][c0+g][ks+tig+4];
            }
            #pragma unroll
            for (int mt = 0; mt < 2; mt++)
                #pragma unroll
                for (int nt = 0; nt < 2; nt++)
                    mma_tf32(acc[mt][nt], af[mt][0], af[mt][1], af[mt][2], af[mt][3],
                             bf[nt][0], bf[nt][1]);
        }
        __syncthreads();
    }

    int rowb = m0 + wm*32, colb = n0 + wn*16;
    #pragma unroll
    for (int nt = 0; nt < 2; nt++) {
        int c = colb + nt*8 + 2*tig;
        float b0 = bias[c], b1 = bias[c+1];
        #pragma unroll
        for (int mt = 0; mt < 2; mt++) {
            int r = rowb + mt*16 + g;
            *(float2*)(C + (size_t)r*ldC + c)     = make_float2(acc[mt][nt][0]+b0, acc[mt][nt][1]+b1);
            *(float2*)(C + (size_t)(r+8)*ldC + c) = make_float2(acc[mt][nt][2]+b0, acc[mt][nt][3]+b1);
        }
    }
}

// ================= fp8 GEMM 128x128 (decoder + FF1) =================
// MODE 1: fp8 out (+bias+relu).  MODE 2: decoder lse partials (no-max, fma-exp).
template<int MODE>
__global__ __launch_bounds__(256, 2) void gemm_fp8_kernel(
    const uint8_t* __restrict__ A, const uint8_t* __restrict__ W,
    const float* __restrict__ bias, void* __restrict__ Cout,
    int K, int ldC, float inv, float outscale)
{
    __shared__ uint32_t As[2][128][20];
    __shared__ uint32_t Bs[2][128][20];

    float acc[4][4][4];
    #pragma unroll
    for (int a = 0; a < 4; a++)
        #pragma unroll
        for (int b = 0; b < 4; b++)
            #pragma unroll
            for (int c = 0; c < 4; c++) acc[a][b][c] = 0.f;

    int m0, n0, nblk = 0;
    if (MODE == 2) { m0 = blockIdx.x * 128; n0 = blockIdx.y * 128; nblk = blockIdx.y; }
    else           { m0 = blockIdx.y * 128; n0 = blockIdx.x * 128; }

    int tid  = threadIdx.x;
    int lane = tid & 31, wid = tid >> 5;
    int wm = wid >> 2, wn = wid & 3;
    int g = lane >> 2, tig = lane & 3;

    int a_row = (lane & 7) + ((lane >> 3) & 1) * 8;
    int a_wrd = (lane >> 4) * 4;
    int b_row = lane & 7;
    int b_wrd = ((lane >> 3) & 1) * 4;

    int r0c = tid >> 2, r1c = r0c + 64;
    int cw = (tid & 3) * 4;
    int ce = (tid & 3) * 16;
    int nr0 = n0 + r0c, nr1 = n0 + r1c;
    if (MODE == 2) { nr0 = (nr0 < NTOK) ? nr0 : (NTOK - 1); nr1 = (nr1 < NTOK) ? nr1 : (NTOK - 1); }
    const uint8_t* pa0 = A + (size_t)(m0 + r0c)*K + ce;
    const uint8_t* pa1 = A + (size_t)(m0 + r1c)*K + ce;
    const uint8_t* pb0 = W + (size_t)nr0*K + ce;
    const uint8_t* pb1 = W + (size_t)nr1*K + ce;

    int niter = K >> 6;
    cp_async16(&As[0][r0c][cw], pa0);
    cp_async16(&As[0][r1c][cw], pa1);
    cp_async16(&Bs[0][r0c][cw], pb0);
    cp_async16(&Bs[0][r1c][cw], pb1);
    cp_commit();

    for (int it = 0; it < niter; it++) {
        int st = it & 1;
        if (it + 1 < niter) {
            int off = (it + 1) << 6;
            int sn = st ^ 1;
            cp_async16(&As[sn][r0c][cw], pa0 + off);
            cp_async16(&As[sn][r1c][cw], pa1 + off);
            cp_async16(&Bs[sn][r0c][cw], pb0 + off);
            cp_async16(&Bs[sn][r1c][cw], pb1 + off);
            cp_commit();
            cp_wait<1>();
        } else {
            cp_wait<0>();
        }
        __syncthreads();
        #pragma unroll
        for (int ks = 0; ks < 2; ks++) {
            int kb = ks*8;
            uint32_t af[4][4], bf[4][2];
            #pragma unroll
            for (int mt = 0; mt < 4; mt++) {
                int r0 = wm*64 + mt*16;
                ldsm_x4(af[mt][0], af[mt][1], af[mt][2], af[mt][3],
                        &As[st][r0 + a_row][kb + a_wrd]);
            }
            #pragma unroll
            for (int nt = 0; nt < 4; nt++) {
                int c0 = wn*32 + nt*8;
                ldsm_x2(bf[nt][0], bf[nt][1],
                        &Bs[st][c0 + b_row][kb + b_wrd]);
            }
            #pragma unroll
            for (int mt = 0; mt < 4; mt++)
                #pragma unroll
                for (int nt = 0; nt < 4; nt++)
                    mma_e4m3(acc[mt][nt], af[mt][0], af[mt][1], af[mt][2], af[mt][3],
                             bf[nt][0], bf[nt][1]);
        }
        __syncthreads();
    }

    #pragma unroll
    for (int a = 0; a < 4; a++)
        #pragma unroll
        for (int b = 0; b < 4; b++)
            #pragma unroll
            for (int c = 0; c < 4; c++) acc[a][b][c] *= inv;

    int rowb = m0 + wm*64, colb = n0 + wn*32;

    if (MODE == 1) {
        uint8_t* C = (uint8_t*)Cout;
        #pragma unroll
        for (int nt = 0; nt < 4; nt++) {
            int c = colb + nt*8 + 2*tig;
            float b0 = bias[c], b1 = bias[c+1];
            #pragma unroll
            for (int mt = 0; mt < 4; mt++) {
                int r = rowb + mt*16 + g;
                float v0 = fmaxf(acc[mt][nt][0]+b0, 0.f)*outscale;
                float v1 = fmaxf(acc[mt][nt][1]+b1, 0.f)*outscale;
                float v2 = fmaxf(acc[mt][nt][2]+b0, 0.f)*outscale;
                float v3 = fmaxf(acc[mt][nt][3]+b1, 0.f)*outscale;
                *(uint16_t*)(C + (size_t)r*ldC + c)     = pack_e4m3(v0, v1);
                *(uint16_t*)(C + (size_t)(r+8)*ldC + c) = pack_e4m3(v2, v3);
            }
        }
    } else {
        // no-max online sum of exp(logit) on the FMA pipe (logits bounded, fp32 safe)
        __shared__ float red_s[4][128];
        #pragma unroll
        for (int mt = 0; mt < 4; mt++) {
            #pragma unroll
            for (int h = 0; h < 2; h++) {
                float s = 0.f;
                #pragma unroll
                for (int nt = 0; nt < 4; nt++) {
                    int c = colb + nt*8 + 2*tig;
                    if (c     < NTOK) s += fast_exp(acc[mt][nt][h*2+0]);
                    if (c + 1 < NTOK) s += fast_exp(acc[mt][nt][h*2+1]);
                }
                s += __shfl_xor_sync(0xffffffffu, s, 1);
                s += __shfl_xor_sync(0xffffffffu, s, 2);
                if (tig == 0) {
                    int lr = wm*64 + mt*16 + h*8 + g;
                    red_s[wn][lr] = s;
                }
            }
        }
        __syncthreads();
        if (tid < 128) {
            float s = red_s[0][tid] + red_s[1][tid] + red_s[2][tid] + red_s[3][tid];
            int row = m0 + tid;
            g_psum[(size_t)row*NBLK_V + nblk] = s;
        }
    }
}

// ================= fp8 GEMM 64x64 (small-grid encoder GEMMs) =================
template<int MODE>
__global__ __launch_bounds__(256) void gemm_fp8_64_kernel(
    const uint8_t* __restrict__ A, const uint8_t* __restrict__ W,
    const float* __restrict__ bias, void* __restrict__ Cout,
    int K, int ldC, float inv, float outscale)
{
    __shared__ uint32_t As[2][64][20];
    __shared__ uint32_t Bs[2][64][20];

    float acc[2][2][4];
    #pragma unroll
    for (int a = 0; a < 2; a++)
        #pragma unroll
        for (int b = 0; b < 2; b++)
            #pragma unroll
            for (int c = 0; c < 4; c++) acc[a][b][c] = 0.f;

    int m0 = blockIdx.y * 64, n0 = blockIdx.x * 64;

    int tid  = threadIdx.x;
    int lane = tid & 31, wid = tid >> 5;
    int wm = wid >> 2, wn = wid & 3;
    int g = lane >> 2, tig = lane & 3;

    int a_row = (lane & 7) + ((lane >> 3) & 1) * 8;
    int a_wrd = (lane >> 4) * 4;
    int b_row = lane & 7;
    int b_wrd = ((lane >> 3) & 1) * 4;

    int r0c = tid >> 2;
    int cw = (tid & 3) * 4;
    int ce = (tid & 3) * 16;
    const uint8_t* pa0 = A + (size_t)(m0 + r0c)*K + ce;
    const uint8_t* pb0 = W + (size_t)(n0 + r0c)*K + ce;

    int niter = K >> 6;
    cp_async16(&As[0][r0c][cw], pa0);
    cp_async16(&Bs[0][r0c][cw], pb0);
    cp_commit();

    for (int it = 0; it < niter; it++) {
        int st = it & 1;
        if (it + 1 < niter) {
            int off = (it + 1) << 6;
            int sn = st ^ 1;
            cp_async16(&As[sn][r0c][cw], pa0 + off);
            cp_async16(&Bs[sn][r0c][cw], pb0 + off);
            cp_commit();
            cp_wait<1>();
        } else {
            cp_wait<0>();
        }
        __syncthreads();
        #pragma unroll
        for (int ks = 0; ks < 2; ks++) {
            int kb = ks*8;
            uint32_t af[2][4], bf[2][2];
            #pragma unroll
            for (int mt = 0; mt < 2; mt++) {
                int r0 = wm*32 + mt*16;
                ldsm_x4(af[mt][0], af[mt][1], af[mt][2], af[mt][3],
                        &As[st][r0 + a_row][kb + a_wrd]);
            }
            #pragma unroll
            for (int nt = 0; nt < 2; nt++) {
                int c0 = wn*16 + nt*8;
                ldsm_x2(bf[nt][0], bf[nt][1],
                        &Bs[st][c0 + b_row][kb + b_wrd]);
            }
            #pragma unroll
            for (int mt = 0; mt < 2; mt++)
                #pragma unroll
                for (int nt = 0; nt < 2; nt++)
                    mma_e4m3(acc[mt][nt], af[mt][0], af[mt][1], af[mt][2], af[mt][3],
                             bf[nt][0], bf[nt][1]);
        }
        __syncthreads();
    }

    #pragma unroll
    for (int a = 0; a < 2; a++)
        #pragma unroll
        for (int b = 0; b < 2; b++)
            #pragma unroll
            for (int c = 0; c < 4; c++) acc[a][b][c] *= inv;

    int rowb = m0 + wm*32, colb = n0 + wn*16;
    if (MODE == 0) {
        float* C = (float*)Cout;
        #pragma unroll
        for (int nt = 0; nt < 2; nt++) {
            int c = colb + nt*8 + 2*tig;
            float b0 = bias[c], b1 = bias[c+1];
            #pragma unroll
            for (int mt = 0; mt < 2; mt++) {
                int r = rowb + mt*16 + g;
                *(float2*)(C + (size_t)r*ldC + c)     = make_float2(acc[mt][nt][0]+b0, acc[mt][nt][1]+b1);
                *(float2*)(C + (size_t)(r+8)*ldC + c) = make_float2(acc[mt][nt][2]+b0, acc[mt][nt][3]+b1);
            }
        }
    } else {
        uint8_t* C = (uint8_t*)Cout;
        #pragma unroll
        for (int nt = 0; nt < 2; nt++) {
            int c = colb + nt*8 + 2*tig;
            float b0 = bias[c], b1 = bias[c+1];
            #pragma unroll
            for (int mt = 0; mt < 2; mt++) {
                int r = rowb + mt*16 + g;
                float v0 = fmaxf(acc[mt][nt][0]+b0, 0.f)*outscale;
                float v1 = fmaxf(acc[mt][nt][1]+b1, 0.f)*outscale;
                float v2 = fmaxf(acc[mt][nt][2]+b0, 0.f)*outscale;
                float v3 = fmaxf(acc[mt][nt][3]+b1, 0.f)*outscale;
                *(uint16_t*)(C + (size_t)r*ldC + c)     = pack_e4m3(v0, v1);
                *(uint16_t*)(C + (size_t)(r+8)*ldC + c) = pack_e4m3(v2, v3);
            }
        }
    }
}

__global__ void lse_reduce_kernel()
{
    int r = blockIdx.x, tid = threadIdx.x;
    double sum = 0.0;
    for (int i = tid; i < NBLK_V; i += 128)
        sum += (double)g_psum[(size_t)r*NBLK_V + i];
    __shared__ double redd[128];
    redd[tid] = sum; __syncthreads();
    for (int s = 64; s > 0; s >>= 1) { if (tid < s) redd[tid] += redd[tid+s]; __syncthreads(); }
    if (tid == 0) g_lse[r] = (float)log(redd[0]);
}

// ---------------- small-M GEMM (one (n,m) pair per block) ----------------
__global__ void rowdot_kernel(
    const float* __restrict__ A, long strideA,
    const float* __restrict__ W, const float* __restrict__ bias,
    float* __restrict__ C, long strideC,
    int K, float alpha, int relu)
{
    int n = blockIdx.x, m = blockIdx.y;
    int tid = threadIdx.x;   // 128
    const float* w = W + (size_t)n * K;
    const float* a = A + (size_t)m * strideA;
    __shared__ float red[128];
    float s = 0.f;
    for (int k = tid; k < K; k += 128) s += a[k]*w[k];
    red[tid] = s; __syncthreads();
    for (int st = 64; st > 0; st >>= 1) { if (tid < st) red[tid] += red[tid+st]; __syncthreads(); }
    if (tid == 0) {
        float v = alpha*red[0] + (bias ? bias[n] : 0.f);
        if (relu) v = fmaxf(v, 0.f);
        C[(size_t)m*strideC + n] = v;
    }
}

// ---------------- attention, 8 queries per block, fp8 out ----------------
#define QT 8
__global__ __launch_bounds__(256) void attn8_kernel(
    const float* __restrict__ qkv, uint8_t* __restrict__ out)
{
    int qt = blockIdx.x, h = blockIdx.y, b = blockIdx.z;
    int tid = threadIdx.x;
    __shared__ float qs[QT][DHEAD];
    __shared__ float sc[QT][NSEQ];
    __shared__ float den[QT];
    const float* base = qkv + (size_t)b*NSEQ*QKV_LD;
    if (tid < 128) {
        int q = tid >> 4;
        int c = (tid & 15) * 4;
        *(float4*)&qs[q][c] =
            *(const float4*)(base + (size_t)(qt*QT+q)*QKV_LD + h*DHEAD + c);
    }
    __syncthreads();
    {
        int j = tid;
        float4 kreg[16];
        const float4* kr = (const float4*)(base + (size_t)j*QKV_LD + D_MODEL + h*DHEAD);
        #pragma unroll
        for (int t = 0; t < 16; t++) kreg[t] = kr[t];
        #pragma unroll
        for (int q = 0; q < QT; q++) {
            float d = 0.f;
            #pragma unroll
            for (int t = 0; t < 16; t++) {
                float4 q4 = *(float4*)&qs[q][t*4];
                d += q4.x*kreg[t].x + q4.y*kreg[t].y + q4.z*kreg[t].z + q4.w*kreg[t].w;
            }
            sc[q][j] = d * 0.125f;
        }
    }
    __syncthreads();
    {
        int w = tid >> 5, lane = tid & 31;
        float v[8];
        float m = -INFINITY;
        #pragma unroll
        for (int t = 0; t < 8; t++) { v[t] = sc[w][lane + 32*t]; m = fmaxf(m, v[t]); }
        #pragma unroll
        for (int o = 16; o; o >>= 1) m = fmaxf(m, __shfl_xor_sync(0xffffffffu, m, o));
        float s = 0.f;
        #pragma unroll
        for (int t = 0; t < 8; t++) { v[t] = fast_exp(v[t]-m); s += v[t]; }
        #pragma unroll
        for (int o = 16; o; o >>= 1) s += __shfl_xor_sync(0xffffffffu, s, o);
        #pragma unroll
        for (int t = 0; t < 8; t++) sc[w][lane + 32*t] = v[t];
        if (lane == 0) den[w] = s;
    }
    __syncthreads();
    {
        int d = tid & 63, qp = tid >> 6;
        int q0 = qp*2, q1 = qp*2+1;
        const float* vb = base + 2*D_MODEL + h*DHEAD + d;
        float a0 = 0.f, a1 = 0.f;
        #pragma unroll 8
        for (int j = 0; j < NSEQ; j++) {
            float v = vb[(size_t)j*QKV_LD];
            a0 += sc[q0][j]*v;
            a1 += sc[q1][j]*v;
        }
        uint16_t p0 = pack_e4m3(a0/den[q0]*SA, 0.f);
        uint16_t p1 = pack_e4m3(a1/den[q1]*SA, 0.f);
        out[((size_t)(b*NSEQ + qt*QT + q0))*D_MODEL + h*DHEAD + d] = (uint8_t)p0;
        out[((size_t)(b*NSEQ + qt*QT + q1))*D_MODEL + h*DHEAD + d] = (uint8_t)p1;
    }
}

// ---------------- loc attention (single query per (h,b)), fp32 out ----------------
__global__ __launch_bounds__(256) void attn_kernel(
    const float* __restrict__ qkv, float* __restrict__ out, int nq, int sq_base)
{
    int qi = blockIdx.x, h = blockIdx.y, b = blockIdx.z;
    int sq = sq_base + qi;
    int tid = threadIdx.x;
    __shared__ float4 qrow[DHEAD/4];
    __shared__ float sc[NSEQ];
    __shared__ float red[256];
    __shared__ float sden;
    __shared__ float osum[4][DHEAD];
    const float* base = qkv + (size_t)b * NSEQ * QKV_LD;
    if (tid < DHEAD/4)
        qrow[tid] = ((const float4*)(base + (size_t)sq*QKV_LD + h*DHEAD))[tid];
    __syncthreads();
    {
        const float4* krow = (const float4*)(base + (size_t)tid*QKV_LD + D_MODEL + h*DHEAD);
        float d = 0.f;
        #pragma unroll
        for (int t = 0; t < DHEAD/4; t++) {
            float4 k4 = krow[t];
            float4 q4 = qrow[t];
            d += q4.x*k4.x + q4.y*k4.y + q4.z*k4.z + q4.w*k4.w;
        }
        sc[tid] = d * 0.125f;
    }
    __syncthreads();
    red[tid] = sc[tid]; __syncthreads();
    for (int s = 128; s > 0; s >>= 1) { if (tid < s) red[tid] = fmaxf(red[tid], red[tid+s]); __syncthreads(); }
    float mx = red[0]; __syncthreads();
    float e = expf(sc[tid] - mx);
    red[tid] = e; __syncthreads();
    for (int s = 128; s > 0; s >>= 1) { if (tid < s) red[tid] += red[tid+s]; __syncthreads(); }
    if (tid == 0) sden = red[0];
    __syncthreads();
    sc[tid] = e;
    __syncthreads();
    int d = tid & 63, g = tid >> 6;
    const float* vb = base + 2*D_MODEL + h*DHEAD + d;
    float o = 0.f;
    for (int j = g*64; j < (g+1)*64; j++) o += sc[j] * vb[(size_t)j*QKV_LD];
    osum[g][d] = o; __syncthreads();
    if (tid < DHEAD) {
        float r = (osum[0][tid]+osum[1][tid]+osum[2][tid]+osum[3][tid]) / sden;
        out[((size_t)(b*nq + qi))*D_MODEL + h*DHEAD + tid] = r;
    }
}

// ---------------- residual + layernorm (fp32 out + optional fp8 mirror) ----------
__global__ void ln_kernel(
    const float* __restrict__ in1, long s1,
    const float* __restrict__ in2, long s2,
    float* __restrict__ out, long so,
    uint8_t* __restrict__ outq, float qs,
    const float* __restrict__ gam, const float* __restrict__ bet)
{
    int r = blockIdx.x, tid = threadIdx.x;
    __shared__ float xr[D_MODEL];
    __shared__ float red[256];
    const float* p1 = in1 + (size_t)r*s1;
    const float* p2 = in2 + (size_t)r*s2;
    float ls = 0.f;
    for (int d = tid; d < D_MODEL; d += 256) { float v = p1[d]+p2[d]; xr[d] = v; ls += v; }
    red[tid] = ls; __syncthreads();
    for (int s = 128; s > 0; s >>= 1) { if (tid < s) red[tid] += red[tid+s]; __syncthreads(); }
    float mean = red[0] * (1.f/D_MODEL); __syncthreads();
    float lv = 0.f;
    for (int d = tid; d < D_MODEL; d += 256) { float t = xr[d]-mean; lv += t*t; }
    red[tid] = lv; __syncthreads();
    for (int s = 128; s > 0; s >>= 1) { if (tid < s) red[tid] += red[tid+s]; __syncthreads(); }
    float rstd = 1.f / sqrtf(red[0]*(1.f/D_MODEL) + 1e-5f);
    for (int d = tid*2; d < D_MODEL; d += 512) {
        float v0 = (xr[d]  -mean)*rstd*gam[d]   + bet[d];
        float v1 = (xr[d+1]-mean)*rstd*gam[d+1] + bet[d+1];
        *(float2*)(out + (size_t)r*so + d) = make_float2(v0, v1);
        if (outq) *(uint16_t*)(outq + (size_t)r*D_MODEL + d) = pack_e4m3(v0*qs, v1*qs);
    }
}

// ---------------- gating statistics + top-k + softmax + importance ----------------
__global__ void stats_kernel(const float* __restrict__ w, const float* __restrict__ noise)
{
    __shared__ float tot[NEXP];
    __shared__ double redd[256];
    __shared__ float fv[256];
    __shared__ int   fi[256];
    __shared__ float topv[NKTOP];
    __shared__ double smean, sstd;
    int tid = threadIdx.x;
    double ls = 0.0;
    for (int n = tid; n < NEXP; n += 256) {
        float f = 0.25f*(w[n] + w[NEXP+n] + w[2*NEXP+n] + w[3*NEXP+n]);
        tot[n] = f; ls += (double)f;
    }
    redd[tid] = ls; __syncthreads();
    for (int s = 128; s > 0; s >>= 1) { if (tid < s) redd[tid] += redd[tid+s]; __syncthreads(); }
    if (tid == 0) smean = redd[0] / NEXP;
    __syncthreads();
    double mfm = smean;
    ls = 0.0;
    for (int n = tid; n < NEXP; n += 256) { double t = (double)tot[n]-mfm; ls += t*t; }
    redd[tid] = ls; __syncthreads();
    for (int s = 128; s > 0; s >>= 1) { if (tid < s) redd[tid] += redd[tid+s]; __syncthreads(); }
    if (tid == 0) sstd = sqrt(redd[0] / (NEXP-1));
    __syncthreads();
    float stdfm = (float)sstd;
    for (int n = tid; n < NEXP; n += 256) tot[n] = tot[n] + noise[n]*stdfm;
    __syncthreads();
    ls = 0.0;
    for (int n = tid; n < NEXP; n += 256) ls += (double)tot[n];
    redd[tid] = ls; __syncthreads();
    for (int s = 128; s > 0; s >>= 1) { if (tid < s) redd[tid] += redd[tid+s]; __syncthreads(); }
    if (tid == 0) smean = redd[0] / NEXP;
    __syncthreads();
    double mt = smean;
    ls = 0.0;
    for (int n = tid; n < NEXP; n += 256) { double t = (double)tot[n]-mt; ls += t*t; }
    redd[tid] = ls; __syncthreads();
    for (int s = 128; s > 0; s >>= 1) { if (tid < s) redd[tid] += redd[tid+s]; __syncthreads(); }
    if (tid == 0) {
        double st = sqrt(redd[0] / (NEXP-1));
        double ratio = st / mt;
        g_stats[20] = (float)(0.1 * ratio * ratio);
    }
    __syncthreads();
    for (int it = 0; it < NKTOP; it++) {
        float bv = -INFINITY; int bi = 0x7fffffff;
        for (int n = tid; n < NEXP; n += 256) {
            float v = tot[n];
            if (v > bv || (v == bv && n < bi)) { bv = v; bi = n; }
        }
        fv[tid] = bv; fi[tid] = bi; __syncthreads();
        for (int s = 128; s > 0; s >>= 1) {
            if (tid < s) {
                float v2 = fv[tid+s]; int i2 = fi[tid+s];
                if (v2 > fv[tid] || (v2 == fv[tid] && i2 < fi[tid])) { fv[tid] = v2; fi[tid] = i2; }
            }
            __syncthreads();
        }
        if (tid == 0) { topv[it] = fv[0]; tot[fi[0]] = -INFINITY; }
        __syncthreads();
    }
    if (tid == 0) {
        float m = topv[0];
        float s = 0.f;
        float e[NKTOP];
        for (int k = 0; k < NKTOP; k++) { e[k] = expf(topv[k]-m); s += e[k]; }
        for (int k = 0; k < NKTOP; k++) g_stats[k] = e[k]/s;
    }
}

// ---------------- response mixture (fp32 + fp8 mirror) ----------------
__global__ void mix_kernel(const float* __restrict__ responses)
{
    __shared__ float w[NKTOP];
    if (threadIdx.x < NKTOP) w[threadIdx.x] = g_stats[threadIdx.x];
    __syncthreads();
    int i = blockIdx.x*blockDim.x + threadIdx.x;
    if (i < (NROWS*D_MODEL)/4) {
        float4 s = make_float4(0.f, 0.f, 0.f, 0.f);
        #pragma unroll
        for (int k = 0; k < NKTOP; k++) {
            float4 v = ((const float4*)responses)[(size_t)k*((NROWS*D_MODEL)/4) + i];
            float wk = w[k];
            s.x += wk*v.x; s.y += wk*v.y; s.z += wk*v.z; s.w += wk*v.w;
        }
        ((float4*)g_x)[i] = s;
        uint32_t lo = pack_e4m3(s.x*SX, s.y*SX);
        uint32_t hi = pack_e4m3(s.z*SX, s.w*SX);
        ((uint32_t*)q_x)[i] = lo | (hi << 16);
    }
}

// ---------------- label logit + final loss ----------------
__global__ void lablogit_kernel(const int* __restrict__ inputs, const float* __restrict__ dec_w)
{
    int s = blockIdx.x, b = blockIdx.y, tid = threadIdx.x;
    int lbl = inputs[b*NSEQ + s + 1];
    const float* a = g_x + ((size_t)(b*NSEQ + s))*D_MODEL;
    const float* wp = dec_w + (size_t)lbl*D_MODEL;
    __shared__ float red[128];
    float acc = 0.f;
    for (int k = tid; k < D_MODEL; k += 128) acc += a[k]*wp[k];
    red[tid] = acc; __syncthreads();
    for (int st = 64; st > 0; st >>= 1) { if (tid < st) red[tid] += red[tid+st]; __syncthreads(); }
    if (tid == 0) g_lab[b*(NSEQ-1)+s] = red[0];
}

__global__ void final_kernel(float* __restrict__ out)
{
    __shared__ double red[256];
    int tid = threadIdx.x;
    double s = 0.0;
    for (int i = tid; i < NB*(NSEQ-1); i += 256) {
        int b = i/(NSEQ-1), sp = i%(NSEQ-1);
        s += (double)g_lab[i] - (double)g_lse[b*NSEQ+sp];
    }
    red[tid] = s; __syncthreads();
    for (int st = 128; st > 0; st >>= 1) { if (tid < st) red[tid] += red[tid+st]; __syncthreads(); }
    if (tid == 0) {
        double ce = -red[0] / (double)(NB*(NSEQ-1));
        out[0] = (float)(ce + (double)g_stats[20]);
    }
}

// ---------------- host driver ----------------
extern "C" void kernel_launch(void* const* d_in, const int* in_sizes, int n_in,
                              void* d_out, int out_size)
{
    (void)in_sizes; (void)n_in; (void)out_size;
    const int*   inputs    = (const int*)  d_in[0];
    const float* responses = (const float*)d_in[1];
    const float* noise     = (const float*)d_in[2];
    const float* emb       = (const float*)d_in[3];
    const float* loc_Wqkv  = (const float*)d_in[4];
    const float* loc_bqkv  = (const float*)d_in[5];
    const float* loc_Wo    = (const float*)d_in[6];
    const float* loc_bo    = (const float*)d_in[7];
    const float* loc_ln1g  = (const float*)d_in[8];
    const float* loc_ln1b  = (const float*)d_in[9];
    const float* loc_W1    = (const float*)d_in[10];
    const float* loc_b1    = (const float*)d_in[11];
    const float* loc_W2    = (const float*)d_in[12];
    const float* loc_b2    = (const float*)d_in[13];
    const float* loc_ln2g  = (const float*)d_in[14];
    const float* loc_ln2b  = (const float*)d_in[15];
    const float* enc_Wqkv  = (const float*)d_in[16];
    const float* enc_bqkv  = (const float*)d_in[17];
    const float* enc_Wo    = (const float*)d_in[18];
    const float* enc_bo    = (const float*)d_in[19];
    const float* enc_ln1g  = (const float*)d_in[20];
    const float* enc_ln1b  = (const float*)d_in[21];
    const float* enc_W1    = (const float*)d_in[22];
    const float* enc_b1    = (const float*)d_in[23];
    const float* enc_W2    = (const float*)d_in[24];
    const float* enc_b2    = (const float*)d_in[25];
    const float* enc_ln2g  = (const float*)d_in[26];
    const float* enc_ln2b  = (const float*)d_in[27];
    const float* gate_w    = (const float*)d_in[28];
    const float* gate_b    = (const float*)d_in[29];
    const float* dec_w     = (const float*)d_in[30];
    float* out = (float*)d_out;

    float *p_x, *p_qkv, *p_tmp;
    float *p_sm_attn, *p_sm_x, *p_sm_tmp, *p_sm_ctx, *p_sm_ffh;
    uint8_t *p_qWqkv, *p_qWo, *p_qW1, *p_qW2, *p_qdec, *p_qx, *p_qattn, *p_qffh;
    cudaGetSymbolAddress((void**)&p_x, g_x);
    cudaGetSymbolAddress((void**)&p_qkv, g_qkv);
    cudaGetSymbolAddress((void**)&p_tmp, g_tmp);
    cudaGetSymbolAddress((void**)&p_sm_attn, g_sm_attn);
    cudaGetSymbolAddress((void**)&p_sm_x, g_sm_x);
    cudaGetSymbolAddress((void**)&p_sm_tmp, g_sm_tmp);
    cudaGetSymbolAddress((void**)&p_sm_ctx, g_sm_ctx);
    cudaGetSymbolAddress((void**)&p_sm_ffh, g_sm_ffh);
    cudaGetSymbolAddress((void**)&p_qWqkv, q_Wqkv);
    cudaGetSymbolAddress((void**)&p_qWo, q_Wo);
    cudaGetSymbolAddress((void**)&p_qW1, q_W1);
    cudaGetSymbolAddress((void**)&p_qW2, q_W2);
    cudaGetSymbolAddress((void**)&p_qdec, q_dec);
    cudaGetSymbolAddress((void**)&p_qx, q_x);
    cudaGetSymbolAddress((void**)&p_qattn, q_attn);
    cudaGetSymbolAddress((void**)&p_qffh, q_ffh);

    // ---- capture-forked side stream for weight conversions ----
    cudaStream_t s2;
    cudaStreamCreateWithFlags(&s2, cudaStreamNonBlocking);
    cudaEvent_t evFork, evEnc, evDec;
    cudaEventCreateWithFlags(&evFork, cudaEventDisableTiming);
    cudaEventCreateWithFlags(&evEnc,  cudaEventDisableTiming);
    cudaEventCreateWithFlags(&evDec,  cudaEventDisableTiming);

    cudaEventRecord(evFork, 0);
    cudaStreamWaitEvent(s2, evFork, 0);

    q8_kernel<<<(2*QKV_LD*D_MODEL/8 + 255)/256, 256, 0, s2>>>(enc_Wqkv, p_qWqkv, 2*QKV_LD*D_MODEL/4, SW);
    q8_kernel<<<(2*D_MODEL*D_MODEL/8 + 255)/256, 256, 0, s2>>>(enc_Wo, p_qWo, 2*D_MODEL*D_MODEL/4, SW);
    q8_kernel<<<(2*FF_DIM*D_MODEL/8 + 255)/256, 256, 0, s2>>>(enc_W1, p_qW1, 2*FF_DIM*D_MODEL/4, SW);
    q8_kernel<<<(2*D_MODEL*FF_DIM/8 + 255)/256, 256, 0, s2>>>(enc_W2, p_qW2, 2*D_MODEL*FF_DIM/4, SW);
    cudaEventRecord(evEnc, s2);
    q8_kernel<<<(NTOK*D_MODEL/8 + 255)/256, 256, 0, s2>>>(dec_w, p_qdec, NTOK*D_MODEL/4, SW);
    cudaEventRecord(evDec, s2);

    // default stream: embed + loc layer + gating
    embed_kernel<<<NROWS, 256>>>(inputs, emb);
    gemm_tc64_kernel<<<dim3(2048/64, NROWS/64), 256>>>(
        p_x, loc_Wqkv + (size_t)D_MODEL*D_MODEL, loc_bqkv + D_MODEL,
        p_qkv + D_MODEL, D_MODEL, QKV_LD);
    rowdot_kernel<<<dim3(D_MODEL, NB), 128>>>(
        p_x + (size_t)(NSEQ-1)*D_MODEL, (long)NSEQ*D_MODEL,
        loc_Wqkv, loc_bqkv,
        p_qkv + (size_t)(NSEQ-1)*QKV_LD, (long)NSEQ*QKV_LD,
        D_MODEL, 1.f, 0);
    attn_kernel<<<dim3(1, NHEAD, NB), 256>>>(p_qkv, p_sm_attn, 1, NSEQ-1);
    rowdot_kernel<<<dim3(D_MODEL, NB), 128>>>(p_sm_attn, D_MODEL, loc_Wo, loc_bo,
                                              p_sm_tmp, D_MODEL, D_MODEL, 1.f, 0);
    ln_kernel<<<NB, 256>>>(p_x + (size_t)(NSEQ-1)*D_MODEL, (long)NSEQ*D_MODEL,
                           p_sm_tmp, D_MODEL, p_sm_x, D_MODEL, (uint8_t*)0, 0.f,
                           loc_ln1g, loc_ln1b);
    rowdot_kernel<<<dim3(FF_DIM, NB), 128>>>(p_sm_x, D_MODEL, loc_W1, loc_b1,
                                             p_sm_ffh, FF_DIM, D_MODEL, 1.f, 1);
    rowdot_kernel<<<dim3(D_MODEL, NB), 128>>>(p_sm_ffh, FF_DIM, loc_W2, loc_b2,
                                              p_sm_tmp, D_MODEL, FF_DIM, 1.f, 0);
    ln_kernel<<<NB, 256>>>(p_sm_x, D_MODEL, p_sm_tmp, D_MODEL,
                           p_sm_ctx, D_MODEL, (uint8_t*)0, 0.f,
                           loc_ln2g, loc_ln2b);

    rowdot_kernel<<<dim3(NEXP, NB), 128>>>(p_sm_ctx, D_MODEL, gate_w, gate_b,
                                           out + 1, NEXP, D_MODEL, 32.f, 0);
    stats_kernel<<<1, 256>>>(out + 1, noise);
    mix_kernel<<<(NROWS*D_MODEL/4 + 255)/256, 256>>>(responses);

    cudaStreamWaitEvent(0, evEnc, 0);

    // two encoder layers (fp8 tensor cores; 64x64 tiles for small GEMMs)
    const float invXW = 1.f/(SX*SW);
    const float invAW = 1.f/(SA*SW);
    const float invFW = 1.f/(SF*SW);
    for (int l = 0; l < 2; l++) {
        const uint8_t* Wqkv = p_qWqkv + (size_t)l*QKV_LD*D_MODEL;
        const float*   bqkv = enc_bqkv + (size_t)l*QKV_LD;
        const uint8_t* Wo   = p_qWo   + (size_t)l*D_MODEL*D_MODEL;
        const float*   bo   = enc_bo  + (size_t)l*D_MODEL;
        const float* g1   = enc_ln1g + (size_t)l*D_MODEL;
        const float* b1l  = enc_ln1b + (size_t)l*D_MODEL;
        const uint8_t* W1   = p_qW1   + (size_t)l*FF_DIM*D_MODEL;
        const float*   bb1  = enc_b1  + (size_t)l*FF_DIM;
        const uint8_t* W2   = p_qW2   + (size_t)l*D_MODEL*FF_DIM;
        const float*   bb2  = enc_b2  + (size_t)l*D_MODEL;
        const float* g2   = enc_ln2g + (size_t)l*D_MODEL;
        const float* b2l  = enc_ln2b + (size_t)l*D_MODEL;

        gemm_fp8_64_kernel<0><<<dim3(QKV_LD/64, NROWS/64), 256>>>(
            p_qx, Wqkv, bqkv, p_qkv, D_MODEL, QKV_LD, invXW, 0.f);
        attn8_kernel<<<dim3(NSEQ/QT, NHEAD, NB), 256>>>(p_qkv, p_qattn);
        gemm_fp8_64_kernel<0><<<dim3(D_MODEL/64, NROWS/64), 256>>>(
            p_qattn, Wo, bo, p_tmp, D_MODEL, D_MODEL, invAW, 0.f);
        ln_kernel<<<NROWS, 256>>>(p_x, D_MODEL, p_tmp, D_MODEL, p_x, D_MODEL,
                                  p_qx, SX, g1, b1l);
        gemm_fp8_kernel<1><<<dim3(FF_DIM/128, NROWS/128), 256>>>(
            p_qx, W1, bb1, p_qffh, D_MODEL, FF_DIM, invXW, SF);
        gemm_fp8_64_kernel<0><<<dim3(D_MODEL/64, NROWS/64), 256>>>(
            p_qffh, W2, bb2, p_tmp, FF_DIM, D_MODEL, invFW, 0.f);
        ln_kernel<<<NROWS, 256>>>(p_x, D_MODEL, p_tmp, D_MODEL, p_x, D_MODEL,
                                  p_qx, SX, g2, b2l);
    }

    cudaStreamWaitEvent(0, evDec, 0);

    gemm_fp8_kernel<2><<<dim3(NROWS/128, NBLK_V), 256>>>(
        p_qx, p_qdec, (const float*)0, (void*)0, D_MODEL, 0, invXW, 0.f);
    lse_reduce_kernel<<<NROWS, 128>>>();
    lablogit_kernel<<<dim3(NSEQ-1, NB), 128>>>(inputs, dec_w);
    final_kernel<<<1, 256>>>(out);

    cudaEventDestroy(evFork);
    cudaEventDestroy(evEnc);
    cudaEventDestroy(evDec);
    cudaStreamDestroy(s2);
}

// round 14
// speedup vs baseline: 1.4817x; 1.2250x over previous
#include <cuda_runtime.h>
#include <cuda_bf16.h>
#include <math.h>
#include <stdint.h>

// ---------------- problem constants ----------------
#define D_MODEL 1024
#define NHEAD   16
#define DHEAD   64
#define FF_DIM  4096
#define NSEQ    256
#define NB      4
#define NTOK    50257
#define NEXP    2000
#define NKTOP   20
#define NROWS   (NB*NSEQ)      // 1024
#define QKV_LD  3072
#define NBLK_V  393
#define NBH     (NB*NHEAD)     // 64

// fp8 per-tensor scales
#define SX   16.0f
#define SW   512.0f
#define SA   64.0f
#define SF   32.0f
#define SQK  64.0f
#define SP   128.0f

// ---------------- scratch ----------------
__device__ float g_x    [NROWS*D_MODEL];
__device__ float g_qkv  [NROWS*QKV_LD];      // loc layer (fp32 path)
__device__ float g_tmp  [NROWS*D_MODEL];
__device__ float g_sm_attn[NB*D_MODEL];
__device__ float g_sm_x   [NB*D_MODEL];
__device__ float g_sm_tmp [NB*D_MODEL];
__device__ float g_sm_ctx [NB*D_MODEL];
__device__ float g_sm_ffh [NB*FF_DIM];
__device__ float g_psum[NROWS*NBLK_V];
__device__ float g_lse [NROWS];
__device__ float g_lab [NB*(NSEQ-1)];
__device__ float g_stats[32];

// fp8 / bf16 mirrors
__device__ __align__(256) uint8_t q_Wqkv[2*QKV_LD*D_MODEL];
__device__ __align__(256) uint8_t q_Wo  [2*D_MODEL*D_MODEL];
__device__ __align__(256) uint8_t q_W1  [2*FF_DIM*D_MODEL];
__device__ __align__(256) uint8_t q_W2  [2*D_MODEL*FF_DIM];
__device__ __align__(256) uint8_t q_dec [NTOK*D_MODEL];
__device__ __align__(256) uint8_t q_x   [NROWS*D_MODEL];
__device__ __align__(256) uint8_t q_attn[NROWS*D_MODEL];
__device__ __align__(256) uint8_t q_ffh [NROWS*FF_DIM];
__device__ __align__(256) uint8_t q_qkv [NROWS*QKV_LD];          // encoder fp8 QKV
__device__ __align__(256) __nv_bfloat16 g_scores[NBH*NSEQ*NSEQ]; // 8.4 MB
__device__ __align__(256) uint8_t q_p  [NBH*NSEQ*NSEQ];          // 4.2 MB
__device__ __align__(256) uint8_t q_vt [NBH*DHEAD*NSEQ];         // 1 MB

// ---------------- fp8 pack + fast fma-pipe exp ----------------
__device__ __forceinline__ uint16_t pack_e4m3(float lo, float hi)
{
    uint16_t r;
    asm("cvt.rn.satfinite.e4m3x2.f32 %0, %1, %2;" : "=h"(r) : "f"(hi), "f"(lo));
    return r;
}

__device__ __forceinline__ float fast_exp(float x)
{
    float t = x * 1.4426950408889634f;
    float fi = floorf(t);
    float f = t - fi;
    float p = 1.5403530e-4f;
    p = fmaf(p, f, 1.3333558e-3f);
    p = fmaf(p, f, 9.6180489e-3f);
    p = fmaf(p, f, 5.5504109e-2f);
    p = fmaf(p, f, 2.4022651e-1f);
    p = fmaf(p, f, 6.9314718e-1f);
    p = fmaf(p, f, 1.0f);
    return __int_as_float(__float_as_int(p) + (((int)fi) << 23));
}

__global__ void q8_kernel(const float* __restrict__ src, uint8_t* __restrict__ dst,
                          int n4, float scale)
{
    int i = (blockIdx.x*blockDim.x + threadIdx.x) * 2;
    #pragma unroll
    for (int t = 0; t < 2; t++) {
        int j = i + t;
        if (j < n4) {
            float4 v = ((const float4*)src)[j];
            uint32_t lo = pack_e4m3(v.x*scale, v.y*scale);
            uint32_t hi = pack_e4m3(v.z*scale, v.w*scale);
            ((uint32_t*)dst)[j] = lo | (hi << 16);
        }
    }
}

// ---------------- embedding gather ----------------
__global__ void embed_kernel(const int* __restrict__ inputs, const float* __restrict__ emb)
{
    int r = blockIdx.x;
    int tok = inputs[r];
    const float4* src = (const float4*)(emb + (size_t)tok * D_MODEL);
    float4* dst = (float4*)(g_x + (size_t)r * D_MODEL);
    dst[threadIdx.x] = src[threadIdx.x];
}

// ================= cp.async / ldmatrix helpers =================
__device__ __forceinline__ void cp_async16(void* smem, const void* gmem)
{
    uint32_t s = (uint32_t)__cvta_generic_to_shared(smem);
    asm volatile("cp.async.ca.shared.global [%0], [%1], 16;\n" :: "r"(s), "l"(gmem));
}
__device__ __forceinline__ void cp_commit()
{
    asm volatile("cp.async.commit_group;\n" ::: "memory");
}
template<int N> __device__ __forceinline__ void cp_wait()
{
    asm volatile("cp.async.wait_group %0;\n" :: "n"(N) : "memory");
}
__device__ __forceinline__ void ldsm_x4(uint32_t& r0, uint32_t& r1, uint32_t& r2, uint32_t& r3,
                                        const void* smem)
{
    uint32_t a = (uint32_t)__cvta_generic_to_shared(smem);
    asm volatile("ldmatrix.sync.aligned.m8n8.x4.shared.b16 {%0,%1,%2,%3}, [%4];\n"
                 : "=r"(r0), "=r"(r1), "=r"(r2), "=r"(r3) : "r"(a));
}
__device__ __forceinline__ void ldsm_x2(uint32_t& r0, uint32_t& r1, const void* smem)
{
    uint32_t a = (uint32_t)__cvta_generic_to_shared(smem);
    asm volatile("ldmatrix.sync.aligned.m8n8.x2.shared.b16 {%0,%1}, [%2];\n"
                 : "=r"(r0), "=r"(r1) : "r"(a));
}
__device__ __forceinline__ void mma_e4m3(float* a4, uint32_t a0, uint32_t a1, uint32_t a2, uint32_t a3,
                                         uint32_t b0, uint32_t b1)
{
    asm volatile(
        "mma.sync.aligned.m16n8k32.row.col.f32.e4m3.e4m3.f32 "
        "{%0,%1,%2,%3}, {%4,%5,%6,%7}, {%8,%9}, {%0,%1,%2,%3};\n"
        : "+f"(a4[0]), "+f"(a4[1]), "+f"(a4[2]), "+f"(a4[3])
        : "r"(a0), "r"(a1), "r"(a2), "r"(a3), "r"(b0), "r"(b1));
}
__device__ __forceinline__ void mma_tf32(float* a4, uint32_t a0, uint32_t a1, uint32_t a2, uint32_t a3,
                                         uint32_t b0, uint32_t b1)
{
    asm volatile(
        "mma.sync.aligned.m16n8k8.row.col.f32.tf32.tf32.f32 "
        "{%0,%1,%2,%3}, {%4,%5,%6,%7}, {%8,%9}, {%0,%1,%2,%3};\n"
        : "+f"(a4[0]), "+f"(a4[1]), "+f"(a4[2]), "+f"(a4[3])
        : "r"(a0), "r"(a1), "r"(a2), "r"(a3), "r"(b0), "r"(b1));
}

// ================= tf32 GEMM 64x64 (loc KV path) =================
__global__ __launch_bounds__(256) void gemm_tc64_kernel(
    const float* __restrict__ A, const float* __restrict__ W,
    const float* __restrict__ bias, float* __restrict__ C,
    int K, int ldC)
{
    __shared__ uint32_t As[2][64][20];
    __shared__ uint32_t Bs[2][64][20];
    float acc[2][2][4];
    #pragma unroll
    for (int a = 0; a < 2; a++)
        #pragma unroll
        for (int b = 0; b < 2; b++)
            #pragma unroll
            for (int c = 0; c < 4; c++) acc[a][b][c] = 0.f;

    int m0 = blockIdx.y * 64, n0 = blockIdx.x * 64;
    int tid  = threadIdx.x;
    int lane = tid & 31, wid = tid >> 5;
    int wm = wid >> 2, wn = wid & 3;
    int g = lane >> 2, tig = lane & 3;

    int r0c = tid >> 2, c0c = (tid & 3) << 2;
    const float* pa0 = A + (size_t)(m0 + r0c)*K + c0c;
    const float* pb0 = W + (size_t)(n0 + r0c)*K + c0c;

    int niter = K >> 4;
    cp_async16(&As[0][r0c][c0c], pa0);
    cp_async16(&Bs[0][r0c][c0c], pb0);
    cp_commit();

    for (int it = 0; it < niter; it++) {
        int st = it & 1;
        if (it + 1 < niter) {
            int off = (it + 1) << 4;
            int sn = st ^ 1;
            cp_async16(&As[sn][r0c][c0c], pa0 + off);
            cp_async16(&Bs[sn][r0c][c0c], pb0 + off);
            cp_commit();
            cp_wait<1>();
        } else {
            cp_wait<0>();
        }
        __syncthreads();
        #pragma unroll
        for (int ks = 0; ks < 16; ks += 8) {
            uint32_t af[2][4], bf[2][2];
            #pragma unroll
            for (int mt = 0; mt < 2; mt++) {
                int r0 = wm*32 + mt*16;
                af[mt][0] = As[st][r0+g  ][ks+tig  ];
                af[mt][1] = As[st][r0+g+8][ks+tig  ];
                af[mt][2] = As[st][r0+g  ][ks+tig+4];
                af[mt][3] = As[st][r0+g+8][ks+tig+4];
            }
            #pragma unroll
            for (int nt = 0; nt < 2; nt++) {
                int c0 = wn*16 + nt*8;
                bf[nt][0] = Bs[st][c0+g][ks+tig  ];
                bf[nt][1] = Bs[st][c0+g][ks+tig+4];
            }
            #pragma unroll
            for (int mt = 0; mt < 2; mt++)
                #pragma unroll
                for (int nt = 0; nt < 2; nt++)
                    mma_tf32(acc[mt][nt], af[mt][0], af[mt][1], af[mt][2], af[mt][3],
                             bf[nt][0], bf[nt][1]);
        }
        __syncthreads();
    }

    int rowb = m0 + wm*32, colb = n0 + wn*16;
    #pragma unroll
    for (int nt = 0; nt < 2; nt++) {
        int c = colb + nt*8 + 2*tig;
        float b0 = bias[c], b1 = bias[c+1];
        #pragma unroll
        for (int mt = 0; mt < 2; mt++) {
            int r = rowb + mt*16 + g;
            *(float2*)(C + (size_t)r*ldC + c)     = make_float2(acc[mt][nt][0]+b0, acc[mt][nt][1]+b1);
            *(float2*)(C + (size_t)(r+8)*ldC + c) = make_float2(acc[mt][nt][2]+b0, acc[mt][nt][3]+b1);
        }
    }
}

// ================= fp8 GEMM 128x128 (decoder + FF1) =================
// MODE 1: fp8 out (+bias+relu).  MODE 2: decoder lse partials (no-max, fma-exp).
template<int MODE>
__global__ __launch_bounds__(256, 2) void gemm_fp8_kernel(
    const uint8_t* __restrict__ A, const uint8_t* __restrict__ W,
    const float* __restrict__ bias, void* __restrict__ Cout,
    int K, int ldC, float inv, float outscale)
{
    __shared__ uint32_t As[2][128][20];
    __shared__ uint32_t Bs[2][128][20];

    float acc[4][4][4];
    #pragma unroll
    for (int a = 0; a < 4; a++)
        #pragma unroll
        for (int b = 0; b < 4; b++)
            #pragma unroll
            for (int c = 0; c < 4; c++) acc[a][b][c] = 0.f;

    int m0, n0, nblk = 0;
    if (MODE == 2) { m0 = blockIdx.x * 128; n0 = blockIdx.y * 128; nblk = blockIdx.y; }
    else           { m0 = blockIdx.y * 128; n0 = blockIdx.x * 128; }

    int tid  = threadIdx.x;
    int lane = tid & 31, wid = tid >> 5;
    int wm = wid >> 2, wn = wid & 3;
    int g = lane >> 2, tig = lane & 3;

    int a_row = (lane & 7) + ((lane >> 3) & 1) * 8;
    int a_wrd = (lane >> 4) * 4;
    int b_row = lane & 7;
    int b_wrd = ((lane >> 3) & 1) * 4;

    int r0c = tid >> 2, r1c = r0c + 64;
    int cw = (tid & 3) * 4;
    int ce = (tid & 3) * 16;
    int nr0 = n0 + r0c, nr1 = n0 + r1c;
    if (MODE == 2) { nr0 = (nr0 < NTOK) ? nr0 : (NTOK - 1); nr1 = (nr1 < NTOK) ? nr1 : (NTOK - 1); }
    const uint8_t* pa0 = A + (size_t)(m0 + r0c)*K + ce;
    const uint8_t* pa1 = A + (size_t)(m0 + r1c)*K + ce;
    const uint8_t* pb0 = W + (size_t)nr0*K + ce;
    const uint8_t* pb1 = W + (size_t)nr1*K + ce;

    int niter = K >> 6;
    cp_async16(&As[0][r0c][cw], pa0);
    cp_async16(&As[0][r1c][cw], pa1);
    cp_async16(&Bs[0][r0c][cw], pb0);
    cp_async16(&Bs[0][r1c][cw], pb1);
    cp_commit();

    for (int it = 0; it < niter; it++) {
        int st = it & 1;
        if (it + 1 < niter) {
            int off = (it + 1) << 6;
            int sn = st ^ 1;
            cp_async16(&As[sn][r0c][cw], pa0 + off);
            cp_async16(&As[sn][r1c][cw], pa1 + off);
            cp_async16(&Bs[sn][r0c][cw], pb0 + off);
            cp_async16(&Bs[sn][r1c][cw], pb1 + off);
            cp_commit();
            cp_wait<1>();
        } else {
            cp_wait<0>();
        }
        __syncthreads();
        #pragma unroll
        for (int ks = 0; ks < 2; ks++) {
            int kb = ks*8;
            uint32_t af[4][4], bf[4][2];
            #pragma unroll
            for (int mt = 0; mt < 4; mt++) {
                int r0 = wm*64 + mt*16;
                ldsm_x4(af[mt][0], af[mt][1], af[mt][2], af[mt][3],
                        &As[st][r0 + a_row][kb + a_wrd]);
            }
            #pragma unroll
            for (int nt = 0; nt < 4; nt++) {
                int c0 = wn*32 + nt*8;
                ldsm_x2(bf[nt][0], bf[nt][1],
                        &Bs[st][c0 + b_row][kb + b_wrd]);
            }
            #pragma unroll
            for (int mt = 0; mt < 4; mt++)
                #pragma unroll
                for (int nt = 0; nt < 4; nt++)
                    mma_e4m3(acc[mt][nt], af[mt][0], af[mt][1], af[mt][2], af[mt][3],
                             bf[nt][0], bf[nt][1]);
        }
        __syncthreads();
    }

    #pragma unroll
    for (int a = 0; a < 4; a++)
        #pragma unroll
        for (int b = 0; b < 4; b++)
            #pragma unroll
            for (int c = 0; c < 4; c++) acc[a][b][c] *= inv;

    int rowb = m0 + wm*64, colb = n0 + wn*32;

    if (MODE == 1) {
        uint8_t* C = (uint8_t*)Cout;
        #pragma unroll
        for (int nt = 0; nt < 4; nt++) {
            int c = colb + nt*8 + 2*tig;
            float b0 = bias[c], b1 = bias[c+1];
            #pragma unroll
            for (int mt = 0; mt < 4; mt++) {
                int r = rowb + mt*16 + g;
                float v0 = fmaxf(acc[mt][nt][0]+b0, 0.f)*outscale;
                float v1 = fmaxf(acc[mt][nt][1]+b1, 0.f)*outscale;
                float v2 = fmaxf(acc[mt][nt][2]+b0, 0.f)*outscale;
                float v3 = fmaxf(acc[mt][nt][3]+b1, 0.f)*outscale;
                *(uint16_t*)(C + (size_t)r*ldC + c)     = pack_e4m3(v0, v1);
                *(uint16_t*)(C + (size_t)(r+8)*ldC + c) = pack_e4m3(v2, v3);
            }
        }
    } else {
        __shared__ float red_s[4][128];
        #pragma unroll
        for (int mt = 0; mt < 4; mt++) {
            #pragma unroll
            for (int h = 0; h < 2; h++) {
                float s = 0.f;
                #pragma unroll
                for (int nt = 0; nt < 4; nt++) {
                    int c = colb + nt*8 + 2*tig;
                    if (c     < NTOK) s += fast_exp(acc[mt][nt][h*2+0]);
                    if (c + 1 < NTOK) s += fast_exp(acc[mt][nt][h*2+1]);
                }
                s += __shfl_xor_sync(0xffffffffu, s, 1);
                s += __shfl_xor_sync(0xffffffffu, s, 2);
                if (tig == 0) {
                    int lr = wm*64 + mt*16 + h*8 + g;
                    red_s[wn][lr] = s;
                }
            }
        }
        __syncthreads();
        if (tid < 128) {
            float s = red_s[0][tid] + red_s[1][tid] + red_s[2][tid] + red_s[3][tid];
            int row = m0 + tid;
            g_psum[(size_t)row*NBLK_V + nblk] = s;
        }
    }
}

// ================= fp8 GEMM 64x64 (encoder GEMMs) =================
// OUT8=0: fp32 out (+bias).  OUT8=1: fp8 out, bias optional, relu flag.
template<int OUT8>
__global__ __launch_bounds__(256) void gemm_fp8_64_kernel(
    const uint8_t* __restrict__ A, const uint8_t* __restrict__ W,
    const float* __restrict__ bias, void* __restrict__ Cout,
    int K, int ldC, float inv, float outscale, int relu)
{
    __shared__ uint32_t As[2][64][20];
    __shared__ uint32_t Bs[2][64][20];

    float acc[2][2][4];
    #pragma unroll
    for (int a = 0; a < 2; a++)
        #pragma unroll
        for (int b = 0; b < 2; b++)
            #pragma unroll
            for (int c = 0; c < 4; c++) acc[a][b][c] = 0.f;

    int m0 = blockIdx.y * 64, n0 = blockIdx.x * 64;

    int tid  = threadIdx.x;
    int lane = tid & 31, wid = tid >> 5;
    int wm = wid >> 2, wn = wid & 3;
    int g = lane >> 2, tig = lane & 3;

    int a_row = (lane & 7) + ((lane >> 3) & 1) * 8;
    int a_wrd = (lane >> 4) * 4;
    int b_row = lane & 7;
    int b_wrd = ((lane >> 3) & 1) * 4;

    int r0c = tid >> 2;
    int cw = (tid & 3) * 4;
    int ce = (tid & 3) * 16;
    const uint8_t* pa0 = A + (size_t)(m0 + r0c)*K + ce;
    const uint8_t* pb0 = W + (size_t)(n0 + r0c)*K + ce;

    int niter = K >> 6;
    cp_async16(&As[0][r0c][cw], pa0);
    cp_async16(&Bs[0][r0c][cw], pb0);
    cp_commit();

    for (int it = 0; it < niter; it++) {
        int st = it & 1;
        if (it + 1 < niter) {
            int off = (it + 1) << 6;
            int sn = st ^ 1;
            cp_async16(&As[sn][r0c][cw], pa0 + off);
            cp_async16(&Bs[sn][r0c][cw], pb0 + off);
            cp_commit();
            cp_wait<1>();
        } else {
            cp_wait<0>();
        }
        __syncthreads();
        #pragma unroll
        for (int ks = 0; ks < 2; ks++) {
            int kb = ks*8;
            uint32_t af[2][4], bf[2][2];
            #pragma unroll
            for (int mt = 0; mt < 2; mt++) {
                int r0 = wm*32 + mt*16;
                ldsm_x4(af[mt][0], af[mt][1], af[mt][2], af[mt][3],
                        &As[st][r0 + a_row][kb + a_wrd]);
            }
            #pragma unroll
            for (int nt = 0; nt < 2; nt++) {
                int c0 = wn*16 + nt*8;
                ldsm_x2(bf[nt][0], bf[nt][1],
                        &Bs[st][c0 + b_row][kb + b_wrd]);
            }
            #pragma unroll
            for (int mt = 0; mt < 2; mt++)
                #pragma unroll
                for (int nt = 0; nt < 2; nt++)
                    mma_e4m3(acc[mt][nt], af[mt][0], af[mt][1], af[mt][2], af[mt][3],
                             bf[nt][0], bf[nt][1]);
        }
        __syncthreads();
    }

    #pragma unroll
    for (int a = 0; a < 2; a++)
        #pragma unroll
        for (int b = 0; b < 2; b++)
            #pragma unroll
            for (int c = 0; c < 4; c++) acc[a][b][c] *= inv;

    int rowb = m0 + wm*32, colb = n0 + wn*16;
    if (OUT8 == 0) {
        float* C = (float*)Cout;
        #pragma unroll
        for (int nt = 0; nt < 2; nt++) {
            int c = colb + nt*8 + 2*tig;
            float b0 = bias[c], b1 = bias[c+1];
            #pragma unroll
            for (int mt = 0; mt < 2; mt++) {
                int r = rowb + mt*16 + g;
                *(float2*)(C + (size_t)r*ldC + c)     = make_float2(acc[mt][nt][0]+b0, acc[mt][nt][1]+b1);
                *(float2*)(C + (size_t)(r+8)*ldC + c) = make_float2(acc[mt][nt][2]+b0, acc[mt][nt][3]+b1);
            }
        }
    } else {
        uint8_t* C = (uint8_t*)Cout;
        #pragma unroll
        for (int nt = 0; nt < 2; nt++) {
            int c = colb + nt*8 + 2*tig;
            float b0 = bias ? bias[c] : 0.f;
            float b1 = bias ? bias[c+1] : 0.f;
            #pragma unroll
            for (int mt = 0; mt < 2; mt++) {
                int r = rowb + mt*16 + g;
                float v0 = acc[mt][nt][0]+b0, v1 = acc[mt][nt][1]+b1;
                float v2 = acc[mt][nt][2]+b0, v3 = acc[mt][nt][3]+b1;
                if (relu) {
                    v0 = fmaxf(v0, 0.f); v1 = fmaxf(v1, 0.f);
                    v2 = fmaxf(v2, 0.f); v3 = fmaxf(v3, 0.f);
                }
                *(uint16_t*)(C + (size_t)r*ldC + c)     = pack_e4m3(v0*outscale, v1*outscale);
                *(uint16_t*)(C + (size_t)(r+8)*ldC + c) = pack_e4m3(v2*outscale, v3*outscale);
            }
        }
    }
}

// ================= attention: S = Q K^T (fp8, per-head strided) ==============
// grid (2 m-tiles, 2 n-tiles, 64 bh); K=64 (single chunk)
__global__ __launch_bounds__(256) void score_gemm_kernel()
{
    __shared__ uint32_t As[128][20];
    __shared__ uint32_t Bs[128][20];

    int bh = blockIdx.z, b = bh >> 4, h = bh & 15;
    int m0 = blockIdx.x * 128, n0 = blockIdx.y * 128;

    int tid  = threadIdx.x;
    int lane = tid & 31, wid = tid >> 5;
    int wm = wid >> 2, wn = wid & 3;
    int g = lane >> 2, tig = lane & 3;

    int a_row = (lane & 7) + ((lane >> 3) & 1) * 8;
    int a_wrd = (lane >> 4) * 4;
    int b_row = lane & 7;
    int b_wrd = ((lane >> 3) & 1) * 4;

    const uint8_t* Qb = q_qkv + (size_t)(b*NSEQ)*QKV_LD + h*DHEAD;
    const uint8_t* Kb = Qb + D_MODEL;

    int r0c = tid >> 2, r1c = r0c + 64;
    int cw = (tid & 3) * 4, ce = (tid & 3) * 16;
    cp_async16(&As[r0c][cw], Qb + (size_t)(m0 + r0c)*QKV_LD + ce);
    cp_async16(&As[r1c][cw], Qb + (size_t)(m0 + r1c)*QKV_LD + ce);
    cp_async16(&Bs[r0c][cw], Kb + (size_t)(n0 + r0c)*QKV_LD + ce);
    cp_async16(&Bs[r1c][cw], Kb + (size_t)(n0 + r1c)*QKV_LD + ce);
    cp_commit(); cp_wait<0>();
    __syncthreads();

    float acc[4][4][4];
    #pragma unroll
    for (int a = 0; a < 4; a++)
        #pragma unroll
        for (int bb = 0; bb < 4; bb++)
            #pragma unroll
            for (int c = 0; c < 4; c++) acc[a][bb][c] = 0.f;

    #pragma unroll
    for (int ks = 0; ks < 2; ks++) {
        int kb = ks*8;
        uint32_t af[4][4], bf[4][2];
        #pragma unroll
        for (int mt = 0; mt < 4; mt++) {
            int r0 = wm*64 + mt*16;
            ldsm_x4(af[mt][0], af[mt][1], af[mt][2], af[mt][3],
                    &As[r0 + a_row][kb + a_wrd]);
        }
        #pragma unroll
        for (int nt = 0; nt < 4; nt++) {
            int c0 = wn*32 + nt*8;
            ldsm_x2(bf[nt][0], bf[nt][1],
                    &Bs[c0 + b_row][kb + b_wrd]);
        }
        #pragma unroll
        for (int mt = 0; mt < 4; mt++)
            #pragma unroll
            for (int nt = 0; nt < 4; nt++)
                mma_e4m3(acc[mt][nt], af[mt][0], af[mt][1], af[mt][2], af[mt][3],
                         bf[nt][0], bf[nt][1]);
    }

    const float sc = 0.125f / (SQK*SQK);
    __nv_bfloat16* Sb = g_scores + (size_t)bh * NSEQ * NSEQ;
    int rowb = m0 + wm*64, colb = n0 + wn*32;
    #pragma unroll
    for (int nt = 0; nt < 4; nt++) {
        int c = colb + nt*8 + 2*tig;
        #pragma unroll
        for (int mt = 0; mt < 4; mt++) {
            int r = rowb + mt*16 + g;
            *(__nv_bfloat162*)(Sb + (size_t)r*NSEQ + c) =
                __floats2bfloat162_rn(acc[mt][nt][0]*sc, acc[mt][nt][1]*sc);
            *(__nv_bfloat162*)(Sb + (size_t)(r+8)*NSEQ + c) =
                __floats2bfloat162_rn(acc[mt][nt][2]*sc, acc[mt][nt][3]*sc);
        }
    }
}

// ================= attention softmax: warp per row, bf16 -> fp8 P ============
__global__ __launch_bounds__(128) void asoftmax_kernel()
{
    int row = blockIdx.x * 4 + (threadIdx.x >> 5);   // 0 .. NBH*NSEQ
    int lane = threadIdx.x & 31;
    const __nv_bfloat16* src = g_scores + (size_t)row * NSEQ + lane * 8;
    uint4 raw = *(const uint4*)src;
    float v[8];
    {
        uint32_t w4[4] = {raw.x, raw.y, raw.z, raw.w};
        #pragma unroll
        for (int t = 0; t < 4; t++) {
            float2 f = __bfloat1622float2(*(__nv_bfloat162*)&w4[t]);
            v[2*t] = f.x; v[2*t+1] = f.y;
        }
    }
    float m = v[0];
    #pragma unroll
    for (int t = 1; t < 8; t++) m = fmaxf(m, v[t]);
    #pragma unroll
    for (int o = 16; o; o >>= 1) m = fmaxf(m, __shfl_xor_sync(0xffffffffu, m, o));
    float s = 0.f;
    #pragma unroll
    for (int t = 0; t < 8; t++) { v[t] = fast_exp(v[t]-m); s += v[t]; }
    #pragma unroll
    for (int o = 16; o; o >>= 1) s += __shfl_xor_sync(0xffffffffu, s, o);
    float rs = SP / s;
    uint8_t* dst = q_p + (size_t)row * NSEQ + lane * 8;
    uint32_t lo = (uint32_t)pack_e4m3(v[0]*rs, v[1]*rs) | ((uint32_t)pack_e4m3(v[2]*rs, v[3]*rs) << 16);
    uint32_t hi = (uint32_t)pack_e4m3(v[4]*rs, v[5]*rs) | ((uint32_t)pack_e4m3(v[6]*rs, v[7]*rs) << 16);
    ((uint32_t*)dst)[0] = lo;
    ((uint32_t*)dst)[1] = hi;
}

// ================= V transpose (fp8): [s,d] -> VT[bh][d][s] ==================
__global__ void vtrans_kernel()
{
    __shared__ uint8_t t[64][65];
    int bh = blockIdx.y, b = bh >> 4, h = bh & 15;
    int s0 = blockIdx.x * 64;
    int tid = threadIdx.x;
    const uint8_t* src = q_qkv + (size_t)(b*NSEQ)*QKV_LD + 2*D_MODEL + h*DHEAD;
    for (int i = tid; i < 4096; i += 256) {
        int s = i >> 6, d = i & 63;
        t[d][s] = src[(size_t)(s0+s)*QKV_LD + d];
    }
    __syncthreads();
    uint8_t* dst = q_vt + (size_t)bh*DHEAD*NSEQ;
    for (int i = tid; i < 4096; i += 256) {
        int d = i >> 6, s = i & 63;
        dst[(size_t)d*NSEQ + s0 + s] = t[d][s];
    }
}

// ================= attention O = P V^T (fp8 64x64, K=256) ====================
// grid (4 m-tiles, 64 bh)
__global__ __launch_bounds__(256) void attn_o_kernel()
{
    __shared__ uint32_t As[2][64][20];
    __shared__ uint32_t Bs[2][64][20];

    float acc[2][2][4];
    #pragma unroll
    for (int a = 0; a < 2; a++)
        #pragma unroll
        for (int b = 0; b < 2; b++)
            #pragma unroll
            for (int c = 0; c < 4; c++) acc[a][b][c] = 0.f;

    int bh = blockIdx.y, bq = bh >> 4, h = bh & 15;
    int m0 = blockIdx.x * 64;

    int tid  = threadIdx.x;
    int lane = tid & 31, wid = tid >> 5;
    int wm = wid >> 2, wn = wid & 3;
    int g = lane >> 2, tig = lane & 3;

    int a_row = (lane & 7) + ((lane >> 3) & 1) * 8;
    int a_wrd = (lane >> 4) * 4;
    int b_row = lane & 7;
    int b_wrd = ((lane >> 3) & 1) * 4;

    const uint8_t* Ab = q_p + (size_t)bh * NSEQ * NSEQ;
    const uint8_t* Bb = q_vt + (size_t)bh * DHEAD * NSEQ;

    int r0c = tid >> 2;
    int cw = (tid & 3) * 4, ce = (tid & 3) * 16;
    const uint8_t* pa0 = Ab + (size_t)(m0 + r0c)*NSEQ + ce;
    const uint8_t* pb0 = Bb + (size_t)r0c*NSEQ + ce;

    int niter = NSEQ >> 6;   // 4
    cp_async16(&As[0][r0c][cw], pa0);
    cp_async16(&Bs[0][r0c][cw], pb0);
    cp_commit();

    for (int it = 0; it < niter; it++) {
        int st = it & 1;
        if (it + 1 < niter) {
            int off = (it + 1) << 6;
            int sn = st ^ 1;
            cp_async16(&As[sn][r0c][cw], pa0 + off);
            cp_async16(&Bs[sn][r0c][cw], pb0 + off);
            cp_commit();
            cp_wait<1>();
        } else {
            cp_wait<0>();
        }
        __syncthreads();
        #pragma unroll
        for (int ks = 0; ks < 2; ks++) {
            int kb = ks*8;
            uint32_t af[2][4], bf[2][2];
            #pragma unroll
            for (int mt = 0; mt < 2; mt++) {
                int r0 = wm*32 + mt*16;
                ldsm_x4(af[mt][0], af[mt][1], af[mt][2], af[mt][3],
                        &As[st][r0 + a_row][kb + a_wrd]);
            }
            #pragma unroll
            for (int nt = 0; nt < 2; nt++) {
                int c0 = wn*16 + nt*8;
                ldsm_x2(bf[nt][0], bf[nt][1],
                        &Bs[st][c0 + b_row][kb + b_wrd]);
            }
            #pragma unroll
            for (int mt = 0; mt < 2; mt++)
                #pragma unroll
                for (int nt = 0; nt < 2; nt++)
                    mma_e4m3(acc[mt][nt], af[mt][0], af[mt][1], af[mt][2], af[mt][3],
                             bf[nt][0], bf[nt][1]);
        }
        __syncthreads();
    }

    const float inv = SA / (SP * SQK);
    int rowb = m0 + wm*32, colb = wn*16;
    #pragma unroll
    for (int nt = 0; nt < 2; nt++) {
        int c = colb + nt*8 + 2*tig;
        #pragma unroll
        for (int mt = 0; mt < 2; mt++) {
            int r = rowb + mt*16 + g;
            uint8_t* d0 = q_attn + (size_t)(bq*NSEQ + r)*D_MODEL + h*DHEAD + c;
            uint8_t* d1 = q_attn + (size_t)(bq*NSEQ + r + 8)*D_MODEL + h*DHEAD + c;
            *(uint16_t*)d0 = pack_e4m3(acc[mt][nt][0]*inv, acc[mt][nt][1]*inv);
            *(uint16_t*)d1 = pack_e4m3(acc[mt][nt][2]*inv, acc[mt][nt][3]*inv);
        }
    }
}

__global__ void lse_reduce_kernel()
{
    int r = blockIdx.x, tid = threadIdx.x;
    double sum = 0.0;
    for (int i = tid; i < NBLK_V; i += 128)
        sum += (double)g_psum[(size_t)r*NBLK_V + i];
    __shared__ double redd[128];
    redd[tid] = sum; __syncthreads();
    for (int s = 64; s > 0; s >>= 1) { if (tid < s) redd[tid] += redd[tid+s]; __syncthreads(); }
    if (tid == 0) g_lse[r] = (float)log(redd[0]);
}

// ---------------- small-M GEMM (one (n,m) pair per block) ----------------
__global__ void rowdot_kernel(
    const float* __restrict__ A, long strideA,
    const float* __restrict__ W, const float* __restrict__ bias,
    float* __restrict__ C, long strideC,
    int K, float alpha, int relu)
{
    int n = blockIdx.x, m = blockIdx.y;
    int tid = threadIdx.x;   // 128
    const float* w = W + (size_t)n * K;
    const float* a = A + (size_t)m * strideA;
    __shared__ float red[128];
    float s = 0.f;
    for (int k = tid; k < K; k += 128) s += a[k]*w[k];
    red[tid] = s; __syncthreads();
    for (int st = 64; st > 0; st >>= 1) { if (tid < st) red[tid] += red[tid+st]; __syncthreads(); }
    if (tid == 0) {
        float v = alpha*red[0] + (bias ? bias[n] : 0.f);
        if (relu) v = fmaxf(v, 0.f);
        C[(size_t)m*strideC + n] = v;
    }
}

// ---------------- loc attention (single query per (h,b)), fp32 out ----------------
__global__ __launch_bounds__(256) void attn_kernel(
    const float* __restrict__ qkv, float* __restrict__ out, int nq, int sq_base)
{
    int qi = blockIdx.x, h = blockIdx.y, b = blockIdx.z;
    int sq = sq_base + qi;
    int tid = threadIdx.x;
    __shared__ float4 qrow[DHEAD/4];
    __shared__ float sc[NSEQ];
    __shared__ float red[256];
    __shared__ float sden;
    __shared__ float osum[4][DHEAD];
    const float* base = qkv + (size_t)b * NSEQ * QKV_LD;
    if (tid < DHEAD/4)
        qrow[tid] = ((const float4*)(base + (size_t)sq*QKV_LD + h*DHEAD))[tid];
    __syncthreads();
    {
        const float4* krow = (const float4*)(base + (size_t)tid*QKV_LD + D_MODEL + h*DHEAD);
        float d = 0.f;
        #pragma unroll
        for (int t = 0; t < DHEAD/4; t++) {
            float4 k4 = krow[t];
            float4 q4 = qrow[t];
            d += q4.x*k4.x + q4.y*k4.y + q4.z*k4.z + q4.w*k4.w;
        }
        sc[tid] = d * 0.125f;
    }
    __syncthreads();
    red[tid] = sc[tid]; __syncthreads();
    for (int s = 128; s > 0; s >>= 1) { if (tid < s) red[tid] = fmaxf(red[tid], red[tid+s]); __syncthreads(); }
    float mx = red[0]; __syncthreads();
    float e = expf(sc[tid] - mx);
    red[tid] = e; __syncthreads();
    for (int s = 128; s > 0; s >>= 1) { if (tid < s) red[tid] += red[tid+s]; __syncthreads(); }
    if (tid == 0) sden = red[0];
    __syncthreads();
    sc[tid] = e;
    __syncthreads();
    int d = tid & 63, g = tid >> 6;
    const float* vb = base + 2*D_MODEL + h*DHEAD + d;
    float o = 0.f;
    for (int j = g*64; j < (g+1)*64; j++) o += sc[j] * vb[(size_t)j*QKV_LD];
    osum[g][d] = o; __syncthreads();
    if (tid < DHEAD) {
        float r = (osum[0][tid]+osum[1][tid]+osum[2][tid]+osum[3][tid]) / sden;
        out[((size_t)(b*nq + qi))*D_MODEL + h*DHEAD + tid] = r;
    }
}

// ---------------- residual + layernorm (fp32 out + optional fp8 mirror) ----------
__global__ void ln_kernel(
    const float* __restrict__ in1, long s1,
    const float* __restrict__ in2, long s2,
    float* __restrict__ out, long so,
    uint8_t* __restrict__ outq, float qs,
    const float* __restrict__ gam, const float* __restrict__ bet)
{
    int r = blockIdx.x, tid = threadIdx.x;
    __shared__ float xr[D_MODEL];
    __shared__ float red[256];
    const float* p1 = in1 + (size_t)r*s1;
    const float* p2 = in2 + (size_t)r*s2;
    float ls = 0.f;
    for (int d = tid; d < D_MODEL; d += 256) { float v = p1[d]+p2[d]; xr[d] = v; ls += v; }
    red[tid] = ls; __syncthreads();
    for (int s = 128; s > 0; s >>= 1) { if (tid < s) red[tid] += red[tid+s]; __syncthreads(); }
    float mean = red[0] * (1.f/D_MODEL); __syncthreads();
    float lv = 0.f;
    for (int d = tid; d < D_MODEL; d += 256) { float t = xr[d]-mean; lv += t*t; }
    red[tid] = lv; __syncthreads();
    for (int s = 128; s > 0; s >>= 1) { if (tid < s) red[tid] += red[tid+s]; __syncthreads(); }
    float rstd = 1.f / sqrtf(red[0]*(1.f/D_MODEL) + 1e-5f);
    for (int d = tid*2; d < D_MODEL; d += 512) {
        float v0 = (xr[d]  -mean)*rstd*gam[d]   + bet[d];
        float v1 = (xr[d+1]-mean)*rstd*gam[d+1] + bet[d+1];
        *(float2*)(out + (size_t)r*so + d) = make_float2(v0, v1);
        if (outq) *(uint16_t*)(outq + (size_t)r*D_MODEL + d) = pack_e4m3(v0*qs, v1*qs);
    }
}

// ---------------- gating statistics + top-k + softmax + importance ----------------
__global__ void stats_kernel(const float* __restrict__ w, const float* __restrict__ noise)
{
    __shared__ float tot[NEXP];
    __shared__ double redd[256];
    __shared__ float fv[256];
    __shared__ int   fi[256];
    __shared__ float topv[NKTOP];
    __shared__ double smean, sstd;
    int tid = threadIdx.x;
    double ls = 0.0;
    for (int n = tid; n < NEXP; n += 256) {
        float f = 0.25f*(w[n] + w[NEXP+n] + w[2*NEXP+n] + w[3*NEXP+n]);
        tot[n] = f; ls += (double)f;
    }
    redd[tid] = ls; __syncthreads();
    for (int s = 128; s > 0; s >>= 1) { if (tid < s) redd[tid] += redd[tid+s]; __syncthreads(); }
    if (tid == 0) smean = redd[0] / NEXP;
    __syncthreads();
    double mfm = smean;
    ls = 0.0;
    for (int n = tid; n < NEXP; n += 256) { double t = (double)tot[n]-mfm; ls += t*t; }
    redd[tid] = ls; __syncthreads();
    for (int s = 128; s > 0; s >>= 1) { if (tid < s) redd[tid] += redd[tid+s]; __syncthreads(); }
    if (tid == 0) sstd = sqrt(redd[0] / (NEXP-1));
    __syncthreads();
    float stdfm = (float)sstd;
    for (int n = tid; n < NEXP; n += 256) tot[n] = tot[n] + noise[n]*stdfm;
    __syncthreads();
    ls = 0.0;
    for (int n = tid; n < NEXP; n += 256) ls += (double)tot[n];
    redd[tid] = ls; __syncthreads();
    for (int s = 128; s > 0; s >>= 1) { if (tid < s) redd[tid] += redd[tid+s]; __syncthreads(); }
    if (tid == 0) smean = redd[0] / NEXP;
    __syncthreads();
    double mt = smean;
    ls = 0.0;
    for (int n = tid; n < NEXP; n += 256) { double t = (double)tot[n]-mt; ls += t*t; }
    redd[tid] = ls; __syncthreads();
    for (int s = 128; s > 0; s >>= 1) { if (tid < s) redd[tid] += redd[tid+s]; __syncthreads(); }
    if (tid == 0) {
        double st = sqrt(redd[0] / (NEXP-1));
        double ratio = st / mt;
        g_stats[20] = (float)(0.1 * ratio * ratio);
    }
    __syncthreads();
    for (int it = 0; it < NKTOP; it++) {
        float bv = -INFINITY; int bi = 0x7fffffff;
        for (int n = tid; n < NEXP; n += 256) {
            float v = tot[n];
            if (v > bv || (v == bv && n < bi)) { bv = v; bi = n; }
        }
        fv[tid] = bv; fi[tid] = bi; __syncthreads();
        for (int s = 128; s > 0; s >>= 1) {
            if (tid < s) {
                float v2 = fv[tid+s]; int i2 = fi[tid+s];
                if (v2 > fv[tid] || (v2 == fv[tid] && i2 < fi[tid])) { fv[tid] = v2; fi[tid] = i2; }
            }
            __syncthreads();
        }
        if (tid == 0) { topv[it] = fv[0]; tot[fi[0]] = -INFINITY; }
        __syncthreads();
    }
    if (tid == 0) {
        float m = topv[0];
        float s = 0.f;
        float e[NKTOP];
        for (int k = 0; k < NKTOP; k++) { e[k] = expf(topv[k]-m); s += e[k]; }
        for (int k = 0; k < NKTOP; k++) g_stats[k] = e[k]/s;
    }
}

// ---------------- response mixture (fp32 + fp8 mirror) ----------------
__global__ void mix_kernel(const float* __restrict__ responses)
{
    __shared__ float w[NKTOP];
    if (threadIdx.x < NKTOP) w[threadIdx.x] = g_stats[threadIdx.x];
    __syncthreads();
    int i = blockIdx.x*blockDim.x + threadIdx.x;
    if (i < (NROWS*D_MODEL)/4) {
        float4 s = make_float4(0.f, 0.f, 0.f, 0.f);
        #pragma unroll
        for (int k = 0; k < NKTOP; k++) {
            float4 v = ((const float4*)responses)[(size_t)k*((NROWS*D_MODEL)/4) + i];
            float wk = w[k];
            s.x += wk*v.x; s.y += wk*v.y; s.z += wk*v.z; s.w += wk*v.w;
        }
        ((float4*)g_x)[i] = s;
        uint32_t lo = pack_e4m3(s.x*SX, s.y*SX);
        uint32_t hi = pack_e4m3(s.z*SX, s.w*SX);
        ((uint32_t*)q_x)[i] = lo | (hi << 16);
    }
}

// ---------------- label logit + final loss ----------------
__global__ void lablogit_kernel(const int* __restrict__ inputs, const float* __restrict__ dec_w)
{
    int s = blockIdx.x, b = blockIdx.y, tid = threadIdx.x;
    int lbl = inputs[b*NSEQ + s + 1];
    const float* a = g_x + ((size_t)(b*NSEQ + s))*D_MODEL;
    const float* wp = dec_w + (size_t)lbl*D_MODEL;
    __shared__ float red[128];
    float acc = 0.f;
    for (int k = tid; k < D_MODEL; k += 128) acc += a[k]*wp[k];
    red[tid] = acc; __syncthreads();
    for (int st = 64; st > 0; st >>= 1) { if (tid < st) red[tid] += red[tid+st]; __syncthreads(); }
    if (tid == 0) g_lab[b*(NSEQ-1)+s] = red[0];
}

__global__ void final_kernel(float* __restrict__ out)
{
    __shared__ double red[256];
    int tid = threadIdx.x;
    double s = 0.0;
    for (int i = tid; i < NB*(NSEQ-1); i += 256) {
        int b = i/(NSEQ-1), sp = i%(NSEQ-1);
        s += (double)g_lab[i] - (double)g_lse[b*NSEQ+sp];
    }
    red[tid] = s; __syncthreads();
    for (int st = 128; st > 0; st >>= 1) { if (tid < st) red[tid] += red[tid+st]; __syncthreads(); }
    if (tid == 0) {
        double ce = -red[0] / (double)(NB*(NSEQ-1));
        out[0] = (float)(ce + (double)g_stats[20]);
    }
}

// ---------------- host driver ----------------
extern "C" void kernel_launch(void* const* d_in, const int* in_sizes, int n_in,
                              void* d_out, int out_size)
{
    (void)in_sizes; (void)n_in; (void)out_size;
    const int*   inputs    = (const int*)  d_in[0];
    const float* responses = (const float*)d_in[1];
    const float* noise     = (const float*)d_in[2];
    const float* emb       = (const float*)d_in[3];
    const float* loc_Wqkv  = (const float*)d_in[4];
    const float* loc_bqkv  = (const float*)d_in[5];
    const float* loc_Wo    = (const float*)d_in[6];
    const float* loc_bo    = (const float*)d_in[7];
    const float* loc_ln1g  = (const float*)d_in[8];
    const float* loc_ln1b  = (const float*)d_in[9];
    const float* loc_W1    = (const float*)d_in[10];
    const float* loc_b1    = (const float*)d_in[11];
    const float* loc_W2    = (const float*)d_in[12];
    const float* loc_b2    = (const float*)d_in[13];
    const float* loc_ln2g  = (const float*)d_in[14];
    const float* loc_ln2b  = (const float*)d_in[15];
    const float* enc_Wqkv  = (const float*)d_in[16];
    const float* enc_bqkv  = (const float*)d_in[17];
    const float* enc_Wo    = (const float*)d_in[18];
    const float* enc_bo    = (const float*)d_in[19];
    const float* enc_ln1g  = (const float*)d_in[20];
    const float* enc_ln1b  = (const float*)d_in[21];
    const float* enc_W1    = (const float*)d_in[22];
    const float* enc_b1    = (const float*)d_in[23];
    const float* enc_W2    = (const float*)d_in[24];
    const float* enc_b2    = (const float*)d_in[25];
    const float* enc_ln2g  = (const float*)d_in[26];
    const float* enc_ln2b  = (const float*)d_in[27];
    const float* gate_w    = (const float*)d_in[28];
    const float* gate_b    = (const float*)d_in[29];
    const float* dec_w     = (const float*)d_in[30];
    float* out = (float*)d_out;

    float *p_x, *p_qkv, *p_tmp;
    float *p_sm_attn, *p_sm_x, *p_sm_tmp, *p_sm_ctx, *p_sm_ffh;
    uint8_t *p_qWqkv, *p_qWo, *p_qW1, *p_qW2, *p_qdec, *p_qx, *p_qattn, *p_qffh, *p_qqkv;
    cudaGetSymbolAddress((void**)&p_x, g_x);
    cudaGetSymbolAddress((void**)&p_qkv, g_qkv);
    cudaGetSymbolAddress((void**)&p_tmp, g_tmp);
    cudaGetSymbolAddress((void**)&p_sm_attn, g_sm_attn);
    cudaGetSymbolAddress((void**)&p_sm_x, g_sm_x);
    cudaGetSymbolAddress((void**)&p_sm_tmp, g_sm_tmp);
    cudaGetSymbolAddress((void**)&p_sm_ctx, g_sm_ctx);
    cudaGetSymbolAddress((void**)&p_sm_ffh, g_sm_ffh);
    cudaGetSymbolAddress((void**)&p_qWqkv, q_Wqkv);
    cudaGetSymbolAddress((void**)&p_qWo, q_Wo);
    cudaGetSymbolAddress((void**)&p_qW1, q_W1);
    cudaGetSymbolAddress((void**)&p_qW2, q_W2);
    cudaGetSymbolAddress((void**)&p_qdec, q_dec);
    cudaGetSymbolAddress((void**)&p_qx, q_x);
    cudaGetSymbolAddress((void**)&p_qattn, q_attn);
    cudaGetSymbolAddress((void**)&p_qffh, q_ffh);
    cudaGetSymbolAddress((void**)&p_qqkv, q_qkv);

    // ---- capture-forked side stream for weight conversions ----
    cudaStream_t s2;
    cudaStreamCreateWithFlags(&s2, cudaStreamNonBlocking);
    cudaEvent_t evFork, evEnc, evDec;
    cudaEventCreateWithFlags(&evFork, cudaEventDisableTiming);
    cudaEventCreateWithFlags(&evEnc,  cudaEventDisableTiming);
    cudaEventCreateWithFlags(&evDec,  cudaEventDisableTiming);

    cudaEventRecord(evFork, 0);
    cudaStreamWaitEvent(s2, evFork, 0);

    q8_kernel<<<(2*QKV_LD*D_MODEL/8 + 255)/256, 256, 0, s2>>>(enc_Wqkv, p_qWqkv, 2*QKV_LD*D_MODEL/4, SW);
    q8_kernel<<<(2*D_MODEL*D_MODEL/8 + 255)/256, 256, 0, s2>>>(enc_Wo, p_qWo, 2*D_MODEL*D_MODEL/4, SW);
    q8_kernel<<<(2*FF_DIM*D_MODEL/8 + 255)/256, 256, 0, s2>>>(enc_W1, p_qW1, 2*FF_DIM*D_MODEL/4, SW);
    q8_kernel<<<(2*D_MODEL*FF_DIM/8 + 255)/256, 256, 0, s2>>>(enc_W2, p_qW2, 2*D_MODEL*FF_DIM/4, SW);
    cudaEventRecord(evEnc, s2);
    q8_kernel<<<(NTOK*D_MODEL/8 + 255)/256, 256, 0, s2>>>(dec_w, p_qdec, NTOK*D_MODEL/4, SW);
    cudaEventRecord(evDec, s2);

    // default stream: embed + loc layer + gating
    embed_kernel<<<NROWS, 256>>>(inputs, emb);
    gemm_tc64_kernel<<<dim3(2048/64, NROWS/64), 256>>>(
        p_x, loc_Wqkv + (size_t)D_MODEL*D_MODEL, loc_bqkv + D_MODEL,
        p_qkv + D_MODEL, D_MODEL, QKV_LD);
    rowdot_kernel<<<dim3(D_MODEL, NB), 128>>>(
        p_x + (size_t)(NSEQ-1)*D_MODEL, (long)NSEQ*D_MODEL,
        loc_Wqkv, loc_bqkv,
        p_qkv + (size_t)(NSEQ-1)*QKV_LD, (long)NSEQ*QKV_LD,
        D_MODEL, 1.f, 0);
    attn_kernel<<<dim3(1, NHEAD, NB), 256>>>(p_qkv, p_sm_attn, 1, NSEQ-1);
    rowdot_kernel<<<dim3(D_MODEL, NB), 128>>>(p_sm_attn, D_MODEL, loc_Wo, loc_bo,
                                              p_sm_tmp, D_MODEL, D_MODEL, 1.f, 0);
    ln_kernel<<<NB, 256>>>(p_x + (size_t)(NSEQ-1)*D_MODEL, (long)NSEQ*D_MODEL,
                           p_sm_tmp, D_MODEL, p_sm_x, D_MODEL, (uint8_t*)0, 0.f,
                           loc_ln1g, loc_ln1b);
    rowdot_kernel<<<dim3(FF_DIM, NB), 128>>>(p_sm_x, D_MODEL, loc_W1, loc_b1,
                                             p_sm_ffh, FF_DIM, D_MODEL, 1.f, 1);
    rowdot_kernel<<<dim3(D_MODEL, NB), 128>>>(p_sm_ffh, FF_DIM, loc_W2, loc_b2,
                                              p_sm_tmp, D_MODEL, FF_DIM, 1.f, 0);
    ln_kernel<<<NB, 256>>>(p_sm_x, D_MODEL, p_sm_tmp, D_MODEL,
                           p_sm_ctx, D_MODEL, (uint8_t*)0, 0.f,
                           loc_ln2g, loc_ln2b);

    rowdot_kernel<<<dim3(NEXP, NB), 128>>>(p_sm_ctx, D_MODEL, gate_w, gate_b,
                                           out + 1, NEXP, D_MODEL, 32.f, 0);
    stats_kernel<<<1, 256>>>(out + 1, noise);
    mix_kernel<<<(NROWS*D_MODEL/4 + 255)/256, 256>>>(responses);

    cudaStreamWaitEvent(0, evEnc, 0);

    // two encoder layers: fp8 GEMMs + fp8 tensor-core attention
    const float invXW = 1.f/(SX*SW);
    const float invAW = 1.f/(SA*SW);
    const float invFW = 1.f/(SF*SW);
    for (int l = 0; l < 2; l++) {
        const uint8_t* Wqkv = p_qWqkv + (size_t)l*QKV_LD*D_MODEL;
        const float*   bqkv = enc_bqkv + (size_t)l*QKV_LD;
        const uint8_t* Wo   = p_qWo   + (size_t)l*D_MODEL*D_MODEL;
        const float*   bo   = enc_bo  + (size_t)l*D_MODEL;
        const float* g1   = enc_ln1g + (size_t)l*D_MODEL;
        const float* b1l  = enc_ln1b + (size_t)l*D_MODEL;
        const uint8_t* W1   = p_qW1   + (size_t)l*FF_DIM*D_MODEL;
        const float*   bb1  = enc_b1  + (size_t)l*FF_DIM;
        const uint8_t* W2   = p_qW2   + (size_t)l*D_MODEL*FF_DIM;
        const float*   bb2  = enc_b2  + (size_t)l*D_MODEL;
        const float* g2   = enc_ln2g + (size_t)l*D_MODEL;
        const float* b2l  = enc_ln2b + (size_t)l*D_MODEL;

        // QKV -> fp8 (scale SQK)
        gemm_fp8_64_kernel<1><<<dim3(QKV_LD/64, NROWS/64), 256>>>(
            p_qx, Wqkv, bqkv, p_qqkv, D_MODEL, QKV_LD, invXW, SQK, 0);
        // attention on tensor cores
        vtrans_kernel<<<dim3(4, NBH), 256>>>();
        score_gemm_kernel<<<dim3(2, 2, NBH), 256>>>();
        asoftmax_kernel<<<NBH*NSEQ/4, 128>>>();
        attn_o_kernel<<<dim3(4, NBH), 256>>>();
        // Wo
        gemm_fp8_64_kernel<0><<<dim3(D_MODEL/64, NROWS/64), 256>>>(
            p_qattn, Wo, bo, p_tmp, D_MODEL, D_MODEL, invAW, 0.f, 0);
        ln_kernel<<<NROWS, 256>>>(p_x, D_MODEL, p_tmp, D_MODEL, p_x, D_MODEL,
                                  p_qx, SX, g1, b1l);
        gemm_fp8_kernel<1><<<dim3(FF_DIM/128, NROWS/128), 256>>>(
            p_qx, W1, bb1, p_qffh, D_MODEL, FF_DIM, invXW, SF);
        gemm_fp8_64_kernel<0><<<dim3(D_MODEL/64, NROWS/64), 256>>>(
            p_qffh, W2, bb2, p_tmp, FF_DIM, D_MODEL, invFW, 0.f, 0);
        ln_kernel<<<NROWS, 256>>>(p_x, D_MODEL, p_tmp, D_MODEL, p_x, D_MODEL,
                                  p_qx, SX, g2, b2l);
    }

    cudaStreamWaitEvent(0, evDec, 0);

    gemm_fp8_kernel<2><<<dim3(NROWS/128, NBLK_V), 256>>>(
        p_qx, p_qdec, (const float*)0, (void*)0, D_MODEL, 0, invXW, 0.f);
    lse_reduce_kernel<<<NROWS, 128>>>();
    lablogit_kernel<<<dim3(NSEQ-1, NB), 128>>>(inputs, dec_w);
    final_kernel<<<1, 256>>>(out);

    cudaEventDestroy(evFork);
    cudaEventDestroy(evEnc);
    cudaEventDestroy(evDec);
    cudaStreamDestroy(s2);
}

// round 15
// speedup vs baseline: 1.4958x; 1.0095x over previous
#include <cuda_runtime.h>
#include <cuda_bf16.h>
#include <math.h>
#include <stdint.h>

// ---------------- problem constants ----------------
#define D_MODEL 1024
#define NHEAD   16
#define DHEAD   64
#define FF_DIM  4096
#define NSEQ    256
#define NB      4
#define NTOK    50257
#define NEXP    2000
#define NKTOP   20
#define NROWS   (NB*NSEQ)      // 1024
#define QKV_LD  3072
#define NBLK_V  393
#define NBH     (NB*NHEAD)     // 64

// fp8 per-tensor scales
#define SX   16.0f
#define SW   512.0f
#define SA   64.0f
#define SF   32.0f
#define SQK  64.0f
#define SP   128.0f

// ---------------- scratch ----------------
__device__ float g_x    [NROWS*D_MODEL];
__device__ float g_qkv  [NROWS*QKV_LD];      // loc layer (fp32 path)
__device__ float g_tmp  [NROWS*D_MODEL];
__device__ float g_sm_attn[NB*D_MODEL];
__device__ float g_sm_x   [NB*D_MODEL];
__device__ float g_sm_tmp [NB*D_MODEL];
__device__ float g_sm_ctx [NB*D_MODEL];
__device__ float g_sm_ffh [NB*FF_DIM];
__device__ float g_psum[NROWS*NBLK_V];
__device__ float g_lse [NROWS];
__device__ float g_lab [NB*(NSEQ-1)];
__device__ float g_stats[32];

// fp8 mirrors
__device__ __align__(256) uint8_t q_Wqkv[2*QKV_LD*D_MODEL];
__device__ __align__(256) uint8_t q_Wo  [2*D_MODEL*D_MODEL];
__device__ __align__(256) uint8_t q_W1  [2*FF_DIM*D_MODEL];
__device__ __align__(256) uint8_t q_W2  [2*D_MODEL*FF_DIM];
__device__ __align__(256) uint8_t q_dec [NTOK*D_MODEL];
__device__ __align__(256) uint8_t q_x   [NROWS*D_MODEL];
__device__ __align__(256) uint8_t q_attn[NROWS*D_MODEL];
__device__ __align__(256) uint8_t q_ffh [NROWS*FF_DIM];
__device__ __align__(256) uint8_t q_qkv [NROWS*QKV_LD];
__device__ __align__(256) uint8_t q_vt  [NBH*DHEAD*NSEQ];

// ---------------- fp8 pack + fast fma-pipe exp ----------------
__device__ __forceinline__ uint16_t pack_e4m3(float lo, float hi)
{
    uint16_t r;
    asm("cvt.rn.satfinite.e4m3x2.f32 %0, %1, %2;" : "=h"(r) : "f"(hi), "f"(lo));
    return r;
}

__device__ __forceinline__ float fast_exp(float x)
{
    float t = x * 1.4426950408889634f;
    float fi = floorf(t);
    float f = t - fi;
    float p = 1.5403530e-4f;
    p = fmaf(p, f, 1.3333558e-3f);
    p = fmaf(p, f, 9.6180489e-3f);
    p = fmaf(p, f, 5.5504109e-2f);
    p = fmaf(p, f, 2.4022651e-1f);
    p = fmaf(p, f, 6.9314718e-1f);
    p = fmaf(p, f, 1.0f);
    return __int_as_float(__float_as_int(p) + (((int)fi) << 23));
}

__global__ void q8_kernel(const float* __restrict__ src, uint8_t* __restrict__ dst,
                          int n4, float scale)
{
    int i = (blockIdx.x*blockDim.x + threadIdx.x) * 2;
    #pragma unroll
    for (int t = 0; t < 2; t++) {
        int j = i + t;
        if (j < n4) {
            float4 v = ((const float4*)src)[j];
            uint32_t lo = pack_e4m3(v.x*scale, v.y*scale);
            uint32_t hi = pack_e4m3(v.z*scale, v.w*scale);
            ((uint32_t*)dst)[j] = lo | (hi << 16);
        }
    }
}

// ---------------- embedding gather ----------------
__global__ void embed_kernel(const int* __restrict__ inputs, const float* __restrict__ emb)
{
    int r = blockIdx.x;
    int tok = inputs[r];
    const float4* src = (const float4*)(emb + (size_t)tok * D_MODEL);
    float4* dst = (float4*)(g_x + (size_t)r * D_MODEL);
    dst[threadIdx.x] = src[threadIdx.x];
}

// ================= cp.async / ldmatrix helpers =================
__device__ __forceinline__ void cp_async16(void* smem, const void* gmem)
{
    uint32_t s = (uint32_t)__cvta_generic_to_shared(smem);
    asm volatile("cp.async.ca.shared.global [%0], [%1], 16;\n" :: "r"(s), "l"(gmem));
}
__device__ __forceinline__ void cp_commit()
{
    asm volatile("cp.async.commit_group;\n" ::: "memory");
}
template<int N> __device__ __forceinline__ void cp_wait()
{
    asm volatile("cp.async.wait_group %0;\n" :: "n"(N) : "memory");
}
__device__ __forceinline__ void ldsm_x4(uint32_t& r0, uint32_t& r1, uint32_t& r2, uint32_t& r3,
                                        const void* smem)
{
    uint32_t a = (uint32_t)__cvta_generic_to_shared(smem);
    asm volatile("ldmatrix.sync.aligned.m8n8.x4.shared.b16 {%0,%1,%2,%3}, [%4];\n"
                 : "=r"(r0), "=r"(r1), "=r"(r2), "=r"(r3) : "r"(a));
}
__device__ __forceinline__ void ldsm_x2(uint32_t& r0, uint32_t& r1, const void* smem)
{
    uint32_t a = (uint32_t)__cvta_generic_to_shared(smem);
    asm volatile("ldmatrix.sync.aligned.m8n8.x2.shared.b16 {%0,%1}, [%2];\n"
                 : "=r"(r0), "=r"(r1) : "r"(a));
}
__device__ __forceinline__ void mma_e4m3(float* a4, uint32_t a0, uint32_t a1, uint32_t a2, uint32_t a3,
                                         uint32_t b0, uint32_t b1)
{
    asm volatile(
        "mma.sync.aligned.m16n8k32.row.col.f32.e4m3.e4m3.f32 "
        "{%0,%1,%2,%3}, {%4,%5,%6,%7}, {%8,%9}, {%0,%1,%2,%3};\n"
        : "+f"(a4[0]), "+f"(a4[1]), "+f"(a4[2]), "+f"(a4[3])
        : "r"(a0), "r"(a1), "r"(a2), "r"(a3), "r"(b0), "r"(b1));
}
__device__ __forceinline__ void mma_tf32(float* a4, uint32_t a0, uint32_t a1, uint32_t a2, uint32_t a3,
                                         uint32_t b0, uint32_t b1)
{
    asm volatile(
        "mma.sync.aligned.m16n8k8.row.col.f32.tf32.tf32.f32 "
        "{%0,%1,%2,%3}, {%4,%5,%6,%7}, {%8,%9}, {%0,%1,%2,%3};\n"
        : "+f"(a4[0]), "+f"(a4[1]), "+f"(a4[2]), "+f"(a4[3])
        : "r"(a0), "r"(a1), "r"(a2), "r"(a3), "r"(b0), "r"(b1));
}

// ================= tf32 GEMM 64x64 (loc KV path) =================
__global__ __launch_bounds__(256) void gemm_tc64_kernel(
    const float* __restrict__ A, const float* __restrict__ W,
    const float* __restrict__ bias, float* __restrict__ C,
    int K, int ldC)
{
    __shared__ uint32_t As[2][64][20];
    __shared__ uint32_t Bs[2][64][20];
    float acc[2][2][4];
    #pragma unroll
    for (int a = 0; a < 2; a++)
        #pragma unroll
        for (int b = 0; b < 2; b++)
            #pragma unroll
            for (int c = 0; c < 4; c++) acc[a][b][c] = 0.f;

    int m0 = blockIdx.y * 64, n0 = blockIdx.x * 64;
    int tid  = threadIdx.x;
    int lane = tid & 31, wid = tid >> 5;
    int wm = wid >> 2, wn = wid & 3;
    int g = lane >> 2, tig = lane & 3;

    int r0c = tid >> 2, c0c = (tid & 3) << 2;
    const float* pa0 = A + (size_t)(m0 + r0c)*K + c0c;
    const float* pb0 = W + (size_t)(n0 + r0c)*K + c0c;

    int niter = K >> 4;
    cp_async16(&As[0][r0c][c0c], pa0);
    cp_async16(&Bs[0][r0c][c0c], pb0);
    cp_commit();

    for (int it = 0; it < niter; it++) {
        int st = it & 1;
        if (it + 1 < niter) {
            int off = (it + 1) << 4;
            int sn = st ^ 1;
            cp_async16(&As[sn][r0c][c0c], pa0 + off);
            cp_async16(&Bs[sn][r0c][c0c], pb0 + off);
            cp_commit();
            cp_wait<1>();
        } else {
            cp_wait<0>();
        }
        __syncthreads();
        #pragma unroll
        for (int ks = 0; ks < 16; ks += 8) {
            uint32_t af[2][4], bf[2][2];
            #pragma unroll
            for (int mt = 0; mt < 2; mt++) {
                int r0 = wm*32 + mt*16;
                af[mt][0] = As[st][r0+g  ][ks+tig  ];
                af[mt][1] = As[st][r0+g+8][ks+tig  ];
                af[mt][2] = As[st][r0+g  ][ks+tig+4];
                af[mt][3] = As[st][r0+g+8][ks+tig+4];
            }
            #pragma unroll
            for (int nt = 0; nt < 2; nt++) {
                int c0 = wn*16 + nt*8;
                bf[nt][0] = Bs[st][c0+g][ks+tig  ];
                bf[nt][1] = Bs[st][c0+g][ks+tig+4];
            }
            #pragma unroll
            for (int mt = 0; mt < 2; mt++)
                #pragma unroll
                for (int nt = 0; nt < 2; nt++)
                    mma_tf32(acc[mt][nt], af[mt][0], af[mt][1], af[mt][2], af[mt][3],
                             bf[nt][0], bf[nt][1]);
        }
        __syncthreads();
    }

    int rowb = m0 + wm*32, colb = n0 + wn*16;
    #pragma unroll
    for (int nt = 0; nt < 2; nt++) {
        int c = colb + nt*8 + 2*tig;
        float b0 = bias[c], b1 = bias[c+1];
        #pragma unroll
        for (int mt = 0; mt < 2; mt++) {
            int r = rowb + mt*16 + g;
            *(float2*)(C + (size_t)r*ldC + c)     = make_float2(acc[mt][nt][0]+b0, acc[mt][nt][1]+b1);
            *(float2*)(C + (size_t)(r+8)*ldC + c) = make_float2(acc[mt][nt][2]+b0, acc[mt][nt][3]+b1);
        }
    }
}

// ================= fp8 GEMM 128x128 (decoder + FF1) =================
template<int MODE>
__global__ __launch_bounds__(256, 2) void gemm_fp8_kernel(
    const uint8_t* __restrict__ A, const uint8_t* __restrict__ W,
    const float* __restrict__ bias, void* __restrict__ Cout,
    int K, int ldC, float inv, float outscale)
{
    __shared__ uint32_t As[2][128][20];
    __shared__ uint32_t Bs[2][128][20];

    float acc[4][4][4];
    #pragma unroll
    for (int a = 0; a < 4; a++)
        #pragma unroll
        for (int b = 0; b < 4; b++)
            #pragma unroll
            for (int c = 0; c < 4; c++) acc[a][b][c] = 0.f;

    int m0, n0, nblk = 0;
    if (MODE == 2) { m0 = blockIdx.x * 128; n0 = blockIdx.y * 128; nblk = blockIdx.y; }
    else           { m0 = blockIdx.y * 128; n0 = blockIdx.x * 128; }

    int tid  = threadIdx.x;
    int lane = tid & 31, wid = tid >> 5;
    int wm = wid >> 2, wn = wid & 3;
    int g = lane >> 2, tig = lane & 3;

    int a_row = (lane & 7) + ((lane >> 3) & 1) * 8;
    int a_wrd = (lane >> 4) * 4;
    int b_row = lane & 7;
    int b_wrd = ((lane >> 3) & 1) * 4;

    int r0c = tid >> 2, r1c = r0c + 64;
    int cw = (tid & 3) * 4;
    int ce = (tid & 3) * 16;
    int nr0 = n0 + r0c, nr1 = n0 + r1c;
    if (MODE == 2) { nr0 = (nr0 < NTOK) ? nr0 : (NTOK - 1); nr1 = (nr1 < NTOK) ? nr1 : (NTOK - 1); }
    const uint8_t* pa0 = A + (size_t)(m0 + r0c)*K + ce;
    const uint8_t* pa1 = A + (size_t)(m0 + r1c)*K + ce;
    const uint8_t* pb0 = W + (size_t)nr0*K + ce;
    const uint8_t* pb1 = W + (size_t)nr1*K + ce;

    int niter = K >> 6;
    cp_async16(&As[0][r0c][cw], pa0);
    cp_async16(&As[0][r1c][cw], pa1);
    cp_async16(&Bs[0][r0c][cw], pb0);
    cp_async16(&Bs[0][r1c][cw], pb1);
    cp_commit();

    for (int it = 0; it < niter; it++) {
        int st = it & 1;
        if (it + 1 < niter) {
            int off = (it + 1) << 6;
            int sn = st ^ 1;
            cp_async16(&As[sn][r0c][cw], pa0 + off);
            cp_async16(&As[sn][r1c][cw], pa1 + off);
            cp_async16(&Bs[sn][r0c][cw], pb0 + off);
            cp_async16(&Bs[sn][r1c][cw], pb1 + off);
            cp_commit();
            cp_wait<1>();
        } else {
            cp_wait<0>();
        }
        __syncthreads();
        #pragma unroll
        for (int ks = 0; ks < 2; ks++) {
            int kb = ks*8;
            uint32_t af[4][4], bf[4][2];
            #pragma unroll
            for (int mt = 0; mt < 4; mt++) {
                int r0 = wm*64 + mt*16;
                ldsm_x4(af[mt][0], af[mt][1], af[mt][2], af[mt][3],
                        &As[st][r0 + a_row][kb + a_wrd]);
            }
            #pragma unroll
            for (int nt = 0; nt < 4; nt++) {
                int c0 = wn*32 + nt*8;
                ldsm_x2(bf[nt][0], bf[nt][1],
                        &Bs[st][c0 + b_row][kb + b_wrd]);
            }
            #pragma unroll
            for (int mt = 0; mt < 4; mt++)
                #pragma unroll
                for (int nt = 0; nt < 4; nt++)
                    mma_e4m3(acc[mt][nt], af[mt][0], af[mt][1], af[mt][2], af[mt][3],
                             bf[nt][0], bf[nt][1]);
        }
        __syncthreads();
    }

    #pragma unroll
    for (int a = 0; a < 4; a++)
        #pragma unroll
        for (int b = 0; b < 4; b++)
            #pragma unroll
            for (int c = 0; c < 4; c++) acc[a][b][c] *= inv;

    int rowb = m0 + wm*64, colb = n0 + wn*32;

    if (MODE == 1) {
        uint8_t* C = (uint8_t*)Cout;
        #pragma unroll
        for (int nt = 0; nt < 4; nt++) {
            int c = colb + nt*8 + 2*tig;
            float b0 = bias[c], b1 = bias[c+1];
            #pragma unroll
            for (int mt = 0; mt < 4; mt++) {
                int r = rowb + mt*16 + g;
                float v0 = fmaxf(acc[mt][nt][0]+b0, 0.f)*outscale;
                float v1 = fmaxf(acc[mt][nt][1]+b1, 0.f)*outscale;
                float v2 = fmaxf(acc[mt][nt][2]+b0, 0.f)*outscale;
                float v3 = fmaxf(acc[mt][nt][3]+b1, 0.f)*outscale;
                *(uint16_t*)(C + (size_t)r*ldC + c)     = pack_e4m3(v0, v1);
                *(uint16_t*)(C + (size_t)(r+8)*ldC + c) = pack_e4m3(v2, v3);
            }
        }
    } else {
        __shared__ float red_s[4][128];
        #pragma unroll
        for (int mt = 0; mt < 4; mt++) {
            #pragma unroll
            for (int h = 0; h < 2; h++) {
                float s = 0.f;
                #pragma unroll
                for (int nt = 0; nt < 4; nt++) {
                    int c = colb + nt*8 + 2*tig;
                    if (c     < NTOK) s += fast_exp(acc[mt][nt][h*2+0]);
                    if (c + 1 < NTOK) s += fast_exp(acc[mt][nt][h*2+1]);
                }
                s += __shfl_xor_sync(0xffffffffu, s, 1);
                s += __shfl_xor_sync(0xffffffffu, s, 2);
                if (tig == 0) {
                    int lr = wm*64 + mt*16 + h*8 + g;
                    red_s[wn][lr] = s;
                }
            }
        }
        __syncthreads();
        if (tid < 128) {
            float s = red_s[0][tid] + red_s[1][tid] + red_s[2][tid] + red_s[3][tid];
            int row = m0 + tid;
            g_psum[(size_t)row*NBLK_V + nblk] = s;
        }
    }
}

// ================= fp8 GEMM 64x64 (encoder GEMMs) =================
template<int OUT8>
__global__ __launch_bounds__(256) void gemm_fp8_64_kernel(
    const uint8_t* __restrict__ A, const uint8_t* __restrict__ W,
    const float* __restrict__ bias, void* __restrict__ Cout,
    int K, int ldC, float inv, float outscale, int relu)
{
    __shared__ uint32_t As[2][64][20];
    __shared__ uint32_t Bs[2][64][20];

    float acc[2][2][4];
    #pragma unroll
    for (int a = 0; a < 2; a++)
        #pragma unroll
        for (int b = 0; b < 2; b++)
            #pragma unroll
            for (int c = 0; c < 4; c++) acc[a][b][c] = 0.f;

    int m0 = blockIdx.y * 64, n0 = blockIdx.x * 64;

    int tid  = threadIdx.x;
    int lane = tid & 31, wid = tid >> 5;
    int wm = wid >> 2, wn = wid & 3;
    int g = lane >> 2, tig = lane & 3;

    int a_row = (lane & 7) + ((lane >> 3) & 1) * 8;
    int a_wrd = (lane >> 4) * 4;
    int b_row = lane & 7;
    int b_wrd = ((lane >> 3) & 1) * 4;

    int r0c = tid >> 2;
    int cw = (tid & 3) * 4;
    int ce = (tid & 3) * 16;
    const uint8_t* pa0 = A + (size_t)(m0 + r0c)*K + ce;
    const uint8_t* pb0 = W + (size_t)(n0 + r0c)*K + ce;

    int niter = K >> 6;
    cp_async16(&As[0][r0c][cw], pa0);
    cp_async16(&Bs[0][r0c][cw], pb0);
    cp_commit();

    for (int it = 0; it < niter; it++) {
        int st = it & 1;
        if (it + 1 < niter) {
            int off = (it + 1) << 6;
            int sn = st ^ 1;
            cp_async16(&As[sn][r0c][cw], pa0 + off);
            cp_async16(&Bs[sn][r0c][cw], pb0 + off);
            cp_commit();
            cp_wait<1>();
        } else {
            cp_wait<0>();
        }
        __syncthreads();
        #pragma unroll
        for (int ks = 0; ks < 2; ks++) {
            int kb = ks*8;
            uint32_t af[2][4], bf[2][2];
            #pragma unroll
            for (int mt = 0; mt < 2; mt++) {
                int r0 = wm*32 + mt*16;
                ldsm_x4(af[mt][0], af[mt][1], af[mt][2], af[mt][3],
                        &As[st][r0 + a_row][kb + a_wrd]);
            }
            #pragma unroll
            for (int nt = 0; nt < 2; nt++) {
                int c0 = wn*16 + nt*8;
                ldsm_x2(bf[nt][0], bf[nt][1],
                        &Bs[st][c0 + b_row][kb + b_wrd]);
            }
            #pragma unroll
            for (int mt = 0; mt < 2; mt++)
                #pragma unroll
                for (int nt = 0; nt < 2; nt++)
                    mma_e4m3(acc[mt][nt], af[mt][0], af[mt][1], af[mt][2], af[mt][3],
                             bf[nt][0], bf[nt][1]);
        }
        __syncthreads();
    }

    #pragma unroll
    for (int a = 0; a < 2; a++)
        #pragma unroll
        for (int b = 0; b < 2; b++)
            #pragma unroll
            for (int c = 0; c < 4; c++) acc[a][b][c] *= inv;

    int rowb = m0 + wm*32, colb = n0 + wn*16;
    if (OUT8 == 0) {
        float* C = (float*)Cout;
        #pragma unroll
        for (int nt = 0; nt < 2; nt++) {
            int c = colb + nt*8 + 2*tig;
            float b0 = bias[c], b1 = bias[c+1];
            #pragma unroll
            for (int mt = 0; mt < 2; mt++) {
                int r = rowb + mt*16 + g;
                *(float2*)(C + (size_t)r*ldC + c)     = make_float2(acc[mt][nt][0]+b0, acc[mt][nt][1]+b1);
                *(float2*)(C + (size_t)(r+8)*ldC + c) = make_float2(acc[mt][nt][2]+b0, acc[mt][nt][3]+b1);
            }
        }
    } else {
        uint8_t* C = (uint8_t*)Cout;
        #pragma unroll
        for (int nt = 0; nt < 2; nt++) {
            int c = colb + nt*8 + 2*tig;
            float b0 = bias ? bias[c] : 0.f;
            float b1 = bias ? bias[c+1] : 0.f;
            #pragma unroll
            for (int mt = 0; mt < 2; mt++) {
                int r = rowb + mt*16 + g;
                float v0 = acc[mt][nt][0]+b0, v1 = acc[mt][nt][1]+b1;
                float v2 = acc[mt][nt][2]+b0, v3 = acc[mt][nt][3]+b1;
                if (relu) {
                    v0 = fmaxf(v0, 0.f); v1 = fmaxf(v1, 0.f);
                    v2 = fmaxf(v2, 0.f); v3 = fmaxf(v3, 0.f);
                }
                *(uint16_t*)(C + (size_t)r*ldC + c)     = pack_e4m3(v0*outscale, v1*outscale);
                *(uint16_t*)(C + (size_t)(r+8)*ldC + c) = pack_e4m3(v2*outscale, v3*outscale);
            }
        }
    }
}

// ================= V transpose (fp8): [s,d] -> VT[bh][d][s] ==================
__global__ void vtrans_kernel()
{
    __shared__ uint8_t t[64][65];
    int bh = blockIdx.y, b = bh >> 4, h = bh & 15;
    int s0 = blockIdx.x * 64;
    int tid = threadIdx.x;
    const uint8_t* src = q_qkv + (size_t)(b*NSEQ)*QKV_LD + 2*D_MODEL + h*DHEAD;
    for (int i = tid; i < 4096; i += 256) {
        int s = i >> 6, d = i & 63;
        t[d][s] = src[(size_t)(s0+s)*QKV_LD + d];
    }
    __syncthreads();
    uint8_t* dst = q_vt + (size_t)bh*DHEAD*NSEQ;
    for (int i = tid; i < 4096; i += 256) {
        int d = i >> 6, s = i & 63;
        dst[(size_t)d*NSEQ + s0 + s] = t[d][s];
    }
}

// ========== fused attention: scores + softmax + P·V^T per 64-query tile ======
// grid (NSEQ/64 = 4, NBH), 256 threads. smem 45 KB static.
__global__ __launch_bounds__(256) void fattn_kernel()
{
    __shared__ uint32_t sm[11264];                // 45 KB
    uint32_t* Qs = sm;                            // [64][20]
    uint32_t* Ks = sm + 1280;                     // [256][20]
    uint32_t* VT = sm + 6400;                     // [64][68]
    float*    red = (float*)(sm + 10752);         // [64][8]
    uint32_t* Ps = sm;                            // [64][68] (reuses Q/K region)

    int bh = blockIdx.y, b = bh >> 4, h = bh & 15;
    int m0 = blockIdx.x * 64;
    int tid = threadIdx.x, lane = tid & 31, wid = tid >> 5;
    int wm = wid >> 2, wn = wid & 3;              // warps 2 x 4
    int g = lane >> 2, tig = lane & 3;
    int a_row = (lane & 7) + ((lane >> 3) & 1) * 8;
    int a_wrd = (lane >> 4) * 4;
    int b_row = lane & 7;
    int b_wrd = ((lane >> 3) & 1) * 4;

    const uint8_t* Qb  = q_qkv + (size_t)(b*NSEQ)*QKV_LD + h*DHEAD;
    const uint8_t* Kb  = Qb + D_MODEL;
    const uint8_t* VTb = q_vt + (size_t)bh*DHEAD*NSEQ;

    // stage loads: Q 64x64, K 256x64, VT 64x256
    {
        int r = tid >> 2, cw = (tid & 3) * 4, ce = (tid & 3) * 16;
        cp_async16(&Qs[r*20 + cw], Qb + (size_t)(m0 + r)*QKV_LD + ce);
        #pragma unroll
        for (int i = 0; i < 4; i++) {
            int rr = r + i*64;
            cp_async16(&Ks[rr*20 + cw], Kb + (size_t)rr*QKV_LD + ce);
        }
        #pragma unroll
        for (int i = 0; i < 4; i++) {
            int idx = tid + i*256;            // 1024 16B chunks
            int vr = idx >> 4, vcw = (idx & 15) * 4;
            cp_async16(&VT[vr*68 + vcw], VTb + (size_t)vr*NSEQ + (idx & 15)*16);
        }
        cp_commit(); cp_wait<0>();
    }
    __syncthreads();

    // scores: 64x256, warp tile 32x64 (mt 2, nt 8)
    float acc[2][8][4];
    #pragma unroll
    for (int a = 0; a < 2; a++)
        #pragma unroll
        for (int n = 0; n < 8; n++)
            #pragma unroll
            for (int c = 0; c < 4; c++) acc[a][n][c] = 0.f;

    #pragma unroll
    for (int ks = 0; ks < 2; ks++) {
        int kb = ks*8;
        uint32_t af[2][4], bf[8][2];
        #pragma unroll
        for (int mt = 0; mt < 2; mt++) {
            int r0 = wm*32 + mt*16;
            ldsm_x4(af[mt][0], af[mt][1], af[mt][2], af[mt][3],
                    &Qs[(r0 + a_row)*20 + kb + a_wrd]);
        }
        #pragma unroll
        for (int nt = 0; nt < 8; nt++) {
            int c0 = wn*64 + nt*8;
            ldsm_x2(bf[nt][0], bf[nt][1],
                    &Ks[(c0 + b_row)*20 + kb + b_wrd]);
        }
        #pragma unroll
        for (int mt = 0; mt < 2; mt++)
            #pragma unroll
            for (int nt = 0; nt < 8; nt++)
                mma_e4m3(acc[mt][nt], af[mt][0], af[mt][1], af[mt][2], af[mt][3],
                         bf[nt][0], bf[nt][1]);
    }

    const float sc = 0.125f / (SQK*SQK);
    #pragma unroll
    for (int a = 0; a < 2; a++)
        #pragma unroll
        for (int n = 0; n < 8; n++)
            #pragma unroll
            for (int c = 0; c < 4; c++) acc[a][n][c] *= sc;

    // softmax phase 1: per-row max (warp covers 64 cols, 4 warps span 256)
    #pragma unroll
    for (int mt = 0; mt < 2; mt++) {
        #pragma unroll
        for (int hh = 0; hh < 2; hh++) {
            float m = -INFINITY;
            #pragma unroll
            for (int nt = 0; nt < 8; nt++)
                m = fmaxf(m, fmaxf(acc[mt][nt][hh*2+0], acc[mt][nt][hh*2+1]));
            m = fmaxf(m, __shfl_xor_sync(0xffffffffu, m, 1));
            m = fmaxf(m, __shfl_xor_sync(0xffffffffu, m, 2));
            if (tig == 0) {
                int row = wm*32 + mt*16 + hh*8 + g;
                red[row*8 + wn] = m;
            }
        }
    }
    __syncthreads();
    float rmax[2][2];
    #pragma unroll
    for (int mt = 0; mt < 2; mt++)
        #pragma unroll
        for (int hh = 0; hh < 2; hh++) {
            int row = wm*32 + mt*16 + hh*8 + g;
            rmax[mt][hh] = fmaxf(fmaxf(red[row*8+0], red[row*8+1]),
                                 fmaxf(red[row*8+2], red[row*8+3]));
        }
    // phase 2: exp + per-row sum
    #pragma unroll
    for (int mt = 0; mt < 2; mt++) {
        #pragma unroll
        for (int hh = 0; hh < 2; hh++) {
            float s = 0.f;
            #pragma unroll
            for (int nt = 0; nt < 8; nt++) {
                float e0 = fast_exp(acc[mt][nt][hh*2+0] - rmax[mt][hh]);
                float e1 = fast_exp(acc[mt][nt][hh*2+1] - rmax[mt][hh]);
                acc[mt][nt][hh*2+0] = e0;
                acc[mt][nt][hh*2+1] = e1;
                s += e0 + e1;
            }
            s += __shfl_xor_sync(0xffffffffu, s, 1);
            s += __shfl_xor_sync(0xffffffffu, s, 2);
            if (tig == 0) {
                int row = wm*32 + mt*16 + hh*8 + g;
                red[row*8 + 4 + wn] = s;
            }
        }
    }
    __syncthreads();
    float rs[2][2];
    #pragma unroll
    for (int mt = 0; mt < 2; mt++)
        #pragma unroll
        for (int hh = 0; hh < 2; hh++) {
            int row = wm*32 + mt*16 + hh*8 + g;
            rs[mt][hh] = SP / (red[row*8+4] + red[row*8+5] + red[row*8+6] + red[row*8+7]);
        }
    // write P (fp8) into Ps (overwrites Q/K region; all reads complete)
    #pragma unroll
    for (int mt = 0; mt < 2; mt++) {
        #pragma unroll
        for (int nt = 0; nt < 8; nt++) {
            int col = wn*64 + nt*8 + 2*tig;
            #pragma unroll
            for (int hh = 0; hh < 2; hh++) {
                int row = wm*32 + mt*16 + hh*8 + g;
                *(uint16_t*)((uint8_t*)&Ps[row*68] + col) =
                    pack_e4m3(acc[mt][nt][hh*2+0]*rs[mt][hh], acc[mt][nt][hh*2+1]*rs[mt][hh]);
            }
        }
    }
    __syncthreads();

    // O = P (64x256) * VT^T (256x64): warp tile 32x16, K=256
    float accO[2][2][4];
    #pragma unroll
    for (int a = 0; a < 2; a++)
        #pragma unroll
        for (int n = 0; n < 2; n++)
            #pragma unroll
            for (int c = 0; c < 4; c++) accO[a][n][c] = 0.f;

    #pragma unroll
    for (int ks = 0; ks < 8; ks++) {
        int kb = ks*8;
        uint32_t af[2][4], bf[2][2];
        #pragma unroll
        for (int mt = 0; mt < 2; mt++) {
            int r0 = wm*32 + mt*16;
            ldsm_x4(af[mt][0], af[mt][1], af[mt][2], af[mt][3],
                    &Ps[(r0 + a_row)*68 + kb + a_wrd]);
        }
        #pragma unroll
        for (int nt = 0; nt < 2; nt++) {
            int c0 = wn*16 + nt*8;
            ldsm_x2(bf[nt][0], bf[nt][1],
                    &VT[(c0 + b_row)*68 + kb + b_wrd]);
        }
        #pragma unroll
        for (int mt = 0; mt < 2; mt++)
            #pragma unroll
            for (int nt = 0; nt < 2; nt++)
                mma_e4m3(accO[mt][nt], af[mt][0], af[mt][1], af[mt][2], af[mt][3],
                         bf[nt][0], bf[nt][1]);
    }

    const float inv = SA / (SP * SQK);
    #pragma unroll
    for (int nt = 0; nt < 2; nt++) {
        int c = wn*16 + nt*8 + 2*tig;
        #pragma unroll
        for (int mt = 0; mt < 2; mt++) {
            int r = m0 + wm*32 + mt*16 + g;
            uint8_t* d0 = q_attn + (size_t)(b*NSEQ + r)*D_MODEL + h*DHEAD + c;
            uint8_t* d1 = q_attn + (size_t)(b*NSEQ + r + 8)*D_MODEL + h*DHEAD + c;
            *(uint16_t*)d0 = pack_e4m3(accO[mt][nt][0]*inv, accO[mt][nt][1]*inv);
            *(uint16_t*)d1 = pack_e4m3(accO[mt][nt][2]*inv, accO[mt][nt][3]*inv);
        }
    }
}

__global__ void lse_reduce_kernel()
{
    int r = blockIdx.x, tid = threadIdx.x;
    double sum = 0.0;
    for (int i = tid; i < NBLK_V; i += 128)
        sum += (double)g_psum[(size_t)r*NBLK_V + i];
    __shared__ double redd[128];
    redd[tid] = sum; __syncthreads();
    for (int s = 64; s > 0; s >>= 1) { if (tid < s) redd[tid] += redd[tid+s]; __syncthreads(); }
    if (tid == 0) g_lse[r] = (float)log(redd[0]);
}

// ---------------- small-M GEMM (one (n,m) pair per block) ----------------
__global__ void rowdot_kernel(
    const float* __restrict__ A, long strideA,
    const float* __restrict__ W, const float* __restrict__ bias,
    float* __restrict__ C, long strideC,
    int K, float alpha, int relu)
{
    int n = blockIdx.x, m = blockIdx.y;
    int tid = threadIdx.x;   // 128
    const float* w = W + (size_t)n * K;
    const float* a = A + (size_t)m * strideA;
    __shared__ float red[128];
    float s = 0.f;
    for (int k = tid; k < K; k += 128) s += a[k]*w[k];
    red[tid] = s; __syncthreads();
    for (int st = 64; st > 0; st >>= 1) { if (tid < st) red[tid] += red[tid+st]; __syncthreads(); }
    if (tid == 0) {
        float v = alpha*red[0] + (bias ? bias[n] : 0.f);
        if (relu) v = fmaxf(v, 0.f);
        C[(size_t)m*strideC + n] = v;
    }
}

// ---------------- loc attention (single query per (h,b)), fp32 out ----------------
__global__ __launch_bounds__(256) void attn_kernel(
    const float* __restrict__ qkv, float* __restrict__ out, int nq, int sq_base)
{
    int qi = blockIdx.x, h = blockIdx.y, b = blockIdx.z;
    int sq = sq_base + qi;
    int tid = threadIdx.x;
    __shared__ float4 qrow[DHEAD/4];
    __shared__ float sc[NSEQ];
    __shared__ float red[256];
    __shared__ float sden;
    __shared__ float osum[4][DHEAD];
    const float* base = qkv + (size_t)b * NSEQ * QKV_LD;
    if (tid < DHEAD/4)
        qrow[tid] = ((const float4*)(base + (size_t)sq*QKV_LD + h*DHEAD))[tid];
    __syncthreads();
    {
        const float4* krow = (const float4*)(base + (size_t)tid*QKV_LD + D_MODEL + h*DHEAD);
        float d = 0.f;
        #pragma unroll
        for (int t = 0; t < DHEAD/4; t++) {
            float4 k4 = krow[t];
            float4 q4 = qrow[t];
            d += q4.x*k4.x + q4.y*k4.y + q4.z*k4.z + q4.w*k4.w;
        }
        sc[tid] = d * 0.125f;
    }
    __syncthreads();
    red[tid] = sc[tid]; __syncthreads();
    for (int s = 128; s > 0; s >>= 1) { if (tid < s) red[tid] = fmaxf(red[tid], red[tid+s]); __syncthreads(); }
    float mx = red[0]; __syncthreads();
    float e = expf(sc[tid] - mx);
    red[tid] = e; __syncthreads();
    for (int s = 128; s > 0; s >>= 1) { if (tid < s) red[tid] += red[tid+s]; __syncthreads(); }
    if (tid == 0) sden = red[0];
    __syncthreads();
    sc[tid] = e;
    __syncthreads();
    int d = tid & 63, g = tid >> 6;
    const float* vb = base + 2*D_MODEL + h*DHEAD + d;
    float o = 0.f;
    for (int j = g*64; j < (g+1)*64; j++) o += sc[j] * vb[(size_t)j*QKV_LD];
    osum[g][d] = o; __syncthreads();
    if (tid < DHEAD) {
        float r = (osum[0][tid]+osum[1][tid]+osum[2][tid]+osum[3][tid]) / sden;
        out[((size_t)(b*nq + qi))*D_MODEL + h*DHEAD + tid] = r;
    }
}

// ---------------- residual + layernorm (fp32 out + optional fp8 mirror) ----------
__global__ void ln_kernel(
    const float* __restrict__ in1, long s1,
    const float* __restrict__ in2, long s2,
    float* __restrict__ out, long so,
    uint8_t* __restrict__ outq, float qs,
    const float* __restrict__ gam, const float* __restrict__ bet)
{
    int r = blockIdx.x, tid = threadIdx.x;
    __shared__ float xr[D_MODEL];
    __shared__ float red[256];
    const float* p1 = in1 + (size_t)r*s1;
    const float* p2 = in2 + (size_t)r*s2;
    float ls = 0.f;
    for (int d = tid; d < D_MODEL; d += 256) { float v = p1[d]+p2[d]; xr[d] = v; ls += v; }
    red[tid] = ls; __syncthreads();
    for (int s = 128; s > 0; s >>= 1) { if (tid < s) red[tid] += red[tid+s]; __syncthreads(); }
    float mean = red[0] * (1.f/D_MODEL); __syncthreads();
    float lv = 0.f;
    for (int d = tid; d < D_MODEL; d += 256) { float t = xr[d]-mean; lv += t*t; }
    red[tid] = lv; __syncthreads();
    for (int s = 128; s > 0; s >>= 1) { if (tid < s) red[tid] += red[tid+s]; __syncthreads(); }
    float rstd = 1.f / sqrtf(red[0]*(1.f/D_MODEL) + 1e-5f);
    for (int d = tid*2; d < D_MODEL; d += 512) {
        float v0 = (xr[d]  -mean)*rstd*gam[d]   + bet[d];
        float v1 = (xr[d+1]-mean)*rstd*gam[d+1] + bet[d+1];
        *(float2*)(out + (size_t)r*so + d) = make_float2(v0, v1);
        if (outq) *(uint16_t*)(outq + (size_t)r*D_MODEL + d) = pack_e4m3(v0*qs, v1*qs);
    }
}

// ---------------- gating statistics + top-k + softmax + importance ----------------
__global__ void stats_kernel(const float* __restrict__ w, const float* __restrict__ noise)
{
    __shared__ float tot[NEXP];
    __shared__ double redd[256];
    __shared__ float fv[256];
    __shared__ int   fi[256];
    __shared__ float topv[NKTOP];
    __shared__ double smean, sstd;
    int tid = threadIdx.x;
    double ls = 0.0;
    for (int n = tid; n < NEXP; n += 256) {
        float f = 0.25f*(w[n] + w[NEXP+n] + w[2*NEXP+n] + w[3*NEXP+n]);
        tot[n] = f; ls += (double)f;
    }
    redd[tid] = ls; __syncthreads();
    for (int s = 128; s > 0; s >>= 1) { if (tid < s) redd[tid] += redd[tid+s]; __syncthreads(); }
    if (tid == 0) smean = redd[0] / NEXP;
    __syncthreads();
    double mfm = smean;
    ls = 0.0;
    for (int n = tid; n < NEXP; n += 256) { double t = (double)tot[n]-mfm; ls += t*t; }
    redd[tid] = ls; __syncthreads();
    for (int s = 128; s > 0; s >>= 1) { if (tid < s) redd[tid] += redd[tid+s]; __syncthreads(); }
    if (tid == 0) sstd = sqrt(redd[0] / (NEXP-1));
    __syncthreads();
    float stdfm = (float)sstd;
    for (int n = tid; n < NEXP; n += 256) tot[n] = tot[n] + noise[n]*stdfm;
    __syncthreads();
    ls = 0.0;
    for (int n = tid; n < NEXP; n += 256) ls += (double)tot[n];
    redd[tid] = ls; __syncthreads();
    for (int s = 128; s > 0; s >>= 1) { if (tid < s) redd[tid] += redd[tid+s]; __syncthreads(); }
    if (tid == 0) smean = redd[0] / NEXP;
    __syncthreads();
    double mt = smean;
    ls = 0.0;
    for (int n = tid; n < NEXP; n += 256) { double t = (double)tot[n]-mt; ls += t*t; }
    redd[tid] = ls; __syncthreads();
    for (int s = 128; s > 0; s >>= 1) { if (tid < s) redd[tid] += redd[tid+s]; __syncthreads(); }
    if (tid == 0) {
        double st = sqrt(redd[0] / (NEXP-1));
        double ratio = st / mt;
        g_stats[20] = (float)(0.1 * ratio * ratio);
    }
    __syncthreads();
    for (int it = 0; it < NKTOP; it++) {
        float bv = -INFINITY; int bi = 0x7fffffff;
        for (int n = tid; n < NEXP; n += 256) {
            float v = tot[n];
            if (v > bv || (v == bv && n < bi)) { bv = v; bi = n; }
        }
        fv[tid] = bv; fi[tid] = bi; __syncthreads();
        for (int s = 128; s > 0; s >>= 1) {
            if (tid < s) {
                float v2 = fv[tid+s]; int i2 = fi[tid+s];
                if (v2 > fv[tid] || (v2 == fv[tid] && i2 < fi[tid])) { fv[tid] = v2; fi[tid] = i2; }
            }
            __syncthreads();
        }
        if (tid == 0) { topv[it] = fv[0]; tot[fi[0]] = -INFINITY; }
        __syncthreads();
    }
    if (tid == 0) {
        float m = topv[0];
        float s = 0.f;
        float e[NKTOP];
        for (int k = 0; k < NKTOP; k++) { e[k] = expf(topv[k]-m); s += e[k]; }
        for (int k = 0; k < NKTOP; k++) g_stats[k] = e[k]/s;
    }
}

// ---------------- response mixture (fp32 + fp8 mirror) ----------------
__global__ void mix_kernel(const float* __restrict__ responses)
{
    __shared__ float w[NKTOP];
    if (threadIdx.x < NKTOP) w[threadIdx.x] = g_stats[threadIdx.x];
    __syncthreads();
    int i = blockIdx.x*blockDim.x + threadIdx.x;
    if (i < (NROWS*D_MODEL)/4) {
        float4 s = make_float4(0.f, 0.f, 0.f, 0.f);
        #pragma unroll
        for (int k = 0; k < NKTOP; k++) {
            float4 v = ((const float4*)responses)[(size_t)k*((NROWS*D_MODEL)/4) + i];
            float wk = w[k];
            s.x += wk*v.x; s.y += wk*v.y; s.z += wk*v.z; s.w += wk*v.w;
        }
        ((float4*)g_x)[i] = s;
        uint32_t lo = pack_e4m3(s.x*SX, s.y*SX);
        uint32_t hi = pack_e4m3(s.z*SX, s.w*SX);
        ((uint32_t*)q_x)[i] = lo | (hi << 16);
    }
}

// ---------------- label logit + final loss ----------------
__global__ void lablogit_kernel(const int* __restrict__ inputs, const float* __restrict__ dec_w)
{
    int s = blockIdx.x, b = blockIdx.y, tid = threadIdx.x;
    int lbl = inputs[b*NSEQ + s + 1];
    const float* a = g_x + ((size_t)(b*NSEQ + s))*D_MODEL;
    const float* wp = dec_w + (size_t)lbl*D_MODEL;
    __shared__ float red[128];
    float acc = 0.f;
    for (int k = tid; k < D_MODEL; k += 128) acc += a[k]*wp[k];
    red[tid] = acc; __syncthreads();
    for (int st = 64; st > 0; st >>= 1) { if (tid < st) red[tid] += red[tid+st]; __syncthreads(); }
    if (tid == 0) g_lab[b*(NSEQ-1)+s] = red[0];
}

__global__ void final_kernel(float* __restrict__ out)
{
    __shared__ double red[256];
    int tid = threadIdx.x;
    double s = 0.0;
    for (int i = tid; i < NB*(NSEQ-1); i += 256) {
        int b = i/(NSEQ-1), sp = i%(NSEQ-1);
        s += (double)g_lab[i] - (double)g_lse[b*NSEQ+sp];
    }
    red[tid] = s; __syncthreads();
    for (int st = 128; st > 0; st >>= 1) { if (tid < st) red[tid] += red[tid+st]; __syncthreads(); }
    if (tid == 0) {
        double ce = -red[0] / (double)(NB*(NSEQ-1));
        out[0] = (float)(ce + (double)g_stats[20]);
    }
}

// ---------------- host driver ----------------
extern "C" void kernel_launch(void* const* d_in, const int* in_sizes, int n_in,
                              void* d_out, int out_size)
{
    (void)in_sizes; (void)n_in; (void)out_size;
    const int*   inputs    = (const int*)  d_in[0];
    const float* responses = (const float*)d_in[1];
    const float* noise     = (const float*)d_in[2];
    const float* emb       = (const float*)d_in[3];
    const float* loc_Wqkv  = (const float*)d_in[4];
    const float* loc_bqkv  = (const float*)d_in[5];
    const float* loc_Wo    = (const float*)d_in[6];
    const float* loc_bo    = (const float*)d_in[7];
    const float* loc_ln1g  = (const float*)d_in[8];
    const float* loc_ln1b  = (const float*)d_in[9];
    const float* loc_W1    = (const float*)d_in[10];
    const float* loc_b1    = (const float*)d_in[11];
    const float* loc_W2    = (const float*)d_in[12];
    const float* loc_b2    = (const float*)d_in[13];
    const float* loc_ln2g  = (const float*)d_in[14];
    const float* loc_ln2b  = (const float*)d_in[15];
    const float* enc_Wqkv  = (const float*)d_in[16];
    const float* enc_bqkv  = (const float*)d_in[17];
    const float* enc_Wo    = (const float*)d_in[18];
    const float* enc_bo    = (const float*)d_in[19];
    const float* enc_ln1g  = (const float*)d_in[20];
    const float* enc_ln1b  = (const float*)d_in[21];
    const float* enc_W1    = (const float*)d_in[22];
    const float* enc_b1    = (const float*)d_in[23];
    const float* enc_W2    = (const float*)d_in[24];
    const float* enc_b2    = (const float*)d_in[25];
    const float* enc_ln2g  = (const float*)d_in[26];
    const float* enc_ln2b  = (const float*)d_in[27];
    const float* gate_w    = (const float*)d_in[28];
    const float* gate_b    = (const float*)d_in[29];
    const float* dec_w     = (const float*)d_in[30];
    float* out = (float*)d_out;

    float *p_x, *p_qkv, *p_tmp;
    float *p_sm_attn, *p_sm_x, *p_sm_tmp, *p_sm_ctx, *p_sm_ffh;
    uint8_t *p_qWqkv, *p_qWo, *p_qW1, *p_qW2, *p_qdec, *p_qx, *p_qattn, *p_qffh, *p_qqkv;
    cudaGetSymbolAddress((void**)&p_x, g_x);
    cudaGetSymbolAddress((void**)&p_qkv, g_qkv);
    cudaGetSymbolAddress((void**)&p_tmp, g_tmp);
    cudaGetSymbolAddress((void**)&p_sm_attn, g_sm_attn);
    cudaGetSymbolAddress((void**)&p_sm_x, g_sm_x);
    cudaGetSymbolAddress((void**)&p_sm_tmp, g_sm_tmp);
    cudaGetSymbolAddress((void**)&p_sm_ctx, g_sm_ctx);
    cudaGetSymbolAddress((void**)&p_sm_ffh, g_sm_ffh);
    cudaGetSymbolAddress((void**)&p_qWqkv, q_Wqkv);
    cudaGetSymbolAddress((void**)&p_qWo, q_Wo);
    cudaGetSymbolAddress((void**)&p_qW1, q_W1);
    cudaGetSymbolAddress((void**)&p_qW2, q_W2);
    cudaGetSymbolAddress((void**)&p_qdec, q_dec);
    cudaGetSymbolAddress((void**)&p_qx, q_x);
    cudaGetSymbolAddress((void**)&p_qattn, q_attn);
    cudaGetSymbolAddress((void**)&p_qffh, q_ffh);
    cudaGetSymbolAddress((void**)&p_qqkv, q_qkv);

    // ---- capture-forked side stream for weight conversions ----
    cudaStream_t s2;
    cudaStreamCreateWithFlags(&s2, cudaStreamNonBlocking);
    cudaEvent_t evFork, evEnc, evDec;
    cudaEventCreateWithFlags(&evFork, cudaEventDisableTiming);
    cudaEventCreateWithFlags(&evEnc,  cudaEventDisableTiming);
    cudaEventCreateWithFlags(&evDec,  cudaEventDisableTiming);

    cudaEventRecord(evFork, 0);
    cudaStreamWaitEvent(s2, evFork, 0);

    q8_kernel<<<(2*QKV_LD*D_MODEL/8 + 255)/256, 256, 0, s2>>>(enc_Wqkv, p_qWqkv, 2*QKV_LD*D_MODEL/4, SW);
    q8_kernel<<<(2*D_MODEL*D_MODEL/8 + 255)/256, 256, 0, s2>>>(enc_Wo, p_qWo, 2*D_MODEL*D_MODEL/4, SW);
    q8_kernel<<<(2*FF_DIM*D_MODEL/8 + 255)/256, 256, 0, s2>>>(enc_W1, p_qW1, 2*FF_DIM*D_MODEL/4, SW);
    q8_kernel<<<(2*D_MODEL*FF_DIM/8 + 255)/256, 256, 0, s2>>>(enc_W2, p_qW2, 2*D_MODEL*FF_DIM/4, SW);
    cudaEventRecord(evEnc, s2);
    q8_kernel<<<(NTOK*D_MODEL/8 + 255)/256, 256, 0, s2>>>(dec_w, p_qdec, NTOK*D_MODEL/4, SW);
    cudaEventRecord(evDec, s2);

    // default stream: embed + loc layer + gating
    embed_kernel<<<NROWS, 256>>>(inputs, emb);
    gemm_tc64_kernel<<<dim3(2048/64, NROWS/64), 256>>>(
        p_x, loc_Wqkv + (size_t)D_MODEL*D_MODEL, loc_bqkv + D_MODEL,
        p_qkv + D_MODEL, D_MODEL, QKV_LD);
    rowdot_kernel<<<dim3(D_MODEL, NB), 128>>>(
        p_x + (size_t)(NSEQ-1)*D_MODEL, (long)NSEQ*D_MODEL,
        loc_Wqkv, loc_bqkv,
        p_qkv + (size_t)(NSEQ-1)*QKV_LD, (long)NSEQ*QKV_LD,
        D_MODEL, 1.f, 0);
    attn_kernel<<<dim3(1, NHEAD, NB), 256>>>(p_qkv, p_sm_attn, 1, NSEQ-1);
    rowdot_kernel<<<dim3(D_MODEL, NB), 128>>>(p_sm_attn, D_MODEL, loc_Wo, loc_bo,
                                              p_sm_tmp, D_MODEL, D_MODEL, 1.f, 0);
    ln_kernel<<<NB, 256>>>(p_x + (size_t)(NSEQ-1)*D_MODEL, (long)NSEQ*D_MODEL,
                           p_sm_tmp, D_MODEL, p_sm_x, D_MODEL, (uint8_t*)0, 0.f,
                           loc_ln1g, loc_ln1b);
    rowdot_kernel<<<dim3(FF_DIM, NB), 128>>>(p_sm_x, D_MODEL, loc_W1, loc_b1,
                                             p_sm_ffh, FF_DIM, D_MODEL, 1.f, 1);
    rowdot_kernel<<<dim3(D_MODEL, NB), 128>>>(p_sm_ffh, FF_DIM, loc_W2, loc_b2,
                                              p_sm_tmp, D_MODEL, FF_DIM, 1.f, 0);
    ln_kernel<<<NB, 256>>>(p_sm_x, D_MODEL, p_sm_tmp, D_MODEL,
                           p_sm_ctx, D_MODEL, (uint8_t*)0, 0.f,
                           loc_ln2g, loc_ln2b);

    rowdot_kernel<<<dim3(NEXP, NB), 128>>>(p_sm_ctx, D_MODEL, gate_w, gate_b,
                                           out + 1, NEXP, D_MODEL, 32.f, 0);
    stats_kernel<<<1, 256>>>(out + 1, noise);
    mix_kernel<<<(NROWS*D_MODEL/4 + 255)/256, 256>>>(responses);

    cudaStreamWaitEvent(0, evEnc, 0);

    // two encoder layers: fp8 GEMMs + fused fp8 attention
    const float invXW = 1.f/(SX*SW);
    const float invAW = 1.f/(SA*SW);
    const float invFW = 1.f/(SF*SW);
    for (int l = 0; l < 2; l++) {
        const uint8_t* Wqkv = p_qWqkv + (size_t)l*QKV_LD*D_MODEL;
        const float*   bqkv = enc_bqkv + (size_t)l*QKV_LD;
        const uint8_t* Wo   = p_qWo   + (size_t)l*D_MODEL*D_MODEL;
        const float*   bo   = enc_bo  + (size_t)l*D_MODEL;
        const float* g1   = enc_ln1g + (size_t)l*D_MODEL;
        const float* b1l  = enc_ln1b + (size_t)l*D_MODEL;
        const uint8_t* W1   = p_qW1   + (size_t)l*FF_DIM*D_MODEL;
        const float*   bb1  = enc_b1  + (size_t)l*FF_DIM;
        const uint8_t* W2   = p_qW2   + (size_t)l*D_MODEL*FF_DIM;
        const float*   bb2  = enc_b2  + (size_t)l*D_MODEL;
        const float* g2   = enc_ln2g + (size_t)l*D_MODEL;
        const float* b2l  = enc_ln2b + (size_t)l*D_MODEL;

        gemm_fp8_64_kernel<1><<<dim3(QKV_LD/64, NROWS/64), 256>>>(
            p_qx, Wqkv, bqkv, p_qqkv, D_MODEL, QKV_LD, invXW, SQK, 0);
        vtrans_kernel<<<dim3(4, NBH), 256>>>();
        fattn_kernel<<<dim3(NSEQ/64, NBH), 256>>>();
        gemm_fp8_64_kernel<0><<<dim3(D_MODEL/64, NROWS/64), 256>>>(
            p_qattn, Wo, bo, p_tmp, D_MODEL, D_MODEL, invAW, 0.f, 0);
        ln_kernel<<<NROWS, 256>>>(p_x, D_MODEL, p_tmp, D_MODEL, p_x, D_MODEL,
                                  p_qx, SX, g1, b1l);
        gemm_fp8_kernel<1><<<dim3(FF_DIM/128, NROWS/128), 256>>>(
            p_qx, W1, bb1, p_qffh, D_MODEL, FF_DIM, invXW, SF);
        gemm_fp8_64_kernel<0><<<dim3(D_MODEL/64, NROWS/64), 256>>>(
            p_qffh, W2, bb2, p_tmp, FF_DIM, D_MODEL, invFW, 0.f, 0);
        ln_kernel<<<NROWS, 256>>>(p_x, D_MODEL, p_tmp, D_MODEL, p_x, D_MODEL,
                                  p_qx, SX, g2, b2l);
    }

    cudaStreamWaitEvent(0, evDec, 0);

    gemm_fp8_kernel<2><<<dim3(NROWS/128, NBLK_V), 256>>>(
        p_qx, p_qdec, (const float*)0, (void*)0, D_MODEL, 0, invXW, 0.f);
    lse_reduce_kernel<<<NROWS, 128>>>();
    lablogit_kernel<<<dim3(NSEQ-1, NB), 128>>>(inputs, dec_w);
    final_kernel<<<1, 256>>>(out);

    cudaEventDestroy(evFork);
    cudaEventDestroy(evEnc);
    cudaEventDestroy(evDec);
    cudaStreamDestroy(s2);
}

// round 16
// speedup vs baseline: 1.5271x; 1.0209x over previous
#include <cuda_runtime.h>
#include <cuda_bf16.h>
#include <math.h>
#include <stdint.h>

// ---------------- problem constants ----------------
#define D_MODEL 1024
#define NHEAD   16
#define DHEAD   64
#define FF_DIM  4096
#define NSEQ    256
#define NB      4
#define NTOK    50257
#define NEXP    2000
#define NKTOP   20
#define NROWS   (NB*NSEQ)      // 1024
#define QKV_LD  3072
#define NBLK_V  393
#define NBH     (NB*NHEAD)     // 64

// fp8 per-tensor scales
#define SX   16.0f
#define SW   512.0f
#define SA   64.0f
#define SF   32.0f
#define SQK  64.0f
#define SP   128.0f

// ---------------- scratch ----------------
__device__ float g_x    [NROWS*D_MODEL];
__device__ float g_qkv  [NROWS*QKV_LD];
__device__ float g_tmp  [NROWS*D_MODEL];
__device__ float g_sm_attn[NB*D_MODEL];
__device__ float g_sm_x   [NB*D_MODEL];
__device__ float g_sm_tmp [NB*D_MODEL];
__device__ float g_sm_ctx [NB*D_MODEL];
__device__ float g_sm_ffh [NB*FF_DIM];
__device__ float g_psum[NROWS*NBLK_V];
__device__ float g_lse [NROWS];
__device__ float g_lab [NB*(NSEQ-1)];
__device__ float g_stats[32];

// fp8 mirrors
__device__ __align__(256) uint8_t q_Wqkv[2*QKV_LD*D_MODEL];
__device__ __align__(256) uint8_t q_Wo  [2*D_MODEL*D_MODEL];
__device__ __align__(256) uint8_t q_W1  [2*FF_DIM*D_MODEL];
__device__ __align__(256) uint8_t q_W2  [2*D_MODEL*FF_DIM];
__device__ __align__(256) uint8_t q_dec [NTOK*D_MODEL];
__device__ __align__(256) uint8_t q_x   [NROWS*D_MODEL];
__device__ __align__(256) uint8_t q_attn[NROWS*D_MODEL];
__device__ __align__(256) uint8_t q_ffh [NROWS*FF_DIM];
__device__ __align__(256) uint8_t q_qkv [NROWS*QKV_LD];
__device__ __align__(256) uint8_t q_vt  [NBH*DHEAD*NSEQ];

// ---------------- fp8 pack + fast fma-pipe exp ----------------
__device__ __forceinline__ uint16_t pack_e4m3(float lo, float hi)
{
    uint16_t r;
    asm("cvt.rn.satfinite.e4m3x2.f32 %0, %1, %2;" : "=h"(r) : "f"(hi), "f"(lo));
    return r;
}

__device__ __forceinline__ float fast_exp(float x)
{
    float t = x * 1.4426950408889634f;
    float fi = floorf(t);
    float f = t - fi;
    float p = 1.5403530e-4f;
    p = fmaf(p, f, 1.3333558e-3f);
    p = fmaf(p, f, 9.6180489e-3f);
    p = fmaf(p, f, 5.5504109e-2f);
    p = fmaf(p, f, 2.4022651e-1f);
    p = fmaf(p, f, 6.9314718e-1f);
    p = fmaf(p, f, 1.0f);
    return __int_as_float(__float_as_int(p) + (((int)fi) << 23));
}

__global__ void q8_kernel(const float* __restrict__ src, uint8_t* __restrict__ dst,
                          int n4, float scale)
{
    int i = (blockIdx.x*blockDim.x + threadIdx.x) * 2;
    #pragma unroll
    for (int t = 0; t < 2; t++) {
        int j = i + t;
        if (j < n4) {
            float4 v = ((const float4*)src)[j];
            uint32_t lo = pack_e4m3(v.x*scale, v.y*scale);
            uint32_t hi = pack_e4m3(v.z*scale, v.w*scale);
            ((uint32_t*)dst)[j] = lo | (hi << 16);
        }
    }
}

// ---------------- embedding gather ----------------
__global__ void embed_kernel(const int* __restrict__ inputs, const float* __restrict__ emb)
{
    int r = blockIdx.x;
    int tok = inputs[r];
    const float4* src = (const float4*)(emb + (size_t)tok * D_MODEL);
    float4* dst = (float4*)(g_x + (size_t)r * D_MODEL);
    dst[threadIdx.x] = src[threadIdx.x];
}

// ================= cp.async / ldmatrix helpers =================
__device__ __forceinline__ void cp_async16(void* smem, const void* gmem)
{
    uint32_t s = (uint32_t)__cvta_generic_to_shared(smem);
    asm volatile("cp.async.ca.shared.global [%0], [%1], 16;\n" :: "r"(s), "l"(gmem));
}
__device__ __forceinline__ void cp_commit()
{
    asm volatile("cp.async.commit_group;\n" ::: "memory");
}
template<int N> __device__ __forceinline__ void cp_wait()
{
    asm volatile("cp.async.wait_group %0;\n" :: "n"(N) : "memory");
}
__device__ __forceinline__ void ldsm_x4(uint32_t& r0, uint32_t& r1, uint32_t& r2, uint32_t& r3,
                                        const void* smem)
{
    uint32_t a = (uint32_t)__cvta_generic_to_shared(smem);
    asm volatile("ldmatrix.sync.aligned.m8n8.x4.shared.b16 {%0,%1,%2,%3}, [%4];\n"
                 : "=r"(r0), "=r"(r1), "=r"(r2), "=r"(r3) : "r"(a));
}
__device__ __forceinline__ void ldsm_x2(uint32_t& r0, uint32_t& r1, const void* smem)
{
    uint32_t a = (uint32_t)__cvta_generic_to_shared(smem);
    asm volatile("ldmatrix.sync.aligned.m8n8.x2.shared.b16 {%0,%1}, [%2];\n"
                 : "=r"(r0), "=r"(r1) : "r"(a));
}
__device__ __forceinline__ void mma_e4m3(float* a4, uint32_t a0, uint32_t a1, uint32_t a2, uint32_t a3,
                                         uint32_t b0, uint32_t b1)
{
    asm volatile(
        "mma.sync.aligned.m16n8k32.row.col.f32.e4m3.e4m3.f32 "
        "{%0,%1,%2,%3}, {%4,%5,%6,%7}, {%8,%9}, {%0,%1,%2,%3};\n"
        : "+f"(a4[0]), "+f"(a4[1]), "+f"(a4[2]), "+f"(a4[3])
        : "r"(a0), "r"(a1), "r"(a2), "r"(a3), "r"(b0), "r"(b1));
}
__device__ __forceinline__ void mma_tf32(float* a4, uint32_t a0, uint32_t a1, uint32_t a2, uint32_t a3,
                                         uint32_t b0, uint32_t b1)
{
    asm volatile(
        "mma.sync.aligned.m16n8k8.row.col.f32.tf32.tf32.f32 "
        "{%0,%1,%2,%3}, {%4,%5,%6,%7}, {%8,%9}, {%0,%1,%2,%3};\n"
        : "+f"(a4[0]), "+f"(a4[1]), "+f"(a4[2]), "+f"(a4[3])
        : "r"(a0), "r"(a1), "r"(a2), "r"(a3), "r"(b0), "r"(b1));
}

// ================= tf32 GEMM 64x64 (loc KV path) =================
__global__ __launch_bounds__(256) void gemm_tc64_kernel(
    const float* __restrict__ A, const float* __restrict__ W,
    const float* __restrict__ bias, float* __restrict__ C,
    int K, int ldC)
{
    __shared__ uint32_t As[2][64][20];
    __shared__ uint32_t Bs[2][64][20];
    float acc[2][2][4];
    #pragma unroll
    for (int a = 0; a < 2; a++)
        #pragma unroll
        for (int b = 0; b < 2; b++)
            #pragma unroll
            for (int c = 0; c < 4; c++) acc[a][b][c] = 0.f;

    int m0 = blockIdx.y * 64, n0 = blockIdx.x * 64;
    int tid  = threadIdx.x;
    int lane = tid & 31, wid = tid >> 5;
    int wm = wid >> 2, wn = wid & 3;
    int g = lane >> 2, tig = lane & 3;

    int r0c = tid >> 2, c0c = (tid & 3) << 2;
    const float* pa0 = A + (size_t)(m0 + r0c)*K + c0c;
    const float* pb0 = W + (size_t)(n0 + r0c)*K + c0c;

    int niter = K >> 4;
    cp_async16(&As[0][r0c][c0c], pa0);
    cp_async16(&Bs[0][r0c][c0c], pb0);
    cp_commit();

    for (int it = 0; it < niter; it++) {
        int st = it & 1;
        if (it + 1 < niter) {
            int off = (it + 1) << 4;
            int sn = st ^ 1;
            cp_async16(&As[sn][r0c][c0c], pa0 + off);
            cp_async16(&Bs[sn][r0c][c0c], pb0 + off);
            cp_commit();
            cp_wait<1>();
        } else {
            cp_wait<0>();
        }
        __syncthreads();
        #pragma unroll
        for (int ks = 0; ks < 16; ks += 8) {
            uint32_t af[2][4], bf[2][2];
            #pragma unroll
            for (int mt = 0; mt < 2; mt++) {
                int r0 = wm*32 + mt*16;
                af[mt][0] = As[st][r0+g  ][ks+tig  ];
                af[mt][1] = As[st][r0+g+8][ks+tig  ];
                af[mt][2] = As[st][r0+g  ][ks+tig+4];
                af[mt][3] = As[st][r0+g+8][ks+tig+4];
            }
            #pragma unroll
            for (int nt = 0; nt < 2; nt++) {
                int c0 = wn*16 + nt*8;
                bf[nt][0] = Bs[st][c0+g][ks+tig  ];
                bf[nt][1] = Bs[st][c0+g][ks+tig+4];
            }
            #pragma unroll
            for (int mt = 0; mt < 2; mt++)
                #pragma unroll
                for (int nt = 0; nt < 2; nt++)
                    mma_tf32(acc[mt][nt], af[mt][0], af[mt][1], af[mt][2], af[mt][3],
                             bf[nt][0], bf[nt][1]);
        }
        __syncthreads();
    }

    int rowb = m0 + wm*32, colb = n0 + wn*16;
    #pragma unroll
    for (int nt = 0; nt < 2; nt++) {
        int c = colb + nt*8 + 2*tig;
        float b0 = bias[c], b1 = bias[c+1];
        #pragma unroll
        for (int mt = 0; mt < 2; mt++) {
            int r = rowb + mt*16 + g;
            *(float2*)(C + (size_t)r*ldC + c)     = make_float2(acc[mt][nt][0]+b0, acc[mt][nt][1]+b1);
            *(float2*)(C + (size_t)(r+8)*ldC + c) = make_float2(acc[mt][nt][2]+b0, acc[mt][nt][3]+b1);
        }
    }
}

// ================= fp8 GEMM 128x128 (decoder lse) =================
template<int MODE>
__global__ __launch_bounds__(256, 2) void gemm_fp8_kernel(
    const uint8_t* __restrict__ A, const uint8_t* __restrict__ W,
    const float* __restrict__ bias, void* __restrict__ Cout,
    int K, int ldC, float inv, float outscale)
{
    __shared__ uint32_t As[2][128][20];
    __shared__ uint32_t Bs[2][128][20];

    float acc[4][4][4];
    #pragma unroll
    for (int a = 0; a < 4; a++)
        #pragma unroll
        for (int b = 0; b < 4; b++)
            #pragma unroll
            for (int c = 0; c < 4; c++) acc[a][b][c] = 0.f;

    int m0, n0, nblk = 0;
    if (MODE == 2) { m0 = blockIdx.x * 128; n0 = blockIdx.y * 128; nblk = blockIdx.y; }
    else           { m0 = blockIdx.y * 128; n0 = blockIdx.x * 128; }

    int tid  = threadIdx.x;
    int lane = tid & 31, wid = tid >> 5;
    int wm = wid >> 2, wn = wid & 3;
    int g = lane >> 2, tig = lane & 3;

    int a_row = (lane & 7) + ((lane >> 3) & 1) * 8;
    int a_wrd = (lane >> 4) * 4;
    int b_row = lane & 7;
    int b_wrd = ((lane >> 3) & 1) * 4;

    int r0c = tid >> 2, r1c = r0c + 64;
    int cw = (tid & 3) * 4;
    int ce = (tid & 3) * 16;
    int nr0 = n0 + r0c, nr1 = n0 + r1c;
    if (MODE == 2) { nr0 = (nr0 < NTOK) ? nr0 : (NTOK - 1); nr1 = (nr1 < NTOK) ? nr1 : (NTOK - 1); }
    const uint8_t* pa0 = A + (size_t)(m0 + r0c)*K + ce;
    const uint8_t* pa1 = A + (size_t)(m0 + r1c)*K + ce;
    const uint8_t* pb0 = W + (size_t)nr0*K + ce;
    const uint8_t* pb1 = W + (size_t)nr1*K + ce;

    int niter = K >> 6;
    cp_async16(&As[0][r0c][cw], pa0);
    cp_async16(&As[0][r1c][cw], pa1);
    cp_async16(&Bs[0][r0c][cw], pb0);
    cp_async16(&Bs[0][r1c][cw], pb1);
    cp_commit();

    for (int it = 0; it < niter; it++) {
        int st = it & 1;
        if (it + 1 < niter) {
            int off = (it + 1) << 6;
            int sn = st ^ 1;
            cp_async16(&As[sn][r0c][cw], pa0 + off);
            cp_async16(&As[sn][r1c][cw], pa1 + off);
            cp_async16(&Bs[sn][r0c][cw], pb0 + off);
            cp_async16(&Bs[sn][r1c][cw], pb1 + off);
            cp_commit();
            cp_wait<1>();
        } else {
            cp_wait<0>();
        }
        __syncthreads();
        #pragma unroll
        for (int ks = 0; ks < 2; ks++) {
            int kb = ks*8;
            uint32_t af[4][4], bf[4][2];
            #pragma unroll
            for (int mt = 0; mt < 4; mt++) {
                int r0 = wm*64 + mt*16;
                ldsm_x4(af[mt][0], af[mt][1], af[mt][2], af[mt][3],
                        &As[st][r0 + a_row][kb + a_wrd]);
            }
            #pragma unroll
            for (int nt = 0; nt < 4; nt++) {
                int c0 = wn*32 + nt*8;
                ldsm_x2(bf[nt][0], bf[nt][1],
                        &Bs[st][c0 + b_row][kb + b_wrd]);
            }
            #pragma unroll
            for (int mt = 0; mt < 4; mt++)
                #pragma unroll
                for (int nt = 0; nt < 4; nt++)
                    mma_e4m3(acc[mt][nt], af[mt][0], af[mt][1], af[mt][2], af[mt][3],
                             bf[nt][0], bf[nt][1]);
        }
        __syncthreads();
    }

    #pragma unroll
    for (int a = 0; a < 4; a++)
        #pragma unroll
        for (int b = 0; b < 4; b++)
            #pragma unroll
            for (int c = 0; c < 4; c++) acc[a][b][c] *= inv;

    int colb = n0 + wn*32;

    {
        __shared__ float red_s[4][128];
        #pragma unroll
        for (int mt = 0; mt < 4; mt++) {
            #pragma unroll
            for (int h = 0; h < 2; h++) {
                float s = 0.f;
                #pragma unroll
                for (int nt = 0; nt < 4; nt++) {
                    int c = colb + nt*8 + 2*tig;
                    if (c     < NTOK) s += fast_exp(acc[mt][nt][h*2+0]);
                    if (c + 1 < NTOK) s += fast_exp(acc[mt][nt][h*2+1]);
                }
                s += __shfl_xor_sync(0xffffffffu, s, 1);
                s += __shfl_xor_sync(0xffffffffu, s, 2);
                if (tig == 0) {
                    int lr = wm*64 + mt*16 + h*8 + g;
                    red_s[wn][lr] = s;
                }
            }
        }
        __syncthreads();
        if (tid < 128) {
            float s = red_s[0][tid] + red_s[1][tid] + red_s[2][tid] + red_s[3][tid];
            int row = m0 + tid;
            g_psum[(size_t)row*NBLK_V + nblk] = s;
        }
    }
}

// ================= fp8 GEMM 64x128 (QKV + FF1): warp tile 32x32 =================
__global__ __launch_bounds__(256) void gemm_fp8_64x128_kernel(
    const uint8_t* __restrict__ A, const uint8_t* __restrict__ W,
    const float* __restrict__ bias, uint8_t* __restrict__ Cout,
    int K, int ldC, float inv, float outscale, int relu)
{
    __shared__ uint32_t As[2][64][20];
    __shared__ uint32_t Bs[2][128][20];

    float acc[2][4][4];
    #pragma unroll
    for (int a = 0; a < 2; a++)
        #pragma unroll
        for (int b = 0; b < 4; b++)
            #pragma unroll
            for (int c = 0; c < 4; c++) acc[a][b][c] = 0.f;

    int m0 = blockIdx.y * 64, n0 = blockIdx.x * 128;

    int tid  = threadIdx.x;
    int lane = tid & 31, wid = tid >> 5;
    int wm = wid >> 2, wn = wid & 3;      // 2 x 4 warps; warp tile 32 x 32
    int g = lane >> 2, tig = lane & 3;

    int a_row = (lane & 7) + ((lane >> 3) & 1) * 8;
    int a_wrd = (lane >> 4) * 4;
    int b_row = lane & 7;
    int b_wrd = ((lane >> 3) & 1) * 4;

    int r0c = tid >> 2;
    int cw = (tid & 3) * 4;
    int ce = (tid & 3) * 16;
    const uint8_t* pa0 = A + (size_t)(m0 + r0c)*K + ce;
    const uint8_t* pb0 = W + (size_t)(n0 + r0c)*K + ce;
    const uint8_t* pb1 = W + (size_t)(n0 + r0c + 64)*K + ce;

    int niter = K >> 6;
    cp_async16(&As[0][r0c][cw], pa0);
    cp_async16(&Bs[0][r0c][cw], pb0);
    cp_async16(&Bs[0][r0c + 64][cw], pb1);
    cp_commit();

    for (int it = 0; it < niter; it++) {
        int st = it & 1;
        if (it + 1 < niter) {
            int off = (it + 1) << 6;
            int sn = st ^ 1;
            cp_async16(&As[sn][r0c][cw], pa0 + off);
            cp_async16(&Bs[sn][r0c][cw], pb0 + off);
            cp_async16(&Bs[sn][r0c + 64][cw], pb1 + off);
            cp_commit();
            cp_wait<1>();
        } else {
            cp_wait<0>();
        }
        __syncthreads();
        #pragma unroll
        for (int ks = 0; ks < 2; ks++) {
            int kb = ks*8;
            uint32_t af[2][4], bf[4][2];
            #pragma unroll
            for (int mt = 0; mt < 2; mt++) {
                int r0 = wm*32 + mt*16;
                ldsm_x4(af[mt][0], af[mt][1], af[mt][2], af[mt][3],
                        &As[st][r0 + a_row][kb + a_wrd]);
            }
            #pragma unroll
            for (int nt = 0; nt < 4; nt++) {
                int c0 = wn*32 + nt*8;
                ldsm_x2(bf[nt][0], bf[nt][1],
                        &Bs[st][c0 + b_row][kb + b_wrd]);
            }
            #pragma unroll
            for (int mt = 0; mt < 2; mt++)
                #pragma unroll
                for (int nt = 0; nt < 4; nt++)
                    mma_e4m3(acc[mt][nt], af[mt][0], af[mt][1], af[mt][2], af[mt][3],
                             bf[nt][0], bf[nt][1]);
        }
        __syncthreads();
    }

    #pragma unroll
    for (int a = 0; a < 2; a++)
        #pragma unroll
        for (int b = 0; b < 4; b++)
            #pragma unroll
            for (int c = 0; c < 4; c++) acc[a][b][c] *= inv;

    int rowb = m0 + wm*32, colb = n0 + wn*32;
    #pragma unroll
    for (int nt = 0; nt < 4; nt++) {
        int c = colb + nt*8 + 2*tig;
        float b0 = bias[c], b1 = bias[c+1];
        #pragma unroll
        for (int mt = 0; mt < 2; mt++) {
            int r = rowb + mt*16 + g;
            float v0 = acc[mt][nt][0]+b0, v1 = acc[mt][nt][1]+b1;
            float v2 = acc[mt][nt][2]+b0, v3 = acc[mt][nt][3]+b1;
            if (relu) {
                v0 = fmaxf(v0, 0.f); v1 = fmaxf(v1, 0.f);
                v2 = fmaxf(v2, 0.f); v3 = fmaxf(v3, 0.f);
            }
            *(uint16_t*)(Cout + (size_t)r*ldC + c)     = pack_e4m3(v0*outscale, v1*outscale);
            *(uint16_t*)(Cout + (size_t)(r+8)*ldC + c) = pack_e4m3(v2*outscale, v3*outscale);
        }
    }
}

// ================= fp8 GEMM 64x64 (Wo / FF2) =================
template<int OUT8>
__global__ __launch_bounds__(256) void gemm_fp8_64_kernel(
    const uint8_t* __restrict__ A, const uint8_t* __restrict__ W,
    const float* __restrict__ bias, void* __restrict__ Cout,
    int K, int ldC, float inv, float outscale, int relu)
{
    __shared__ uint32_t As[2][64][20];
    __shared__ uint32_t Bs[2][64][20];

    float acc[2][2][4];
    #pragma unroll
    for (int a = 0; a < 2; a++)
        #pragma unroll
        for (int b = 0; b < 2; b++)
            #pragma unroll
            for (int c = 0; c < 4; c++) acc[a][b][c] = 0.f;

    int m0 = blockIdx.y * 64, n0 = blockIdx.x * 64;

    int tid  = threadIdx.x;
    int lane = tid & 31, wid = tid >> 5;
    int wm = wid >> 2, wn = wid & 3;
    int g = lane >> 2, tig = lane & 3;

    int a_row = (lane & 7) + ((lane >> 3) & 1) * 8;
    int a_wrd = (lane >> 4) * 4;
    int b_row = lane & 7;
    int b_wrd = ((lane >> 3) & 1) * 4;

    int r0c = tid >> 2;
    int cw = (tid & 3) * 4;
    int ce = (tid & 3) * 16;
    const uint8_t* pa0 = A + (size_t)(m0 + r0c)*K + ce;
    const uint8_t* pb0 = W + (size_t)(n0 + r0c)*K + ce;

    int niter = K >> 6;
    cp_async16(&As[0][r0c][cw], pa0);
    cp_async16(&Bs[0][r0c][cw], pb0);
    cp_commit();

    for (int it = 0; it < niter; it++) {
        int st = it & 1;
        if (it + 1 < niter) {
            int off = (it + 1) << 6;
            int sn = st ^ 1;
            cp_async16(&As[sn][r0c][cw], pa0 + off);
            cp_async16(&Bs[sn][r0c][cw], pb0 + off);
            cp_commit();
            cp_wait<1>();
        } else {
            cp_wait<0>();
        }
        __syncthreads();
        #pragma unroll
        for (int ks = 0; ks < 2; ks++) {
            int kb = ks*8;
            uint32_t af[2][4], bf[2][2];
            #pragma unroll
            for (int mt = 0; mt < 2; mt++) {
                int r0 = wm*32 + mt*16;
                ldsm_x4(af[mt][0], af[mt][1], af[mt][2], af[mt][3],
                        &As[st][r0 + a_row][kb + a_wrd]);
            }
            #pragma unroll
            for (int nt = 0; nt < 2; nt++) {
                int c0 = wn*16 + nt*8;
                ldsm_x2(bf[nt][0], bf[nt][1],
                        &Bs[st][c0 + b_row][kb + b_wrd]);
            }
            #pragma unroll
            for (int mt = 0; mt < 2; mt++)
                #pragma unroll
                for (int nt = 0; nt < 2; nt++)
                    mma_e4m3(acc[mt][nt], af[mt][0], af[mt][1], af[mt][2], af[mt][3],
                             bf[nt][0], bf[nt][1]);
        }
        __syncthreads();
    }

    #pragma unroll
    for (int a = 0; a < 2; a++)
        #pragma unroll
        for (int b = 0; b < 2; b++)
            #pragma unroll
            for (int c = 0; c < 4; c++) acc[a][b][c] *= inv;

    int rowb = m0 + wm*32, colb = n0 + wn*16;
    if (OUT8 == 0) {
        float* C = (float*)Cout;
        #pragma unroll
        for (int nt = 0; nt < 2; nt++) {
            int c = colb + nt*8 + 2*tig;
            float b0 = bias[c], b1 = bias[c+1];
            #pragma unroll
            for (int mt = 0; mt < 2; mt++) {
                int r = rowb + mt*16 + g;
                *(float2*)(C + (size_t)r*ldC + c)     = make_float2(acc[mt][nt][0]+b0, acc[mt][nt][1]+b1);
                *(float2*)(C + (size_t)(r+8)*ldC + c) = make_float2(acc[mt][nt][2]+b0, acc[mt][nt][3]+b1);
            }
        }
    } else {
        uint8_t* C = (uint8_t*)Cout;
        #pragma unroll
        for (int nt = 0; nt < 2; nt++) {
            int c = colb + nt*8 + 2*tig;
            float b0 = bias ? bias[c] : 0.f;
            float b1 = bias ? bias[c+1] : 0.f;
            #pragma unroll
            for (int mt = 0; mt < 2; mt++) {
                int r = rowb + mt*16 + g;
                float v0 = acc[mt][nt][0]+b0, v1 = acc[mt][nt][1]+b1;
                float v2 = acc[mt][nt][2]+b0, v3 = acc[mt][nt][3]+b1;
                if (relu) {
                    v0 = fmaxf(v0, 0.f); v1 = fmaxf(v1, 0.f);
                    v2 = fmaxf(v2, 0.f); v3 = fmaxf(v3, 0.f);
                }
                *(uint16_t*)(C + (size_t)r*ldC + c)     = pack_e4m3(v0*outscale, v1*outscale);
                *(uint16_t*)(C + (size_t)(r+8)*ldC + c) = pack_e4m3(v2*outscale, v3*outscale);
            }
        }
    }
}

// ================= V transpose (fp8): [s,d] -> VT[bh][d][s] ==================
__global__ void vtrans_kernel()
{
    __shared__ uint8_t t[64][65];
    int bh = blockIdx.y, b = bh >> 4, h = bh & 15;
    int s0 = blockIdx.x * 64;
    int tid = threadIdx.x;
    const uint8_t* src = q_qkv + (size_t)(b*NSEQ)*QKV_LD + 2*D_MODEL + h*DHEAD;
    for (int i = tid; i < 4096; i += 256) {
        int s = i >> 6, d = i & 63;
        t[d][s] = src[(size_t)(s0+s)*QKV_LD + d];
    }
    __syncthreads();
    uint8_t* dst = q_vt + (size_t)bh*DHEAD*NSEQ;
    for (int i = tid; i < 4096; i += 256) {
        int d = i >> 6, s = i & 63;
        dst[(size_t)d*NSEQ + s0 + s] = t[d][s];
    }
}

// ========== fused attention: scores + softmax + P·V^T per 64-query tile ======
__global__ __launch_bounds__(256) void fattn_kernel()
{
    __shared__ uint32_t sm[11264];                // 45 KB
    uint32_t* Qs = sm;                            // [64][20]
    uint32_t* Ks = sm + 1280;                     // [256][20]
    uint32_t* VT = sm + 6400;                     // [64][68]
    float*    red = (float*)(sm + 10752);         // [64][8]
    uint32_t* Ps = sm;                            // [64][68] (reuses Q/K region)

    int bh = blockIdx.y, b = bh >> 4, h = bh & 15;
    int m0 = blockIdx.x * 64;
    int tid = threadIdx.x, lane = tid & 31, wid = tid >> 5;
    int wm = wid >> 2, wn = wid & 3;              // warps 2 x 4
    int g = lane >> 2, tig = lane & 3;
    int a_row = (lane & 7) + ((lane >> 3) & 1) * 8;
    int a_wrd = (lane >> 4) * 4;
    int b_row = lane & 7;
    int b_wrd = ((lane >> 3) & 1) * 4;

    const uint8_t* Qb  = q_qkv + (size_t)(b*NSEQ)*QKV_LD + h*DHEAD;
    const uint8_t* Kb  = Qb + D_MODEL;
    const uint8_t* VTb = q_vt + (size_t)bh*DHEAD*NSEQ;

    {
        int r = tid >> 2, cw = (tid & 3) * 4, ce = (tid & 3) * 16;
        cp_async16(&Qs[r*20 + cw], Qb + (size_t)(m0 + r)*QKV_LD + ce);
        #pragma unroll
        for (int i = 0; i < 4; i++) {
            int rr = r + i*64;
            cp_async16(&Ks[rr*20 + cw], Kb + (size_t)rr*QKV_LD + ce);
        }
        #pragma unroll
        for (int i = 0; i < 4; i++) {
            int idx = tid + i*256;
            int vr = idx >> 4, vcw = (idx & 15) * 4;
            cp_async16(&VT[vr*68 + vcw], VTb + (size_t)vr*NSEQ + (idx & 15)*16);
        }
        cp_commit(); cp_wait<0>();
    }
    __syncthreads();

    float acc[2][8][4];
    #pragma unroll
    for (int a = 0; a < 2; a++)
        #pragma unroll
        for (int n = 0; n < 8; n++)
            #pragma unroll
            for (int c = 0; c < 4; c++) acc[a][n][c] = 0.f;

    #pragma unroll
    for (int ks = 0; ks < 2; ks++) {
        int kb = ks*8;
        uint32_t af[2][4], bf[8][2];
        #pragma unroll
        for (int mt = 0; mt < 2; mt++) {
            int r0 = wm*32 + mt*16;
            ldsm_x4(af[mt][0], af[mt][1], af[mt][2], af[mt][3],
                    &Qs[(r0 + a_row)*20 + kb + a_wrd]);
        }
        #pragma unroll
        for (int nt = 0; nt < 8; nt++) {
            int c0 = wn*64 + nt*8;
            ldsm_x2(bf[nt][0], bf[nt][1],
                    &Ks[(c0 + b_row)*20 + kb + b_wrd]);
        }
        #pragma unroll
        for (int mt = 0; mt < 2; mt++)
            #pragma unroll
            for (int nt = 0; nt < 8; nt++)
                mma_e4m3(acc[mt][nt], af[mt][0], af[mt][1], af[mt][2], af[mt][3],
                         bf[nt][0], bf[nt][1]);
    }

    const float sc = 0.125f / (SQK*SQK);
    #pragma unroll
    for (int a = 0; a < 2; a++)
        #pragma unroll
        for (int n = 0; n < 8; n++)
            #pragma unroll
            for (int c = 0; c < 4; c++) acc[a][n][c] *= sc;

    #pragma unroll
    for (int mt = 0; mt < 2; mt++) {
        #pragma unroll
        for (int hh = 0; hh < 2; hh++) {
            float m = -INFINITY;
            #pragma unroll
            for (int nt = 0; nt < 8; nt++)
                m = fmaxf(m, fmaxf(acc[mt][nt][hh*2+0], acc[mt][nt][hh*2+1]));
            m = fmaxf(m, __shfl_xor_sync(0xffffffffu, m, 1));
            m = fmaxf(m, __shfl_xor_sync(0xffffffffu, m, 2));
            if (tig == 0) {
                int row = wm*32 + mt*16 + hh*8 + g;
                red[row*8 + wn] = m;
            }
        }
    }
    __syncthreads();
    float rmax[2][2];
    #pragma unroll
    for (int mt = 0; mt < 2; mt++)
        #pragma unroll
        for (int hh = 0; hh < 2; hh++) {
            int row = wm*32 + mt*16 + hh*8 + g;
            rmax[mt][hh] = fmaxf(fmaxf(red[row*8+0], red[row*8+1]),
                                 fmaxf(red[row*8+2], red[row*8+3]));
        }
    #pragma unroll
    for (int mt = 0; mt < 2; mt++) {
        #pragma unroll
        for (int hh = 0; hh < 2; hh++) {
            float s = 0.f;
            #pragma unroll
            for (int nt = 0; nt < 8; nt++) {
                float e0 = fast_exp(acc[mt][nt][hh*2+0] - rmax[mt][hh]);
                float e1 = fast_exp(acc[mt][nt][hh*2+1] - rmax[mt][hh]);
                acc[mt][nt][hh*2+0] = e0;
                acc[mt][nt][hh*2+1] = e1;
                s += e0 + e1;
            }
            s += __shfl_xor_sync(0xffffffffu, s, 1);
            s += __shfl_xor_sync(0xffffffffu, s, 2);
            if (tig == 0) {
                int row = wm*32 + mt*16 + hh*8 + g;
                red[row*8 + 4 + wn] = s;
            }
        }
    }
    __syncthreads();
    float rs[2][2];
    #pragma unroll
    for (int mt = 0; mt < 2; mt++)
        #pragma unroll
        for (int hh = 0; hh < 2; hh++) {
            int row = wm*32 + mt*16 + hh*8 + g;
            rs[mt][hh] = SP / (red[row*8+4] + red[row*8+5] + red[row*8+6] + red[row*8+7]);
        }
    #pragma unroll
    for (int mt = 0; mt < 2; mt++) {
        #pragma unroll
        for (int nt = 0; nt < 8; nt++) {
            int col = wn*64 + nt*8 + 2*tig;
            #pragma unroll
            for (int hh = 0; hh < 2; hh++) {
                int row = wm*32 + mt*16 + hh*8 + g;
                *(uint16_t*)((uint8_t*)&Ps[row*68] + col) =
                    pack_e4m3(acc[mt][nt][hh*2+0]*rs[mt][hh], acc[mt][nt][hh*2+1]*rs[mt][hh]);
            }
        }
    }
    __syncthreads();

    float accO[2][2][4];
    #pragma unroll
    for (int a = 0; a < 2; a++)
        #pragma unroll
        for (int n = 0; n < 2; n++)
            #pragma unroll
            for (int c = 0; c < 4; c++) accO[a][n][c] = 0.f;

    #pragma unroll
    for (int ks = 0; ks < 8; ks++) {
        int kb = ks*8;
        uint32_t af[2][4], bf[2][2];
        #pragma unroll
        for (int mt = 0; mt < 2; mt++) {
            int r0 = wm*32 + mt*16;
            ldsm_x4(af[mt][0], af[mt][1], af[mt][2], af[mt][3],
                    &Ps[(r0 + a_row)*68 + kb + a_wrd]);
        }
        #pragma unroll
        for (int nt = 0; nt < 2; nt++) {
            int c0 = wn*16 + nt*8;
            ldsm_x2(bf[nt][0], bf[nt][1],
                    &VT[(c0 + b_row)*68 + kb + b_wrd]);
        }
        #pragma unroll
        for (int mt = 0; mt < 2; mt++)
            #pragma unroll
            for (int nt = 0; nt < 2; nt++)
                mma_e4m3(accO[mt][nt], af[mt][0], af[mt][1], af[mt][2], af[mt][3],
                         bf[nt][0], bf[nt][1]);
    }

    const float inv = SA / (SP * SQK);
    #pragma unroll
    for (int nt = 0; nt < 2; nt++) {
        int c = wn*16 + nt*8 + 2*tig;
        #pragma unroll
        for (int mt = 0; mt < 2; mt++) {
            int r = m0 + wm*32 + mt*16 + g;
            uint8_t* d0 = q_attn + (size_t)(b*NSEQ + r)*D_MODEL + h*DHEAD + c;
            uint8_t* d1 = q_attn + (size_t)(b*NSEQ + r + 8)*D_MODEL + h*DHEAD + c;
            *(uint16_t*)d0 = pack_e4m3(accO[mt][nt][0]*inv, accO[mt][nt][1]*inv);
            *(uint16_t*)d1 = pack_e4m3(accO[mt][nt][2]*inv, accO[mt][nt][3]*inv);
        }
    }
}

__global__ void lse_reduce_kernel()
{
    int r = blockIdx.x, tid = threadIdx.x;
    double sum = 0.0;
    for (int i = tid; i < NBLK_V; i += 128)
        sum += (double)g_psum[(size_t)r*NBLK_V + i];
    __shared__ double redd[128];
    redd[tid] = sum; __syncthreads();
    for (int s = 64; s > 0; s >>= 1) { if (tid < s) redd[tid] += redd[tid+s]; __syncthreads(); }
    if (tid == 0) g_lse[r] = (float)log(redd[0]);
}

// ---------------- small-M GEMM (one (n,m) pair per block) ----------------
__global__ void rowdot_kernel(
    const float* __restrict__ A, long strideA,
    const float* __restrict__ W, const float* __restrict__ bias,
    float* __restrict__ C, long strideC,
    int K, float alpha, int relu)
{
    int n = blockIdx.x, m = blockIdx.y;
    int tid = threadIdx.x;   // 128
    const float* w = W + (size_t)n * K;
    const float* a = A + (size_t)m * strideA;
    __shared__ float red[128];
    float s = 0.f;
    for (int k = tid; k < K; k += 128) s += a[k]*w[k];
    red[tid] = s; __syncthreads();
    for (int st = 64; st > 0; st >>= 1) { if (tid < st) red[tid] += red[tid+st]; __syncthreads(); }
    if (tid == 0) {
        float v = alpha*red[0] + (bias ? bias[n] : 0.f);
        if (relu) v = fmaxf(v, 0.f);
        C[(size_t)m*strideC + n] = v;
    }
}

// ---------------- loc attention (single query per (h,b)), fp32 out ----------------
__global__ __launch_bounds__(256) void attn_kernel(
    const float* __restrict__ qkv, float* __restrict__ out, int nq, int sq_base)
{
    int qi = blockIdx.x, h = blockIdx.y, b = blockIdx.z;
    int sq = sq_base + qi;
    int tid = threadIdx.x;
    __shared__ float4 qrow[DHEAD/4];
    __shared__ float sc[NSEQ];
    __shared__ float red[256];
    __shared__ float sden;
    __shared__ float osum[4][DHEAD];
    const float* base = qkv + (size_t)b * NSEQ * QKV_LD;
    if (tid < DHEAD/4)
        qrow[tid] = ((const float4*)(base + (size_t)sq*QKV_LD + h*DHEAD))[tid];
    __syncthreads();
    {
        const float4* krow = (const float4*)(base + (size_t)tid*QKV_LD + D_MODEL + h*DHEAD);
        float d = 0.f;
        #pragma unroll
        for (int t = 0; t < DHEAD/4; t++) {
            float4 k4 = krow[t];
            float4 q4 = qrow[t];
            d += q4.x*k4.x + q4.y*k4.y + q4.z*k4.z + q4.w*k4.w;
        }
        sc[tid] = d * 0.125f;
    }
    __syncthreads();
    red[tid] = sc[tid]; __syncthreads();
    for (int s = 128; s > 0; s >>= 1) { if (tid < s) red[tid] = fmaxf(red[tid], red[tid+s]); __syncthreads(); }
    float mx = red[0]; __syncthreads();
    float e = expf(sc[tid] - mx);
    red[tid] = e; __syncthreads();
    for (int s = 128; s > 0; s >>= 1) { if (tid < s) red[tid] += red[tid+s]; __syncthreads(); }
    if (tid == 0) sden = red[0];
    __syncthreads();
    sc[tid] = e;
    __syncthreads();
    int d = tid & 63, g = tid >> 6;
    const float* vb = base + 2*D_MODEL + h*DHEAD + d;
    float o = 0.f;
    for (int j = g*64; j < (g+1)*64; j++) o += sc[j] * vb[(size_t)j*QKV_LD];
    osum[g][d] = o; __syncthreads();
    if (tid < DHEAD) {
        float r = (osum[0][tid]+osum[1][tid]+osum[2][tid]+osum[3][tid]) / sden;
        out[((size_t)(b*nq + qi))*D_MODEL + h*DHEAD + tid] = r;
    }
}

// ---------------- residual + layernorm (fp32 out + optional fp8 mirror) ----------
__global__ void ln_kernel(
    const float* __restrict__ in1, long s1,
    const float* __restrict__ in2, long s2,
    float* __restrict__ out, long so,
    uint8_t* __restrict__ outq, float qs,
    const float* __restrict__ gam, const float* __restrict__ bet)
{
    int r = blockIdx.x, tid = threadIdx.x;
    __shared__ float xr[D_MODEL];
    __shared__ float red[256];
    const float* p1 = in1 + (size_t)r*s1;
    const float* p2 = in2 + (size_t)r*s2;
    float ls = 0.f;
    for (int d = tid; d < D_MODEL; d += 256) { float v = p1[d]+p2[d]; xr[d] = v; ls += v; }
    red[tid] = ls; __syncthreads();
    for (int s = 128; s > 0; s >>= 1) { if (tid < s) red[tid] += red[tid+s]; __syncthreads(); }
    float mean = red[0] * (1.f/D_MODEL); __syncthreads();
    float lv = 0.f;
    for (int d = tid; d < D_MODEL; d += 256) { float t = xr[d]-mean; lv += t*t; }
    red[tid] = lv; __syncthreads();
    for (int s = 128; s > 0; s >>= 1) { if (tid < s) red[tid] += red[tid+s]; __syncthreads(); }
    float rstd = 1.f / sqrtf(red[0]*(1.f/D_MODEL) + 1e-5f);
    for (int d = tid*2; d < D_MODEL; d += 512) {
        float v0 = (xr[d]  -mean)*rstd*gam[d]   + bet[d];
        float v1 = (xr[d+1]-mean)*rstd*gam[d+1] + bet[d+1];
        *(float2*)(out + (size_t)r*so + d) = make_float2(v0, v1);
        if (outq) *(uint16_t*)(outq + (size_t)r*D_MODEL + d) = pack_e4m3(v0*qs, v1*qs);
    }
}

// ---------------- gating statistics + top-k + softmax + importance ----------------
__global__ void stats_kernel(const float* __restrict__ w, const float* __restrict__ noise)
{
    __shared__ float tot[NEXP];
    __shared__ double redd[256];
    __shared__ float wv[8];
    __shared__ int   wi[8];
    __shared__ float topv[NKTOP];
    __shared__ double smean, sstd;
    int tid = threadIdx.x;
    double ls = 0.0;
    for (int n = tid; n < NEXP; n += 256) {
        float f = 0.25f*(w[n] + w[NEXP+n] + w[2*NEXP+n] + w[3*NEXP+n]);
        tot[n] = f; ls += (double)f;
    }
    redd[tid] = ls; __syncthreads();
    for (int s = 128; s > 0; s >>= 1) { if (tid < s) redd[tid] += redd[tid+s]; __syncthreads(); }
    if (tid == 0) smean = redd[0] / NEXP;
    __syncthreads();
    double mfm = smean;
    ls = 0.0;
    for (int n = tid; n < NEXP; n += 256) { double t = (double)tot[n]-mfm; ls += t*t; }
    redd[tid] = ls; __syncthreads();
    for (int s = 128; s > 0; s >>= 1) { if (tid < s) redd[tid] += redd[tid+s]; __syncthreads(); }
    if (tid == 0) sstd = sqrt(redd[0] / (NEXP-1));
    __syncthreads();
    float stdfm = (float)sstd;
    for (int n = tid; n < NEXP; n += 256) tot[n] = tot[n] + noise[n]*stdfm;
    __syncthreads();
    ls = 0.0;
    for (int n = tid; n < NEXP; n += 256) ls += (double)tot[n];
    redd[tid] = ls; __syncthreads();
    for (int s = 128; s > 0; s >>= 1) { if (tid < s) redd[tid] += redd[tid+s]; __syncthreads(); }
    if (tid == 0) smean = redd[0] / NEXP;
    __syncthreads();
    double mt = smean;
    ls = 0.0;
    for (int n = tid; n < NEXP; n += 256) { double t = (double)tot[n]-mt; ls += t*t; }
    redd[tid] = ls; __syncthreads();
    for (int s = 128; s > 0; s >>= 1) { if (tid < s) redd[tid] += redd[tid+s]; __syncthreads(); }
    if (tid == 0) {
        double st = sqrt(redd[0] / (NEXP-1));
        double ratio = st / mt;
        g_stats[20] = (float)(0.1 * ratio * ratio);
    }
    __syncthreads();
    // top-k: warp-shuffle argmax, 2 barriers per iteration
    for (int it = 0; it < NKTOP; it++) {
        float bv = -INFINITY; int bi = 0x7fffffff;
        for (int n = tid; n < NEXP; n += 256) {
            float v = tot[n];
            if (v > bv || (v == bv && n < bi)) { bv = v; bi = n; }
        }
        #pragma unroll
        for (int o = 16; o; o >>= 1) {
            float ov = __shfl_down_sync(0xffffffffu, bv, o);
            int   oi = __shfl_down_sync(0xffffffffu, bi, o);
            if (ov > bv || (ov == bv && oi < bi)) { bv = ov; bi = oi; }
        }
        if ((tid & 31) == 0) { wv[tid >> 5] = bv; wi[tid >> 5] = bi; }
        __syncthreads();
        if (tid == 0) {
            float fbv = wv[0]; int fbi = wi[0];
            #pragma unroll
            for (int ww = 1; ww < 8; ww++)
                if (wv[ww] > fbv || (wv[ww] == fbv && wi[ww] < fbi)) { fbv = wv[ww]; fbi = wi[ww]; }
            topv[it] = fbv; tot[fbi] = -INFINITY;
        }
        __syncthreads();
    }
    if (tid == 0) {
        float m = topv[0];
        float s = 0.f;
        float e[NKTOP];
        for (int k = 0; k < NKTOP; k++) { e[k] = expf(topv[k]-m); s += e[k]; }
        for (int k = 0; k < NKTOP; k++) g_stats[k] = e[k]/s;
    }
}

// ---------------- response mixture (fp32 + fp8 mirror) ----------------
__global__ void mix_kernel(const float* __restrict__ responses)
{
    __shared__ float w[NKTOP];
    if (threadIdx.x < NKTOP) w[threadIdx.x] = g_stats[threadIdx.x];
    __syncthreads();
    int i = blockIdx.x*blockDim.x + threadIdx.x;
    if (i < (NROWS*D_MODEL)/4) {
        float4 s = make_float4(0.f, 0.f, 0.f, 0.f);
        #pragma unroll
        for (int k = 0; k < NKTOP; k++) {
            float4 v = ((const float4*)responses)[(size_t)k*((NROWS*D_MODEL)/4) + i];
            float wk = w[k];
            s.x += wk*v.x; s.y += wk*v.y; s.z += wk*v.z; s.w += wk*v.w;
        }
        ((float4*)g_x)[i] = s;
        uint32_t lo = pack_e4m3(s.x*SX, s.y*SX);
        uint32_t hi = pack_e4m3(s.z*SX, s.w*SX);
        ((uint32_t*)q_x)[i] = lo | (hi << 16);
    }
}

// ---------------- label logit + final loss ----------------
__global__ void lablogit_kernel(const int* __restrict__ inputs, const float* __restrict__ dec_w)
{
    int s = blockIdx.x, b = blockIdx.y, tid = threadIdx.x;
    int lbl = inputs[b*NSEQ + s + 1];
    const float* a = g_x + ((size_t)(b*NSEQ + s))*D_MODEL;
    const float* wp = dec_w + (size_t)lbl*D_MODEL;
    __shared__ float red[128];
    float acc = 0.f;
    for (int k = tid; k < D_MODEL; k += 128) acc += a[k]*wp[k];
    red[tid] = acc; __syncthreads();
    for (int st = 64; st > 0; st >>= 1) { if (tid < st) red[tid] += red[tid+st]; __syncthreads(); }
    if (tid == 0) g_lab[b*(NSEQ-1)+s] = red[0];
}

__global__ void final_kernel(float* __restrict__ out)
{
    __shared__ double red[256];
    int tid = threadIdx.x;
    double s = 0.0;
    for (int i = tid; i < NB*(NSEQ-1); i += 256) {
        int b = i/(NSEQ-1), sp = i%(NSEQ-1);
        s += (double)g_lab[i] - (double)g_lse[b*NSEQ+sp];
    }
    red[tid] = s; __syncthreads();
    for (int st = 128; st > 0; st >>= 1) { if (tid < st) red[tid] += red[tid+st]; __syncthreads(); }
    if (tid == 0) {
        double ce = -red[0] / (double)(NB*(NSEQ-1));
        out[0] = (float)(ce + (double)g_stats[20]);
    }
}

// ---------------- host driver ----------------
extern "C" void kernel_launch(void* const* d_in, const int* in_sizes, int n_in,
                              void* d_out, int out_size)
{
    (void)in_sizes; (void)n_in; (void)out_size;
    const int*   inputs    = (const int*)  d_in[0];
    const float* responses = (const float*)d_in[1];
    const float* noise     = (const float*)d_in[2];
    const float* emb       = (const float*)d_in[3];
    const float* loc_Wqkv  = (const float*)d_in[4];
    const float* loc_bqkv  = (const float*)d_in[5];
    const float* loc_Wo    = (const float*)d_in[6];
    const float* loc_bo    = (const float*)d_in[7];
    const float* loc_ln1g  = (const float*)d_in[8];
    const float* loc_ln1b  = (const float*)d_in[9];
    const float* loc_W1    = (const float*)d_in[10];
    const float* loc_b1    = (const float*)d_in[11];
    const float* loc_W2    = (const float*)d_in[12];
    const float* loc_b2    = (const float*)d_in[13];
    const float* loc_ln2g  = (const float*)d_in[14];
    const float* loc_ln2b  = (const float*)d_in[15];
    const float* enc_Wqkv  = (const float*)d_in[16];
    const float* enc_bqkv  = (const float*)d_in[17];
    const float* enc_Wo    = (const float*)d_in[18];
    const float* enc_bo    = (const float*)d_in[19];
    const float* enc_ln1g  = (const float*)d_in[20];
    const float* enc_ln1b  = (const float*)d_in[21];
    const float* enc_W1    = (const float*)d_in[22];
    const float* enc_b1    = (const float*)d_in[23];
    const float* enc_W2    = (const float*)d_in[24];
    const float* enc_b2    = (const float*)d_in[25];
    const float* enc_ln2g  = (const float*)d_in[26];
    const float* enc_ln2b  = (const float*)d_in[27];
    const float* gate_w    = (const float*)d_in[28];
    const float* gate_b    = (const float*)d_in[29];
    const float* dec_w     = (const float*)d_in[30];
    float* out = (float*)d_out;

    float *p_x, *p_qkv, *p_tmp;
    float *p_sm_attn, *p_sm_x, *p_sm_tmp, *p_sm_ctx, *p_sm_ffh;
    uint8_t *p_qWqkv, *p_qWo, *p_qW1, *p_qW2, *p_qdec, *p_qx, *p_qattn, *p_qffh, *p_qqkv;
    cudaGetSymbolAddress((void**)&p_x, g_x);
    cudaGetSymbolAddress((void**)&p_qkv, g_qkv);
    cudaGetSymbolAddress((void**)&p_tmp, g_tmp);
    cudaGetSymbolAddress((void**)&p_sm_attn, g_sm_attn);
    cudaGetSymbolAddress((void**)&p_sm_x, g_sm_x);
    cudaGetSymbolAddress((void**)&p_sm_tmp, g_sm_tmp);
    cudaGetSymbolAddress((void**)&p_sm_ctx, g_sm_ctx);
    cudaGetSymbolAddress((void**)&p_sm_ffh, g_sm_ffh);
    cudaGetSymbolAddress((void**)&p_qWqkv, q_Wqkv);
    cudaGetSymbolAddress((void**)&p_qWo, q_Wo);
    cudaGetSymbolAddress((void**)&p_qW1, q_W1);
    cudaGetSymbolAddress((void**)&p_qW2, q_W2);
    cudaGetSymbolAddress((void**)&p_qdec, q_dec);
    cudaGetSymbolAddress((void**)&p_qx, q_x);
    cudaGetSymbolAddress((void**)&p_qattn, q_attn);
    cudaGetSymbolAddress((void**)&p_qffh, q_ffh);
    cudaGetSymbolAddress((void**)&p_qqkv, q_qkv);

    // ---- capture-forked side stream for weight conversions ----
    cudaStream_t s2;
    cudaStreamCreateWithFlags(&s2, cudaStreamNonBlocking);
    cudaEvent_t evFork, evEnc, evDec;
    cudaEventCreateWithFlags(&evFork, cudaEventDisableTiming);
    cudaEventCreateWithFlags(&evEnc,  cudaEventDisableTiming);
    cudaEventCreateWithFlags(&evDec,  cudaEventDisableTiming);

    cudaEventRecord(evFork, 0);
    cudaStreamWaitEvent(s2, evFork, 0);

    q8_kernel<<<(2*QKV_LD*D_MODEL/8 + 255)/256, 256, 0, s2>>>(enc_Wqkv, p_qWqkv, 2*QKV_LD*D_MODEL/4, SW);
    q8_kernel<<<(2*D_MODEL*D_MODEL/8 + 255)/256, 256, 0, s2>>>(enc_Wo, p_qWo, 2*D_MODEL*D_MODEL/4, SW);
    q8_kernel<<<(2*FF_DIM*D_MODEL/8 + 255)/256, 256, 0, s2>>>(enc_W1, p_qW1, 2*FF_DIM*D_MODEL/4, SW);
    q8_kernel<<<(2*D_MODEL*FF_DIM/8 + 255)/256, 256, 0, s2>>>(enc_W2, p_qW2, 2*D_MODEL*FF_DIM/4, SW);
    cudaEventRecord(evEnc, s2);
    q8_kernel<<<(NTOK*D_MODEL/8 + 255)/256, 256, 0, s2>>>(dec_w, p_qdec, NTOK*D_MODEL/4, SW);
    cudaEventRecord(evDec, s2);

    // default stream: embed + loc layer + gating
    embed_kernel<<<NROWS, 256>>>(inputs, emb);
    gemm_tc64_kernel<<<dim3(2048/64, NROWS/64), 256>>>(
        p_x, loc_Wqkv + (size_t)D_MODEL*D_MODEL, loc_bqkv + D_MODEL,
        p_qkv + D_MODEL, D_MODEL, QKV_LD);
    rowdot_kernel<<<dim3(D_MODEL, NB), 128>>>(
        p_x + (size_t)(NSEQ-1)*D_MODEL, (long)NSEQ*D_MODEL,
        loc_Wqkv, loc_bqkv,
        p_qkv + (size_t)(NSEQ-1)*QKV_LD, (long)NSEQ*QKV_LD,
        D_MODEL, 1.f, 0);
    attn_kernel<<<dim3(1, NHEAD, NB), 256>>>(p_qkv, p_sm_attn, 1, NSEQ-1);
    rowdot_kernel<<<dim3(D_MODEL, NB), 128>>>(p_sm_attn, D_MODEL, loc_Wo, loc_bo,
                                              p_sm_tmp, D_MODEL, D_MODEL, 1.f, 0);
    ln_kernel<<<NB, 256>>>(p_x + (size_t)(NSEQ-1)*D_MODEL, (long)NSEQ*D_MODEL,
                           p_sm_tmp, D_MODEL, p_sm_x, D_MODEL, (uint8_t*)0, 0.f,
                           loc_ln1g, loc_ln1b);
    rowdot_kernel<<<dim3(FF_DIM, NB), 128>>>(p_sm_x, D_MODEL, loc_W1, loc_b1,
                                             p_sm_ffh, FF_DIM, D_MODEL, 1.f, 1);
    rowdot_kernel<<<dim3(D_MODEL, NB), 128>>>(p_sm_ffh, FF_DIM, loc_W2, loc_b2,
                                              p_sm_tmp, D_MODEL, FF_DIM, 1.f, 0);
    ln_kernel<<<NB, 256>>>(p_sm_x, D_MODEL, p_sm_tmp, D_MODEL,
                           p_sm_ctx, D_MODEL, (uint8_t*)0, 0.f,
                           loc_ln2g, loc_ln2b);

    rowdot_kernel<<<dim3(NEXP, NB), 128>>>(p_sm_ctx, D_MODEL, gate_w, gate_b,
                                           out + 1, NEXP, D_MODEL, 32.f, 0);
    stats_kernel<<<1, 256>>>(out + 1, noise);
    mix_kernel<<<(NROWS*D_MODEL/4 + 255)/256, 256>>>(responses);

    cudaStreamWaitEvent(0, evEnc, 0);

    // two encoder layers: fp8 GEMMs + fused fp8 attention
    const float invXW = 1.f/(SX*SW);
    const float invAW = 1.f/(SA*SW);
    const float invFW = 1.f/(SF*SW);
    for (int l = 0; l < 2; l++) {
        const uint8_t* Wqkv = p_qWqkv + (size_t)l*QKV_LD*D_MODEL;
        const float*   bqkv = enc_bqkv + (size_t)l*QKV_LD;
        const uint8_t* Wo   = p_qWo   + (size_t)l*D_MODEL*D_MODEL;
        const float*   bo   = enc_bo  + (size_t)l*D_MODEL;
        const float* g1   = enc_ln1g + (size_t)l*D_MODEL;
        const float* b1l  = enc_ln1b + (size_t)l*D_MODEL;
        const uint8_t* W1   = p_qW1   + (size_t)l*FF_DIM*D_MODEL;
        const float*   bb1  = enc_b1  + (size_t)l*FF_DIM;
        const uint8_t* W2   = p_qW2   + (size_t)l*D_MODEL*FF_DIM;
        const float*   bb2  = enc_b2  + (size_t)l*D_MODEL;
        const float* g2   = enc_ln2g + (size_t)l*D_MODEL;
        const float* b2l  = enc_ln2b + (size_t)l*D_MODEL;

        gemm_fp8_64x128_kernel<<<dim3(QKV_LD/128, NROWS/64), 256>>>(
            p_qx, Wqkv, bqkv, p_qqkv, D_MODEL, QKV_LD, invXW, SQK, 0);
        vtrans_kernel<<<dim3(4, NBH), 256>>>();
        fattn_kernel<<<dim3(NSEQ/64, NBH), 256>>>();
        gemm_fp8_64_kernel<0><<<dim3(D_MODEL/64, NROWS/64), 256>>>(
            p_qattn, Wo, bo, p_tmp, D_MODEL, D_MODEL, invAW, 0.f, 0);
        ln_kernel<<<NROWS, 256>>>(p_x, D_MODEL, p_tmp, D_MODEL, p_x, D_MODEL,
                                  p_qx, SX, g1, b1l);
        gemm_fp8_64x128_kernel<<<dim3(FF_DIM/128, NROWS/64), 256>>>(
            p_qx, W1, bb1, p_qffh, D_MODEL, FF_DIM, invXW, SF, 1);
        gemm_fp8_64_kernel<0><<<dim3(D_MODEL/64, NROWS/64), 256>>>(
            p_qffh, W2, bb2, p_tmp, FF_DIM, D_MODEL, invFW, 0.f, 0);
        ln_kernel<<<NROWS, 256>>>(p_x, D_MODEL, p_tmp, D_MODEL, p_x, D_MODEL,
                                  p_qx, SX, g2, b2l);
    }

    cudaStreamWaitEvent(0, evDec, 0);

    gemm_fp8_kernel<2><<<dim3(NROWS/128, NBLK_V), 256>>>(
        p_qx, p_qdec, (const float*)0, (void*)0, D_MODEL, 0, invXW, 0.f);
    lse_reduce_kernel<<<NROWS, 128>>>();
    lablogit_kernel<<<dim3(NSEQ-1, NB), 128>>>(inputs, dec_w);
    final_kernel<<<1, 256>>>(out);

    cudaEventDestroy(evFork);
    cudaEventDestroy(evEnc);
    cudaEventDestroy(evDec);
    cudaStreamDestroy(s2);
}